// round 1
// baseline (speedup 1.0000x reference)
#include <cuda_runtime.h>
#include <math.h>

// Problem constants
#define BB 8
#define LL 4096
#define CC 256
#define HH 8
#define DD 32
#define CH 128
#define NC 32          // LL / CH
#define TT (BB*LL)     // 32768 tokens

// ---------------- static device scratch (no allocations allowed) ----------------
__device__ float g_qkv[(size_t)TT * 768];            // 96 MB: qkv per token
__device__ float g_o  [(size_t)TT * CC];             // 32 MB: attention output [B,L,H,D]
__device__ float g_C  [(size_t)BB*HH*NC * DD*DD];    // 8 MB: per-chunk KV contributions
__device__ float g_kvp[(size_t)BB*HH*NC * DD*DD];    // 8 MB: exclusive KV prefixes

// ======================= Tiled fp32 GEMM: C = A @ B^T (+bias) =======================
// A: [M,K] row-major (optionally fused A = x + rel_pos), Bw: [N,K] row-major.
// BM=128, BN=64, BK=16, 256 threads, 8x4 outputs/thread.
template<bool FUSE, bool BIAS>
__global__ void sgemm128x64(const float* __restrict__ A,
                            const float* __restrict__ Bw,
                            const float* __restrict__ bias,
                            float* __restrict__ Cmat,
                            int M, int N, int K,
                            const float* __restrict__ x,
                            const float* __restrict__ rp)
{
    __shared__ float As[16][128];
    __shared__ float Bs[16][64];

    const int tid = threadIdx.x;
    const int tx = tid & 15;
    const int ty = tid >> 4;
    const int m0 = blockIdx.y * 128;
    const int n0 = blockIdx.x * 64;

    float acc[8][4];
#pragma unroll
    for (int i = 0; i < 8; i++)
#pragma unroll
        for (int j = 0; j < 4; j++) acc[i][j] = 0.f;

    for (int k0 = 0; k0 < K; k0 += 16) {
        // Load A tile: 2048 floats = 512 float4, 2 per thread
#pragma unroll
        for (int l = 0; l < 2; l++) {
            int li = tid + l * 256;
            int r = li >> 2;              // 0..127
            int c = (li & 3) << 2;        // 0,4,8,12
            int gm = m0 + r;
            float4 v;
            if (FUSE) {
                float4 xv = *(const float4*)&x [(size_t)gm * K + k0 + c];
                float4 rv = *(const float4*)&rp[(size_t)(gm & (LL-1)) * K + k0 + c];
                v = make_float4(xv.x + rv.x, xv.y + rv.y, xv.z + rv.z, xv.w + rv.w);
            } else {
                v = *(const float4*)&A[(size_t)gm * K + k0 + c];
            }
            As[c+0][r] = v.x; As[c+1][r] = v.y; As[c+2][r] = v.z; As[c+3][r] = v.w;
        }
        // Load B tile: 1024 floats = 256 float4, 1 per thread
        {
            int r = tid >> 2;             // 0..63
            int c = (tid & 3) << 2;
            float4 v = *(const float4*)&Bw[(size_t)(n0 + r) * K + k0 + c];
            Bs[c+0][r] = v.x; Bs[c+1][r] = v.y; Bs[c+2][r] = v.z; Bs[c+3][r] = v.w;
        }
        __syncthreads();

#pragma unroll
        for (int kk = 0; kk < 16; kk++) {
            float a[8], bm[4];
            *(float4*)&a[0] = *(const float4*)&As[kk][ty*8];
            *(float4*)&a[4] = *(const float4*)&As[kk][ty*8+4];
            *(float4*)&bm[0] = *(const float4*)&Bs[kk][tx*4];
#pragma unroll
            for (int i = 0; i < 8; i++)
#pragma unroll
                for (int j = 0; j < 4; j++)
                    acc[i][j] += a[i] * bm[j];
        }
        __syncthreads();
    }

#pragma unroll
    for (int i = 0; i < 8; i++) {
        int gm = m0 + ty*8 + i;
        float4 o;
        o.x = acc[i][0]; o.y = acc[i][1]; o.z = acc[i][2]; o.w = acc[i][3];
        if (BIAS) {
            const float4 bv = *(const float4*)&bias[n0 + tx*4];
            o.x += bv.x; o.y += bv.y; o.z += bv.z; o.w += bv.w;
        }
        *(float4*)&Cmat[(size_t)gm * N + n0 + tx*4] = o;
    }
}

// ======================= attention: intra + per-chunk KV contribution =======================
// One block per (chunk n, head h, batch b). 256 threads.
// Dynamic smem: qs/ks/vs [128][33], sc [128][129], nq/nk [128], ed [129].
#define SMEM_ATTN_BYTES ((3*128*33 + 128*129 + 128 + 128 + 129) * 4)

__global__ void attn_chunk_kernel(const float* __restrict__ qg, const float* __restrict__ kg)
{
    extern __shared__ float sm[];
    float* qs = sm;
    float* ks = sm + 128*33;
    float* vs = sm + 2*128*33;
    float* sc = sm + 3*128*33;
    float* nq = sc + 128*129;
    float* nk = nq + 128;
    float* ed = nk + 128;

    const int n = blockIdx.x, h = blockIdx.y, b = blockIdx.z;
    const int tid = threadIdx.x;
    const int lane = tid & 31, warp = tid >> 5;
    const float s = exp2f(-(float)(h + 1));   // slopes are exact powers of 2

    for (int i = tid; i <= CH; i += 256) ed[i] = expf(-s * (float)i);

    // Load q,k,v chunk (128 rows x 32) from g_qkv
    const size_t base = ((size_t)(b*LL + n*CH)) * 768 + h*DD;
    for (int i = tid; i < 1024; i += 256) {
        int r = i >> 3, c4 = (i & 7) << 2;
        const float* rowp = &g_qkv[base + (size_t)r * 768 + c4];
        float4 a  = *(const float4*)(rowp);
        float4 bb = *(const float4*)(rowp + 256);
        float4 cc = *(const float4*)(rowp + 512);
        int so = r*33 + c4;
        qs[so+0]=a.x;  qs[so+1]=a.y;  qs[so+2]=a.z;  qs[so+3]=a.w;
        ks[so+0]=bb.x; ks[so+1]=bb.y; ks[so+2]=bb.z; ks[so+3]=bb.w;
        vs[so+0]=cc.x; vs[so+1]=cc.y; vs[so+2]=cc.z; vs[so+3]=cc.w;
    }
    __syncthreads();

    // Row norms (q's D^-0.5 prescale cancels under normalization)
    if (tid < 128) {
        float sq = 0.f, sk = 0.f;
#pragma unroll
        for (int d = 0; d < DD; d++) {
            float a = qs[tid*33+d]; sq += a*a;
            float c = ks[tid*33+d]; sk += c*c;
        }
        nq[tid] = sqrtf(sq);
        nk[tid] = sqrtf(sk);
    }
    __syncthreads();

    const float sqD = 5.656854249492380f;  // sqrt(32)
    for (int i = tid; i < 4096; i += 256) {
        int r = i >> 5, d = i & 31;
        qs[r*33+d] *= sqD * __ldg(&qg[h*DD + d]) / fmaxf(nq[r], 1e-12f);
        ks[r*33+d] *= sqD * __ldg(&kg[h*DD + d]) / fmaxf(nk[r], 1e-12f);
    }
    __syncthreads();

    // scores[c][m] = (q_hat[c] . k_hat[m]) * mask; 4x4 microtile, m lane-interleaved
#pragma unroll
    for (int i = 0; i < 4; i++) {
        const int c0 = warp*4 + i*32;
        float acc[4][4];
#pragma unroll
        for (int j = 0; j < 4; j++)
#pragma unroll
            for (int t = 0; t < 4; t++) acc[j][t] = 0.f;

#pragma unroll 8
        for (int d = 0; d < DD; d++) {
            float qv[4], kv[4];
#pragma unroll
            for (int j = 0; j < 4; j++) qv[j] = qs[(c0+j)*33 + d];
#pragma unroll
            for (int t = 0; t < 4; t++) kv[t] = ks[(lane + 32*t)*33 + d];
#pragma unroll
            for (int j = 0; j < 4; j++)
#pragma unroll
                for (int t = 0; t < 4; t++) acc[j][t] += qv[j]*kv[t];
        }
#pragma unroll
        for (int j = 0; j < 4; j++) {
            int c = c0 + j;
#pragma unroll
            for (int t = 0; t < 4; t++) {
                int m = lane + 32*t;
                int diff = c - m;
                sc[c*129 + m] = (diff >= 0) ? acc[j][t]*ed[diff] : 0.f;
            }
        }
    }
    __syncthreads();

    // C_n[d][e] = sum_c k_hat[c][d]*k_decay[c]*v[c][e]
    {
        float acc[4] = {0.f, 0.f, 0.f, 0.f};
        for (int c = 0; c < CH; c++) {
            float vkd = vs[c*33 + lane] * ed[CH - c];
#pragma unroll
            for (int j = 0; j < 4; j++) acc[j] += ks[c*33 + warp*4 + j] * vkd;
        }
        const size_t cb = ((size_t)((b*HH + h)*NC + n)) * 1024;
#pragma unroll
        for (int j = 0; j < 4; j++) g_C[cb + (warp*4+j)*32 + lane] = acc[j];
    }

    // o_intra[c][e] = sum_m sc[c][m]*v[m][e]; 4x4 microtile on (c,e)
    {
        const int cb0 = (tid >> 3) * 4;
        const int e0  = (tid & 7) * 4;
        float oacc[4][4];
#pragma unroll
        for (int j = 0; j < 4; j++)
#pragma unroll
            for (int t = 0; t < 4; t++) oacc[j][t] = 0.f;

        for (int m = 0; m < CH; m++) {
            float sv[4], vv[4];
#pragma unroll
            for (int j = 0; j < 4; j++) sv[j] = sc[(cb0+j)*129 + m];
#pragma unroll
            for (int t = 0; t < 4; t++) vv[t] = vs[m*33 + e0 + t];
#pragma unroll
            for (int j = 0; j < 4; j++)
#pragma unroll
                for (int t = 0; t < 4; t++) oacc[j][t] += sv[j]*vv[t];
        }
#pragma unroll
        for (int j = 0; j < 4; j++) {
            int c = cb0 + j;
            size_t go = ((size_t)(b*LL + n*CH + c)) * CC + h*DD + e0;
            *(float4*)&g_o[go] = make_float4(oacc[j][0], oacc[j][1], oacc[j][2], oacc[j][3]);
        }
    }
}

// ======================= sequential KV scan (exclusive prefix) =======================
__global__ void kv_scan_kernel()
{
    const int bh = blockIdx.x;           // 64 blocks
    const int h = bh & 7;
    const int tid = threadIdx.x;         // 256 threads, 4 elems each
    const float bd = expf(-exp2f(-(float)(h+1)) * (float)CH);
    float4 kv = make_float4(0.f, 0.f, 0.f, 0.f);
    const size_t base = (size_t)bh * NC * 1024 + tid*4;
    for (int n = 0; n < NC; n++) {
        const size_t o = base + (size_t)n * 1024;
        *(float4*)&g_kvp[o] = kv;
        float4 c = *(const float4*)&g_C[o];
        kv.x = bd*kv.x + c.x; kv.y = bd*kv.y + c.y;
        kv.z = bd*kv.z + c.z; kv.w = bd*kv.w + c.w;
    }
}

// ======================= inter-chunk contribution =======================
// o[c][e] += q_decay[c] * sum_d q_hat[c][d] * kv_prefix[d][e]
__global__ void attn_inter_kernel(const float* __restrict__ qg)
{
    const int n = blockIdx.x;
    if (n == 0) return;   // kv prefix is zero for chunk 0
    const int h = blockIdx.y, b = blockIdx.z;

    __shared__ float qs[128*33];
    __shared__ float kvs[32*33];
    __shared__ float nq[128];
    __shared__ float ed[128];

    const int tid = threadIdx.x;
    const float s = exp2f(-(float)(h+1));
    const float sqD = 5.656854249492380f;
    for (int i = tid; i < CH; i += 256) ed[i] = expf(-s * (float)i);

    const size_t base = ((size_t)(b*LL + n*CH)) * 768 + h*DD;
    for (int i = tid; i < 1024; i += 256) {
        int r = i >> 3, c4 = (i & 7) << 2;
        float4 a = *(const float4*)&g_qkv[base + (size_t)r * 768 + c4];
        int so = r*33 + c4;
        qs[so+0]=a.x; qs[so+1]=a.y; qs[so+2]=a.z; qs[so+3]=a.w;
    }
    // KV prefix, gamma + sqrt(D) folded in along d
    const size_t kb = ((size_t)((b*HH + h)*NC + n)) * 1024;
    for (int i = tid; i < 1024; i += 256) {
        int d = i >> 5, e = i & 31;
        kvs[d*33 + e] = g_kvp[kb + i] * sqD * __ldg(&qg[h*DD + d]);
    }
    __syncthreads();

    if (tid < 128) {
        float sq = 0.f;
#pragma unroll
        for (int d = 0; d < DD; d++) { float a = qs[tid*33+d]; sq += a*a; }
        nq[tid] = sqrtf(sq);
    }
    __syncthreads();

    const int cb0 = (tid >> 3) * 4;
    const int e0  = (tid & 7) * 4;
    float oacc[4][4];
#pragma unroll
    for (int j = 0; j < 4; j++)
#pragma unroll
        for (int t = 0; t < 4; t++) oacc[j][t] = 0.f;

#pragma unroll 8
    for (int d = 0; d < DD; d++) {
        float qv[4], kv[4];
#pragma unroll
        for (int j = 0; j < 4; j++) qv[j] = qs[(cb0+j)*33 + d];
#pragma unroll
        for (int t = 0; t < 4; t++) kv[t] = kvs[d*33 + e0 + t];
#pragma unroll
        for (int j = 0; j < 4; j++)
#pragma unroll
            for (int t = 0; t < 4; t++) oacc[j][t] += qv[j]*kv[t];
    }
#pragma unroll
    for (int j = 0; j < 4; j++) {
        int c = cb0 + j;
        float alpha = ed[c] / fmaxf(nq[c], 1e-12f);
        size_t go = ((size_t)(b*LL + n*CH + c)) * CC + h*DD + e0;
        float4 o = *(float4*)&g_o[go];
        o.x += alpha*oacc[j][0]; o.y += alpha*oacc[j][1];
        o.z += alpha*oacc[j][2]; o.w += alpha*oacc[j][3];
        *(float4*)&g_o[go] = o;
    }
}

// ======================= launch =======================
extern "C" void kernel_launch(void* const* d_in, const int* in_sizes, int n_in,
                              void* d_out, int out_size)
{
    const float* x    = (const float*)d_in[0];
    const float* rel  = (const float*)d_in[1];
    const float* qkvw = (const float*)d_in[2];
    const float* qg   = (const float*)d_in[3];
    const float* kg   = (const float*)d_in[4];
    const float* pw   = (const float*)d_in[5];
    const float* pb   = (const float*)d_in[6];
    float* out = (float*)d_out;

    void* p_qkv = nullptr; cudaGetSymbolAddress(&p_qkv, g_qkv);
    void* p_o   = nullptr; cudaGetSymbolAddress(&p_o,   g_o);

    // 1) qkv = (x + rel_pos) @ qkv_w^T     [32768 x 768 x 256]
    sgemm128x64<true, false><<<dim3(768/64, TT/128), 256>>>(
        nullptr, qkvw, nullptr, (float*)p_qkv, TT, 768, CC, x, rel);

    // 2) per-chunk: norms, intra attention, KV contributions
    cudaFuncSetAttribute(attn_chunk_kernel,
                         cudaFuncAttributeMaxDynamicSharedMemorySize, SMEM_ATTN_BYTES);
    attn_chunk_kernel<<<dim3(NC, HH, BB), 256, SMEM_ATTN_BYTES>>>(qg, kg);

    // 3) sequential KV prefix scan per (b,h)
    kv_scan_kernel<<<BB*HH, 256>>>();

    // 4) inter-chunk contribution
    attn_inter_kernel<<<dim3(NC, HH, BB), 256>>>(qg);

    // 5) out = o @ proj_w^T + proj_b       [32768 x 256 x 256]
    sgemm128x64<false, true><<<dim3(CC/64, TT/128), 256>>>(
        (float*)p_o, pw, pb, out, TT, CC, CC, nullptr, nullptr);
}

// round 3
// speedup vs baseline: 1.5658x; 1.5658x over previous
#include <cuda_runtime.h>
#include <cuda_bf16.h>
#include <math.h>
#include <stdint.h>

// Problem constants
#define BB 8
#define LL 4096
#define CC 256
#define HH 8
#define DD 32
#define CH 128
#define NC 32          // LL / CH
#define TT (BB*LL)     // 32768 tokens
#define KTOT 768

// ---------------- static device scratch (no allocations allowed) ----------------
__device__ float g_qkv[(size_t)TT * 768];                 // 96 MB: qkv per token (fp32)
__device__ float g_o  [(size_t)TT * CC];                  // 32 MB: attention output
__device__ float g_C  [(size_t)BB*HH*NC * DD*DD];         // per-chunk KV contributions
__device__ float g_kvp[(size_t)BB*HH*NC * DD*DD];         // exclusive KV prefixes
__device__ __nv_bfloat16 g_A2 [(size_t)TT * 768];         // 48 MB: [Ahi, Alo, Ahi] activations
__device__ __nv_bfloat16 g_W1b[(size_t)768 * 768];        // [Whi, Whi, Wlo] qkv weight
__device__ __nv_bfloat16 g_W2b[(size_t)256 * 768];        // [Whi, Whi, Wlo] proj weight

// =========================== small PTX helpers ===========================
__device__ __forceinline__ uint32_t smem_u32(const void* p) {
    uint32_t a;
    asm("{ .reg .u64 t; cvta.to.shared.u64 t, %1; cvt.u32.u64 %0, t; }" : "=r"(a) : "l"(p));
    return a;
}
__device__ __forceinline__ void cpasync16(uint32_t dst, const void* src) {
    asm volatile("cp.async.cg.shared.global [%0], [%1], 16;" :: "r"(dst), "l"(src));
}
__device__ __forceinline__ void cp_commit() {
    asm volatile("cp.async.commit_group;" ::: "memory");
}
template<int N>
__device__ __forceinline__ void cp_wait() {
    asm volatile("cp.async.wait_group %0;" :: "n"(N) : "memory");
}
__device__ __forceinline__ void ldsm4(uint32_t* r, uint32_t addr) {
    asm volatile("ldmatrix.sync.aligned.m8n8.x4.shared.b16 {%0,%1,%2,%3}, [%4];"
                 : "=r"(r[0]), "=r"(r[1]), "=r"(r[2]), "=r"(r[3]) : "r"(addr));
}
__device__ __forceinline__ void mma_bf16(float* c, const uint32_t* a, const uint32_t* b) {
    asm volatile("mma.sync.aligned.m16n8k16.row.col.f32.bf16.bf16.f32 "
                 "{%0,%1,%2,%3}, {%4,%5,%6,%7}, {%8,%9}, {%0,%1,%2,%3};"
                 : "+f"(c[0]), "+f"(c[1]), "+f"(c[2]), "+f"(c[3])
                 : "r"(a[0]), "r"(a[1]), "r"(a[2]), "r"(a[3]), "r"(b[0]), "r"(b[1]));
}
// xor swizzle of 16B chunk index within a 64B row (4 chunks)
__device__ __forceinline__ int sw_chunk(int r, int c) {
    return c ^ (r & 3) ^ ((r >> 2) & 1);
}

// =========================== hi/lo split conversion kernels ===========================
// A2 row: [hi(0:256), lo(256:512), hi(512:768)] ; W2 row: [hi, hi, lo]
__global__ void conv_act_kernel(const float* __restrict__ x, const float* __restrict__ rp,
                                __nv_bfloat16* __restrict__ A2, int fuse_rel)
{
    int idx = blockIdx.x * 256 + threadIdx.x;
    int m = idx >> 6, c4 = (idx & 63) << 2;
    float4 h = *(const float4*)&x[(size_t)m * 256 + c4];
    if (fuse_rel) {
        float4 r = *(const float4*)&rp[(size_t)(m & (LL-1)) * 256 + c4];
        h.x += r.x; h.y += r.y; h.z += r.z; h.w += r.w;
    }
    float hv[4] = {h.x, h.y, h.z, h.w};
    __nv_bfloat16 hi[4], lo[4];
#pragma unroll
    for (int j = 0; j < 4; j++) {
        hi[j] = __float2bfloat16(hv[j]);
        lo[j] = __float2bfloat16(hv[j] - __bfloat162float(hi[j]));
    }
    size_t base = (size_t)m * 768 + c4;
    *(uint2*)&A2[base]       = *(uint2*)hi;
    *(uint2*)&A2[base + 256] = *(uint2*)lo;
    *(uint2*)&A2[base + 512] = *(uint2*)hi;
}

__global__ void conv_w_kernel(const float* __restrict__ W, __nv_bfloat16* __restrict__ W2)
{
    int idx = blockIdx.x * 256 + threadIdx.x;
    int n = idx >> 6, c4 = (idx & 63) << 2;
    float4 h = *(const float4*)&W[(size_t)n * 256 + c4];
    float hv[4] = {h.x, h.y, h.z, h.w};
    __nv_bfloat16 hi[4], lo[4];
#pragma unroll
    for (int j = 0; j < 4; j++) {
        hi[j] = __float2bfloat16(hv[j]);
        lo[j] = __float2bfloat16(hv[j] - __bfloat162float(hi[j]));
    }
    size_t base = (size_t)n * 768 + c4;
    *(uint2*)&W2[base]       = *(uint2*)hi;
    *(uint2*)&W2[base + 256] = *(uint2*)hi;
    *(uint2*)&W2[base + 512] = *(uint2*)lo;
}

// =========================== HMMA bf16 GEMM: C = A2 @ W2^T (+bias) ===========================
// BM=128, BN=128, BK=32, 256 threads (8 warps as 2m x 4n), warp tile 64x32.
#define NSTG (KTOT/32)   // 24

template<bool BIAS>
__global__ void __launch_bounds__(256, 2) gemm_bf16_hmma(
    const __nv_bfloat16* __restrict__ A,
    const __nv_bfloat16* __restrict__ Bw,
    const float* __restrict__ bias,
    float* __restrict__ Cmat, int Ntot)
{
    __shared__ __align__(16) __nv_bfloat16 As[2][128][32];
    __shared__ __align__(16) __nv_bfloat16 Bs[2][128][32];

    const int tid = threadIdx.x;
    const int wid = tid >> 5, lane = tid & 31;
    const int warp_m = wid & 1, warp_n = wid >> 1;
    const int m0 = blockIdx.y * 128;
    const int n0 = blockIdx.x * 128;

    const uint32_t as_base = smem_u32(As);
    const uint32_t bs_base = smem_u32(Bs);

    float acc[4][4][4];
#pragma unroll
    for (int mt = 0; mt < 4; mt++)
#pragma unroll
        for (int nt = 0; nt < 4; nt++)
#pragma unroll
            for (int e = 0; e < 4; e++) acc[mt][nt][e] = 0.f;

    // loader mapping: 2 chunks of 16B per thread per tile per stage
    const int lr = tid >> 2;          // rows tid>>2 and (tid>>2)+64
    const int lc = tid & 3;           // chunk 0..3

    auto load_stage = [&](int s, int b) {
#pragma unroll
        for (int l = 0; l < 2; l++) {
            int r = lr + l * 64;
            int ch = sw_chunk(r, lc);
            const __nv_bfloat16* asrc = A  + (size_t)(m0 + r) * KTOT + s * 32 + lc * 8;
            const __nv_bfloat16* bsrc = Bw + (size_t)(n0 + r) * KTOT + s * 32 + lc * 8;
            cpasync16(as_base + (b * 128 + r) * 64 + ch * 16, asrc);
            cpasync16(bs_base + (b * 128 + r) * 64 + ch * 16, bsrc);
        }
    };

    load_stage(0, 0);
    cp_commit();

    for (int i = 0; i < NSTG; i++) {
        const int b = i & 1;
        if (i + 1 < NSTG) {
            load_stage(i + 1, (i + 1) & 1);
            cp_commit();
            cp_wait<1>();
        } else {
            cp_wait<0>();
        }
        __syncthreads();

#pragma unroll
        for (int kk = 0; kk < 2; kk++) {
            uint32_t af[4][4];
#pragma unroll
            for (int mt = 0; mt < 4; mt++) {
                int row = warp_m * 64 + mt * 16 + (lane & 15);
                int ch = sw_chunk(row, kk * 2 + (lane >> 4));
                ldsm4(af[mt], as_base + (b * 128 + row) * 64 + ch * 16);
            }
            uint32_t bf[2][4];
#pragma unroll
            for (int nt2 = 0; nt2 < 2; nt2++) {
                int g = lane >> 3, l8 = lane & 7;
                int row = warp_n * 32 + nt2 * 16 + (g >> 1) * 8 + l8;
                int ch = sw_chunk(row, kk * 2 + (g & 1));
                ldsm4(bf[nt2], bs_base + (b * 128 + row) * 64 + ch * 16);
            }
#pragma unroll
            for (int mt = 0; mt < 4; mt++)
#pragma unroll
                for (int nt = 0; nt < 4; nt++)
                    mma_bf16(acc[mt][nt], af[mt], &bf[nt >> 1][(nt & 1) * 2]);
        }
        __syncthreads();
    }

    // epilogue
#pragma unroll
    for (int mt = 0; mt < 4; mt++) {
        int row = m0 + warp_m * 64 + mt * 16 + (lane >> 2);
#pragma unroll
        for (int nt = 0; nt < 4; nt++) {
            int col = n0 + warp_n * 32 + nt * 8 + (lane & 3) * 2;
            float2 v0 = make_float2(acc[mt][nt][0], acc[mt][nt][1]);
            float2 v1 = make_float2(acc[mt][nt][2], acc[mt][nt][3]);
            if (BIAS) {
                float2 bv = *(const float2*)&bias[col];
                v0.x += bv.x; v0.y += bv.y;
                v1.x += bv.x; v1.y += bv.y;
            }
            *(float2*)&Cmat[(size_t)row * Ntot + col]       = v0;
            *(float2*)&Cmat[(size_t)(row + 8) * Ntot + col] = v1;
        }
    }
}

// ======================= attention: intra + per-chunk KV contribution =======================
#define SMEM_ATTN_BYTES ((3*128*33 + 128*129 + 128 + 128 + 129) * 4)

__global__ void attn_chunk_kernel(const float* __restrict__ qg, const float* __restrict__ kg)
{
    extern __shared__ float sm[];
    float* qs = sm;
    float* ks = sm + 128*33;
    float* vs = sm + 2*128*33;
    float* sc = sm + 3*128*33;
    float* nq = sc + 128*129;
    float* nk = nq + 128;
    float* ed = nk + 128;

    const int n = blockIdx.x, h = blockIdx.y, b = blockIdx.z;
    const int tid = threadIdx.x;
    const int lane = tid & 31, warp = tid >> 5;
    const float s = exp2f(-(float)(h + 1));

    for (int i = tid; i <= CH; i += 256) ed[i] = expf(-s * (float)i);

    const size_t base = ((size_t)(b*LL + n*CH)) * 768 + h*DD;
    for (int i = tid; i < 1024; i += 256) {
        int r = i >> 3, c4 = (i & 7) << 2;
        const float* rowp = &g_qkv[base + (size_t)r * 768 + c4];
        float4 a  = *(const float4*)(rowp);
        float4 bb = *(const float4*)(rowp + 256);
        float4 cc = *(const float4*)(rowp + 512);
        int so = r*33 + c4;
        qs[so+0]=a.x;  qs[so+1]=a.y;  qs[so+2]=a.z;  qs[so+3]=a.w;
        ks[so+0]=bb.x; ks[so+1]=bb.y; ks[so+2]=bb.z; ks[so+3]=bb.w;
        vs[so+0]=cc.x; vs[so+1]=cc.y; vs[so+2]=cc.z; vs[so+3]=cc.w;
    }
    __syncthreads();

    if (tid < 128) {
        float sq = 0.f, sk = 0.f;
#pragma unroll
        for (int d = 0; d < DD; d++) {
            float a = qs[tid*33+d]; sq += a*a;
            float c = ks[tid*33+d]; sk += c*c;
        }
        nq[tid] = sqrtf(sq);
        nk[tid] = sqrtf(sk);
    }
    __syncthreads();

    const float sqD = 5.656854249492380f;
    for (int i = tid; i < 4096; i += 256) {
        int r = i >> 5, d = i & 31;
        qs[r*33+d] *= sqD * __ldg(&qg[h*DD + d]) / fmaxf(nq[r], 1e-12f);
        ks[r*33+d] *= sqD * __ldg(&kg[h*DD + d]) / fmaxf(nk[r], 1e-12f);
    }
    __syncthreads();

#pragma unroll
    for (int i = 0; i < 4; i++) {
        const int c0 = warp*4 + i*32;
        float acc[4][4];
#pragma unroll
        for (int j = 0; j < 4; j++)
#pragma unroll
            for (int t = 0; t < 4; t++) acc[j][t] = 0.f;

#pragma unroll 8
        for (int d = 0; d < DD; d++) {
            float qv[4], kv[4];
#pragma unroll
            for (int j = 0; j < 4; j++) qv[j] = qs[(c0+j)*33 + d];
#pragma unroll
            for (int t = 0; t < 4; t++) kv[t] = ks[(lane + 32*t)*33 + d];
#pragma unroll
            for (int j = 0; j < 4; j++)
#pragma unroll
                for (int t = 0; t < 4; t++) acc[j][t] += qv[j]*kv[t];
        }
#pragma unroll
        for (int j = 0; j < 4; j++) {
            int c = c0 + j;
#pragma unroll
            for (int t = 0; t < 4; t++) {
                int m = lane + 32*t;
                int diff = c - m;
                sc[c*129 + m] = (diff >= 0) ? acc[j][t]*ed[diff] : 0.f;
            }
        }
    }
    __syncthreads();

    {
        float acc[4] = {0.f, 0.f, 0.f, 0.f};
        for (int c = 0; c < CH; c++) {
            float vkd = vs[c*33 + lane] * ed[CH - c];
#pragma unroll
            for (int j = 0; j < 4; j++) acc[j] += ks[c*33 + warp*4 + j] * vkd;
        }
        const size_t cb = ((size_t)((b*HH + h)*NC + n)) * 1024;
#pragma unroll
        for (int j = 0; j < 4; j++) g_C[cb + (warp*4+j)*32 + lane] = acc[j];
    }

    {
        const int cb0 = (tid >> 3) * 4;
        const int e0  = (tid & 7) * 4;
        float oacc[4][4];
#pragma unroll
        for (int j = 0; j < 4; j++)
#pragma unroll
            for (int t = 0; t < 4; t++) oacc[j][t] = 0.f;

        for (int m = 0; m < CH; m++) {
            float sv[4], vv[4];
#pragma unroll
            for (int j = 0; j < 4; j++) sv[j] = sc[(cb0+j)*129 + m];
#pragma unroll
            for (int t = 0; t < 4; t++) vv[t] = vs[m*33 + e0 + t];
#pragma unroll
            for (int j = 0; j < 4; j++)
#pragma unroll
                for (int t = 0; t < 4; t++) oacc[j][t] += sv[j]*vv[t];
        }
#pragma unroll
        for (int j = 0; j < 4; j++) {
            int c = cb0 + j;
            size_t go = ((size_t)(b*LL + n*CH + c)) * CC + h*DD + e0;
            *(float4*)&g_o[go] = make_float4(oacc[j][0], oacc[j][1], oacc[j][2], oacc[j][3]);
        }
    }
}

// ======================= sequential KV scan (exclusive prefix) =======================
__global__ void kv_scan_kernel()
{
    const int bh = blockIdx.x;
    const int h = bh & 7;
    const int tid = threadIdx.x;
    const float bd = expf(-exp2f(-(float)(h+1)) * (float)CH);
    float4 kv = make_float4(0.f, 0.f, 0.f, 0.f);
    const size_t base = (size_t)bh * NC * 1024 + tid*4;
    for (int n = 0; n < NC; n++) {
        const size_t o = base + (size_t)n * 1024;
        *(float4*)&g_kvp[o] = kv;
        float4 c = *(const float4*)&g_C[o];
        kv.x = bd*kv.x + c.x; kv.y = bd*kv.y + c.y;
        kv.z = bd*kv.z + c.z; kv.w = bd*kv.w + c.w;
    }
}

// ======================= inter-chunk contribution =======================
__global__ void attn_inter_kernel(const float* __restrict__ qg)
{
    const int n = blockIdx.x;
    if (n == 0) return;
    const int h = blockIdx.y, b = blockIdx.z;

    __shared__ float qs[128*33];
    __shared__ float kvs[32*33];
    __shared__ float nq[128];
    __shared__ float ed[128];

    const int tid = threadIdx.x;
    const float s = exp2f(-(float)(h+1));
    const float sqD = 5.656854249492380f;
    for (int i = tid; i < CH; i += 256) ed[i] = expf(-s * (float)i);

    const size_t base = ((size_t)(b*LL + n*CH)) * 768 + h*DD;
    for (int i = tid; i < 1024; i += 256) {
        int r = i >> 3, c4 = (i & 7) << 2;
        float4 a = *(const float4*)&g_qkv[base + (size_t)r * 768 + c4];
        int so = r*33 + c4;
        qs[so+0]=a.x; qs[so+1]=a.y; qs[so+2]=a.z; qs[so+3]=a.w;
    }
    const size_t kb = ((size_t)((b*HH + h)*NC + n)) * 1024;
    for (int i = tid; i < 1024; i += 256) {
        int d = i >> 5, e = i & 31;
        kvs[d*33 + e] = g_kvp[kb + i] * sqD * __ldg(&qg[h*DD + d]);
    }
    __syncthreads();

    if (tid < 128) {
        float sq = 0.f;
#pragma unroll
        for (int d = 0; d < DD; d++) { float a = qs[tid*33+d]; sq += a*a; }
        nq[tid] = sqrtf(sq);
    }
    __syncthreads();

    const int cb0 = (tid >> 3) * 4;
    const int e0  = (tid & 7) * 4;
    float oacc[4][4];
#pragma unroll
    for (int j = 0; j < 4; j++)
#pragma unroll
        for (int t = 0; t < 4; t++) oacc[j][t] = 0.f;

#pragma unroll 8
    for (int d = 0; d < DD; d++) {
        float qv[4], kv[4];
#pragma unroll
        for (int j = 0; j < 4; j++) qv[j] = qs[(cb0+j)*33 + d];
#pragma unroll
        for (int t = 0; t < 4; t++) kv[t] = kvs[d*33 + e0 + t];
#pragma unroll
        for (int j = 0; j < 4; j++)
#pragma unroll
            for (int t = 0; t < 4; t++) oacc[j][t] += qv[j]*kv[t];
    }
#pragma unroll
    for (int j = 0; j < 4; j++) {
        int c = cb0 + j;
        float alpha = ed[c] / fmaxf(nq[c], 1e-12f);
        size_t go = ((size_t)(b*LL + n*CH + c)) * CC + h*DD + e0;
        float4 o = *(float4*)&g_o[go];
        o.x += alpha*oacc[j][0]; o.y += alpha*oacc[j][1];
        o.z += alpha*oacc[j][2]; o.w += alpha*oacc[j][3];
        *(float4*)&g_o[go] = o;
    }
}

// ======================= launch =======================
extern "C" void kernel_launch(void* const* d_in, const int* in_sizes, int n_in,
                              void* d_out, int out_size)
{
    const float* x    = (const float*)d_in[0];
    const float* rel  = (const float*)d_in[1];
    const float* qkvw = (const float*)d_in[2];
    const float* qg   = (const float*)d_in[3];
    const float* kg   = (const float*)d_in[4];
    const float* pw   = (const float*)d_in[5];
    const float* pb   = (const float*)d_in[6];
    float* out = (float*)d_out;

    void* p_qkv = nullptr; cudaGetSymbolAddress(&p_qkv, g_qkv);
    void* p_o   = nullptr; cudaGetSymbolAddress(&p_o,   g_o);
    void* p_A2  = nullptr; cudaGetSymbolAddress(&p_A2,  g_A2);
    void* p_W1b = nullptr; cudaGetSymbolAddress(&p_W1b, g_W1b);
    void* p_W2b = nullptr; cudaGetSymbolAddress(&p_W2b, g_W2b);

    cudaFuncSetAttribute(attn_chunk_kernel,
                         cudaFuncAttributeMaxDynamicSharedMemorySize, SMEM_ATTN_BYTES);

    // 1) split (x + rel_pos) and qkv_w into bf16 hi/lo triplets
    conv_act_kernel<<<TT*64/256, 256>>>(x, rel, (__nv_bfloat16*)p_A2, 1);
    conv_w_kernel<<<768*64/256, 256>>>(qkvw, (__nv_bfloat16*)p_W1b);

    // 2) qkv = A2 @ W1b^T  (HMMA bf16, K=768) -> fp32 g_qkv
    gemm_bf16_hmma<false><<<dim3(768/128, TT/128), 256>>>(
        (const __nv_bfloat16*)p_A2, (const __nv_bfloat16*)p_W1b, nullptr,
        (float*)p_qkv, 768);

    // 3) attention
    attn_chunk_kernel<<<dim3(NC, HH, BB), 256, SMEM_ATTN_BYTES>>>(qg, kg);
    kv_scan_kernel<<<BB*HH, 256>>>();
    attn_inter_kernel<<<dim3(NC, HH, BB), 256>>>(qg);

    // 4) split attention output and proj_w
    conv_act_kernel<<<TT*64/256, 256>>>((const float*)p_o, nullptr, (__nv_bfloat16*)p_A2, 0);
    conv_w_kernel<<<256*64/256, 256>>>(pw, (__nv_bfloat16*)p_W2b);

    // 5) out = O2 @ W2b^T + bias
    gemm_bf16_hmma<true><<<dim3(256/128, TT/128), 256>>>(
        (const __nv_bfloat16*)p_A2, (const __nv_bfloat16*)p_W2b, pb,
        out, 256);
}

// round 5
// speedup vs baseline: 1.8577x; 1.1864x over previous
#include <cuda_runtime.h>
#include <cuda_bf16.h>
#include <math.h>
#include <stdint.h>

// Problem constants
#define BB 8
#define LL 4096
#define CC 256
#define HH 8
#define DD 32
#define CH 128
#define NC 32          // LL / CH
#define TT (BB*LL)     // 32768 tokens
#define KTOT 768

// ---------------- static device scratch (no allocations allowed) ----------------
__device__ float g_qkv[(size_t)TT * 768];                 // qkv per token (fp32)
__device__ float g_o  [(size_t)TT * CC];                  // attention output
__device__ float g_C  [(size_t)BB*HH*NC * DD*DD];         // per-chunk KV contributions
__device__ float g_kvp[(size_t)BB*HH*NC * DD*DD];         // exclusive KV prefixes
__device__ __nv_bfloat16 g_A2 [(size_t)TT * 768];         // [Ahi, Alo, Ahi] activations
__device__ __nv_bfloat16 g_W1b[(size_t)768 * 768];        // [Whi, Whi, Wlo] qkv weight
__device__ __nv_bfloat16 g_W2b[(size_t)256 * 768];        // [Whi, Whi, Wlo] proj weight
__device__ __nv_bfloat16 g_qh [(size_t)TT * CC];          // normalized q hat (hi), per (token, h*D+d)
__device__ __nv_bfloat16 g_ql [(size_t)TT * CC];          // normalized q hat (lo)

// =========================== small PTX helpers ===========================
__device__ __forceinline__ uint32_t smem_u32(const void* p) {
    uint32_t a;
    asm("{ .reg .u64 t; cvta.to.shared.u64 t, %1; cvt.u32.u64 %0, t; }" : "=r"(a) : "l"(p));
    return a;
}
__device__ __forceinline__ void cpasync16(uint32_t dst, const void* src) {
    asm volatile("cp.async.cg.shared.global [%0], [%1], 16;" :: "r"(dst), "l"(src));
}
__device__ __forceinline__ void cp_commit() {
    asm volatile("cp.async.commit_group;" ::: "memory");
}
template<int N>
__device__ __forceinline__ void cp_wait() {
    asm volatile("cp.async.wait_group %0;" :: "n"(N) : "memory");
}
__device__ __forceinline__ void ldsm4(uint32_t* r, uint32_t addr) {
    asm volatile("ldmatrix.sync.aligned.m8n8.x4.shared.b16 {%0,%1,%2,%3}, [%4];"
                 : "=r"(r[0]), "=r"(r[1]), "=r"(r[2]), "=r"(r[3]) : "r"(addr));
}
__device__ __forceinline__ void mma_bf16(float* c, const uint32_t* a, const uint32_t* b) {
    asm volatile("mma.sync.aligned.m16n8k16.row.col.f32.bf16.bf16.f32 "
                 "{%0,%1,%2,%3}, {%4,%5,%6,%7}, {%8,%9}, {%0,%1,%2,%3};"
                 : "+f"(c[0]), "+f"(c[1]), "+f"(c[2]), "+f"(c[3])
                 : "r"(a[0]), "r"(a[1]), "r"(a[2]), "r"(a[3]), "r"(b[0]), "r"(b[1]));
}
// xor swizzle of 16B chunk index within a 64B row (4 chunks)
__device__ __forceinline__ int sw_chunk(int r, int c) {
    return c ^ (r & 3) ^ ((r >> 2) & 1);
}
__device__ __forceinline__ uint32_t pack_bf2(__nv_bfloat16 a, __nv_bfloat16 b) {
    uint32_t lo16 = *(uint16_t*)&a, hi16 = *(uint16_t*)&b;
    return lo16 | (hi16 << 16);
}

// =========================== hi/lo split conversion kernels ===========================
__global__ void conv_act_kernel(const float* __restrict__ x, const float* __restrict__ rp,
                                __nv_bfloat16* __restrict__ A2, int fuse_rel)
{
    int idx = blockIdx.x * 256 + threadIdx.x;
    int m = idx >> 6, c4 = (idx & 63) << 2;
    float4 h = *(const float4*)&x[(size_t)m * 256 + c4];
    if (fuse_rel) {
        float4 r = *(const float4*)&rp[(size_t)(m & (LL-1)) * 256 + c4];
        h.x += r.x; h.y += r.y; h.z += r.z; h.w += r.w;
    }
    float hv[4] = {h.x, h.y, h.z, h.w};
    __nv_bfloat16 hi[4], lo[4];
#pragma unroll
    for (int j = 0; j < 4; j++) {
        hi[j] = __float2bfloat16(hv[j]);
        lo[j] = __float2bfloat16(hv[j] - __bfloat162float(hi[j]));
    }
    size_t base = (size_t)m * 768 + c4;
    *(uint2*)&A2[base]       = *(uint2*)hi;
    *(uint2*)&A2[base + 256] = *(uint2*)lo;
    *(uint2*)&A2[base + 512] = *(uint2*)hi;
}

__global__ void conv_w_kernel(const float* __restrict__ W, __nv_bfloat16* __restrict__ W2)
{
    int idx = blockIdx.x * 256 + threadIdx.x;
    int n = idx >> 6, c4 = (idx & 63) << 2;
    float4 h = *(const float4*)&W[(size_t)n * 256 + c4];
    float hv[4] = {h.x, h.y, h.z, h.w};
    __nv_bfloat16 hi[4], lo[4];
#pragma unroll
    for (int j = 0; j < 4; j++) {
        hi[j] = __float2bfloat16(hv[j]);
        lo[j] = __float2bfloat16(hv[j] - __bfloat162float(hi[j]));
    }
    size_t base = (size_t)n * 768 + c4;
    *(uint2*)&W2[base]       = *(uint2*)hi;
    *(uint2*)&W2[base + 256] = *(uint2*)hi;
    *(uint2*)&W2[base + 512] = *(uint2*)lo;
}

// =========================== HMMA bf16 GEMM: C = A2 @ W2^T (+bias) ===========================
#define NSTG (KTOT/32)   // 24

template<bool BIAS>
__global__ void __launch_bounds__(256, 2) gemm_bf16_hmma(
    const __nv_bfloat16* __restrict__ A,
    const __nv_bfloat16* __restrict__ Bw,
    const float* __restrict__ bias,
    float* __restrict__ Cmat, int Ntot)
{
    __shared__ __align__(16) __nv_bfloat16 As[2][128][32];
    __shared__ __align__(16) __nv_bfloat16 Bs[2][128][32];

    const int tid = threadIdx.x;
    const int wid = tid >> 5, lane = tid & 31;
    const int warp_m = wid & 1, warp_n = wid >> 1;
    const int m0 = blockIdx.y * 128;
    const int n0 = blockIdx.x * 128;

    const uint32_t as_base = smem_u32(As);
    const uint32_t bs_base = smem_u32(Bs);

    float acc[4][4][4];
#pragma unroll
    for (int mt = 0; mt < 4; mt++)
#pragma unroll
        for (int nt = 0; nt < 4; nt++)
#pragma unroll
            for (int e = 0; e < 4; e++) acc[mt][nt][e] = 0.f;

    const int lr = tid >> 2;
    const int lc = tid & 3;

    auto load_stage = [&](int s, int b) {
#pragma unroll
        for (int l = 0; l < 2; l++) {
            int r = lr + l * 64;
            int ch = sw_chunk(r, lc);
            const __nv_bfloat16* asrc = A  + (size_t)(m0 + r) * KTOT + s * 32 + lc * 8;
            const __nv_bfloat16* bsrc = Bw + (size_t)(n0 + r) * KTOT + s * 32 + lc * 8;
            cpasync16(as_base + (b * 128 + r) * 64 + ch * 16, asrc);
            cpasync16(bs_base + (b * 128 + r) * 64 + ch * 16, bsrc);
        }
    };

    load_stage(0, 0);
    cp_commit();

    for (int i = 0; i < NSTG; i++) {
        const int b = i & 1;
        if (i + 1 < NSTG) {
            load_stage(i + 1, (i + 1) & 1);
            cp_commit();
            cp_wait<1>();
        } else {
            cp_wait<0>();
        }
        __syncthreads();

#pragma unroll
        for (int kk = 0; kk < 2; kk++) {
            uint32_t af[4][4];
#pragma unroll
            for (int mt = 0; mt < 4; mt++) {
                int row = warp_m * 64 + mt * 16 + (lane & 15);
                int ch = sw_chunk(row, kk * 2 + (lane >> 4));
                ldsm4(af[mt], as_base + (b * 128 + row) * 64 + ch * 16);
            }
            uint32_t bf[2][4];
#pragma unroll
            for (int nt2 = 0; nt2 < 2; nt2++) {
                int g = lane >> 3, l8 = lane & 7;
                int row = warp_n * 32 + nt2 * 16 + (g >> 1) * 8 + l8;
                int ch = sw_chunk(row, kk * 2 + (g & 1));
                ldsm4(bf[nt2], bs_base + (b * 128 + row) * 64 + ch * 16);
            }
#pragma unroll
            for (int mt = 0; mt < 4; mt++)
#pragma unroll
                for (int nt = 0; nt < 4; nt++)
                    mma_bf16(acc[mt][nt], af[mt], &bf[nt >> 1][(nt & 1) * 2]);
        }
        __syncthreads();
    }

#pragma unroll
    for (int mt = 0; mt < 4; mt++) {
        int row = m0 + warp_m * 64 + mt * 16 + (lane >> 2);
#pragma unroll
        for (int nt = 0; nt < 4; nt++) {
            int col = n0 + warp_n * 32 + nt * 8 + (lane & 3) * 2;
            float2 v0 = make_float2(acc[mt][nt][0], acc[mt][nt][1]);
            float2 v1 = make_float2(acc[mt][nt][2], acc[mt][nt][3]);
            if (BIAS) {
                float2 bv = *(const float2*)&bias[col];
                v0.x += bv.x; v0.y += bv.y;
                v1.x += bv.x; v1.y += bv.y;
            }
            *(float2*)&Cmat[(size_t)row * Ntot + col]       = v0;
            *(float2*)&Cmat[(size_t)(row + 8) * Ntot + col] = v1;
        }
    }
}

// ======================= HMMA attention: intra + per-chunk KV contribution =======================
// smem layout (bytes)
#define AT_ED   0
#define AT_NQ   1024
#define AT_NK   1536
#define AT_QHI  2048
#define AT_QLO  (AT_QHI  + 8192)
#define AT_KHI  (AT_QLO  + 8192)
#define AT_KLO  (AT_KHI  + 8192)
#define AT_KTHI (AT_KLO  + 8192)
#define AT_KTLO (AT_KTHI + 8192)
#define AT_VTHI (AT_KTLO + 8192)
#define AT_VTLO (AT_VTHI + 8192)
#define AT_SCHI (AT_VTLO + 8192)      // 67584
#define AT_SCLO (AT_SCHI + 32768)
#define AT_CRED (AT_SCLO + 32768)
#define AT_QF   AT_SCHI               // fp32 staging overlaps sc region
#define AT_KF   (AT_QF + 16896)
#define AT_VF   (AT_KF + 16896)
#define AT_SMEM (AT_CRED + 16384)     // 149504

__global__ void __launch_bounds__(256, 1) attn_chunk_hmma(
    const float* __restrict__ qg, const float* __restrict__ kg,
    __nv_bfloat16* __restrict__ qhout, __nv_bfloat16* __restrict__ qlout)
{
    extern __shared__ char sm[];
    float* ed = (float*)(sm + AT_ED);
    float* nq = (float*)(sm + AT_NQ);
    float* nk = (float*)(sm + AT_NK);
    float* qf = (float*)(sm + AT_QF);
    float* kf = (float*)(sm + AT_KF);
    float* vf = (float*)(sm + AT_VF);
    const uint32_t sb = smem_u32(sm);

    const int n = blockIdx.x, h = blockIdx.y, b = blockIdx.z;
    const int tid = threadIdx.x, lane = tid & 31, wid = tid >> 5;
    const float s = exp2f(-(float)(h + 1));
    for (int i = tid; i <= CH; i += 256) ed[i] = expf(-s * (float)i);

    const size_t tok0 = (size_t)(b*LL + n*CH);
    const size_t base = tok0 * 768 + h*DD;
    for (int i = tid; i < 1024; i += 256) {
        int r = i >> 3, c4 = (i & 7) << 2;
        const float* rowp = &g_qkv[base + (size_t)r * 768 + c4];
        float4 a  = *(const float4*)(rowp);
        float4 bb = *(const float4*)(rowp + 256);
        float4 cc = *(const float4*)(rowp + 512);
        int so = r*33 + c4;
        qf[so+0]=a.x;  qf[so+1]=a.y;  qf[so+2]=a.z;  qf[so+3]=a.w;
        kf[so+0]=bb.x; kf[so+1]=bb.y; kf[so+2]=bb.z; kf[so+3]=bb.w;
        vf[so+0]=cc.x; vf[so+1]=cc.y; vf[so+2]=cc.z; vf[so+3]=cc.w;
    }
    __syncthreads();

    if (tid < 128) {
        float sq = 0.f, sk = 0.f;
#pragma unroll
        for (int d = 0; d < DD; d++) {
            float a = qf[tid*33+d]; sq += a*a;
            float c = kf[tid*33+d]; sk += c*c;
        }
        nq[tid] = sqrtf(sq);
        nk[tid] = sqrtf(sk);
    }
    __syncthreads();

    const float sqD = 5.656854249492380f;
    // conversion: q,k (normalized), kT (decay-folded), vT
    for (int i = tid; i < 4096; i += 256) {
        int r = i >> 5, d = i & 31;
        float qv = qf[r*33+d] * (sqD * __ldg(&qg[h*DD + d]) / fmaxf(nq[r], 1e-12f));
        float kv = kf[r*33+d] * (sqD * __ldg(&kg[h*DD + d]) / fmaxf(nk[r], 1e-12f));
        float vv = vf[r*33+d];

        __nv_bfloat16 qh = __float2bfloat16(qv);
        __nv_bfloat16 ql = __float2bfloat16(qv - __bfloat162float(qh));
        __nv_bfloat16 kh = __float2bfloat16(kv);
        __nv_bfloat16 kl = __float2bfloat16(kv - __bfloat162float(kh));
        int a64 = r*64 + sw_chunk(r, d >> 3) * 16 + (d & 7) * 2;
        *(__nv_bfloat16*)(sm + AT_QHI + a64) = qh;
        *(__nv_bfloat16*)(sm + AT_QLO + a64) = ql;
        *(__nv_bfloat16*)(sm + AT_KHI + a64) = kh;
        *(__nv_bfloat16*)(sm + AT_KLO + a64) = kl;
        // per-(token, head) slots -- no cross-head collision
        qhout[(tok0 + r)*CC + h*DD + d] = qh;
        qlout[(tok0 + r)*CC + h*DD + d] = ql;

        float ktv = kv * ed[CH - r];
        __nv_bfloat16 kth = __float2bfloat16(ktv);
        __nv_bfloat16 ktl = __float2bfloat16(ktv - __bfloat162float(kth));
        __nv_bfloat16 vth = __float2bfloat16(vv);
        __nv_bfloat16 vtl = __float2bfloat16(vv - __bfloat162float(vth));
        int aT = d*256 + (((r >> 3) ^ (d & 7)) * 16) + ((r & 7) * 2);
        *(__nv_bfloat16*)(sm + AT_KTHI + aT) = kth;
        *(__nv_bfloat16*)(sm + AT_KTLO + aT) = ktl;
        *(__nv_bfloat16*)(sm + AT_VTHI + aT) = vth;
        *(__nv_bfloat16*)(sm + AT_VTLO + aT) = vtl;
    }
    __syncthreads();

    // ---- scores: S = qhat @ khat^T  (128x128, K=32, 3 hi/lo passes) ----
    const int warp_m = wid & 1;
    const int wn = wid >> 1;
    float acc[4][4][4];
#pragma unroll
    for (int mt = 0; mt < 4; mt++)
#pragma unroll
        for (int nt = 0; nt < 4; nt++)
#pragma unroll
            for (int e = 0; e < 4; e++) acc[mt][nt][e] = 0.f;

    {
        const uint32_t QB[3] = {sb + AT_QHI, sb + AT_QLO, sb + AT_QHI};
        const uint32_t KB[3] = {sb + AT_KHI, sb + AT_KHI, sb + AT_KLO};
#pragma unroll
        for (int p = 0; p < 3; p++) {
#pragma unroll
            for (int kk = 0; kk < 2; kk++) {
                uint32_t af[4][4];
#pragma unroll
                for (int mt = 0; mt < 4; mt++) {
                    int row = warp_m * 64 + mt * 16 + (lane & 15);
                    int ch = sw_chunk(row, kk * 2 + (lane >> 4));
                    ldsm4(af[mt], QB[p] + row * 64 + ch * 16);
                }
                uint32_t bf[2][4];
#pragma unroll
                for (int nt2 = 0; nt2 < 2; nt2++) {
                    int g = lane >> 3, l8 = lane & 7;
                    int row = wn * 32 + nt2 * 16 + (g >> 1) * 8 + l8;
                    int ch = sw_chunk(row, kk * 2 + (g & 1));
                    ldsm4(bf[nt2], KB[p] + row * 64 + ch * 16);
                }
#pragma unroll
                for (int mt = 0; mt < 4; mt++)
#pragma unroll
                    for (int nt = 0; nt < 4; nt++)
                        mma_bf16(acc[mt][nt], af[mt], &bf[nt >> 1][(nt & 1) * 2]);
            }
        }
    }

    // ---- mask + decay, write sc hi/lo to swizzled smem ----
#pragma unroll
    for (int mt = 0; mt < 4; mt++) {
#pragma unroll
        for (int nt = 0; nt < 4; nt++) {
            int c0 = warp_m * 64 + mt * 16 + (lane >> 2);
            int m0_ = wn * 32 + nt * 8 + (lane & 3) * 2;
#pragma unroll
            for (int half = 0; half < 2; half++) {
                int c = c0 + half * 8;
                float v0 = acc[mt][nt][half*2+0], v1 = acc[mt][nt][half*2+1];
                int d0 = c - m0_, d1 = c - (m0_ + 1);
                float s0 = (d0 >= 0) ? v0 * ed[d0] : 0.f;
                float s1 = (d1 >= 0) ? v1 * ed[d1] : 0.f;
                __nv_bfloat16 h0 = __float2bfloat16(s0);
                __nv_bfloat16 h1 = __float2bfloat16(s1);
                __nv_bfloat16 l0 = __float2bfloat16(s0 - __bfloat162float(h0));
                __nv_bfloat16 l1 = __float2bfloat16(s1 - __bfloat162float(h1));
                int addr = c * 256 + (((m0_ >> 3) ^ (c & 7)) * 16) + ((m0_ * 2) & 15);
                *(uint32_t*)(sm + AT_SCHI + addr) = pack_bf2(h0, h1);
                *(uint32_t*)(sm + AT_SCLO + addr) = pack_bf2(l0, l1);
            }
        }
    }
    __syncthreads();

    // ---- o_intra = sc @ v : each warp 16 rows, N=32, K=128, 3 passes ----
    {
        float oacc[4][4];
#pragma unroll
        for (int nt = 0; nt < 4; nt++)
#pragma unroll
            for (int e = 0; e < 4; e++) oacc[nt][e] = 0.f;

        const int r0 = wid * 16;
        const uint32_t AB[3] = {sb + AT_SCHI, sb + AT_SCLO, sb + AT_SCHI};
        const uint32_t BV[3] = {sb + AT_VTHI, sb + AT_VTHI, sb + AT_VTLO};
#pragma unroll
        for (int p = 0; p < 3; p++) {
#pragma unroll
            for (int kk = 0; kk < 8; kk++) {
                uint32_t af[4];
                int row = r0 + (lane & 15);
                int ch = (kk * 2 + (lane >> 4)) ^ (row & 7);
                ldsm4(af, AB[p] + row * 256 + ch * 16);
                uint32_t bf[2][4];
#pragma unroll
                for (int nt2 = 0; nt2 < 2; nt2++) {
                    int g = lane >> 3, l8 = lane & 7;
                    int row2 = nt2 * 16 + (g >> 1) * 8 + l8;
                    int ch2 = (kk * 2 + (g & 1)) ^ (row2 & 7);
                    ldsm4(bf[nt2], BV[p] + row2 * 256 + ch2 * 16);
                }
#pragma unroll
                for (int nt = 0; nt < 4; nt++)
                    mma_bf16(oacc[nt], af, &bf[nt >> 1][(nt & 1) * 2]);
            }
        }
        int c = r0 + (lane >> 2);
#pragma unroll
        for (int nt = 0; nt < 4; nt++) {
            int e = nt * 8 + (lane & 3) * 2;
            size_t go = (tok0 + c) * CC + h*DD + e;
            *(float2*)&g_o[go]          = make_float2(oacc[nt][0], oacc[nt][1]);
            *(float2*)&g_o[go + 8*CC]   = make_float2(oacc[nt][2], oacc[nt][3]);
        }
    }

    // ---- C_n = kT_decay @ v : 32x32, K=128 split over warps 0-3, 3 passes ----
    if (wid < 4) {
        float cacc[2][4][4];
#pragma unroll
        for (int mt = 0; mt < 2; mt++)
#pragma unroll
            for (int nt = 0; nt < 4; nt++)
#pragma unroll
                for (int e = 0; e < 4; e++) cacc[mt][nt][e] = 0.f;

        const uint32_t KA[3] = {sb + AT_KTHI, sb + AT_KTLO, sb + AT_KTHI};
        const uint32_t VB[3] = {sb + AT_VTHI, sb + AT_VTHI, sb + AT_VTLO};
#pragma unroll
        for (int p = 0; p < 3; p++) {
#pragma unroll
            for (int kl = 0; kl < 2; kl++) {
                int kk = wid * 2 + kl;
                uint32_t af[2][4];
#pragma unroll
                for (int mt = 0; mt < 2; mt++) {
                    int row = mt * 16 + (lane & 15);
                    int ch = (kk * 2 + (lane >> 4)) ^ (row & 7);
                    ldsm4(af[mt], KA[p] + row * 256 + ch * 16);
                }
                uint32_t bf[2][4];
#pragma unroll
                for (int nt2 = 0; nt2 < 2; nt2++) {
                    int g = lane >> 3, l8 = lane & 7;
                    int row2 = nt2 * 16 + (g >> 1) * 8 + l8;
                    int ch2 = (kk * 2 + (g & 1)) ^ (row2 & 7);
                    ldsm4(bf[nt2], VB[p] + row2 * 256 + ch2 * 16);
                }
#pragma unroll
                for (int mt = 0; mt < 2; mt++)
#pragma unroll
                    for (int nt = 0; nt < 4; nt++)
                        mma_bf16(cacc[mt][nt], af[mt], &bf[nt >> 1][(nt & 1) * 2]);
            }
        }
        float* red = (float*)(sm + AT_CRED) + wid * 1024;
#pragma unroll
        for (int mt = 0; mt < 2; mt++) {
            int d = mt * 16 + (lane >> 2);
#pragma unroll
            for (int nt = 0; nt < 4; nt++) {
                int e = nt * 8 + (lane & 3) * 2;
                *(float2*)&red[d * 32 + e]       = make_float2(cacc[mt][nt][0], cacc[mt][nt][1]);
                *(float2*)&red[(d + 8) * 32 + e] = make_float2(cacc[mt][nt][2], cacc[mt][nt][3]);
            }
        }
    }
    __syncthreads();
    {
        const float* red = (const float*)(sm + AT_CRED);
        const size_t cb = ((size_t)((b*HH + h)*NC + n)) * 1024;
        for (int i = tid; i < 1024; i += 256)
            g_C[cb + i] = red[i] + red[1024 + i] + red[2048 + i] + red[3072 + i];
    }
}

// ======================= sequential KV scan (exclusive prefix) =======================
__global__ void kv_scan_kernel()
{
    const int bh = blockIdx.x;
    const int h = bh & 7;
    const int tid = threadIdx.x;
    const float bd = expf(-exp2f(-(float)(h+1)) * (float)CH);
    float4 kv = make_float4(0.f, 0.f, 0.f, 0.f);
    const size_t base = (size_t)bh * NC * 1024 + tid*4;
    for (int n = 0; n < NC; n++) {
        const size_t o = base + (size_t)n * 1024;
        *(float4*)&g_kvp[o] = kv;
        float4 c = *(const float4*)&g_C[o];
        kv.x = bd*kv.x + c.x; kv.y = bd*kv.y + c.y;
        kv.z = bd*kv.z + c.z; kv.w = bd*kv.w + c.w;
    }
}

// ======================= HMMA inter-chunk contribution =======================
__global__ void __launch_bounds__(256) attn_inter_hmma(
    const __nv_bfloat16* __restrict__ qh, const __nv_bfloat16* __restrict__ ql)
{
    const int n = blockIdx.x;
    if (n == 0) return;
    const int h = blockIdx.y, b = blockIdx.z;

    __shared__ __align__(16) char sm[8192*2 + 2048*2 + 1024];
    const int QHI = 0, QLO = 8192, KVHI = 16384, KVLO = 18432, EDO = 20480;
    float* ed = (float*)(sm + EDO);
    const uint32_t sb = smem_u32(sm);

    const int tid = threadIdx.x, lane = tid & 31, wid = tid >> 5;
    const float s = exp2f(-(float)(h+1));
    for (int i = tid; i < CH; i += 256) ed[i] = expf(-s * (float)i);

    const size_t tok0 = (size_t)(b*LL + n*CH);
    for (int i = tid; i < 512; i += 256) {
        int r = i >> 2, c = i & 3;
        uint4 v = *(const uint4*)(qh + (tok0 + r)*CC + h*DD + c*8);
        *(uint4*)(sm + QHI + r*64 + sw_chunk(r, c)*16) = v;
        uint4 w = *(const uint4*)(ql + (tok0 + r)*CC + h*DD + c*8);
        *(uint4*)(sm + QLO + r*64 + sw_chunk(r, c)*16) = w;
    }
    const size_t kb = ((size_t)((b*HH + h)*NC + n)) * 1024;
    for (int i = tid; i < 1024; i += 256) {
        int d = i >> 5, e = i & 31;
        float v = g_kvp[kb + i];
        __nv_bfloat16 hh = __float2bfloat16(v);
        __nv_bfloat16 ll = __float2bfloat16(v - __bfloat162float(hh));
        int a = e*64 + sw_chunk(e, d >> 3)*16 + (d & 7)*2;
        *(__nv_bfloat16*)(sm + KVHI + a) = hh;
        *(__nv_bfloat16*)(sm + KVLO + a) = ll;
    }
    __syncthreads();

    float acc[4][4];
#pragma unroll
    for (int nt = 0; nt < 4; nt++)
#pragma unroll
        for (int e = 0; e < 4; e++) acc[nt][e] = 0.f;

    const int r0 = wid * 16;
    const uint32_t QB[3] = {sb + QHI, sb + QLO, sb + QHI};
    const uint32_t KB[3] = {sb + KVHI, sb + KVHI, sb + KVLO};
#pragma unroll
    for (int p = 0; p < 3; p++) {
#pragma unroll
        for (int kk = 0; kk < 2; kk++) {
            uint32_t af[4];
            int row = r0 + (lane & 15);
            int ch = sw_chunk(row, kk * 2 + (lane >> 4));
            ldsm4(af, QB[p] + row * 64 + ch * 16);
            uint32_t bf[2][4];
#pragma unroll
            for (int nt2 = 0; nt2 < 2; nt2++) {
                int g = lane >> 3, l8 = lane & 7;
                int row2 = nt2 * 16 + (g >> 1) * 8 + l8;
                int ch2 = sw_chunk(row2, kk * 2 + (g & 1));
                ldsm4(bf[nt2], KB[p] + row2 * 64 + ch2 * 16);
            }
#pragma unroll
            for (int nt = 0; nt < 4; nt++)
                mma_bf16(acc[nt], af, &bf[nt >> 1][(nt & 1) * 2]);
        }
    }

    int c = r0 + (lane >> 2);
    float a0 = ed[c], a1 = ed[c + 8];
#pragma unroll
    for (int nt = 0; nt < 4; nt++) {
        int e = nt * 8 + (lane & 3) * 2;
        size_t go = (tok0 + c) * CC + h*DD + e;
        float2 o0 = *(float2*)&g_o[go];
        o0.x += a0 * acc[nt][0]; o0.y += a0 * acc[nt][1];
        *(float2*)&g_o[go] = o0;
        float2 o1 = *(float2*)&g_o[go + 8*CC];
        o1.x += a1 * acc[nt][2]; o1.y += a1 * acc[nt][3];
        *(float2*)&g_o[go + 8*CC] = o1;
    }
}

// ======================= launch =======================
extern "C" void kernel_launch(void* const* d_in, const int* in_sizes, int n_in,
                              void* d_out, int out_size)
{
    const float* x    = (const float*)d_in[0];
    const float* rel  = (const float*)d_in[1];
    const float* qkvw = (const float*)d_in[2];
    const float* qg   = (const float*)d_in[3];
    const float* kg   = (const float*)d_in[4];
    const float* pw   = (const float*)d_in[5];
    const float* pb   = (const float*)d_in[6];
    float* out = (float*)d_out;

    void* p_qkv = nullptr; cudaGetSymbolAddress(&p_qkv, g_qkv);
    void* p_o   = nullptr; cudaGetSymbolAddress(&p_o,   g_o);
    void* p_A2  = nullptr; cudaGetSymbolAddress(&p_A2,  g_A2);
    void* p_W1b = nullptr; cudaGetSymbolAddress(&p_W1b, g_W1b);
    void* p_W2b = nullptr; cudaGetSymbolAddress(&p_W2b, g_W2b);
    void* p_qh  = nullptr; cudaGetSymbolAddress(&p_qh,  g_qh);
    void* p_ql  = nullptr; cudaGetSymbolAddress(&p_ql,  g_ql);

    cudaFuncSetAttribute(attn_chunk_hmma,
                         cudaFuncAttributeMaxDynamicSharedMemorySize, AT_SMEM);

    // 1) split (x + rel_pos) and qkv_w into bf16 hi/lo triplets
    conv_act_kernel<<<TT*64/256, 256>>>(x, rel, (__nv_bfloat16*)p_A2, 1);
    conv_w_kernel<<<768*64/256, 256>>>(qkvw, (__nv_bfloat16*)p_W1b);

    // 2) qkv = A2 @ W1b^T  (HMMA bf16, K=768) -> fp32 g_qkv
    gemm_bf16_hmma<false><<<dim3(768/128, TT/128), 256>>>(
        (const __nv_bfloat16*)p_A2, (const __nv_bfloat16*)p_W1b, nullptr,
        (float*)p_qkv, 768);

    // 3) attention (HMMA intra + C_n), scan, HMMA inter
    attn_chunk_hmma<<<dim3(NC, HH, BB), 256, AT_SMEM>>>(
        qg, kg, (__nv_bfloat16*)p_qh, (__nv_bfloat16*)p_ql);
    kv_scan_kernel<<<BB*HH, 256>>>();
    attn_inter_hmma<<<dim3(NC, HH, BB), 256>>>(
        (const __nv_bfloat16*)p_qh, (const __nv_bfloat16*)p_ql);

    // 4) split attention output and proj_w
    conv_act_kernel<<<TT*64/256, 256>>>((const float*)p_o, nullptr, (__nv_bfloat16*)p_A2, 0);
    conv_w_kernel<<<256*64/256, 256>>>(pw, (__nv_bfloat16*)p_W2b);

    // 5) out = O2 @ W2b^T + bias
    gemm_bf16_hmma<true><<<dim3(256/128, TT/128), 256>>>(
        (const __nv_bfloat16*)p_A2, (const __nv_bfloat16*)p_W2b, pb,
        out, 256);
}

// round 6
// speedup vs baseline: 2.3019x; 1.2391x over previous
#include <cuda_runtime.h>
#include <cuda_bf16.h>
#include <math.h>
#include <stdint.h>

// Problem constants
#define BB 8
#define LL 4096
#define CC 256
#define HH 8
#define DD 32
#define CH 128
#define NC 32          // LL / CH
#define TT (BB*LL)     // 32768 tokens
#define KTOT 768

// ---------------- static device scratch (no allocations allowed) ----------------
__device__ float g_qkv[(size_t)TT * 768];                 // qkv per token (fp32)
__device__ float g_o  [(size_t)TT * CC];                  // attention output (intra)
__device__ float g_C  [(size_t)BB*HH*NC * DD*DD];         // per-chunk KV contributions
__device__ float g_kvp[(size_t)BB*HH*NC * DD*DD];         // exclusive KV prefixes
__device__ __nv_bfloat16 g_A2 [(size_t)TT * 768];         // [hi, lo, hi] activations
__device__ __nv_bfloat16 g_W1b[(size_t)768 * 768];        // [hi, hi, lo] qkv weight
__device__ __nv_bfloat16 g_W2b[(size_t)256 * 768];        // [hi, hi, lo] proj weight
__device__ __nv_bfloat16 g_qh [(size_t)TT * CC];          // normalized q hat (hi)
__device__ __nv_bfloat16 g_ql [(size_t)TT * CC];          // normalized q hat (lo)

// =========================== small PTX helpers ===========================
__device__ __forceinline__ uint32_t smem_u32(const void* p) {
    uint32_t a;
    asm("{ .reg .u64 t; cvta.to.shared.u64 t, %1; cvt.u32.u64 %0, t; }" : "=r"(a) : "l"(p));
    return a;
}
__device__ __forceinline__ void cpasync16(uint32_t dst, const void* src) {
    asm volatile("cp.async.cg.shared.global [%0], [%1], 16;" :: "r"(dst), "l"(src));
}
__device__ __forceinline__ void cp_commit() {
    asm volatile("cp.async.commit_group;" ::: "memory");
}
template<int N>
__device__ __forceinline__ void cp_wait() {
    asm volatile("cp.async.wait_group %0;" :: "n"(N) : "memory");
}
__device__ __forceinline__ void ldsm4(uint32_t* r, uint32_t addr) {
    asm volatile("ldmatrix.sync.aligned.m8n8.x4.shared.b16 {%0,%1,%2,%3}, [%4];"
                 : "=r"(r[0]), "=r"(r[1]), "=r"(r[2]), "=r"(r[3]) : "r"(addr));
}
__device__ __forceinline__ void mma_bf16(float* c, const uint32_t* a, const uint32_t* b) {
    asm volatile("mma.sync.aligned.m16n8k16.row.col.f32.bf16.bf16.f32 "
                 "{%0,%1,%2,%3}, {%4,%5,%6,%7}, {%8,%9}, {%0,%1,%2,%3};"
                 : "+f"(c[0]), "+f"(c[1]), "+f"(c[2]), "+f"(c[3])
                 : "r"(a[0]), "r"(a[1]), "r"(a[2]), "r"(a[3]), "r"(b[0]), "r"(b[1]));
}
// xor swizzle of 16B chunk index within a 64B row (4 chunks)
__device__ __forceinline__ int sw_chunk(int r, int c) {
    return c ^ (r & 3) ^ ((r >> 2) & 1);
}
__device__ __forceinline__ uint32_t pack_bf2(__nv_bfloat16 a, __nv_bfloat16 b) {
    uint32_t lo16 = *(uint16_t*)&a, hi16 = *(uint16_t*)&b;
    return lo16 | (hi16 << 16);
}

// =========================== hi/lo split conversion kernels ===========================
__global__ void conv_act_kernel(const float* __restrict__ x, const float* __restrict__ rp,
                                __nv_bfloat16* __restrict__ A2, int fuse_rel)
{
    int idx = blockIdx.x * 256 + threadIdx.x;
    int m = idx >> 6, c4 = (idx & 63) << 2;
    float4 h = *(const float4*)&x[(size_t)m * 256 + c4];
    if (fuse_rel) {
        float4 r = *(const float4*)&rp[(size_t)(m & (LL-1)) * 256 + c4];
        h.x += r.x; h.y += r.y; h.z += r.z; h.w += r.w;
    }
    float hv[4] = {h.x, h.y, h.z, h.w};
    __nv_bfloat16 hi[4], lo[4];
#pragma unroll
    for (int j = 0; j < 4; j++) {
        hi[j] = __float2bfloat16(hv[j]);
        lo[j] = __float2bfloat16(hv[j] - __bfloat162float(hi[j]));
    }
    size_t base = (size_t)m * 768 + c4;
    *(uint2*)&A2[base]       = *(uint2*)hi;
    *(uint2*)&A2[base + 256] = *(uint2*)lo;
    *(uint2*)&A2[base + 512] = *(uint2*)hi;
}

__global__ void conv_w_kernel(const float* __restrict__ W, __nv_bfloat16* __restrict__ W2)
{
    int idx = blockIdx.x * 256 + threadIdx.x;
    int n = idx >> 6, c4 = (idx & 63) << 2;
    float4 h = *(const float4*)&W[(size_t)n * 256 + c4];
    float hv[4] = {h.x, h.y, h.z, h.w};
    __nv_bfloat16 hi[4], lo[4];
#pragma unroll
    for (int j = 0; j < 4; j++) {
        hi[j] = __float2bfloat16(hv[j]);
        lo[j] = __float2bfloat16(hv[j] - __bfloat162float(hi[j]));
    }
    size_t base = (size_t)n * 768 + c4;
    *(uint2*)&W2[base]       = *(uint2*)hi;
    *(uint2*)&W2[base + 256] = *(uint2*)hi;
    *(uint2*)&W2[base + 512] = *(uint2*)lo;
}

// =========================== HMMA bf16 GEMM: C = A2 @ W2^T (+bias) ===========================
#define NSTG (KTOT/32)   // 24

template<bool BIAS>
__global__ void __launch_bounds__(256, 2) gemm_bf16_hmma(
    const __nv_bfloat16* __restrict__ A,
    const __nv_bfloat16* __restrict__ Bw,
    const float* __restrict__ bias,
    float* __restrict__ Cmat, int Ntot)
{
    __shared__ __align__(16) __nv_bfloat16 As[2][128][32];
    __shared__ __align__(16) __nv_bfloat16 Bs[2][128][32];

    const int tid = threadIdx.x;
    const int wid = tid >> 5, lane = tid & 31;
    const int warp_m = wid & 1, warp_n = wid >> 1;
    const int m0 = blockIdx.y * 128;
    const int n0 = blockIdx.x * 128;

    const uint32_t as_base = smem_u32(As);
    const uint32_t bs_base = smem_u32(Bs);

    float acc[4][4][4];
#pragma unroll
    for (int mt = 0; mt < 4; mt++)
#pragma unroll
        for (int nt = 0; nt < 4; nt++)
#pragma unroll
            for (int e = 0; e < 4; e++) acc[mt][nt][e] = 0.f;

    const int lr = tid >> 2;
    const int lc = tid & 3;

    auto load_stage = [&](int s, int b) {
#pragma unroll
        for (int l = 0; l < 2; l++) {
            int r = lr + l * 64;
            int ch = sw_chunk(r, lc);
            const __nv_bfloat16* asrc = A  + (size_t)(m0 + r) * KTOT + s * 32 + lc * 8;
            const __nv_bfloat16* bsrc = Bw + (size_t)(n0 + r) * KTOT + s * 32 + lc * 8;
            cpasync16(as_base + (b * 128 + r) * 64 + ch * 16, asrc);
            cpasync16(bs_base + (b * 128 + r) * 64 + ch * 16, bsrc);
        }
    };

    load_stage(0, 0);
    cp_commit();

    for (int i = 0; i < NSTG; i++) {
        const int b = i & 1;
        if (i + 1 < NSTG) {
            load_stage(i + 1, (i + 1) & 1);
            cp_commit();
            cp_wait<1>();
        } else {
            cp_wait<0>();
        }
        __syncthreads();

#pragma unroll
        for (int kk = 0; kk < 2; kk++) {
            uint32_t af[4][4];
#pragma unroll
            for (int mt = 0; mt < 4; mt++) {
                int row = warp_m * 64 + mt * 16 + (lane & 15);
                int ch = sw_chunk(row, kk * 2 + (lane >> 4));
                ldsm4(af[mt], as_base + (b * 128 + row) * 64 + ch * 16);
            }
            uint32_t bf[2][4];
#pragma unroll
            for (int nt2 = 0; nt2 < 2; nt2++) {
                int g = lane >> 3, l8 = lane & 7;
                int row = warp_n * 32 + nt2 * 16 + (g >> 1) * 8 + l8;
                int ch = sw_chunk(row, kk * 2 + (g & 1));
                ldsm4(bf[nt2], bs_base + (b * 128 + row) * 64 + ch * 16);
            }
#pragma unroll
            for (int mt = 0; mt < 4; mt++)
#pragma unroll
                for (int nt = 0; nt < 4; nt++)
                    mma_bf16(acc[mt][nt], af[mt], &bf[nt >> 1][(nt & 1) * 2]);
        }
        __syncthreads();
    }

#pragma unroll
    for (int mt = 0; mt < 4; mt++) {
        int row = m0 + warp_m * 64 + mt * 16 + (lane >> 2);
#pragma unroll
        for (int nt = 0; nt < 4; nt++) {
            int col = n0 + warp_n * 32 + nt * 8 + (lane & 3) * 2;
            float2 v0 = make_float2(acc[mt][nt][0], acc[mt][nt][1]);
            float2 v1 = make_float2(acc[mt][nt][2], acc[mt][nt][3]);
            if (BIAS) {
                float2 bv = *(const float2*)&bias[col];
                v0.x += bv.x; v0.y += bv.y;
                v1.x += bv.x; v1.y += bv.y;
            }
            *(float2*)&Cmat[(size_t)row * Ntot + col]       = v0;
            *(float2*)&Cmat[(size_t)(row + 8) * Ntot + col] = v1;
        }
    }
}

// ======================= HMMA attention: intra + per-chunk KV contribution =======================
// smem layout (bytes); total 98 KB -> 2 CTAs/SM
#define AT_ED   0                     // 129 floats
#define AT_NQ   640
#define AT_NK   1152
#define AT_QHI  2048
#define AT_QLO  (AT_QHI  + 8192)
#define AT_KHI  (AT_QLO  + 8192)
#define AT_KLO  (AT_KHI  + 8192)
#define AT_KTHI (AT_KLO  + 8192)
#define AT_KTLO (AT_KTHI + 8192)
#define AT_VTHI (AT_KTLO + 8192)
#define AT_VTLO (AT_VTHI + 8192)
#define AT_SC0H (AT_VTLO + 8192)      // 128 rows x 128 B
#define AT_SC0L (AT_SC0H + 16384)
#define AT_SMEM (AT_SC0L + 16384)     // 100352 bytes
// aliases (regions dead by the time they're reused)
#define AT_SC1H AT_QHI                // 64 rows x 128 B
#define AT_SC1L AT_QLO
#define AT_CRED AT_KHI                // 16 KB: 4 warps x 4 KB

__global__ void __launch_bounds__(256, 2) attn_chunk_hmma(
    const float* __restrict__ qg, const float* __restrict__ kg,
    __nv_bfloat16* __restrict__ qhout, __nv_bfloat16* __restrict__ qlout)
{
    extern __shared__ char sm[];
    float* ed = (float*)(sm + AT_ED);
    float* nq = (float*)(sm + AT_NQ);
    float* nk = (float*)(sm + AT_NK);
    const uint32_t sb = smem_u32(sm);

    const int n = blockIdx.x, h = blockIdx.y, b = blockIdx.z;
    const int tid = threadIdx.x, lane = tid & 31, wid = tid >> 5;
    const float s = exp2f(-(float)(h + 1));
    for (int i = tid; i <= CH; i += 256) ed[i] = expf(-s * (float)i);

    const size_t tok0 = (size_t)(b*LL + n*CH);
    const size_t base = tok0 * 768 + h*DD;
    const int c4 = (tid & 7) * 4;

    // ---- P1: load q,k (norm partial sums) + convert v -> VT hi/lo ----
    float sq[4], sk[4];
#pragma unroll
    for (int l = 0; l < 4; l++) {
        int r = (tid >> 3) + l * 32;
        const float* rowp = &g_qkv[base + (size_t)r * 768 + c4];
        float4 a  = *(const float4*)(rowp);
        float4 bb = *(const float4*)(rowp + 256);
        float4 cc = *(const float4*)(rowp + 512);
        sq[l] = a.x*a.x + a.y*a.y + a.z*a.z + a.w*a.w;
        sk[l] = bb.x*bb.x + bb.y*bb.y + bb.z*bb.z + bb.w*bb.w;
        float vv[4] = {cc.x, cc.y, cc.z, cc.w};
#pragma unroll
        for (int j = 0; j < 4; j++) {
            int d = c4 + j;
            __nv_bfloat16 vh = __float2bfloat16(vv[j]);
            __nv_bfloat16 vl = __float2bfloat16(vv[j] - __bfloat162float(vh));
            int aT = d*256 + (((r >> 3) ^ (d & 7)) * 16) + ((r & 7) * 2);
            *(__nv_bfloat16*)(sm + AT_VTHI + aT) = vh;
            *(__nv_bfloat16*)(sm + AT_VTLO + aT) = vl;
        }
    }
#pragma unroll
    for (int m = 1; m < 8; m <<= 1) {
#pragma unroll
        for (int l = 0; l < 4; l++) {
            sq[l] += __shfl_xor_sync(0xffffffffu, sq[l], m);
            sk[l] += __shfl_xor_sync(0xffffffffu, sk[l], m);
        }
    }
    if ((tid & 7) == 0) {
        const float sqD = 5.656854249492380f;
#pragma unroll
        for (int l = 0; l < 4; l++) {
            int r = (tid >> 3) + l * 32;
            nq[r] = (sq[l] > 1e-24f) ? sqD * rsqrtf(sq[l]) : sqD * 1e12f;
            nk[r] = (sk[l] > 1e-24f) ? sqD * rsqrtf(sk[l]) : sqD * 1e12f;
        }
    }
    __syncthreads();

    // ---- P2: convert q,k (re-read gmem; L2-hot) ----
    float gq[4], gk[4];
#pragma unroll
    for (int j = 0; j < 4; j++) {
        gq[j] = __ldg(&qg[h*DD + c4 + j]);
        gk[j] = __ldg(&kg[h*DD + c4 + j]);
    }
#pragma unroll
    for (int l = 0; l < 4; l++) {
        int r = (tid >> 3) + l * 32;
        const float* rowp = &g_qkv[base + (size_t)r * 768 + c4];
        float4 a  = *(const float4*)(rowp);
        float4 bb = *(const float4*)(rowp + 256);
        float rq = nq[r], rk = nk[r], dk = ed[CH - r];
        float qv[4] = {a.x, a.y, a.z, a.w};
        float kv[4] = {bb.x, bb.y, bb.z, bb.w};
        __nv_bfloat16 qh4[4], ql4[4], kh4[4], kl4[4];
#pragma unroll
        for (int j = 0; j < 4; j++) {
            int d = c4 + j;
            float qn = qv[j] * rq * gq[j];
            float kn = kv[j] * rk * gk[j];
            qh4[j] = __float2bfloat16(qn);
            ql4[j] = __float2bfloat16(qn - __bfloat162float(qh4[j]));
            kh4[j] = __float2bfloat16(kn);
            kl4[j] = __float2bfloat16(kn - __bfloat162float(kh4[j]));
            float kt = kn * dk;
            __nv_bfloat16 kth = __float2bfloat16(kt);
            __nv_bfloat16 ktl = __float2bfloat16(kt - __bfloat162float(kth));
            int aT = d*256 + (((r >> 3) ^ (d & 7)) * 16) + ((r & 7) * 2);
            *(__nv_bfloat16*)(sm + AT_KTHI + aT) = kth;
            *(__nv_bfloat16*)(sm + AT_KTLO + aT) = ktl;
        }
        int a64 = r*64 + sw_chunk(r, c4 >> 3) * 16 + ((c4 & 7) * 2);
        *(uint2*)(sm + AT_QHI + a64) = *(uint2*)qh4;
        *(uint2*)(sm + AT_QLO + a64) = *(uint2*)ql4;
        *(uint2*)(sm + AT_KHI + a64) = *(uint2*)kh4;
        *(uint2*)(sm + AT_KLO + a64) = *(uint2*)kl4;
        *(uint2*)(qhout + (tok0 + r)*CC + h*DD + c4) = *(uint2*)qh4;
        *(uint2*)(qlout + (tok0 + r)*CC + h*DD + c4) = *(uint2*)ql4;
    }
    __syncthreads();

    const uint32_t QB[3] = {sb + AT_QHI, sb + AT_QLO, sb + AT_QHI};
    const uint32_t KB[3] = {sb + AT_KHI, sb + AT_KHI, sb + AT_KLO};
    const uint32_t BV[3] = {sb + AT_VTHI, sb + AT_VTHI, sb + AT_VTLO};
    const int g = lane >> 3, l8 = lane & 7;

    // ---- P3: scores half0  S[:, 0:64]  (all 128 rows) ----
    float acc0[8][4];
#pragma unroll
    for (int nt = 0; nt < 8; nt++)
#pragma unroll
        for (int e = 0; e < 4; e++) acc0[nt][e] = 0.f;
#pragma unroll
    for (int p = 0; p < 3; p++) {
#pragma unroll
        for (int kk = 0; kk < 2; kk++) {
            uint32_t af[4];
            int row = wid * 16 + (lane & 15);
            ldsm4(af, QB[p] + row * 64 + sw_chunk(row, kk * 2 + (lane >> 4)) * 16);
            uint32_t bf[4][4];
#pragma unroll
            for (int nt2 = 0; nt2 < 4; nt2++) {
                int row2 = nt2 * 16 + (g >> 1) * 8 + l8;
                ldsm4(bf[nt2], KB[p] + row2 * 64 + sw_chunk(row2, kk * 2 + (g & 1)) * 16);
            }
#pragma unroll
            for (int nt = 0; nt < 8; nt++)
                mma_bf16(acc0[nt], af, &bf[nt >> 1][(nt & 1) * 2]);
        }
    }
    // mask + decay + write sc0
    {
        int c_lo = wid * 16 + (lane >> 2);
#pragma unroll
        for (int nt = 0; nt < 8; nt++) {
            int mm = nt * 8 + (lane & 3) * 2;
#pragma unroll
            for (int half = 0; half < 2; half++) {
                int c = c_lo + half * 8;
                float v0 = acc0[nt][half*2+0], v1 = acc0[nt][half*2+1];
                int d0 = c - mm, d1 = c - mm - 1;
                float s0 = (d0 >= 0) ? v0 * ed[d0] : 0.f;
                float s1 = (d1 >= 0) ? v1 * ed[d1] : 0.f;
                __nv_bfloat16 h0 = __float2bfloat16(s0);
                __nv_bfloat16 h1 = __float2bfloat16(s1);
                __nv_bfloat16 l0 = __float2bfloat16(s0 - __bfloat162float(h0));
                __nv_bfloat16 l1 = __float2bfloat16(s1 - __bfloat162float(h1));
                int addr = c * 128 + (((mm >> 3) ^ (c & 7)) * 16) + ((mm * 2) & 15);
                *(uint32_t*)(sm + AT_SC0H + addr) = pack_bf2(h0, h1);
                *(uint32_t*)(sm + AT_SC0L + addr) = pack_bf2(l0, l1);
            }
        }
    }
    __syncthreads();

    // ---- P4: o_intra part A (K = 0..64, all rows) ----
    float oacc[4][4];
#pragma unroll
    for (int nt = 0; nt < 4; nt++)
#pragma unroll
        for (int e = 0; e < 4; e++) oacc[nt][e] = 0.f;
    {
        const uint32_t AB[3] = {sb + AT_SC0H, sb + AT_SC0L, sb + AT_SC0H};
        const int r0 = wid * 16;
#pragma unroll
        for (int p = 0; p < 3; p++) {
#pragma unroll
            for (int kk = 0; kk < 4; kk++) {
                uint32_t af[4];
                int row = r0 + (lane & 15);
                int ch = (kk * 2 + (lane >> 4)) ^ (row & 7);
                ldsm4(af, AB[p] + row * 128 + ch * 16);
                uint32_t bf[2][4];
#pragma unroll
                for (int nt2 = 0; nt2 < 2; nt2++) {
                    int row2 = nt2 * 16 + (g >> 1) * 8 + l8;
                    int ch2 = (kk * 2 + (g & 1)) ^ (row2 & 7);
                    ldsm4(bf[nt2], BV[p] + row2 * 256 + ch2 * 16);
                }
#pragma unroll
                for (int nt = 0; nt < 4; nt++)
                    mma_bf16(oacc[nt], af, &bf[nt >> 1][(nt & 1) * 2]);
            }
        }
    }
    // rows 0..63 are complete (cols 64+ masked to zero) -> store now
    if (wid < 4) {
        int c = wid * 16 + (lane >> 2);
#pragma unroll
        for (int nt = 0; nt < 4; nt++) {
            int e = nt * 8 + (lane & 3) * 2;
            size_t go = (tok0 + c) * CC + h*DD + e;
            *(float2*)&g_o[go]        = make_float2(oacc[nt][0], oacc[nt][1]);
            *(float2*)&g_o[go + 8*CC] = make_float2(oacc[nt][2], oacc[nt][3]);
        }
    }

    // ---- P5: scores half1  S[64:128, 64:128]  (all 8 warps) ----
    float acc1[4][4];
#pragma unroll
    for (int nt = 0; nt < 4; nt++)
#pragma unroll
        for (int e = 0; e < 4; e++) acc1[nt][e] = 0.f;
    const int c0s = 64 + (wid & 3) * 16;
    const int mbs = 64 + (wid >> 2) * 32;
#pragma unroll
    for (int p = 0; p < 3; p++) {
#pragma unroll
        for (int kk = 0; kk < 2; kk++) {
            uint32_t af[4];
            int row = c0s + (lane & 15);
            ldsm4(af, QB[p] + row * 64 + sw_chunk(row, kk * 2 + (lane >> 4)) * 16);
            uint32_t bf[2][4];
#pragma unroll
            for (int nt2 = 0; nt2 < 2; nt2++) {
                int row2 = mbs + nt2 * 16 + (g >> 1) * 8 + l8;
                ldsm4(bf[nt2], KB[p] + row2 * 64 + sw_chunk(row2, kk * 2 + (g & 1)) * 16);
            }
#pragma unroll
            for (int nt = 0; nt < 4; nt++)
                mma_bf16(acc1[nt], af, &bf[nt >> 1][(nt & 1) * 2]);
        }
    }
    __syncthreads();   // all Q/K fragment reads done; QHI/QLO become sc1

    {
        int c_lo = c0s + (lane >> 2);
#pragma unroll
        for (int nt = 0; nt < 4; nt++) {
            int mm = mbs + nt * 8 + (lane & 3) * 2;
#pragma unroll
            for (int half = 0; half < 2; half++) {
                int c = c_lo + half * 8;
                float v0 = acc1[nt][half*2+0], v1 = acc1[nt][half*2+1];
                int d0 = c - mm, d1 = c - mm - 1;
                float s0 = (d0 >= 0) ? v0 * ed[d0] : 0.f;
                float s1 = (d1 >= 0) ? v1 * ed[d1] : 0.f;
                __nv_bfloat16 h0 = __float2bfloat16(s0);
                __nv_bfloat16 h1 = __float2bfloat16(s1);
                __nv_bfloat16 l0 = __float2bfloat16(s0 - __bfloat162float(h0));
                __nv_bfloat16 l1 = __float2bfloat16(s1 - __bfloat162float(h1));
                int cr = c - 64, mr = mm - 64;
                int addr = cr * 128 + (((mr >> 3) ^ (cr & 7)) * 16) + ((mr * 2) & 15);
                *(uint32_t*)(sm + AT_SC1H + addr) = pack_bf2(h0, h1);
                *(uint32_t*)(sm + AT_SC1L + addr) = pack_bf2(l0, l1);
            }
        }
    }
    __syncthreads();

    // ---- P6: warps 4-7: o_intra part B (rows 64..127, K=64..128); warps 0-3: C_n ----
    if (wid >= 4) {
        const uint32_t AB1[3] = {sb + AT_SC1H, sb + AT_SC1L, sb + AT_SC1H};
        const int r0 = (wid - 4) * 16;
#pragma unroll
        for (int p = 0; p < 3; p++) {
#pragma unroll
            for (int kk = 0; kk < 4; kk++) {
                uint32_t af[4];
                int row = r0 + (lane & 15);
                int ch = (kk * 2 + (lane >> 4)) ^ (row & 7);
                ldsm4(af, AB1[p] + row * 128 + ch * 16);
                uint32_t bf[2][4];
#pragma unroll
                for (int nt2 = 0; nt2 < 2; nt2++) {
                    int row2 = nt2 * 16 + (g >> 1) * 8 + l8;
                    int ch2 = ((kk + 4) * 2 + (g & 1)) ^ (row2 & 7);
                    ldsm4(bf[nt2], BV[p] + row2 * 256 + ch2 * 16);
                }
#pragma unroll
                for (int nt = 0; nt < 4; nt++)
                    mma_bf16(oacc[nt], af, &bf[nt >> 1][(nt & 1) * 2]);
            }
        }
        int c = wid * 16 + (lane >> 2);
#pragma unroll
        for (int nt = 0; nt < 4; nt++) {
            int e = nt * 8 + (lane & 3) * 2;
            size_t go = (tok0 + c) * CC + h*DD + e;
            *(float2*)&g_o[go]        = make_float2(oacc[nt][0], oacc[nt][1]);
            *(float2*)&g_o[go + 8*CC] = make_float2(oacc[nt][2], oacc[nt][3]);
        }
    } else {
        float cacc[2][4][4];
#pragma unroll
        for (int mt = 0; mt < 2; mt++)
#pragma unroll
            for (int nt = 0; nt < 4; nt++)
#pragma unroll
                for (int e = 0; e < 4; e++) cacc[mt][nt][e] = 0.f;

        const uint32_t KA[3] = {sb + AT_KTHI, sb + AT_KTLO, sb + AT_KTHI};
#pragma unroll
        for (int p = 0; p < 3; p++) {
#pragma unroll
            for (int kl = 0; kl < 2; kl++) {
                int kk = wid * 2 + kl;
                uint32_t af[2][4];
#pragma unroll
                for (int mt = 0; mt < 2; mt++) {
                    int row = mt * 16 + (lane & 15);
                    int ch = (kk * 2 + (lane >> 4)) ^ (row & 7);
                    ldsm4(af[mt], KA[p] + row * 256 + ch * 16);
                }
                uint32_t bf[2][4];
#pragma unroll
                for (int nt2 = 0; nt2 < 2; nt2++) {
                    int row2 = nt2 * 16 + (g >> 1) * 8 + l8;
                    int ch2 = (kk * 2 + (g & 1)) ^ (row2 & 7);
                    ldsm4(bf[nt2], BV[p] + row2 * 256 + ch2 * 16);
                }
#pragma unroll
                for (int mt = 0; mt < 2; mt++)
#pragma unroll
                    for (int nt = 0; nt < 4; nt++)
                        mma_bf16(cacc[mt][nt], af[mt], &bf[nt >> 1][(nt & 1) * 2]);
            }
        }
        float* red = (float*)(sm + AT_CRED) + wid * 1024;
#pragma unroll
        for (int mt = 0; mt < 2; mt++) {
            int d = mt * 16 + (lane >> 2);
#pragma unroll
            for (int nt = 0; nt < 4; nt++) {
                int e = nt * 8 + (lane & 3) * 2;
                *(float2*)&red[d * 32 + e]       = make_float2(cacc[mt][nt][0], cacc[mt][nt][1]);
                *(float2*)&red[(d + 8) * 32 + e] = make_float2(cacc[mt][nt][2], cacc[mt][nt][3]);
            }
        }
    }
    __syncthreads();
    {
        const float* red = (const float*)(sm + AT_CRED);
        const size_t cb = ((size_t)((b*HH + h)*NC + n)) * 1024;
        for (int i = tid; i < 1024; i += 256)
            g_C[cb + i] = red[i] + red[1024 + i] + red[2048 + i] + red[3072 + i];
    }
}

// ======================= sequential KV scan (exclusive prefix) =======================
__global__ void kv_scan_kernel()
{
    const int bh = blockIdx.x;
    const int h = bh & 7;
    const int tid = threadIdx.x;
    const float bd = expf(-exp2f(-(float)(h+1)) * (float)CH);
    float4 kv = make_float4(0.f, 0.f, 0.f, 0.f);
    const size_t base = (size_t)bh * NC * 1024 + tid*4;
    for (int n = 0; n < NC; n++) {
        const size_t o = base + (size_t)n * 1024;
        *(float4*)&g_kvp[o] = kv;
        float4 c = *(const float4*)&g_C[o];
        kv.x = bd*kv.x + c.x; kv.y = bd*kv.y + c.y;
        kv.z = bd*kv.z + c.z; kv.w = bd*kv.w + c.w;
    }
}

// ======================= HMMA inter-chunk + fused hi/lo split of o -> A2 =======================
__global__ void __launch_bounds__(256) attn_inter_hmma(
    const __nv_bfloat16* __restrict__ qh, const __nv_bfloat16* __restrict__ ql,
    __nv_bfloat16* __restrict__ A2)
{
    const int n = blockIdx.x;
    const int h = blockIdx.y, b = blockIdx.z;

    __shared__ __align__(16) char sm[8192*2 + 2048*2 + 1024];
    const int QHI = 0, QLO = 8192, KVHI = 16384, KVLO = 18432, EDO = 20480;
    float* ed = (float*)(sm + EDO);
    const uint32_t sb = smem_u32(sm);

    const int tid = threadIdx.x, lane = tid & 31, wid = tid >> 5;
    const float s = exp2f(-(float)(h+1));
    for (int i = tid; i < CH; i += 256) ed[i] = expf(-s * (float)i);

    const size_t tok0 = (size_t)(b*LL + n*CH);
    for (int i = tid; i < 512; i += 256) {
        int r = i >> 2, c = i & 3;
        uint4 v = *(const uint4*)(qh + (tok0 + r)*CC + h*DD + c*8);
        *(uint4*)(sm + QHI + r*64 + sw_chunk(r, c)*16) = v;
        uint4 w = *(const uint4*)(ql + (tok0 + r)*CC + h*DD + c*8);
        *(uint4*)(sm + QLO + r*64 + sw_chunk(r, c)*16) = w;
    }
    const size_t kb = ((size_t)((b*HH + h)*NC + n)) * 1024;
    for (int i = tid; i < 1024; i += 256) {
        int d = i >> 5, e = i & 31;
        float v = g_kvp[kb + i];
        __nv_bfloat16 hh = __float2bfloat16(v);
        __nv_bfloat16 ll = __float2bfloat16(v - __bfloat162float(hh));
        int a = e*64 + sw_chunk(e, d >> 3)*16 + (d & 7)*2;
        *(__nv_bfloat16*)(sm + KVHI + a) = hh;
        *(__nv_bfloat16*)(sm + KVLO + a) = ll;
    }
    __syncthreads();

    float acc[4][4];
#pragma unroll
    for (int nt = 0; nt < 4; nt++)
#pragma unroll
        for (int e = 0; e < 4; e++) acc[nt][e] = 0.f;

    const int r0 = wid * 16;
    const uint32_t QB[3] = {sb + QHI, sb + QLO, sb + QHI};
    const uint32_t KB[3] = {sb + KVHI, sb + KVHI, sb + KVLO};
#pragma unroll
    for (int p = 0; p < 3; p++) {
#pragma unroll
        for (int kk = 0; kk < 2; kk++) {
            uint32_t af[4];
            int row = r0 + (lane & 15);
            int ch = sw_chunk(row, kk * 2 + (lane >> 4));
            ldsm4(af, QB[p] + row * 64 + ch * 16);
            uint32_t bf[2][4];
#pragma unroll
            for (int nt2 = 0; nt2 < 2; nt2++) {
                int g = lane >> 3, l8 = lane & 7;
                int row2 = nt2 * 16 + (g >> 1) * 8 + l8;
                int ch2 = sw_chunk(row2, kk * 2 + (g & 1));
                ldsm4(bf[nt2], KB[p] + row2 * 64 + ch2 * 16);
            }
#pragma unroll
            for (int nt = 0; nt < 4; nt++)
                mma_bf16(acc[nt], af, &bf[nt >> 1][(nt & 1) * 2]);
        }
    }

    int c = r0 + (lane >> 2);
    float a0 = ed[c], a1 = ed[c + 8];
#pragma unroll
    for (int nt = 0; nt < 4; nt++) {
        int e = nt * 8 + (lane & 3) * 2;
#pragma unroll
        for (int half = 0; half < 2; half++) {
            int cc2 = c + half * 8;
            float al = half ? a1 : a0;
            size_t go = (tok0 + cc2) * CC + h*DD + e;
            float2 o0 = *(float2*)&g_o[go];
            o0.x += al * acc[nt][half*2+0];
            o0.y += al * acc[nt][half*2+1];
            __nv_bfloat16 h0 = __float2bfloat16(o0.x);
            __nv_bfloat16 h1 = __float2bfloat16(o0.y);
            __nv_bfloat16 l0 = __float2bfloat16(o0.x - __bfloat162float(h0));
            __nv_bfloat16 l1 = __float2bfloat16(o0.y - __bfloat162float(h1));
            size_t a2b = (tok0 + cc2) * 768 + h*DD + e;
            uint32_t ph = pack_bf2(h0, h1);
            *(uint32_t*)&A2[a2b]       = ph;
            *(uint32_t*)&A2[a2b + 256] = pack_bf2(l0, l1);
            *(uint32_t*)&A2[a2b + 512] = ph;
        }
    }
}

// ======================= launch =======================
extern "C" void kernel_launch(void* const* d_in, const int* in_sizes, int n_in,
                              void* d_out, int out_size)
{
    const float* x    = (const float*)d_in[0];
    const float* rel  = (const float*)d_in[1];
    const float* qkvw = (const float*)d_in[2];
    const float* qg   = (const float*)d_in[3];
    const float* kg   = (const float*)d_in[4];
    const float* pw   = (const float*)d_in[5];
    const float* pb   = (const float*)d_in[6];
    float* out = (float*)d_out;

    void* p_qkv = nullptr; cudaGetSymbolAddress(&p_qkv, g_qkv);
    void* p_A2  = nullptr; cudaGetSymbolAddress(&p_A2,  g_A2);
    void* p_W1b = nullptr; cudaGetSymbolAddress(&p_W1b, g_W1b);
    void* p_W2b = nullptr; cudaGetSymbolAddress(&p_W2b, g_W2b);
    void* p_qh  = nullptr; cudaGetSymbolAddress(&p_qh,  g_qh);
    void* p_ql  = nullptr; cudaGetSymbolAddress(&p_ql,  g_ql);

    cudaFuncSetAttribute(attn_chunk_hmma,
                         cudaFuncAttributeMaxDynamicSharedMemorySize, AT_SMEM);

    // 1) split (x + rel_pos) and weights into bf16 hi/lo triplets
    conv_act_kernel<<<TT*64/256, 256>>>(x, rel, (__nv_bfloat16*)p_A2, 1);
    conv_w_kernel<<<768*64/256, 256>>>(qkvw, (__nv_bfloat16*)p_W1b);
    conv_w_kernel<<<256*64/256, 256>>>(pw, (__nv_bfloat16*)p_W2b);

    // 2) qkv = A2 @ W1b^T  (HMMA bf16, K=768) -> fp32 g_qkv
    gemm_bf16_hmma<false><<<dim3(768/128, TT/128), 256>>>(
        (const __nv_bfloat16*)p_A2, (const __nv_bfloat16*)p_W1b, nullptr,
        (float*)p_qkv, 768);

    // 3) attention: intra + C_n, scan, inter (writes A2 triplet directly)
    attn_chunk_hmma<<<dim3(NC, HH, BB), 256, AT_SMEM>>>(
        qg, kg, (__nv_bfloat16*)p_qh, (__nv_bfloat16*)p_ql);
    kv_scan_kernel<<<BB*HH, 256>>>();
    attn_inter_hmma<<<dim3(NC, HH, BB), 256>>>(
        (const __nv_bfloat16*)p_qh, (const __nv_bfloat16*)p_ql,
        (__nv_bfloat16*)p_A2);

    // 4) out = O2 @ W2b^T + bias
    gemm_bf16_hmma<true><<<dim3(256/128, TT/128), 256>>>(
        (const __nv_bfloat16*)p_A2, (const __nv_bfloat16*)p_W2b, pb,
        out, 256);
}

// round 7
// speedup vs baseline: 2.4238x; 1.0530x over previous
#include <cuda_runtime.h>
#include <cuda_bf16.h>
#include <math.h>
#include <stdint.h>

// Problem constants
#define BB 8
#define LL 4096
#define CC 256
#define HH 8
#define DD 32
#define CH 128
#define NC 32          // LL / CH
#define TT (BB*LL)     // 32768 tokens
#define KTOT 768       // B-operand K width (3 passes x 256)
#define KA2  512       // A-operand storage width ([hi, lo])

// ---------------- static device scratch (no allocations allowed) ----------------
__device__ float g_qkv[(size_t)TT * 768];                 // qkv per token (fp32)
__device__ float g_o  [(size_t)TT * CC];                  // attention output (intra)
__device__ float g_C  [(size_t)BB*HH*NC * DD*DD];         // per-chunk KV contributions
__device__ float g_kvp[(size_t)BB*HH*NC * DD*DD];         // exclusive KV prefixes
__device__ __nv_bfloat16 g_A2 [(size_t)TT * KA2];         // [hi, lo] activations
__device__ __nv_bfloat16 g_W1b[(size_t)768 * 768];        // [hi, hi, lo] qkv weight
__device__ __nv_bfloat16 g_W2b[(size_t)256 * 768];        // [hi, hi, lo] proj weight
__device__ __nv_bfloat16 g_qh [(size_t)TT * CC];          // normalized q hat (hi)
__device__ __nv_bfloat16 g_ql [(size_t)TT * CC];          // normalized q hat (lo)

// =========================== small PTX helpers ===========================
__device__ __forceinline__ uint32_t smem_u32(const void* p) {
    uint32_t a;
    asm("{ .reg .u64 t; cvta.to.shared.u64 t, %1; cvt.u32.u64 %0, t; }" : "=r"(a) : "l"(p));
    return a;
}
__device__ __forceinline__ void cpasync16(uint32_t dst, const void* src) {
    asm volatile("cp.async.cg.shared.global [%0], [%1], 16;" :: "r"(dst), "l"(src));
}
__device__ __forceinline__ void cp_commit() {
    asm volatile("cp.async.commit_group;" ::: "memory");
}
template<int N>
__device__ __forceinline__ void cp_wait() {
    asm volatile("cp.async.wait_group %0;" :: "n"(N) : "memory");
}
__device__ __forceinline__ void ldsm4(uint32_t* r, uint32_t addr) {
    asm volatile("ldmatrix.sync.aligned.m8n8.x4.shared.b16 {%0,%1,%2,%3}, [%4];"
                 : "=r"(r[0]), "=r"(r[1]), "=r"(r[2]), "=r"(r[3]) : "r"(addr));
}
__device__ __forceinline__ void mma_bf16(float* c, const uint32_t* a, const uint32_t* b) {
    asm volatile("mma.sync.aligned.m16n8k16.row.col.f32.bf16.bf16.f32 "
                 "{%0,%1,%2,%3}, {%4,%5,%6,%7}, {%8,%9}, {%0,%1,%2,%3};"
                 : "+f"(c[0]), "+f"(c[1]), "+f"(c[2]), "+f"(c[3])
                 : "r"(a[0]), "r"(a[1]), "r"(a[2]), "r"(a[3]), "r"(b[0]), "r"(b[1]));
}
// xor swizzle of 16B chunk index within a 64B row (4 chunks)
__device__ __forceinline__ int sw_chunk(int r, int c) {
    return c ^ (r & 3) ^ ((r >> 2) & 1);
}
__device__ __forceinline__ uint32_t pack_bf2(__nv_bfloat16 a, __nv_bfloat16 b) {
    uint32_t lo16 = *(uint16_t*)&a, hi16 = *(uint16_t*)&b;
    return lo16 | (hi16 << 16);
}

// =========================== hi/lo split conversion kernels ===========================
__global__ void conv_act_kernel(const float* __restrict__ x, const float* __restrict__ rp,
                                __nv_bfloat16* __restrict__ A2)
{
    int idx = blockIdx.x * 256 + threadIdx.x;
    int m = idx >> 6, c4 = (idx & 63) << 2;
    float4 h = *(const float4*)&x[(size_t)m * 256 + c4];
    float4 r = *(const float4*)&rp[(size_t)(m & (LL-1)) * 256 + c4];
    h.x += r.x; h.y += r.y; h.z += r.z; h.w += r.w;
    float hv[4] = {h.x, h.y, h.z, h.w};
    __nv_bfloat16 hi[4], lo[4];
#pragma unroll
    for (int j = 0; j < 4; j++) {
        hi[j] = __float2bfloat16(hv[j]);
        lo[j] = __float2bfloat16(hv[j] - __bfloat162float(hi[j]));
    }
    size_t base = (size_t)m * KA2 + c4;
    *(uint2*)&A2[base]       = *(uint2*)hi;
    *(uint2*)&A2[base + 256] = *(uint2*)lo;
}

__global__ void conv_w_kernel(const float* __restrict__ W, __nv_bfloat16* __restrict__ W2)
{
    int idx = blockIdx.x * 256 + threadIdx.x;
    int n = idx >> 6, c4 = (idx & 63) << 2;
    float4 h = *(const float4*)&W[(size_t)n * 256 + c4];
    float hv[4] = {h.x, h.y, h.z, h.w};
    __nv_bfloat16 hi[4], lo[4];
#pragma unroll
    for (int j = 0; j < 4; j++) {
        hi[j] = __float2bfloat16(hv[j]);
        lo[j] = __float2bfloat16(hv[j] - __bfloat162float(hi[j]));
    }
    size_t base = (size_t)n * 768 + c4;
    *(uint2*)&W2[base]       = *(uint2*)hi;
    *(uint2*)&W2[base + 256] = *(uint2*)hi;
    *(uint2*)&W2[base + 512] = *(uint2*)lo;
}

// =========================== HMMA bf16 GEMM: C = A2 @ W2^T (+bias) ===========================
// A2 is [hi,lo] (512 wide); W2 is [hi,hi,lo] (768 wide). K slab s in 0..23 reads
// A columns (s<16 ? s : s-16)*32 — the 3rd pass reuses the hi slab.
// 3-stage cp.async ring, ONE __syncthreads per slab.
#define NSTG (KTOT/32)   // 24

template<bool BIAS>
__global__ void __launch_bounds__(256, 2) gemm_bf16_hmma(
    const __nv_bfloat16* __restrict__ A,
    const __nv_bfloat16* __restrict__ Bw,
    const float* __restrict__ bias,
    float* __restrict__ Cmat, int Ntot)
{
    __shared__ __align__(16) __nv_bfloat16 As[3][128][32];
    __shared__ __align__(16) __nv_bfloat16 Bs[3][128][32];

    const int tid = threadIdx.x;
    const int wid = tid >> 5, lane = tid & 31;
    const int warp_m = wid & 1, warp_n = wid >> 1;
    const int m0 = blockIdx.y * 128;
    const int n0 = blockIdx.x * 128;

    const uint32_t as_base = smem_u32(As);
    const uint32_t bs_base = smem_u32(Bs);

    float acc[4][4][4];
#pragma unroll
    for (int mt = 0; mt < 4; mt++)
#pragma unroll
        for (int nt = 0; nt < 4; nt++)
#pragma unroll
            for (int e = 0; e < 4; e++) acc[mt][nt][e] = 0.f;

    const int lr = tid >> 2;
    const int lc = tid & 3;

    auto load_stage = [&](int s, int b) {
        const int sa = (s < 16) ? s : s - 16;
#pragma unroll
        for (int l = 0; l < 2; l++) {
            int r = lr + l * 64;
            int ch = sw_chunk(r, lc);
            const __nv_bfloat16* asrc = A  + (size_t)(m0 + r) * KA2 + sa * 32 + lc * 8;
            const __nv_bfloat16* bsrc = Bw + (size_t)(n0 + r) * KTOT + s * 32 + lc * 8;
            cpasync16(as_base + (b * 128 + r) * 64 + ch * 16, asrc);
            cpasync16(bs_base + (b * 128 + r) * 64 + ch * 16, bsrc);
        }
        cp_commit();
    };

    load_stage(0, 0);
    load_stage(1, 1);

    int b = 0;
    for (int i = 0; i < NSTG; i++) {
        if (i + 1 < NSTG) cp_wait<1>(); else cp_wait<0>();
        __syncthreads();

#pragma unroll
        for (int kk = 0; kk < 2; kk++) {
            uint32_t af[4][4];
#pragma unroll
            for (int mt = 0; mt < 4; mt++) {
                int row = warp_m * 64 + mt * 16 + (lane & 15);
                int ch = sw_chunk(row, kk * 2 + (lane >> 4));
                ldsm4(af[mt], as_base + (b * 128 + row) * 64 + ch * 16);
            }
            uint32_t bf[2][4];
#pragma unroll
            for (int nt2 = 0; nt2 < 2; nt2++) {
                int g = lane >> 3, l8 = lane & 7;
                int row = warp_n * 32 + nt2 * 16 + (g >> 1) * 8 + l8;
                int ch = sw_chunk(row, kk * 2 + (g & 1));
                ldsm4(bf[nt2], bs_base + (b * 128 + row) * 64 + ch * 16);
            }
#pragma unroll
            for (int mt = 0; mt < 4; mt++)
#pragma unroll
                for (int nt = 0; nt < 4; nt++)
                    mma_bf16(acc[mt][nt], af[mt], &bf[nt >> 1][(nt & 1) * 2]);
        }

        if (i + 2 < NSTG) {
            int b2 = b + 2; if (b2 >= 3) b2 -= 3;
            load_stage(i + 2, b2);
        }
        if (++b == 3) b = 0;
    }

#pragma unroll
    for (int mt = 0; mt < 4; mt++) {
        int row = m0 + warp_m * 64 + mt * 16 + (lane >> 2);
#pragma unroll
        for (int nt = 0; nt < 4; nt++) {
            int col = n0 + warp_n * 32 + nt * 8 + (lane & 3) * 2;
            float2 v0 = make_float2(acc[mt][nt][0], acc[mt][nt][1]);
            float2 v1 = make_float2(acc[mt][nt][2], acc[mt][nt][3]);
            if (BIAS) {
                float2 bv = *(const float2*)&bias[col];
                v0.x += bv.x; v0.y += bv.y;
                v1.x += bv.x; v1.y += bv.y;
            }
            *(float2*)&Cmat[(size_t)row * Ntot + col]       = v0;
            *(float2*)&Cmat[(size_t)(row + 8) * Ntot + col] = v1;
        }
    }
}

// ======================= HMMA attention: intra + per-chunk KV contribution =======================
// smem layout (bytes); total 98 KB -> 2 CTAs/SM
#define AT_ED   0                     // 129 floats
#define AT_NQ   640
#define AT_NK   1152
#define AT_QHI  2048
#define AT_QLO  (AT_QHI  + 8192)
#define AT_KHI  (AT_QLO  + 8192)
#define AT_KLO  (AT_KHI  + 8192)
#define AT_KTHI (AT_KLO  + 8192)
#define AT_KTLO (AT_KTHI + 8192)
#define AT_VTHI (AT_KTLO + 8192)
#define AT_VTLO (AT_VTHI + 8192)
#define AT_SC0H (AT_VTLO + 8192)      // 128 rows x 128 B
#define AT_SC0L (AT_SC0H + 16384)
#define AT_SMEM (AT_SC0L + 16384)     // 100352 bytes
// aliases (regions dead by the time they're reused)
#define AT_SC1H AT_QHI                // 64 rows x 128 B
#define AT_SC1L AT_QLO
#define AT_CRED AT_KHI                // 16 KB: 4 warps x 4 KB

__global__ void __launch_bounds__(256, 2) attn_chunk_hmma(
    const float* __restrict__ qg, const float* __restrict__ kg,
    __nv_bfloat16* __restrict__ qhout, __nv_bfloat16* __restrict__ qlout)
{
    extern __shared__ char sm[];
    float* ed = (float*)(sm + AT_ED);
    float* nq = (float*)(sm + AT_NQ);
    float* nk = (float*)(sm + AT_NK);
    const uint32_t sb = smem_u32(sm);

    const int n = blockIdx.x, h = blockIdx.y, b = blockIdx.z;
    const int tid = threadIdx.x, lane = tid & 31, wid = tid >> 5;
    const float s = exp2f(-(float)(h + 1));
    for (int i = tid; i <= CH; i += 256) ed[i] = expf(-s * (float)i);

    const size_t tok0 = (size_t)(b*LL + n*CH);
    const size_t base = tok0 * 768 + h*DD;
    const int c4 = (tid & 7) * 4;

    // ---- P1: load q,k (norm partial sums) + convert v -> VT hi/lo ----
    float sq[4], sk[4];
#pragma unroll
    for (int l = 0; l < 4; l++) {
        int r = (tid >> 3) + l * 32;
        const float* rowp = &g_qkv[base + (size_t)r * 768 + c4];
        float4 a  = *(const float4*)(rowp);
        float4 bb = *(const float4*)(rowp + 256);
        float4 cc = *(const float4*)(rowp + 512);
        sq[l] = a.x*a.x + a.y*a.y + a.z*a.z + a.w*a.w;
        sk[l] = bb.x*bb.x + bb.y*bb.y + bb.z*bb.z + bb.w*bb.w;
        float vv[4] = {cc.x, cc.y, cc.z, cc.w};
#pragma unroll
        for (int j = 0; j < 4; j++) {
            int d = c4 + j;
            __nv_bfloat16 vh = __float2bfloat16(vv[j]);
            __nv_bfloat16 vl = __float2bfloat16(vv[j] - __bfloat162float(vh));
            int aT = d*256 + (((r >> 3) ^ (d & 7)) * 16) + ((r & 7) * 2);
            *(__nv_bfloat16*)(sm + AT_VTHI + aT) = vh;
            *(__nv_bfloat16*)(sm + AT_VTLO + aT) = vl;
        }
    }
#pragma unroll
    for (int m = 1; m < 8; m <<= 1) {
#pragma unroll
        for (int l = 0; l < 4; l++) {
            sq[l] += __shfl_xor_sync(0xffffffffu, sq[l], m);
            sk[l] += __shfl_xor_sync(0xffffffffu, sk[l], m);
        }
    }
    if ((tid & 7) == 0) {
        const float sqD = 5.656854249492380f;
#pragma unroll
        for (int l = 0; l < 4; l++) {
            int r = (tid >> 3) + l * 32;
            nq[r] = (sq[l] > 1e-24f) ? sqD * rsqrtf(sq[l]) : sqD * 1e12f;
            nk[r] = (sk[l] > 1e-24f) ? sqD * rsqrtf(sk[l]) : sqD * 1e12f;
        }
    }
    __syncthreads();

    // ---- P2: convert q,k (re-read gmem; L2-hot) ----
    float gq[4], gk[4];
#pragma unroll
    for (int j = 0; j < 4; j++) {
        gq[j] = __ldg(&qg[h*DD + c4 + j]);
        gk[j] = __ldg(&kg[h*DD + c4 + j]);
    }
#pragma unroll
    for (int l = 0; l < 4; l++) {
        int r = (tid >> 3) + l * 32;
        const float* rowp = &g_qkv[base + (size_t)r * 768 + c4];
        float4 a  = *(const float4*)(rowp);
        float4 bb = *(const float4*)(rowp + 256);
        float rq = nq[r], rk = nk[r], dk = ed[CH - r];
        float qv[4] = {a.x, a.y, a.z, a.w};
        float kv[4] = {bb.x, bb.y, bb.z, bb.w};
        __nv_bfloat16 qh4[4], ql4[4], kh4[4], kl4[4];
#pragma unroll
        for (int j = 0; j < 4; j++) {
            int d = c4 + j;
            float qn = qv[j] * rq * gq[j];
            float kn = kv[j] * rk * gk[j];
            qh4[j] = __float2bfloat16(qn);
            ql4[j] = __float2bfloat16(qn - __bfloat162float(qh4[j]));
            kh4[j] = __float2bfloat16(kn);
            kl4[j] = __float2bfloat16(kn - __bfloat162float(kh4[j]));
            float kt = kn * dk;
            __nv_bfloat16 kth = __float2bfloat16(kt);
            __nv_bfloat16 ktl = __float2bfloat16(kt - __bfloat162float(kth));
            int aT = d*256 + (((r >> 3) ^ (d & 7)) * 16) + ((r & 7) * 2);
            *(__nv_bfloat16*)(sm + AT_KTHI + aT) = kth;
            *(__nv_bfloat16*)(sm + AT_KTLO + aT) = ktl;
        }
        int a64 = r*64 + sw_chunk(r, c4 >> 3) * 16 + ((c4 & 7) * 2);
        *(uint2*)(sm + AT_QHI + a64) = *(uint2*)qh4;
        *(uint2*)(sm + AT_QLO + a64) = *(uint2*)ql4;
        *(uint2*)(sm + AT_KHI + a64) = *(uint2*)kh4;
        *(uint2*)(sm + AT_KLO + a64) = *(uint2*)kl4;
        *(uint2*)(qhout + (tok0 + r)*CC + h*DD + c4) = *(uint2*)qh4;
        *(uint2*)(qlout + (tok0 + r)*CC + h*DD + c4) = *(uint2*)ql4;
    }
    __syncthreads();

    const uint32_t QB[3] = {sb + AT_QHI, sb + AT_QLO, sb + AT_QHI};
    const uint32_t KB[3] = {sb + AT_KHI, sb + AT_KHI, sb + AT_KLO};
    const uint32_t BV[3] = {sb + AT_VTHI, sb + AT_VTHI, sb + AT_VTLO};
    const int g = lane >> 3, l8 = lane & 7;

    // ---- P3: scores half0  S[:, 0:64]  (all 128 rows) ----
    float acc0[8][4];
#pragma unroll
    for (int nt = 0; nt < 8; nt++)
#pragma unroll
        for (int e = 0; e < 4; e++) acc0[nt][e] = 0.f;
#pragma unroll
    for (int p = 0; p < 3; p++) {
#pragma unroll
        for (int kk = 0; kk < 2; kk++) {
            uint32_t af[4];
            int row = wid * 16 + (lane & 15);
            ldsm4(af, QB[p] + row * 64 + sw_chunk(row, kk * 2 + (lane >> 4)) * 16);
            uint32_t bf[4][4];
#pragma unroll
            for (int nt2 = 0; nt2 < 4; nt2++) {
                int row2 = nt2 * 16 + (g >> 1) * 8 + l8;
                ldsm4(bf[nt2], KB[p] + row2 * 64 + sw_chunk(row2, kk * 2 + (g & 1)) * 16);
            }
#pragma unroll
            for (int nt = 0; nt < 8; nt++)
                mma_bf16(acc0[nt], af, &bf[nt >> 1][(nt & 1) * 2]);
        }
    }
    // mask + decay + write sc0
    {
        int c_lo = wid * 16 + (lane >> 2);
#pragma unroll
        for (int nt = 0; nt < 8; nt++) {
            int mm = nt * 8 + (lane & 3) * 2;
#pragma unroll
            for (int half = 0; half < 2; half++) {
                int c = c_lo + half * 8;
                float v0 = acc0[nt][half*2+0], v1 = acc0[nt][half*2+1];
                int d0 = c - mm, d1 = c - mm - 1;
                float s0 = (d0 >= 0) ? v0 * ed[d0] : 0.f;
                float s1 = (d1 >= 0) ? v1 * ed[d1] : 0.f;
                __nv_bfloat16 h0 = __float2bfloat16(s0);
                __nv_bfloat16 h1 = __float2bfloat16(s1);
                __nv_bfloat16 l0 = __float2bfloat16(s0 - __bfloat162float(h0));
                __nv_bfloat16 l1 = __float2bfloat16(s1 - __bfloat162float(h1));
                int addr = c * 128 + (((mm >> 3) ^ (c & 7)) * 16) + ((mm * 2) & 15);
                *(uint32_t*)(sm + AT_SC0H + addr) = pack_bf2(h0, h1);
                *(uint32_t*)(sm + AT_SC0L + addr) = pack_bf2(l0, l1);
            }
        }
    }
    __syncthreads();

    // ---- P4: o_intra part A (K = 0..64, all rows) ----
    float oacc[4][4];
#pragma unroll
    for (int nt = 0; nt < 4; nt++)
#pragma unroll
        for (int e = 0; e < 4; e++) oacc[nt][e] = 0.f;
    {
        const uint32_t AB[3] = {sb + AT_SC0H, sb + AT_SC0L, sb + AT_SC0H};
        const int r0 = wid * 16;
#pragma unroll
        for (int p = 0; p < 3; p++) {
#pragma unroll
            for (int kk = 0; kk < 4; kk++) {
                uint32_t af[4];
                int row = r0 + (lane & 15);
                int ch = (kk * 2 + (lane >> 4)) ^ (row & 7);
                ldsm4(af, AB[p] + row * 128 + ch * 16);
                uint32_t bf[2][4];
#pragma unroll
                for (int nt2 = 0; nt2 < 2; nt2++) {
                    int row2 = nt2 * 16 + (g >> 1) * 8 + l8;
                    int ch2 = (kk * 2 + (g & 1)) ^ (row2 & 7);
                    ldsm4(bf[nt2], BV[p] + row2 * 256 + ch2 * 16);
                }
#pragma unroll
                for (int nt = 0; nt < 4; nt++)
                    mma_bf16(oacc[nt], af, &bf[nt >> 1][(nt & 1) * 2]);
            }
        }
    }
    // rows 0..63 are complete (cols 64+ masked to zero) -> store now
    if (wid < 4) {
        int c = wid * 16 + (lane >> 2);
#pragma unroll
        for (int nt = 0; nt < 4; nt++) {
            int e = nt * 8 + (lane & 3) * 2;
            size_t go = (tok0 + c) * CC + h*DD + e;
            *(float2*)&g_o[go]        = make_float2(oacc[nt][0], oacc[nt][1]);
            *(float2*)&g_o[go + 8*CC] = make_float2(oacc[nt][2], oacc[nt][3]);
        }
    }

    // ---- P5: scores half1  S[64:128, 64:128]  (all 8 warps) ----
    float acc1[4][4];
#pragma unroll
    for (int nt = 0; nt < 4; nt++)
#pragma unroll
        for (int e = 0; e < 4; e++) acc1[nt][e] = 0.f;
    const int c0s = 64 + (wid & 3) * 16;
    const int mbs = 64 + (wid >> 2) * 32;
#pragma unroll
    for (int p = 0; p < 3; p++) {
#pragma unroll
        for (int kk = 0; kk < 2; kk++) {
            uint32_t af[4];
            int row = c0s + (lane & 15);
            ldsm4(af, QB[p] + row * 64 + sw_chunk(row, kk * 2 + (lane >> 4)) * 16);
            uint32_t bf[2][4];
#pragma unroll
            for (int nt2 = 0; nt2 < 2; nt2++) {
                int row2 = mbs + nt2 * 16 + (g >> 1) * 8 + l8;
                ldsm4(bf[nt2], KB[p] + row2 * 64 + sw_chunk(row2, kk * 2 + (g & 1)) * 16);
            }
#pragma unroll
            for (int nt = 0; nt < 4; nt++)
                mma_bf16(acc1[nt], af, &bf[nt >> 1][(nt & 1) * 2]);
        }
    }
    __syncthreads();   // all Q/K fragment reads done; QHI/QLO become sc1

    {
        int c_lo = c0s + (lane >> 2);
#pragma unroll
        for (int nt = 0; nt < 4; nt++) {
            int mm = mbs + nt * 8 + (lane & 3) * 2;
#pragma unroll
            for (int half = 0; half < 2; half++) {
                int c = c_lo + half * 8;
                float v0 = acc1[nt][half*2+0], v1 = acc1[nt][half*2+1];
                int d0 = c - mm, d1 = c - mm - 1;
                float s0 = (d0 >= 0) ? v0 * ed[d0] : 0.f;
                float s1 = (d1 >= 0) ? v1 * ed[d1] : 0.f;
                __nv_bfloat16 h0 = __float2bfloat16(s0);
                __nv_bfloat16 h1 = __float2bfloat16(s1);
                __nv_bfloat16 l0 = __float2bfloat16(s0 - __bfloat162float(h0));
                __nv_bfloat16 l1 = __float2bfloat16(s1 - __bfloat162float(h1));
                int cr = c - 64, mr = mm - 64;
                int addr = cr * 128 + (((mr >> 3) ^ (cr & 7)) * 16) + ((mr * 2) & 15);
                *(uint32_t*)(sm + AT_SC1H + addr) = pack_bf2(h0, h1);
                *(uint32_t*)(sm + AT_SC1L + addr) = pack_bf2(l0, l1);
            }
        }
    }
    __syncthreads();

    // ---- P6: warps 4-7: o_intra part B (rows 64..127, K=64..128); warps 0-3: C_n ----
    if (wid >= 4) {
        const uint32_t AB1[3] = {sb + AT_SC1H, sb + AT_SC1L, sb + AT_SC1H};
        const int r0 = (wid - 4) * 16;
#pragma unroll
        for (int p = 0; p < 3; p++) {
#pragma unroll
            for (int kk = 0; kk < 4; kk++) {
                uint32_t af[4];
                int row = r0 + (lane & 15);
                int ch = (kk * 2 + (lane >> 4)) ^ (row & 7);
                ldsm4(af, AB1[p] + row * 128 + ch * 16);
                uint32_t bf[2][4];
#pragma unroll
                for (int nt2 = 0; nt2 < 2; nt2++) {
                    int row2 = nt2 * 16 + (g >> 1) * 8 + l8;
                    int ch2 = ((kk + 4) * 2 + (g & 1)) ^ (row2 & 7);
                    ldsm4(bf[nt2], BV[p] + row2 * 256 + ch2 * 16);
                }
#pragma unroll
                for (int nt = 0; nt < 4; nt++)
                    mma_bf16(oacc[nt], af, &bf[nt >> 1][(nt & 1) * 2]);
            }
        }
        int c = wid * 16 + (lane >> 2);
#pragma unroll
        for (int nt = 0; nt < 4; nt++) {
            int e = nt * 8 + (lane & 3) * 2;
            size_t go = (tok0 + c) * CC + h*DD + e;
            *(float2*)&g_o[go]        = make_float2(oacc[nt][0], oacc[nt][1]);
            *(float2*)&g_o[go + 8*CC] = make_float2(oacc[nt][2], oacc[nt][3]);
        }
    } else {
        float cacc[2][4][4];
#pragma unroll
        for (int mt = 0; mt < 2; mt++)
#pragma unroll
            for (int nt = 0; nt < 4; nt++)
#pragma unroll
                for (int e = 0; e < 4; e++) cacc[mt][nt][e] = 0.f;

        const uint32_t KA[3] = {sb + AT_KTHI, sb + AT_KTLO, sb + AT_KTHI};
#pragma unroll
        for (int p = 0; p < 3; p++) {
#pragma unroll
            for (int kl = 0; kl < 2; kl++) {
                int kk = wid * 2 + kl;
                uint32_t af[2][4];
#pragma unroll
                for (int mt = 0; mt < 2; mt++) {
                    int row = mt * 16 + (lane & 15);
                    int ch = (kk * 2 + (lane >> 4)) ^ (row & 7);
                    ldsm4(af[mt], KA[p] + row * 256 + ch * 16);
                }
                uint32_t bf[2][4];
#pragma unroll
                for (int nt2 = 0; nt2 < 2; nt2++) {
                    int row2 = nt2 * 16 + (g >> 1) * 8 + l8;
                    int ch2 = (kk * 2 + (g & 1)) ^ (row2 & 7);
                    ldsm4(bf[nt2], BV[p] + row2 * 256 + ch2 * 16);
                }
#pragma unroll
                for (int mt = 0; mt < 2; mt++)
#pragma unroll
                    for (int nt = 0; nt < 4; nt++)
                        mma_bf16(cacc[mt][nt], af[mt], &bf[nt >> 1][(nt & 1) * 2]);
            }
        }
        float* red = (float*)(sm + AT_CRED) + wid * 1024;
#pragma unroll
        for (int mt = 0; mt < 2; mt++) {
            int d = mt * 16 + (lane >> 2);
#pragma unroll
            for (int nt = 0; nt < 4; nt++) {
                int e = nt * 8 + (lane & 3) * 2;
                *(float2*)&red[d * 32 + e]       = make_float2(cacc[mt][nt][0], cacc[mt][nt][1]);
                *(float2*)&red[(d + 8) * 32 + e] = make_float2(cacc[mt][nt][2], cacc[mt][nt][3]);
            }
        }
    }
    __syncthreads();
    {
        const float* red = (const float*)(sm + AT_CRED);
        const size_t cb = ((size_t)((b*HH + h)*NC + n)) * 1024;
        for (int i = tid; i < 1024; i += 256)
            g_C[cb + i] = red[i] + red[1024 + i] + red[2048 + i] + red[3072 + i];
    }
}

// ======================= sequential KV scan (exclusive prefix) =======================
__global__ void kv_scan_kernel()
{
    const int bh = blockIdx.x;
    const int h = bh & 7;
    const int tid = threadIdx.x;
    const float bd = expf(-exp2f(-(float)(h+1)) * (float)CH);
    float4 kv = make_float4(0.f, 0.f, 0.f, 0.f);
    const size_t base = (size_t)bh * NC * 1024 + tid*4;
    for (int n = 0; n < NC; n++) {
        const size_t o = base + (size_t)n * 1024;
        *(float4*)&g_kvp[o] = kv;
        float4 c = *(const float4*)&g_C[o];
        kv.x = bd*kv.x + c.x; kv.y = bd*kv.y + c.y;
        kv.z = bd*kv.z + c.z; kv.w = bd*kv.w + c.w;
    }
}

// ======================= HMMA inter-chunk + fused hi/lo split of o -> A2 =======================
__global__ void __launch_bounds__(256) attn_inter_hmma(
    const __nv_bfloat16* __restrict__ qh, const __nv_bfloat16* __restrict__ ql,
    __nv_bfloat16* __restrict__ A2)
{
    const int n = blockIdx.x;
    const int h = blockIdx.y, b = blockIdx.z;

    __shared__ __align__(16) char sm[8192*2 + 2048*2 + 1024];
    const int QHI = 0, QLO = 8192, KVHI = 16384, KVLO = 18432, EDO = 20480;
    float* ed = (float*)(sm + EDO);
    const uint32_t sb = smem_u32(sm);

    const int tid = threadIdx.x, lane = tid & 31, wid = tid >> 5;
    const float s = exp2f(-(float)(h+1));
    for (int i = tid; i < CH; i += 256) ed[i] = expf(-s * (float)i);

    const size_t tok0 = (size_t)(b*LL + n*CH);
    for (int i = tid; i < 512; i += 256) {
        int r = i >> 2, c = i & 3;
        uint4 v = *(const uint4*)(qh + (tok0 + r)*CC + h*DD + c*8);
        *(uint4*)(sm + QHI + r*64 + sw_chunk(r, c)*16) = v;
        uint4 w = *(const uint4*)(ql + (tok0 + r)*CC + h*DD + c*8);
        *(uint4*)(sm + QLO + r*64 + sw_chunk(r, c)*16) = w;
    }
    const size_t kb = ((size_t)((b*HH + h)*NC + n)) * 1024;
    for (int i = tid; i < 1024; i += 256) {
        int d = i >> 5, e = i & 31;
        float v = g_kvp[kb + i];
        __nv_bfloat16 hh = __float2bfloat16(v);
        __nv_bfloat16 ll = __float2bfloat16(v - __bfloat162float(hh));
        int a = e*64 + sw_chunk(e, d >> 3)*16 + (d & 7)*2;
        *(__nv_bfloat16*)(sm + KVHI + a) = hh;
        *(__nv_bfloat16*)(sm + KVLO + a) = ll;
    }
    __syncthreads();

    float acc[4][4];
#pragma unroll
    for (int nt = 0; nt < 4; nt++)
#pragma unroll
        for (int e = 0; e < 4; e++) acc[nt][e] = 0.f;

    const int r0 = wid * 16;
    const uint32_t QB[3] = {sb + QHI, sb + QLO, sb + QHI};
    const uint32_t KB[3] = {sb + KVHI, sb + KVHI, sb + KVLO};
#pragma unroll
    for (int p = 0; p < 3; p++) {
#pragma unroll
        for (int kk = 0; kk < 2; kk++) {
            uint32_t af[4];
            int row = r0 + (lane & 15);
            int ch = sw_chunk(row, kk * 2 + (lane >> 4));
            ldsm4(af, QB[p] + row * 64 + ch * 16);
            uint32_t bf[2][4];
#pragma unroll
            for (int nt2 = 0; nt2 < 2; nt2++) {
                int g = lane >> 3, l8 = lane & 7;
                int row2 = nt2 * 16 + (g >> 1) * 8 + l8;
                int ch2 = sw_chunk(row2, kk * 2 + (g & 1));
                ldsm4(bf[nt2], KB[p] + row2 * 64 + ch2 * 16);
            }
#pragma unroll
            for (int nt = 0; nt < 4; nt++)
                mma_bf16(acc[nt], af, &bf[nt >> 1][(nt & 1) * 2]);
        }
    }

    int c = r0 + (lane >> 2);
    float a0 = ed[c], a1 = ed[c + 8];
#pragma unroll
    for (int nt = 0; nt < 4; nt++) {
        int e = nt * 8 + (lane & 3) * 2;
#pragma unroll
        for (int half = 0; half < 2; half++) {
            int cc2 = c + half * 8;
            float al = half ? a1 : a0;
            size_t go = (tok0 + cc2) * CC + h*DD + e;
            float2 o0 = *(float2*)&g_o[go];
            o0.x += al * acc[nt][half*2+0];
            o0.y += al * acc[nt][half*2+1];
            __nv_bfloat16 h0 = __float2bfloat16(o0.x);
            __nv_bfloat16 h1 = __float2bfloat16(o0.y);
            __nv_bfloat16 l0 = __float2bfloat16(o0.x - __bfloat162float(h0));
            __nv_bfloat16 l1 = __float2bfloat16(o0.y - __bfloat162float(h1));
            size_t a2b = (tok0 + cc2) * KA2 + h*DD + e;
            *(uint32_t*)&A2[a2b]       = pack_bf2(h0, h1);
            *(uint32_t*)&A2[a2b + 256] = pack_bf2(l0, l1);
        }
    }
}

// ======================= launch =======================
extern "C" void kernel_launch(void* const* d_in, const int* in_sizes, int n_in,
                              void* d_out, int out_size)
{
    const float* x    = (const float*)d_in[0];
    const float* rel  = (const float*)d_in[1];
    const float* qkvw = (const float*)d_in[2];
    const float* qg   = (const float*)d_in[3];
    const float* kg   = (const float*)d_in[4];
    const float* pw   = (const float*)d_in[5];
    const float* pb   = (const float*)d_in[6];
    float* out = (float*)d_out;

    void* p_qkv = nullptr; cudaGetSymbolAddress(&p_qkv, g_qkv);
    void* p_A2  = nullptr; cudaGetSymbolAddress(&p_A2,  g_A2);
    void* p_W1b = nullptr; cudaGetSymbolAddress(&p_W1b, g_W1b);
    void* p_W2b = nullptr; cudaGetSymbolAddress(&p_W2b, g_W2b);
    void* p_qh  = nullptr; cudaGetSymbolAddress(&p_qh,  g_qh);
    void* p_ql  = nullptr; cudaGetSymbolAddress(&p_ql,  g_ql);

    cudaFuncSetAttribute(attn_chunk_hmma,
                         cudaFuncAttributeMaxDynamicSharedMemorySize, AT_SMEM);

    // 1) split (x + rel_pos) and weights into bf16 hi/lo
    conv_act_kernel<<<TT*64/256, 256>>>(x, rel, (__nv_bfloat16*)p_A2);
    conv_w_kernel<<<768*64/256, 256>>>(qkvw, (__nv_bfloat16*)p_W1b);
    conv_w_kernel<<<256*64/256, 256>>>(pw, (__nv_bfloat16*)p_W2b);

    // 2) qkv = A2 @ W1b^T  (HMMA bf16, 3-pass K) -> fp32 g_qkv
    gemm_bf16_hmma<false><<<dim3(768/128, TT/128), 256>>>(
        (const __nv_bfloat16*)p_A2, (const __nv_bfloat16*)p_W1b, nullptr,
        (float*)p_qkv, 768);

    // 3) attention: intra + C_n, scan, inter (writes A2 [hi,lo] directly)
    attn_chunk_hmma<<<dim3(NC, HH, BB), 256, AT_SMEM>>>(
        qg, kg, (__nv_bfloat16*)p_qh, (__nv_bfloat16*)p_ql);
    kv_scan_kernel<<<BB*HH, 256>>>();
    attn_inter_hmma<<<dim3(NC, HH, BB), 256>>>(
        (const __nv_bfloat16*)p_qh, (const __nv_bfloat16*)p_ql,
        (__nv_bfloat16*)p_A2);

    // 4) out = O2 @ W2b^T + bias
    gemm_bf16_hmma<true><<<dim3(256/128, TT/128), 256>>>(
        (const __nv_bfloat16*)p_A2, (const __nv_bfloat16*)p_W2b, pb,
        out, 256);
}

// round 8
// speedup vs baseline: 3.1123x; 1.2840x over previous
#include <cuda_runtime.h>
#include <cuda_fp16.h>
#include <math.h>
#include <stdint.h>

// Problem constants
#define BB 8
#define LL 4096
#define CC 256
#define HH 8
#define DD 32
#define CH 128
#define NC 32          // LL / CH
#define TT (BB*LL)     // 32768 tokens
#define KA2  512       // A-operand storage width ([hi, lo])

// ---------------- static device scratch (no allocations allowed) ----------------
__device__ float g_qkv[(size_t)TT * 768];                 // qkv per token (fp32)
__device__ float g_o  [(size_t)TT * CC];                  // attention output (intra)
__device__ float g_C  [(size_t)BB*HH*NC * DD*DD];         // per-chunk KV contributions
__device__ float g_kvp[(size_t)BB*HH*NC * DD*DD];         // exclusive KV prefixes
__device__ __half g_A2 [(size_t)TT * KA2];                // [hi, lo] activations (fp16)
__device__ __half g_W1h[(size_t)768 * 256];               // qkv weight (fp16 hi only)
__device__ __half g_W2h[(size_t)256 * 256];               // proj weight (fp16 hi only)
__device__ __half g_qh [(size_t)TT * CC];                 // normalized q hat (hi)
__device__ __half g_ql [(size_t)TT * CC];                 // normalized q hat (lo)

// =========================== small PTX helpers ===========================
__device__ __forceinline__ uint32_t smem_u32(const void* p) {
    uint32_t a;
    asm("{ .reg .u64 t; cvta.to.shared.u64 t, %1; cvt.u32.u64 %0, t; }" : "=r"(a) : "l"(p));
    return a;
}
__device__ __forceinline__ void cpasync16(uint32_t dst, const void* src) {
    asm volatile("cp.async.cg.shared.global [%0], [%1], 16;" :: "r"(dst), "l"(src));
}
__device__ __forceinline__ void cp_commit() {
    asm volatile("cp.async.commit_group;" ::: "memory");
}
template<int N>
__device__ __forceinline__ void cp_wait() {
    asm volatile("cp.async.wait_group %0;" :: "n"(N) : "memory");
}
__device__ __forceinline__ void ldsm4(uint32_t* r, uint32_t addr) {
    asm volatile("ldmatrix.sync.aligned.m8n8.x4.shared.b16 {%0,%1,%2,%3}, [%4];"
                 : "=r"(r[0]), "=r"(r[1]), "=r"(r[2]), "=r"(r[3]) : "r"(addr));
}
__device__ __forceinline__ void mma_f16(float* c, const uint32_t* a, const uint32_t* b) {
    asm volatile("mma.sync.aligned.m16n8k16.row.col.f32.f16.f16.f32 "
                 "{%0,%1,%2,%3}, {%4,%5,%6,%7}, {%8,%9}, {%0,%1,%2,%3};"
                 : "+f"(c[0]), "+f"(c[1]), "+f"(c[2]), "+f"(c[3])
                 : "r"(a[0]), "r"(a[1]), "r"(a[2]), "r"(a[3]), "r"(b[0]), "r"(b[1]));
}
// xor swizzle of 16B chunk index within a 64B row (4 chunks)
__device__ __forceinline__ int sw_chunk(int r, int c) {
    return c ^ (r & 3) ^ ((r >> 2) & 1);
}
__device__ __forceinline__ uint32_t pack_h2(__half a, __half b) {
    uint32_t lo16 = *(uint16_t*)&a, hi16 = *(uint16_t*)&b;
    return lo16 | (hi16 << 16);
}

// =========================== hi/lo split conversion kernels ===========================
__global__ void conv_act_kernel(const float* __restrict__ x, const float* __restrict__ rp,
                                __half* __restrict__ A2)
{
    int idx = blockIdx.x * 256 + threadIdx.x;
    int m = idx >> 6, c4 = (idx & 63) << 2;
    float4 h = *(const float4*)&x[(size_t)m * 256 + c4];
    float4 r = *(const float4*)&rp[(size_t)(m & (LL-1)) * 256 + c4];
    h.x += r.x; h.y += r.y; h.z += r.z; h.w += r.w;
    float hv[4] = {h.x, h.y, h.z, h.w};
    __half hi[4], lo[4];
#pragma unroll
    for (int j = 0; j < 4; j++) {
        hi[j] = __float2half_rn(hv[j]);
        lo[j] = __float2half_rn(hv[j] - __half2float(hi[j]));
    }
    size_t base = (size_t)m * KA2 + c4;
    *(uint2*)&A2[base]       = *(uint2*)hi;
    *(uint2*)&A2[base + 256] = *(uint2*)lo;
}

__global__ void conv_w_kernel(const float* __restrict__ W, __half* __restrict__ Wh)
{
    int idx = blockIdx.x * 256 + threadIdx.x;
    int n = idx >> 6, c4 = (idx & 63) << 2;
    float4 h = *(const float4*)&W[(size_t)n * 256 + c4];
    float hv[4] = {h.x, h.y, h.z, h.w};
    __half hi[4];
#pragma unroll
    for (int j = 0; j < 4; j++) hi[j] = __float2half_rn(hv[j]);
    *(uint2*)&Wh[(size_t)n * 256 + c4] = *(uint2*)hi;
}

// =========================== HMMA fp16 GEMM: C = [Ahi,Alo] @ Wh^T (+bias) ===========================
// A2 [hi,lo] 512-wide fp16; Wh 256-wide fp16. K slab s in 0..15: A col s*32, B col (s&7)*32.
// 3-stage cp.async ring, ONE __syncthreads per slab.
#define NSTG 16

template<bool BIAS>
__global__ void __launch_bounds__(256, 2) gemm_f16_hmma(
    const __half* __restrict__ A,
    const __half* __restrict__ Bw,
    const float* __restrict__ bias,
    float* __restrict__ Cmat, int Ntot)
{
    __shared__ __align__(16) __half As[3][128][32];
    __shared__ __align__(16) __half Bs[3][128][32];

    const int tid = threadIdx.x;
    const int wid = tid >> 5, lane = tid & 31;
    const int warp_m = wid & 1, warp_n = wid >> 1;
    const int m0 = blockIdx.y * 128;
    const int n0 = blockIdx.x * 128;

    const uint32_t as_base = smem_u32(As);
    const uint32_t bs_base = smem_u32(Bs);

    float acc[4][4][4];
#pragma unroll
    for (int mt = 0; mt < 4; mt++)
#pragma unroll
        for (int nt = 0; nt < 4; nt++)
#pragma unroll
            for (int e = 0; e < 4; e++) acc[mt][nt][e] = 0.f;

    const int lr = tid >> 2;
    const int lc = tid & 3;

    auto load_stage = [&](int s, int b) {
        const int sb_ = s & 7;
#pragma unroll
        for (int l = 0; l < 2; l++) {
            int r = lr + l * 64;
            int ch = sw_chunk(r, lc);
            const __half* asrc = A  + (size_t)(m0 + r) * KA2 + s * 32 + lc * 8;
            const __half* bsrc = Bw + (size_t)(n0 + r) * 256 + sb_ * 32 + lc * 8;
            cpasync16(as_base + (b * 128 + r) * 64 + ch * 16, asrc);
            cpasync16(bs_base + (b * 128 + r) * 64 + ch * 16, bsrc);
        }
        cp_commit();
    };

    load_stage(0, 0);
    load_stage(1, 1);

    int b = 0;
    for (int i = 0; i < NSTG; i++) {
        if (i + 1 < NSTG) cp_wait<1>(); else cp_wait<0>();
        __syncthreads();

#pragma unroll
        for (int kk = 0; kk < 2; kk++) {
            uint32_t af[4][4];
#pragma unroll
            for (int mt = 0; mt < 4; mt++) {
                int row = warp_m * 64 + mt * 16 + (lane & 15);
                int ch = sw_chunk(row, kk * 2 + (lane >> 4));
                ldsm4(af[mt], as_base + (b * 128 + row) * 64 + ch * 16);
            }
            uint32_t bf[2][4];
#pragma unroll
            for (int nt2 = 0; nt2 < 2; nt2++) {
                int g = lane >> 3, l8 = lane & 7;
                int row = warp_n * 32 + nt2 * 16 + (g >> 1) * 8 + l8;
                int ch = sw_chunk(row, kk * 2 + (g & 1));
                ldsm4(bf[nt2], bs_base + (b * 128 + row) * 64 + ch * 16);
            }
#pragma unroll
            for (int mt = 0; mt < 4; mt++)
#pragma unroll
                for (int nt = 0; nt < 4; nt++)
                    mma_f16(acc[mt][nt], af[mt], &bf[nt >> 1][(nt & 1) * 2]);
        }

        if (i + 2 < NSTG) {
            int b2 = b + 2; if (b2 >= 3) b2 -= 3;
            load_stage(i + 2, b2);
        }
        if (++b == 3) b = 0;
    }

#pragma unroll
    for (int mt = 0; mt < 4; mt++) {
        int row = m0 + warp_m * 64 + mt * 16 + (lane >> 2);
#pragma unroll
        for (int nt = 0; nt < 4; nt++) {
            int col = n0 + warp_n * 32 + nt * 8 + (lane & 3) * 2;
            float2 v0 = make_float2(acc[mt][nt][0], acc[mt][nt][1]);
            float2 v1 = make_float2(acc[mt][nt][2], acc[mt][nt][3]);
            if (BIAS) {
                float2 bv = *(const float2*)&bias[col];
                v0.x += bv.x; v0.y += bv.y;
                v1.x += bv.x; v1.y += bv.y;
            }
            *(float2*)&Cmat[(size_t)row * Ntot + col]       = v0;
            *(float2*)&Cmat[(size_t)(row + 8) * Ntot + col] = v1;
        }
    }
}

// ======================= HMMA attention: intra + per-chunk KV contribution =======================
// smem layout (bytes); total 84 KB -> 2 CTAs/SM
#define AT_ED   0                     // 129 floats
#define AT_NQ   640
#define AT_NK   1152
#define AT_QHI  2048
#define AT_QLO  (AT_QHI  + 8192)
#define AT_KHI  (AT_QLO  + 8192)
#define AT_KTHI (AT_KHI  + 8192)
#define AT_KTLO (AT_KTHI + 8192)
#define AT_VTHI (AT_KTLO + 8192)
#define AT_SC0H (AT_VTHI + 8192)      // 128 rows x 128 B
#define AT_SC0L (AT_SC0H + 16384)
#define AT_SMEM (AT_SC0L + 16384)     // 83968 bytes
// aliases (regions dead by the time they're reused)
#define AT_SC1H AT_QHI                // 64 rows x 128 B
#define AT_SC1L AT_QLO
#define AT_CRED AT_SC0H               // 16 KB: 4 warps x 4 KB (sc0 dead after P4)

__global__ void __launch_bounds__(256, 2) attn_chunk_hmma(
    const float* __restrict__ qg, const float* __restrict__ kg,
    __half* __restrict__ qhout, __half* __restrict__ qlout)
{
    extern __shared__ char sm[];
    float* ed = (float*)(sm + AT_ED);
    float* nq = (float*)(sm + AT_NQ);
    float* nk = (float*)(sm + AT_NK);
    const uint32_t sb = smem_u32(sm);

    const int n = blockIdx.x, h = blockIdx.y, b = blockIdx.z;
    const int tid = threadIdx.x, lane = tid & 31, wid = tid >> 5;
    const float s = exp2f(-(float)(h + 1));
    for (int i = tid; i <= CH; i += 256) ed[i] = expf(-s * (float)i);

    const size_t tok0 = (size_t)(b*LL + n*CH);
    const size_t base = tok0 * 768 + h*DD;
    const int c4 = (tid & 7) * 4;

    // ---- P1: load q,k (norm partial sums) + convert v -> VT hi ----
    float sq[4], sk[4];
#pragma unroll
    for (int l = 0; l < 4; l++) {
        int r = (tid >> 3) + l * 32;
        const float* rowp = &g_qkv[base + (size_t)r * 768 + c4];
        float4 a  = *(const float4*)(rowp);
        float4 bb = *(const float4*)(rowp + 256);
        float4 cc = *(const float4*)(rowp + 512);
        sq[l] = a.x*a.x + a.y*a.y + a.z*a.z + a.w*a.w;
        sk[l] = bb.x*bb.x + bb.y*bb.y + bb.z*bb.z + bb.w*bb.w;
        float vv[4] = {cc.x, cc.y, cc.z, cc.w};
#pragma unroll
        for (int j = 0; j < 4; j++) {
            int d = c4 + j;
            __half vh = __float2half_rn(vv[j]);
            int aT = d*256 + (((r >> 3) ^ (d & 7)) * 16) + ((r & 7) * 2);
            *(__half*)(sm + AT_VTHI + aT) = vh;
        }
    }
#pragma unroll
    for (int m = 1; m < 8; m <<= 1) {
#pragma unroll
        for (int l = 0; l < 4; l++) {
            sq[l] += __shfl_xor_sync(0xffffffffu, sq[l], m);
            sk[l] += __shfl_xor_sync(0xffffffffu, sk[l], m);
        }
    }
    if ((tid & 7) == 0) {
        const float sqD = 5.656854249492380f;
#pragma unroll
        for (int l = 0; l < 4; l++) {
            int r = (tid >> 3) + l * 32;
            nq[r] = (sq[l] > 1e-24f) ? sqD * rsqrtf(sq[l]) : sqD * 1e12f;
            nk[r] = (sk[l] > 1e-24f) ? sqD * rsqrtf(sk[l]) : sqD * 1e12f;
        }
    }
    __syncthreads();

    // ---- P2: convert q (hi/lo), k (hi), kT (hi/lo, decay-folded) ----
    float gq[4], gk[4];
#pragma unroll
    for (int j = 0; j < 4; j++) {
        gq[j] = __ldg(&qg[h*DD + c4 + j]);
        gk[j] = __ldg(&kg[h*DD + c4 + j]);
    }
#pragma unroll
    for (int l = 0; l < 4; l++) {
        int r = (tid >> 3) + l * 32;
        const float* rowp = &g_qkv[base + (size_t)r * 768 + c4];
        float4 a  = *(const float4*)(rowp);
        float4 bb = *(const float4*)(rowp + 256);
        float rq = nq[r], rk = nk[r], dk = ed[CH - r];
        float qv[4] = {a.x, a.y, a.z, a.w};
        float kv[4] = {bb.x, bb.y, bb.z, bb.w};
        __half qh4[4], ql4[4], kh4[4];
#pragma unroll
        for (int j = 0; j < 4; j++) {
            int d = c4 + j;
            float qn = qv[j] * rq * gq[j];
            float kn = kv[j] * rk * gk[j];
            qh4[j] = __float2half_rn(qn);
            ql4[j] = __float2half_rn(qn - __half2float(qh4[j]));
            kh4[j] = __float2half_rn(kn);
            float kt = kn * dk;
            __half kth = __float2half_rn(kt);
            __half ktl = __float2half_rn(kt - __half2float(kth));
            int aT = d*256 + (((r >> 3) ^ (d & 7)) * 16) + ((r & 7) * 2);
            *(__half*)(sm + AT_KTHI + aT) = kth;
            *(__half*)(sm + AT_KTLO + aT) = ktl;
        }
        int a64 = r*64 + sw_chunk(r, c4 >> 3) * 16 + ((c4 & 7) * 2);
        *(uint2*)(sm + AT_QHI + a64) = *(uint2*)qh4;
        *(uint2*)(sm + AT_QLO + a64) = *(uint2*)ql4;
        *(uint2*)(sm + AT_KHI + a64) = *(uint2*)kh4;
        *(uint2*)(qhout + (tok0 + r)*CC + h*DD + c4) = *(uint2*)qh4;
        *(uint2*)(qlout + (tok0 + r)*CC + h*DD + c4) = *(uint2*)ql4;
    }
    __syncthreads();

    const uint32_t QB[2] = {sb + AT_QHI, sb + AT_QLO};
    const int g = lane >> 3, l8 = lane & 7;

    // ---- P3: scores half0  S[:, 0:64]  (all 128 rows), 2 passes ----
    float acc0[8][4];
#pragma unroll
    for (int nt = 0; nt < 8; nt++)
#pragma unroll
        for (int e = 0; e < 4; e++) acc0[nt][e] = 0.f;
#pragma unroll
    for (int p = 0; p < 2; p++) {
#pragma unroll
        for (int kk = 0; kk < 2; kk++) {
            uint32_t af[4];
            int row = wid * 16 + (lane & 15);
            ldsm4(af, QB[p] + row * 64 + sw_chunk(row, kk * 2 + (lane >> 4)) * 16);
            uint32_t bf[4][4];
#pragma unroll
            for (int nt2 = 0; nt2 < 4; nt2++) {
                int row2 = nt2 * 16 + (g >> 1) * 8 + l8;
                ldsm4(bf[nt2], sb + AT_KHI + row2 * 64 + sw_chunk(row2, kk * 2 + (g & 1)) * 16);
            }
#pragma unroll
            for (int nt = 0; nt < 8; nt++)
                mma_f16(acc0[nt], af, &bf[nt >> 1][(nt & 1) * 2]);
        }
    }
    // mask + decay + write sc0
    {
        int c_lo = wid * 16 + (lane >> 2);
#pragma unroll
        for (int nt = 0; nt < 8; nt++) {
            int mm = nt * 8 + (lane & 3) * 2;
#pragma unroll
            for (int half = 0; half < 2; half++) {
                int c = c_lo + half * 8;
                float v0 = acc0[nt][half*2+0], v1 = acc0[nt][half*2+1];
                int d0 = c - mm, d1 = c - mm - 1;
                float s0 = (d0 >= 0) ? v0 * ed[d0] : 0.f;
                float s1 = (d1 >= 0) ? v1 * ed[d1] : 0.f;
                __half h0 = __float2half_rn(s0);
                __half h1 = __float2half_rn(s1);
                __half l0 = __float2half_rn(s0 - __half2float(h0));
                __half l1 = __float2half_rn(s1 - __half2float(h1));
                int addr = c * 128 + (((mm >> 3) ^ (c & 7)) * 16) + ((mm * 2) & 15);
                *(uint32_t*)(sm + AT_SC0H + addr) = pack_h2(h0, h1);
                *(uint32_t*)(sm + AT_SC0L + addr) = pack_h2(l0, l1);
            }
        }
    }
    __syncthreads();

    // ---- P4: o_intra part A (K = 0..64, all rows), 2 passes ----
    float oacc[4][4];
#pragma unroll
    for (int nt = 0; nt < 4; nt++)
#pragma unroll
        for (int e = 0; e < 4; e++) oacc[nt][e] = 0.f;
    {
        const uint32_t AB[2] = {sb + AT_SC0H, sb + AT_SC0L};
        const int r0 = wid * 16;
#pragma unroll
        for (int p = 0; p < 2; p++) {
#pragma unroll
            for (int kk = 0; kk < 4; kk++) {
                uint32_t af[4];
                int row = r0 + (lane & 15);
                int ch = (kk * 2 + (lane >> 4)) ^ (row & 7);
                ldsm4(af, AB[p] + row * 128 + ch * 16);
                uint32_t bf[2][4];
#pragma unroll
                for (int nt2 = 0; nt2 < 2; nt2++) {
                    int row2 = nt2 * 16 + (g >> 1) * 8 + l8;
                    int ch2 = (kk * 2 + (g & 1)) ^ (row2 & 7);
                    ldsm4(bf[nt2], sb + AT_VTHI + row2 * 256 + ch2 * 16);
                }
#pragma unroll
                for (int nt = 0; nt < 4; nt++)
                    mma_f16(oacc[nt], af, &bf[nt >> 1][(nt & 1) * 2]);
            }
        }
    }
    // rows 0..63 are complete (cols 64+ masked to zero) -> store now
    if (wid < 4) {
        int c = wid * 16 + (lane >> 2);
#pragma unroll
        for (int nt = 0; nt < 4; nt++) {
            int e = nt * 8 + (lane & 3) * 2;
            size_t go = (tok0 + c) * CC + h*DD + e;
            *(float2*)&g_o[go]        = make_float2(oacc[nt][0], oacc[nt][1]);
            *(float2*)&g_o[go + 8*CC] = make_float2(oacc[nt][2], oacc[nt][3]);
        }
    }

    // ---- P5: scores half1  S[64:128, 64:128]  (all 8 warps), 2 passes ----
    float acc1[4][4];
#pragma unroll
    for (int nt = 0; nt < 4; nt++)
#pragma unroll
        for (int e = 0; e < 4; e++) acc1[nt][e] = 0.f;
    const int c0s = 64 + (wid & 3) * 16;
    const int mbs = 64 + (wid >> 2) * 32;
#pragma unroll
    for (int p = 0; p < 2; p++) {
#pragma unroll
        for (int kk = 0; kk < 2; kk++) {
            uint32_t af[4];
            int row = c0s + (lane & 15);
            ldsm4(af, QB[p] + row * 64 + sw_chunk(row, kk * 2 + (lane >> 4)) * 16);
            uint32_t bf[2][4];
#pragma unroll
            for (int nt2 = 0; nt2 < 2; nt2++) {
                int row2 = mbs + nt2 * 16 + (g >> 1) * 8 + l8;
                ldsm4(bf[nt2], sb + AT_KHI + row2 * 64 + sw_chunk(row2, kk * 2 + (g & 1)) * 16);
            }
#pragma unroll
            for (int nt = 0; nt < 4; nt++)
                mma_f16(acc1[nt], af, &bf[nt >> 1][(nt & 1) * 2]);
        }
    }
    __syncthreads();   // all Q/K fragment reads done; QHI/QLO become sc1

    {
        int c_lo = c0s + (lane >> 2);
#pragma unroll
        for (int nt = 0; nt < 4; nt++) {
            int mm = mbs + nt * 8 + (lane & 3) * 2;
#pragma unroll
            for (int half = 0; half < 2; half++) {
                int c = c_lo + half * 8;
                float v0 = acc1[nt][half*2+0], v1 = acc1[nt][half*2+1];
                int d0 = c - mm, d1 = c - mm - 1;
                float s0 = (d0 >= 0) ? v0 * ed[d0] : 0.f;
                float s1 = (d1 >= 0) ? v1 * ed[d1] : 0.f;
                __half h0 = __float2half_rn(s0);
                __half h1 = __float2half_rn(s1);
                __half l0 = __float2half_rn(s0 - __half2float(h0));
                __half l1 = __float2half_rn(s1 - __half2float(h1));
                int cr = c - 64, mr = mm - 64;
                int addr = cr * 128 + (((mr >> 3) ^ (cr & 7)) * 16) + ((mr * 2) & 15);
                *(uint32_t*)(sm + AT_SC1H + addr) = pack_h2(h0, h1);
                *(uint32_t*)(sm + AT_SC1L + addr) = pack_h2(l0, l1);
            }
        }
    }
    __syncthreads();

    // ---- P6: warps 4-7: o_intra part B (rows 64..127, K=64..128); warps 0-3: C_n ----
    if (wid >= 4) {
        const uint32_t AB1[2] = {sb + AT_SC1H, sb + AT_SC1L};
        const int r0 = (wid - 4) * 16;
#pragma unroll
        for (int p = 0; p < 2; p++) {
#pragma unroll
            for (int kk = 0; kk < 4; kk++) {
                uint32_t af[4];
                int row = r0 + (lane & 15);
                int ch = (kk * 2 + (lane >> 4)) ^ (row & 7);
                ldsm4(af, AB1[p] + row * 128 + ch * 16);
                uint32_t bf[2][4];
#pragma unroll
                for (int nt2 = 0; nt2 < 2; nt2++) {
                    int row2 = nt2 * 16 + (g >> 1) * 8 + l8;
                    int ch2 = ((kk + 4) * 2 + (g & 1)) ^ (row2 & 7);
                    ldsm4(bf[nt2], sb + AT_VTHI + row2 * 256 + ch2 * 16);
                }
#pragma unroll
                for (int nt = 0; nt < 4; nt++)
                    mma_f16(oacc[nt], af, &bf[nt >> 1][(nt & 1) * 2]);
            }
        }
        int c = wid * 16 + (lane >> 2);
#pragma unroll
        for (int nt = 0; nt < 4; nt++) {
            int e = nt * 8 + (lane & 3) * 2;
            size_t go = (tok0 + c) * CC + h*DD + e;
            *(float2*)&g_o[go]        = make_float2(oacc[nt][0], oacc[nt][1]);
            *(float2*)&g_o[go + 8*CC] = make_float2(oacc[nt][2], oacc[nt][3]);
        }
    } else {
        float cacc[2][4][4];
#pragma unroll
        for (int mt = 0; mt < 2; mt++)
#pragma unroll
            for (int nt = 0; nt < 4; nt++)
#pragma unroll
                for (int e = 0; e < 4; e++) cacc[mt][nt][e] = 0.f;

        const uint32_t KA[2] = {sb + AT_KTHI, sb + AT_KTLO};
#pragma unroll
        for (int p = 0; p < 2; p++) {
#pragma unroll
            for (int kl = 0; kl < 2; kl++) {
                int kk = wid * 2 + kl;
                uint32_t af[2][4];
#pragma unroll
                for (int mt = 0; mt < 2; mt++) {
                    int row = mt * 16 + (lane & 15);
                    int ch = (kk * 2 + (lane >> 4)) ^ (row & 7);
                    ldsm4(af[mt], KA[p] + row * 256 + ch * 16);
                }
                uint32_t bf[2][4];
#pragma unroll
                for (int nt2 = 0; nt2 < 2; nt2++) {
                    int row2 = nt2 * 16 + (g >> 1) * 8 + l8;
                    int ch2 = (kk * 2 + (g & 1)) ^ (row2 & 7);
                    ldsm4(bf[nt2], sb + AT_VTHI + row2 * 256 + ch2 * 16);
                }
#pragma unroll
                for (int mt = 0; mt < 2; mt++)
#pragma unroll
                    for (int nt = 0; nt < 4; nt++)
                        mma_f16(cacc[mt][nt], af[mt], &bf[nt >> 1][(nt & 1) * 2]);
            }
        }
        float* red = (float*)(sm + AT_CRED) + wid * 1024;
#pragma unroll
        for (int mt = 0; mt < 2; mt++) {
            int d = mt * 16 + (lane >> 2);
#pragma unroll
            for (int nt = 0; nt < 4; nt++) {
                int e = nt * 8 + (lane & 3) * 2;
                *(float2*)&red[d * 32 + e]       = make_float2(cacc[mt][nt][0], cacc[mt][nt][1]);
                *(float2*)&red[(d + 8) * 32 + e] = make_float2(cacc[mt][nt][2], cacc[mt][nt][3]);
            }
        }
    }
    __syncthreads();
    {
        const float* red = (const float*)(sm + AT_CRED);
        const size_t cb = ((size_t)((b*HH + h)*NC + n)) * 1024;
        for (int i = tid; i < 1024; i += 256)
            g_C[cb + i] = red[i] + red[1024 + i] + red[2048 + i] + red[3072 + i];
    }
}

// ======================= sequential KV scan (exclusive prefix) =======================
__global__ void kv_scan_kernel()
{
    const int bh = blockIdx.x;
    const int h = bh & 7;
    const int tid = threadIdx.x;
    const float bd = expf(-exp2f(-(float)(h+1)) * (float)CH);
    float4 kv = make_float4(0.f, 0.f, 0.f, 0.f);
    const size_t base = (size_t)bh * NC * 1024 + tid*4;
    for (int n = 0; n < NC; n++) {
        const size_t o = base + (size_t)n * 1024;
        *(float4*)&g_kvp[o] = kv;
        float4 c = *(const float4*)&g_C[o];
        kv.x = bd*kv.x + c.x; kv.y = bd*kv.y + c.y;
        kv.z = bd*kv.z + c.z; kv.w = bd*kv.w + c.w;
    }
}

// ======================= HMMA inter-chunk + fused hi/lo split of o -> A2 =======================
__global__ void __launch_bounds__(256) attn_inter_hmma(
    const __half* __restrict__ qh, const __half* __restrict__ ql,
    __half* __restrict__ A2)
{
    const int n = blockIdx.x;
    const int h = blockIdx.y, b = blockIdx.z;

    __shared__ __align__(16) char sm[8192*2 + 2048 + 1024];
    const int QHI = 0, QLO = 8192, KVHI = 16384, EDO = 18432;
    float* ed = (float*)(sm + EDO);
    const uint32_t sb = smem_u32(sm);

    const int tid = threadIdx.x, lane = tid & 31, wid = tid >> 5;
    const float s = exp2f(-(float)(h+1));
    for (int i = tid; i < CH; i += 256) ed[i] = expf(-s * (float)i);

    const size_t tok0 = (size_t)(b*LL + n*CH);
    for (int i = tid; i < 512; i += 256) {
        int r = i >> 2, c = i & 3;
        uint4 v = *(const uint4*)(qh + (tok0 + r)*CC + h*DD + c*8);
        *(uint4*)(sm + QHI + r*64 + sw_chunk(r, c)*16) = v;
        uint4 w = *(const uint4*)(ql + (tok0 + r)*CC + h*DD + c*8);
        *(uint4*)(sm + QLO + r*64 + sw_chunk(r, c)*16) = w;
    }
    const size_t kb = ((size_t)((b*HH + h)*NC + n)) * 1024;
    for (int i = tid; i < 1024; i += 256) {
        int d = i >> 5, e = i & 31;
        float v = g_kvp[kb + i];
        __half hh = __float2half_rn(v);
        int a = e*64 + sw_chunk(e, d >> 3)*16 + (d & 7)*2;
        *(__half*)(sm + KVHI + a) = hh;
    }
    __syncthreads();

    float acc[4][4];
#pragma unroll
    for (int nt = 0; nt < 4; nt++)
#pragma unroll
        for (int e = 0; e < 4; e++) acc[nt][e] = 0.f;

    const int r0 = wid * 16;
    const uint32_t QB[2] = {sb + QHI, sb + QLO};
#pragma unroll
    for (int p = 0; p < 2; p++) {
#pragma unroll
        for (int kk = 0; kk < 2; kk++) {
            uint32_t af[4];
            int row = r0 + (lane & 15);
            int ch = sw_chunk(row, kk * 2 + (lane >> 4));
            ldsm4(af, QB[p] + row * 64 + ch * 16);
            uint32_t bf[2][4];
#pragma unroll
            for (int nt2 = 0; nt2 < 2; nt2++) {
                int g = lane >> 3, l8 = lane & 7;
                int row2 = nt2 * 16 + (g >> 1) * 8 + l8;
                int ch2 = sw_chunk(row2, kk * 2 + (g & 1));
                ldsm4(bf[nt2], sb + KVHI + row2 * 64 + ch2 * 16);
            }
#pragma unroll
            for (int nt = 0; nt < 4; nt++)
                mma_f16(acc[nt], af, &bf[nt >> 1][(nt & 1) * 2]);
        }
    }

    int c = r0 + (lane >> 2);
    float a0 = ed[c], a1 = ed[c + 8];
#pragma unroll
    for (int nt = 0; nt < 4; nt++) {
        int e = nt * 8 + (lane & 3) * 2;
#pragma unroll
        for (int half = 0; half < 2; half++) {
            int cc2 = c + half * 8;
            float al = half ? a1 : a0;
            size_t go = (tok0 + cc2) * CC + h*DD + e;
            float2 o0 = *(float2*)&g_o[go];
            o0.x += al * acc[nt][half*2+0];
            o0.y += al * acc[nt][half*2+1];
            __half h0 = __float2half_rn(o0.x);
            __half h1 = __float2half_rn(o0.y);
            __half l0 = __float2half_rn(o0.x - __half2float(h0));
            __half l1 = __float2half_rn(o0.y - __half2float(h1));
            size_t a2b = (tok0 + cc2) * KA2 + h*DD + e;
            *(uint32_t*)&A2[a2b]       = pack_h2(h0, h1);
            *(uint32_t*)&A2[a2b + 256] = pack_h2(l0, l1);
        }
    }
}

// ======================= launch =======================
extern "C" void kernel_launch(void* const* d_in, const int* in_sizes, int n_in,
                              void* d_out, int out_size)
{
    const float* x    = (const float*)d_in[0];
    const float* rel  = (const float*)d_in[1];
    const float* qkvw = (const float*)d_in[2];
    const float* qg   = (const float*)d_in[3];
    const float* kg   = (const float*)d_in[4];
    const float* pw   = (const float*)d_in[5];
    const float* pb   = (const float*)d_in[6];
    float* out = (float*)d_out;

    void* p_qkv = nullptr; cudaGetSymbolAddress(&p_qkv, g_qkv);
    void* p_A2  = nullptr; cudaGetSymbolAddress(&p_A2,  g_A2);
    void* p_W1h = nullptr; cudaGetSymbolAddress(&p_W1h, g_W1h);
    void* p_W2h = nullptr; cudaGetSymbolAddress(&p_W2h, g_W2h);
    void* p_qh  = nullptr; cudaGetSymbolAddress(&p_qh,  g_qh);
    void* p_ql  = nullptr; cudaGetSymbolAddress(&p_ql,  g_ql);

    cudaFuncSetAttribute(attn_chunk_hmma,
                         cudaFuncAttributeMaxDynamicSharedMemorySize, AT_SMEM);

    // 1) split (x + rel_pos) into fp16 hi/lo; weights to fp16 (hi only)
    conv_act_kernel<<<TT*64/256, 256>>>(x, rel, (__half*)p_A2);
    conv_w_kernel<<<768*64/256, 256>>>(qkvw, (__half*)p_W1h);
    conv_w_kernel<<<256*64/256, 256>>>(pw, (__half*)p_W2h);

    // 2) qkv = [Ahi,Alo] @ W1h^T  (HMMA fp16, 2-pass K) -> fp32 g_qkv
    gemm_f16_hmma<false><<<dim3(768/128, TT/128), 256>>>(
        (const __half*)p_A2, (const __half*)p_W1h, nullptr,
        (float*)p_qkv, 768);

    // 3) attention: intra + C_n, scan, inter (writes A2 [hi,lo] directly)
    attn_chunk_hmma<<<dim3(NC, HH, BB), 256, AT_SMEM>>>(
        qg, kg, (__half*)p_qh, (__half*)p_ql);
    kv_scan_kernel<<<BB*HH, 256>>>();
    attn_inter_hmma<<<dim3(NC, HH, BB), 256>>>(
        (const __half*)p_qh, (const __half*)p_ql, (__half*)p_A2);

    // 4) out = O2 @ W2h^T + bias
    gemm_f16_hmma<true><<<dim3(256/128, TT/128), 256>>>(
        (const __half*)p_A2, (const __half*)p_W2h, pb,
        out, 256);
}

// round 9
// speedup vs baseline: 3.1243x; 1.0039x over previous
#include <cuda_runtime.h>
#include <cuda_fp16.h>
#include <math.h>
#include <stdint.h>

// Problem constants
#define BB 8
#define LL 4096
#define CC 256
#define HH 8
#define DD 32
#define CH 128
#define NC 32          // LL / CH
#define TT (BB*LL)     // 32768 tokens
#define KA2  512       // A-operand storage width ([hi, lo])

// ---------------- static device scratch (no allocations allowed) ----------------
__device__ float g_qkv[(size_t)TT * 768];                 // qkv per token (fp32)
__device__ float g_o  [(size_t)TT * CC];                  // attention output (intra)
__device__ float g_C  [(size_t)BB*HH*NC * DD*DD];         // per-chunk KV contributions
__device__ float g_kvp[(size_t)BB*HH*NC * DD*DD];         // exclusive KV prefixes
__device__ __half g_A2 [(size_t)TT * KA2];                // [hi, lo] activations (fp16)
__device__ __half g_W1h[(size_t)768 * 256];               // qkv weight (fp16 hi only)
__device__ __half g_W2h[(size_t)256 * 256];               // proj weight (fp16 hi only)
__device__ __half g_qh [(size_t)TT * CC];                 // normalized q hat (hi)
__device__ __half g_ql [(size_t)TT * CC];                 // normalized q hat (lo)

// =========================== small PTX helpers ===========================
__device__ __forceinline__ uint32_t smem_u32(const void* p) {
    uint32_t a;
    asm("{ .reg .u64 t; cvta.to.shared.u64 t, %1; cvt.u32.u64 %0, t; }" : "=r"(a) : "l"(p));
    return a;
}
__device__ __forceinline__ void cpasync16(uint32_t dst, const void* src) {
    asm volatile("cp.async.cg.shared.global [%0], [%1], 16;" :: "r"(dst), "l"(src));
}
__device__ __forceinline__ void cp_commit() {
    asm volatile("cp.async.commit_group;" ::: "memory");
}
template<int N>
__device__ __forceinline__ void cp_wait() {
    asm volatile("cp.async.wait_group %0;" :: "n"(N) : "memory");
}
__device__ __forceinline__ void ldsm4(uint32_t* r, uint32_t addr) {
    asm volatile("ldmatrix.sync.aligned.m8n8.x4.shared.b16 {%0,%1,%2,%3}, [%4];"
                 : "=r"(r[0]), "=r"(r[1]), "=r"(r[2]), "=r"(r[3]) : "r"(addr));
}
__device__ __forceinline__ void mma_f16(float* c, const uint32_t* a, const uint32_t* b) {
    asm volatile("mma.sync.aligned.m16n8k16.row.col.f32.f16.f16.f32 "
                 "{%0,%1,%2,%3}, {%4,%5,%6,%7}, {%8,%9}, {%0,%1,%2,%3};"
                 : "+f"(c[0]), "+f"(c[1]), "+f"(c[2]), "+f"(c[3])
                 : "r"(a[0]), "r"(a[1]), "r"(a[2]), "r"(a[3]), "r"(b[0]), "r"(b[1]));
}
// xor swizzle of 16B chunk index within a 64B row (4 chunks)
__device__ __forceinline__ int sw_chunk(int r, int c) {
    return c ^ (r & 3) ^ ((r >> 2) & 1);
}
__device__ __forceinline__ uint32_t pack_h2(__half a, __half b) {
    uint32_t lo16 = *(uint16_t*)&a, hi16 = *(uint16_t*)&b;
    return lo16 | (hi16 << 16);
}

// =========================== hi/lo split conversion kernels ===========================
__global__ void conv_act_kernel(const float* __restrict__ x, const float* __restrict__ rp,
                                __half* __restrict__ A2)
{
    int idx = blockIdx.x * 256 + threadIdx.x;
    int m = idx >> 6, c4 = (idx & 63) << 2;
    float4 h = *(const float4*)&x[(size_t)m * 256 + c4];
    float4 r = *(const float4*)&rp[(size_t)(m & (LL-1)) * 256 + c4];
    h.x += r.x; h.y += r.y; h.z += r.z; h.w += r.w;
    float hv[4] = {h.x, h.y, h.z, h.w};
    __half hi[4], lo[4];
#pragma unroll
    for (int j = 0; j < 4; j++) {
        hi[j] = __float2half_rn(hv[j]);
        lo[j] = __float2half_rn(hv[j] - __half2float(hi[j]));
    }
    size_t base = (size_t)m * KA2 + c4;
    *(uint2*)&A2[base]       = *(uint2*)hi;
    *(uint2*)&A2[base + 256] = *(uint2*)lo;
}

__global__ void conv_w_kernel(const float* __restrict__ W, __half* __restrict__ Wh)
{
    int idx = blockIdx.x * 256 + threadIdx.x;
    int n = idx >> 6, c4 = (idx & 63) << 2;
    float4 h = *(const float4*)&W[(size_t)n * 256 + c4];
    float hv[4] = {h.x, h.y, h.z, h.w};
    __half hi[4];
#pragma unroll
    for (int j = 0; j < 4; j++) hi[j] = __float2half_rn(hv[j]);
    *(uint2*)&Wh[(size_t)n * 256 + c4] = *(uint2*)hi;
}

// =========================== HMMA fp16 GEMM: C = [Ahi,Alo] @ Wh^T (+bias) ===========================
// A2 [hi,lo] 512-wide fp16; Wh 256-wide fp16. K slab s in 0..15: A col s*32, B col (s&7)*32.
// 3-stage cp.async ring, ONE __syncthreads per slab; all LDSM hoisted before MMAs.
#define NSTG 16

template<bool BIAS>
__global__ void __launch_bounds__(256, 2) gemm_f16_hmma(
    const __half* __restrict__ A,
    const __half* __restrict__ Bw,
    const float* __restrict__ bias,
    float* __restrict__ Cmat, int Ntot)
{
    __shared__ __align__(16) __half As[3][128][32];
    __shared__ __align__(16) __half Bs[3][128][32];

    const int tid = threadIdx.x;
    const int wid = tid >> 5, lane = tid & 31;
    const int warp_m = wid & 1, warp_n = wid >> 1;
    const int m0 = blockIdx.y * 128;
    const int n0 = blockIdx.x * 128;

    const uint32_t as_base = smem_u32(As);
    const uint32_t bs_base = smem_u32(Bs);

    float acc[4][4][4];
#pragma unroll
    for (int mt = 0; mt < 4; mt++)
#pragma unroll
        for (int nt = 0; nt < 4; nt++)
#pragma unroll
            for (int e = 0; e < 4; e++) acc[mt][nt][e] = 0.f;

    const int lr = tid >> 2;
    const int lc = tid & 3;

    auto load_stage = [&](int s, int b) {
        const int sb_ = s & 7;
#pragma unroll
        for (int l = 0; l < 2; l++) {
            int r = lr + l * 64;
            int ch = sw_chunk(r, lc);
            const __half* asrc = A  + (size_t)(m0 + r) * KA2 + s * 32 + lc * 8;
            const __half* bsrc = Bw + (size_t)(n0 + r) * 256 + sb_ * 32 + lc * 8;
            cpasync16(as_base + (b * 128 + r) * 64 + ch * 16, asrc);
            cpasync16(bs_base + (b * 128 + r) * 64 + ch * 16, bsrc);
        }
        cp_commit();
    };

    load_stage(0, 0);
    load_stage(1, 1);

    int b = 0;
    for (int i = 0; i < NSTG; i++) {
        if (i + 1 < NSTG) cp_wait<1>(); else cp_wait<0>();
        __syncthreads();

        // hoist ALL fragment loads for this slab (both k-halves) before MMAs
        uint32_t af[2][4][4];
        uint32_t bf[2][2][4];
#pragma unroll
        for (int kk = 0; kk < 2; kk++) {
#pragma unroll
            for (int mt = 0; mt < 4; mt++) {
                int row = warp_m * 64 + mt * 16 + (lane & 15);
                int ch = sw_chunk(row, kk * 2 + (lane >> 4));
                ldsm4(af[kk][mt], as_base + (b * 128 + row) * 64 + ch * 16);
            }
#pragma unroll
            for (int nt2 = 0; nt2 < 2; nt2++) {
                int g = lane >> 3, l8 = lane & 7;
                int row = warp_n * 32 + nt2 * 16 + (g >> 1) * 8 + l8;
                int ch = sw_chunk(row, kk * 2 + (g & 1));
                ldsm4(bf[kk][nt2], bs_base + (b * 128 + row) * 64 + ch * 16);
            }
        }
#pragma unroll
        for (int kk = 0; kk < 2; kk++)
#pragma unroll
            for (int mt = 0; mt < 4; mt++)
#pragma unroll
                for (int nt = 0; nt < 4; nt++)
                    mma_f16(acc[mt][nt], af[kk][mt], &bf[kk][nt >> 1][(nt & 1) * 2]);

        if (i + 2 < NSTG) {
            int b2 = b + 2; if (b2 >= 3) b2 -= 3;
            load_stage(i + 2, b2);
        }
        if (++b == 3) b = 0;
    }

#pragma unroll
    for (int mt = 0; mt < 4; mt++) {
        int row = m0 + warp_m * 64 + mt * 16 + (lane >> 2);
#pragma unroll
        for (int nt = 0; nt < 4; nt++) {
            int col = n0 + warp_n * 32 + nt * 8 + (lane & 3) * 2;
            float2 v0 = make_float2(acc[mt][nt][0], acc[mt][nt][1]);
            float2 v1 = make_float2(acc[mt][nt][2], acc[mt][nt][3]);
            if (BIAS) {
                float2 bv = *(const float2*)&bias[col];
                v0.x += bv.x; v0.y += bv.y;
                v1.x += bv.x; v1.y += bv.y;
            }
            *(float2*)&Cmat[(size_t)row * Ntot + col]       = v0;
            *(float2*)&Cmat[(size_t)(row + 8) * Ntot + col] = v1;
        }
    }
}

// ======================= HMMA attention: intra + per-chunk KV contribution =======================
// smem layout (bytes); total 84 KB -> 2 CTAs/SM
#define AT_ED   0                     // 129 floats
#define AT_NQ   640
#define AT_NK   1152
#define AT_QHI  2048
#define AT_QLO  (AT_QHI  + 8192)
#define AT_KHI  (AT_QLO  + 8192)
#define AT_KTHI (AT_KHI  + 8192)
#define AT_KTLO (AT_KTHI + 8192)
#define AT_VTHI (AT_KTLO + 8192)
#define AT_SC0H (AT_VTHI + 8192)      // 128 rows x 128 B
#define AT_SC0L (AT_SC0H + 16384)
#define AT_SMEM (AT_SC0L + 16384)     // 83968 bytes
// aliases (regions dead by the time they're reused)
#define AT_SC1H AT_QHI                // 64 rows x 128 B
#define AT_SC1L AT_QLO
#define AT_CRED AT_SC0H               // 16 KB: 4 warps x 4 KB (sc0 dead after P4)
#define AT_STGQ AT_SC0H               // fp32 q staging (P1->P2), dead before P3
#define AT_STGK AT_SC0L               // fp32 k staging

__global__ void __launch_bounds__(256, 2) attn_chunk_hmma(
    const float* __restrict__ qg, const float* __restrict__ kg,
    __half* __restrict__ qhout, __half* __restrict__ qlout)
{
    extern __shared__ char sm[];
    float* ed = (float*)(sm + AT_ED);
    float* nq = (float*)(sm + AT_NQ);
    float* nk = (float*)(sm + AT_NK);
    const uint32_t sb = smem_u32(sm);

    const int n = blockIdx.x, h = blockIdx.y, b = blockIdx.z;
    const int tid = threadIdx.x, lane = tid & 31, wid = tid >> 5;
    const float s = exp2f(-(float)(h + 1));
    for (int i = tid; i <= CH; i += 256) ed[i] = expf(-s * (float)i);

    const size_t tok0 = (size_t)(b*LL + n*CH);
    const size_t base = tok0 * 768 + h*DD;
    const int c4 = (tid & 7) * 4;

    // ---- P1: load q,k,v once; stage q,k fp32 in smem; convert v -> VT hi ----
    float sq[4], sk[4];
#pragma unroll
    for (int l = 0; l < 4; l++) {
        int r = (tid >> 3) + l * 32;
        const float* rowp = &g_qkv[base + (size_t)r * 768 + c4];
        float4 a  = *(const float4*)(rowp);
        float4 bb = *(const float4*)(rowp + 256);
        float4 cc = *(const float4*)(rowp + 512);
        sq[l] = a.x*a.x + a.y*a.y + a.z*a.z + a.w*a.w;
        sk[l] = bb.x*bb.x + bb.y*bb.y + bb.z*bb.z + bb.w*bb.w;
        // stage q,k (per-thread slots, lane-stride 16B -> conflict-free)
        *(float4*)(sm + AT_STGQ + l*4096 + tid*16) = a;
        *(float4*)(sm + AT_STGK + l*4096 + tid*16) = bb;
        float vv[4] = {cc.x, cc.y, cc.z, cc.w};
#pragma unroll
        for (int j = 0; j < 4; j++) {
            int d = c4 + j;
            __half vh = __float2half_rn(vv[j]);
            int aT = d*256 + (((r >> 3) ^ (d & 7)) * 16) + ((r & 7) * 2);
            *(__half*)(sm + AT_VTHI + aT) = vh;
        }
    }
#pragma unroll
    for (int m = 1; m < 8; m <<= 1) {
#pragma unroll
        for (int l = 0; l < 4; l++) {
            sq[l] += __shfl_xor_sync(0xffffffffu, sq[l], m);
            sk[l] += __shfl_xor_sync(0xffffffffu, sk[l], m);
        }
    }
    if ((tid & 7) == 0) {
        const float sqD = 5.656854249492380f;
#pragma unroll
        for (int l = 0; l < 4; l++) {
            int r = (tid >> 3) + l * 32;
            nq[r] = (sq[l] > 1e-24f) ? sqD * rsqrtf(sq[l]) : sqD * 1e12f;
            nk[r] = (sk[l] > 1e-24f) ? sqD * rsqrtf(sk[l]) : sqD * 1e12f;
        }
    }
    __syncthreads();

    // ---- P2: convert q (hi/lo), k (hi), kT (hi/lo, decay-folded) from staged fp32 ----
    float gq[4], gk[4];
#pragma unroll
    for (int j = 0; j < 4; j++) {
        gq[j] = __ldg(&qg[h*DD + c4 + j]);
        gk[j] = __ldg(&kg[h*DD + c4 + j]);
    }
#pragma unroll
    for (int l = 0; l < 4; l++) {
        int r = (tid >> 3) + l * 32;
        float4 a  = *(const float4*)(sm + AT_STGQ + l*4096 + tid*16);
        float4 bb = *(const float4*)(sm + AT_STGK + l*4096 + tid*16);
        float rq = nq[r], rk = nk[r], dk = ed[CH - r];
        float qv[4] = {a.x, a.y, a.z, a.w};
        float kv[4] = {bb.x, bb.y, bb.z, bb.w};
        __half qh4[4], ql4[4], kh4[4];
#pragma unroll
        for (int j = 0; j < 4; j++) {
            int d = c4 + j;
            float qn = qv[j] * rq * gq[j];
            float kn = kv[j] * rk * gk[j];
            qh4[j] = __float2half_rn(qn);
            ql4[j] = __float2half_rn(qn - __half2float(qh4[j]));
            kh4[j] = __float2half_rn(kn);
            float kt = kn * dk;
            __half kth = __float2half_rn(kt);
            __half ktl = __float2half_rn(kt - __half2float(kth));
            int aT = d*256 + (((r >> 3) ^ (d & 7)) * 16) + ((r & 7) * 2);
            *(__half*)(sm + AT_KTHI + aT) = kth;
            *(__half*)(sm + AT_KTLO + aT) = ktl;
        }
        int a64 = r*64 + sw_chunk(r, c4 >> 3) * 16 + ((c4 & 7) * 2);
        *(uint2*)(sm + AT_QHI + a64) = *(uint2*)qh4;
        *(uint2*)(sm + AT_QLO + a64) = *(uint2*)ql4;
        *(uint2*)(sm + AT_KHI + a64) = *(uint2*)kh4;
        *(uint2*)(qhout + (tok0 + r)*CC + h*DD + c4) = *(uint2*)qh4;
        *(uint2*)(qlout + (tok0 + r)*CC + h*DD + c4) = *(uint2*)ql4;
    }
    __syncthreads();

    const uint32_t QB[2] = {sb + AT_QHI, sb + AT_QLO};
    const int g = lane >> 3, l8 = lane & 7;

    // ---- P3: scores half0  S[:, 0:64]  (all 128 rows), 2 passes ----
    float acc0[8][4];
#pragma unroll
    for (int nt = 0; nt < 8; nt++)
#pragma unroll
        for (int e = 0; e < 4; e++) acc0[nt][e] = 0.f;
#pragma unroll
    for (int p = 0; p < 2; p++) {
#pragma unroll
        for (int kk = 0; kk < 2; kk++) {
            uint32_t af[4];
            int row = wid * 16 + (lane & 15);
            ldsm4(af, QB[p] + row * 64 + sw_chunk(row, kk * 2 + (lane >> 4)) * 16);
            uint32_t bf[4][4];
#pragma unroll
            for (int nt2 = 0; nt2 < 4; nt2++) {
                int row2 = nt2 * 16 + (g >> 1) * 8 + l8;
                ldsm4(bf[nt2], sb + AT_KHI + row2 * 64 + sw_chunk(row2, kk * 2 + (g & 1)) * 16);
            }
#pragma unroll
            for (int nt = 0; nt < 8; nt++)
                mma_f16(acc0[nt], af, &bf[nt >> 1][(nt & 1) * 2]);
        }
    }
    // mask + decay + write sc0
    {
        int c_lo = wid * 16 + (lane >> 2);
#pragma unroll
        for (int nt = 0; nt < 8; nt++) {
            int mm = nt * 8 + (lane & 3) * 2;
#pragma unroll
            for (int half = 0; half < 2; half++) {
                int c = c_lo + half * 8;
                float v0 = acc0[nt][half*2+0], v1 = acc0[nt][half*2+1];
                int d0 = c - mm, d1 = c - mm - 1;
                float s0 = (d0 >= 0) ? v0 * ed[d0] : 0.f;
                float s1 = (d1 >= 0) ? v1 * ed[d1] : 0.f;
                __half h0 = __float2half_rn(s0);
                __half h1 = __float2half_rn(s1);
                __half l0 = __float2half_rn(s0 - __half2float(h0));
                __half l1 = __float2half_rn(s1 - __half2float(h1));
                int addr = c * 128 + (((mm >> 3) ^ (c & 7)) * 16) + ((mm * 2) & 15);
                *(uint32_t*)(sm + AT_SC0H + addr) = pack_h2(h0, h1);
                *(uint32_t*)(sm + AT_SC0L + addr) = pack_h2(l0, l1);
            }
        }
    }
    __syncthreads();

    // ---- P4: o_intra part A (K = 0..64, all rows), 2 passes ----
    float oacc[4][4];
#pragma unroll
    for (int nt = 0; nt < 4; nt++)
#pragma unroll
        for (int e = 0; e < 4; e++) oacc[nt][e] = 0.f;
    {
        const uint32_t AB[2] = {sb + AT_SC0H, sb + AT_SC0L};
        const int r0 = wid * 16;
#pragma unroll
        for (int p = 0; p < 2; p++) {
#pragma unroll
            for (int kk = 0; kk < 4; kk++) {
                uint32_t af[4];
                int row = r0 + (lane & 15);
                int ch = (kk * 2 + (lane >> 4)) ^ (row & 7);
                ldsm4(af, AB[p] + row * 128 + ch * 16);
                uint32_t bf[2][4];
#pragma unroll
                for (int nt2 = 0; nt2 < 2; nt2++) {
                    int row2 = nt2 * 16 + (g >> 1) * 8 + l8;
                    int ch2 = (kk * 2 + (g & 1)) ^ (row2 & 7);
                    ldsm4(bf[nt2], sb + AT_VTHI + row2 * 256 + ch2 * 16);
                }
#pragma unroll
                for (int nt = 0; nt < 4; nt++)
                    mma_f16(oacc[nt], af, &bf[nt >> 1][(nt & 1) * 2]);
            }
        }
    }
    // rows 0..63 are complete (cols 64+ masked to zero) -> store now
    if (wid < 4) {
        int c = wid * 16 + (lane >> 2);
#pragma unroll
        for (int nt = 0; nt < 4; nt++) {
            int e = nt * 8 + (lane & 3) * 2;
            size_t go = (tok0 + c) * CC + h*DD + e;
            *(float2*)&g_o[go]        = make_float2(oacc[nt][0], oacc[nt][1]);
            *(float2*)&g_o[go + 8*CC] = make_float2(oacc[nt][2], oacc[nt][3]);
        }
    }

    // ---- P5: scores half1  S[64:128, 64:128]  (all 8 warps), 2 passes ----
    float acc1[4][4];
#pragma unroll
    for (int nt = 0; nt < 4; nt++)
#pragma unroll
        for (int e = 0; e < 4; e++) acc1[nt][e] = 0.f;
    const int c0s = 64 + (wid & 3) * 16;
    const int mbs = 64 + (wid >> 2) * 32;
#pragma unroll
    for (int p = 0; p < 2; p++) {
#pragma unroll
        for (int kk = 0; kk < 2; kk++) {
            uint32_t af[4];
            int row = c0s + (lane & 15);
            ldsm4(af, QB[p] + row * 64 + sw_chunk(row, kk * 2 + (lane >> 4)) * 16);
            uint32_t bf[2][4];
#pragma unroll
            for (int nt2 = 0; nt2 < 2; nt2++) {
                int row2 = mbs + nt2 * 16 + (g >> 1) * 8 + l8;
                ldsm4(bf[nt2], sb + AT_KHI + row2 * 64 + sw_chunk(row2, kk * 2 + (g & 1)) * 16);
            }
#pragma unroll
            for (int nt = 0; nt < 4; nt++)
                mma_f16(acc1[nt], af, &bf[nt >> 1][(nt & 1) * 2]);
        }
    }
    __syncthreads();   // all Q/K fragment reads done; QHI/QLO become sc1

    {
        int c_lo = c0s + (lane >> 2);
#pragma unroll
        for (int nt = 0; nt < 4; nt++) {
            int mm = mbs + nt * 8 + (lane & 3) * 2;
#pragma unroll
            for (int half = 0; half < 2; half++) {
                int c = c_lo + half * 8;
                float v0 = acc1[nt][half*2+0], v1 = acc1[nt][half*2+1];
                int d0 = c - mm, d1 = c - mm - 1;
                float s0 = (d0 >= 0) ? v0 * ed[d0] : 0.f;
                float s1 = (d1 >= 0) ? v1 * ed[d1] : 0.f;
                __half h0 = __float2half_rn(s0);
                __half h1 = __float2half_rn(s1);
                __half l0 = __float2half_rn(s0 - __half2float(h0));
                __half l1 = __float2half_rn(s1 - __half2float(h1));
                int cr = c - 64, mr = mm - 64;
                int addr = cr * 128 + (((mr >> 3) ^ (cr & 7)) * 16) + ((mr * 2) & 15);
                *(uint32_t*)(sm + AT_SC1H + addr) = pack_h2(h0, h1);
                *(uint32_t*)(sm + AT_SC1L + addr) = pack_h2(l0, l1);
            }
        }
    }
    __syncthreads();

    // ---- P6: warps 4-7: o_intra part B (rows 64..127, K=64..128); warps 0-3: C_n ----
    if (wid >= 4) {
        const uint32_t AB1[2] = {sb + AT_SC1H, sb + AT_SC1L};
        const int r0 = (wid - 4) * 16;
#pragma unroll
        for (int p = 0; p < 2; p++) {
#pragma unroll
            for (int kk = 0; kk < 4; kk++) {
                uint32_t af[4];
                int row = r0 + (lane & 15);
                int ch = (kk * 2 + (lane >> 4)) ^ (row & 7);
                ldsm4(af, AB1[p] + row * 128 + ch * 16);
                uint32_t bf[2][4];
#pragma unroll
                for (int nt2 = 0; nt2 < 2; nt2++) {
                    int row2 = nt2 * 16 + (g >> 1) * 8 + l8;
                    int ch2 = ((kk + 4) * 2 + (g & 1)) ^ (row2 & 7);
                    ldsm4(bf[nt2], sb + AT_VTHI + row2 * 256 + ch2 * 16);
                }
#pragma unroll
                for (int nt = 0; nt < 4; nt++)
                    mma_f16(oacc[nt], af, &bf[nt >> 1][(nt & 1) * 2]);
            }
        }
        int c = wid * 16 + (lane >> 2);
#pragma unroll
        for (int nt = 0; nt < 4; nt++) {
            int e = nt * 8 + (lane & 3) * 2;
            size_t go = (tok0 + c) * CC + h*DD + e;
            *(float2*)&g_o[go]        = make_float2(oacc[nt][0], oacc[nt][1]);
            *(float2*)&g_o[go + 8*CC] = make_float2(oacc[nt][2], oacc[nt][3]);
        }
    } else {
        float cacc[2][4][4];
#pragma unroll
        for (int mt = 0; mt < 2; mt++)
#pragma unroll
            for (int nt = 0; nt < 4; nt++)
#pragma unroll
                for (int e = 0; e < 4; e++) cacc[mt][nt][e] = 0.f;

        const uint32_t KA[2] = {sb + AT_KTHI, sb + AT_KTLO};
#pragma unroll
        for (int p = 0; p < 2; p++) {
#pragma unroll
            for (int kl = 0; kl < 2; kl++) {
                int kk = wid * 2 + kl;
                uint32_t af[2][4];
#pragma unroll
                for (int mt = 0; mt < 2; mt++) {
                    int row = mt * 16 + (lane & 15);
                    int ch = (kk * 2 + (lane >> 4)) ^ (row & 7);
                    ldsm4(af[mt], KA[p] + row * 256 + ch * 16);
                }
                uint32_t bf[2][4];
#pragma unroll
                for (int nt2 = 0; nt2 < 2; nt2++) {
                    int row2 = nt2 * 16 + (g >> 1) * 8 + l8;
                    int ch2 = (kk * 2 + (g & 1)) ^ (row2 & 7);
                    ldsm4(bf[nt2], sb + AT_VTHI + row2 * 256 + ch2 * 16);
                }
#pragma unroll
                for (int mt = 0; mt < 2; mt++)
#pragma unroll
                    for (int nt = 0; nt < 4; nt++)
                        mma_f16(cacc[mt][nt], af[mt], &bf[nt >> 1][(nt & 1) * 2]);
            }
        }
        float* red = (float*)(sm + AT_CRED) + wid * 1024;
#pragma unroll
        for (int mt = 0; mt < 2; mt++) {
            int d = mt * 16 + (lane >> 2);
#pragma unroll
            for (int nt = 0; nt < 4; nt++) {
                int e = nt * 8 + (lane & 3) * 2;
                *(float2*)&red[d * 32 + e]       = make_float2(cacc[mt][nt][0], cacc[mt][nt][1]);
                *(float2*)&red[(d + 8) * 32 + e] = make_float2(cacc[mt][nt][2], cacc[mt][nt][3]);
            }
        }
    }
    __syncthreads();
    {
        const float* red = (const float*)(sm + AT_CRED);
        const size_t cb = ((size_t)((b*HH + h)*NC + n)) * 1024;
        for (int i = tid; i < 1024; i += 256)
            g_C[cb + i] = red[i] + red[1024 + i] + red[2048 + i] + red[3072 + i];
    }
}

// ======================= sequential KV scan (exclusive prefix) =======================
__global__ void kv_scan_kernel()
{
    const int bh = blockIdx.x;
    const int h = bh & 7;
    const int tid = threadIdx.x;
    const float bd = expf(-exp2f(-(float)(h+1)) * (float)CH);
    float4 kv = make_float4(0.f, 0.f, 0.f, 0.f);
    const size_t base = (size_t)bh * NC * 1024 + tid*4;
    for (int n = 0; n < NC; n++) {
        const size_t o = base + (size_t)n * 1024;
        *(float4*)&g_kvp[o] = kv;
        float4 c = *(const float4*)&g_C[o];
        kv.x = bd*kv.x + c.x; kv.y = bd*kv.y + c.y;
        kv.z = bd*kv.z + c.z; kv.w = bd*kv.w + c.w;
    }
}

// ======================= HMMA inter-chunk + fused hi/lo split of o -> A2 =======================
__global__ void __launch_bounds__(256) attn_inter_hmma(
    const __half* __restrict__ qh, const __half* __restrict__ ql,
    __half* __restrict__ A2)
{
    const int n = blockIdx.x;
    const int h = blockIdx.y, b = blockIdx.z;

    __shared__ __align__(16) char sm[8192*2 + 2048 + 1024];
    const int QHI = 0, QLO = 8192, KVHI = 16384, EDO = 18432;
    float* ed = (float*)(sm + EDO);
    const uint32_t sb = smem_u32(sm);

    const int tid = threadIdx.x, lane = tid & 31, wid = tid >> 5;
    const float s = exp2f(-(float)(h+1));
    for (int i = tid; i < CH; i += 256) ed[i] = expf(-s * (float)i);

    const size_t tok0 = (size_t)(b*LL + n*CH);
    for (int i = tid; i < 512; i += 256) {
        int r = i >> 2, c = i & 3;
        uint4 v = *(const uint4*)(qh + (tok0 + r)*CC + h*DD + c*8);
        *(uint4*)(sm + QHI + r*64 + sw_chunk(r, c)*16) = v;
        uint4 w = *(const uint4*)(ql + (tok0 + r)*CC + h*DD + c*8);
        *(uint4*)(sm + QLO + r*64 + sw_chunk(r, c)*16) = w;
    }
    const size_t kb = ((size_t)((b*HH + h)*NC + n)) * 1024;
    for (int i = tid; i < 1024; i += 256) {
        int d = i >> 5, e = i & 31;
        float v = g_kvp[kb + i];
        __half hh = __float2half_rn(v);
        int a = e*64 + sw_chunk(e, d >> 3)*16 + (d & 7)*2;
        *(__half*)(sm + KVHI + a) = hh;
    }
    __syncthreads();

    float acc[4][4];
#pragma unroll
    for (int nt = 0; nt < 4; nt++)
#pragma unroll
        for (int e = 0; e < 4; e++) acc[nt][e] = 0.f;

    const int r0 = wid * 16;
    const uint32_t QB[2] = {sb + QHI, sb + QLO};
#pragma unroll
    for (int p = 0; p < 2; p++) {
#pragma unroll
        for (int kk = 0; kk < 2; kk++) {
            uint32_t af[4];
            int row = r0 + (lane & 15);
            int ch = sw_chunk(row, kk * 2 + (lane >> 4));
            ldsm4(af, QB[p] + row * 64 + ch * 16);
            uint32_t bf[2][4];
#pragma unroll
            for (int nt2 = 0; nt2 < 2; nt2++) {
                int g = lane >> 3, l8 = lane & 7;
                int row2 = nt2 * 16 + (g >> 1) * 8 + l8;
                int ch2 = sw_chunk(row2, kk * 2 + (g & 1));
                ldsm4(bf[nt2], sb + KVHI + row2 * 64 + ch2 * 16);
            }
#pragma unroll
            for (int nt = 0; nt < 4; nt++)
                mma_f16(acc[nt], af, &bf[nt >> 1][(nt & 1) * 2]);
        }
    }

    int c = r0 + (lane >> 2);
    float a0 = ed[c], a1 = ed[c + 8];
#pragma unroll
    for (int nt = 0; nt < 4; nt++) {
        int e = nt * 8 + (lane & 3) * 2;
#pragma unroll
        for (int half = 0; half < 2; half++) {
            int cc2 = c + half * 8;
            float al = half ? a1 : a0;
            size_t go = (tok0 + cc2) * CC + h*DD + e;
            float2 o0 = *(float2*)&g_o[go];
            o0.x += al * acc[nt][half*2+0];
            o0.y += al * acc[nt][half*2+1];
            __half h0 = __float2half_rn(o0.x);
            __half h1 = __float2half_rn(o0.y);
            __half l0 = __float2half_rn(o0.x - __half2float(h0));
            __half l1 = __float2half_rn(o0.y - __half2float(h1));
            size_t a2b = (tok0 + cc2) * KA2 + h*DD + e;
            *(uint32_t*)&A2[a2b]       = pack_h2(h0, h1);
            *(uint32_t*)&A2[a2b + 256] = pack_h2(l0, l1);
        }
    }
}

// ======================= launch =======================
extern "C" void kernel_launch(void* const* d_in, const int* in_sizes, int n_in,
                              void* d_out, int out_size)
{
    const float* x    = (const float*)d_in[0];
    const float* rel  = (const float*)d_in[1];
    const float* qkvw = (const float*)d_in[2];
    const float* qg   = (const float*)d_in[3];
    const float* kg   = (const float*)d_in[4];
    const float* pw   = (const float*)d_in[5];
    const float* pb   = (const float*)d_in[6];
    float* out = (float*)d_out;

    void* p_qkv = nullptr; cudaGetSymbolAddress(&p_qkv, g_qkv);
    void* p_A2  = nullptr; cudaGetSymbolAddress(&p_A2,  g_A2);
    void* p_W1h = nullptr; cudaGetSymbolAddress(&p_W1h, g_W1h);
    void* p_W2h = nullptr; cudaGetSymbolAddress(&p_W2h, g_W2h);
    void* p_qh  = nullptr; cudaGetSymbolAddress(&p_qh,  g_qh);
    void* p_ql  = nullptr; cudaGetSymbolAddress(&p_ql,  g_ql);

    cudaFuncSetAttribute(attn_chunk_hmma,
                         cudaFuncAttributeMaxDynamicSharedMemorySize, AT_SMEM);

    // 1) split (x + rel_pos) into fp16 hi/lo; weights to fp16 (hi only)
    conv_act_kernel<<<TT*64/256, 256>>>(x, rel, (__half*)p_A2);
    conv_w_kernel<<<768*64/256, 256>>>(qkvw, (__half*)p_W1h);
    conv_w_kernel<<<256*64/256, 256>>>(pw, (__half*)p_W2h);

    // 2) qkv = [Ahi,Alo] @ W1h^T  (HMMA fp16, 2-pass K) -> fp32 g_qkv
    gemm_f16_hmma<false><<<dim3(768/128, TT/128), 256>>>(
        (const __half*)p_A2, (const __half*)p_W1h, nullptr,
        (float*)p_qkv, 768);

    // 3) attention: intra + C_n, scan, inter (writes A2 [hi,lo] directly)
    attn_chunk_hmma<<<dim3(NC, HH, BB), 256, AT_SMEM>>>(
        qg, kg, (__half*)p_qh, (__half*)p_ql);
    kv_scan_kernel<<<BB*HH, 256>>>();
    attn_inter_hmma<<<dim3(NC, HH, BB), 256>>>(
        (const __half*)p_qh, (const __half*)p_ql, (__half*)p_A2);

    // 4) out = O2 @ W2h^T + bias
    gemm_f16_hmma<true><<<dim3(256/128, TT/128), 256>>>(
        (const __half*)p_A2, (const __half*)p_W2h, pb,
        out, 256);
}

// round 10
// speedup vs baseline: 3.1281x; 1.0012x over previous
#include <cuda_runtime.h>
#include <cuda_fp16.h>
#include <math.h>
#include <stdint.h>

// Problem constants
#define BB 8
#define LL 4096
#define CC 256
#define HH 8
#define DD 32
#define CH 128
#define NC 32          // LL / CH
#define TT (BB*LL)     // 32768 tokens
#define KA2  512       // A-operand storage width ([hi, lo])

// ---------------- static device scratch (no allocations allowed) ----------------
__device__ float g_qkv[(size_t)TT * 768];                 // qkv per token (fp32)
__device__ float g_o  [(size_t)TT * CC];                  // attention output (intra)
__device__ float g_C  [(size_t)BB*HH*NC * DD*DD];         // per-chunk KV contributions
__device__ float g_kvp[(size_t)BB*HH*NC * DD*DD];         // exclusive KV prefixes
__device__ __half g_A2 [(size_t)TT * KA2];                // [hi, lo] activations (fp16)
__device__ __half g_W1h[(size_t)768 * 256];               // qkv weight (fp16 hi only)
__device__ __half g_W2h[(size_t)256 * 256];               // proj weight (fp16 hi only)
__device__ __half g_qh [(size_t)TT * CC];                 // normalized q hat (hi)
__device__ __half g_ql [(size_t)TT * CC];                 // normalized q hat (lo)

// =========================== small PTX helpers ===========================
__device__ __forceinline__ uint32_t smem_u32(const void* p) {
    uint32_t a;
    asm("{ .reg .u64 t; cvta.to.shared.u64 t, %1; cvt.u32.u64 %0, t; }" : "=r"(a) : "l"(p));
    return a;
}
__device__ __forceinline__ void cpasync16(uint32_t dst, const void* src) {
    asm volatile("cp.async.cg.shared.global [%0], [%1], 16;" :: "r"(dst), "l"(src));
}
__device__ __forceinline__ void cp_commit() {
    asm volatile("cp.async.commit_group;" ::: "memory");
}
template<int N>
__device__ __forceinline__ void cp_wait() {
    asm volatile("cp.async.wait_group %0;" :: "n"(N) : "memory");
}
__device__ __forceinline__ void ldsm4(uint32_t* r, uint32_t addr) {
    asm volatile("ldmatrix.sync.aligned.m8n8.x4.shared.b16 {%0,%1,%2,%3}, [%4];"
                 : "=r"(r[0]), "=r"(r[1]), "=r"(r[2]), "=r"(r[3]) : "r"(addr));
}
__device__ __forceinline__ void mma_f16(float* c, const uint32_t* a, const uint32_t* b) {
    asm volatile("mma.sync.aligned.m16n8k16.row.col.f32.f16.f16.f32 "
                 "{%0,%1,%2,%3}, {%4,%5,%6,%7}, {%8,%9}, {%0,%1,%2,%3};"
                 : "+f"(c[0]), "+f"(c[1]), "+f"(c[2]), "+f"(c[3])
                 : "r"(a[0]), "r"(a[1]), "r"(a[2]), "r"(a[3]), "r"(b[0]), "r"(b[1]));
}
// xor swizzle of 16B chunk index within a 64B row (4 chunks)
__device__ __forceinline__ int sw_chunk(int r, int c) {
    return c ^ (r & 3) ^ ((r >> 2) & 1);
}
__device__ __forceinline__ uint32_t pack_h2(__half a, __half b) {
    uint32_t lo16 = *(uint16_t*)&a, hi16 = *(uint16_t*)&b;
    return lo16 | (hi16 << 16);
}

// =========================== hi/lo split conversion kernels ===========================
__global__ void conv_act_kernel(const float* __restrict__ x, const float* __restrict__ rp,
                                __half* __restrict__ A2)
{
    int idx = blockIdx.x * 256 + threadIdx.x;
    int m = idx >> 6, c4 = (idx & 63) << 2;
    float4 h = *(const float4*)&x[(size_t)m * 256 + c4];
    float4 r = *(const float4*)&rp[(size_t)(m & (LL-1)) * 256 + c4];
    h.x += r.x; h.y += r.y; h.z += r.z; h.w += r.w;
    float hv[4] = {h.x, h.y, h.z, h.w};
    __half hi[4], lo[4];
#pragma unroll
    for (int j = 0; j < 4; j++) {
        hi[j] = __float2half_rn(hv[j]);
        lo[j] = __float2half_rn(hv[j] - __half2float(hi[j]));
    }
    size_t base = (size_t)m * KA2 + c4;
    *(uint2*)&A2[base]       = *(uint2*)hi;
    *(uint2*)&A2[base + 256] = *(uint2*)lo;
}

__global__ void conv_w_kernel(const float* __restrict__ W, __half* __restrict__ Wh)
{
    int idx = blockIdx.x * 256 + threadIdx.x;
    int n = idx >> 6, c4 = (idx & 63) << 2;
    float4 h = *(const float4*)&W[(size_t)n * 256 + c4];
    float hv[4] = {h.x, h.y, h.z, h.w};
    __half hi[4];
#pragma unroll
    for (int j = 0; j < 4; j++) hi[j] = __float2half_rn(hv[j]);
    *(uint2*)&Wh[(size_t)n * 256 + c4] = *(uint2*)hi;
}

// =========================== HMMA fp16 GEMM: C = [Ahi,Alo] @ Wh^T (+bias) ===========================
// BK=64 slabs (8 total): A col s*64 (s 0-3 hi, 4-7 lo), B col (s&3)*64.
// 3-stage cp.async ring in dynamic smem (96 KB), ONE __syncthreads per slab.
// smem tile: 128 rows x 128 B, chunk swizzle ch = c ^ (row & 7).
#define NSTG 8
#define GS_STG 16384
#define GS_B0  (3*GS_STG)
#define GS_SMEM (6*GS_STG)   // 98304 bytes

template<bool BIAS>
__global__ void __launch_bounds__(256, 2) gemm_f16_hmma(
    const __half* __restrict__ A,
    const __half* __restrict__ Bw,
    const float* __restrict__ bias,
    float* __restrict__ Cmat, int Ntot)
{
    extern __shared__ __align__(16) char gsm[];
    const uint32_t as_base = smem_u32(gsm);
    const uint32_t bs_base = as_base + GS_B0;

    const int tid = threadIdx.x;
    const int wid = tid >> 5, lane = tid & 31;
    const int warp_m = wid & 1, warp_n = wid >> 1;
    const int m0 = blockIdx.y * 128;
    const int n0 = blockIdx.x * 128;

    float acc[4][4][4];
#pragma unroll
    for (int mt = 0; mt < 4; mt++)
#pragma unroll
        for (int nt = 0; nt < 4; nt++)
#pragma unroll
            for (int e = 0; e < 4; e++) acc[mt][nt][e] = 0.f;

    auto load_stage = [&](int s, int b) {
        const int sb_ = s & 3;
#pragma unroll
        for (int l = 0; l < 4; l++) {
            int i = tid + l * 256;
            int r = i >> 3, c = i & 7;
            int ch = c ^ (r & 7);
            cpasync16(as_base + b*GS_STG + r*128 + ch*16,
                      A  + (size_t)(m0 + r) * KA2 + s * 64 + c * 8);
            cpasync16(bs_base + b*GS_STG + r*128 + ch*16,
                      Bw + (size_t)(n0 + r) * 256 + sb_ * 64 + c * 8);
        }
        cp_commit();
    };

    load_stage(0, 0);
    load_stage(1, 1);

    int b = 0;
    for (int i = 0; i < NSTG; i++) {
        if (i + 1 < NSTG) cp_wait<1>(); else cp_wait<0>();
        __syncthreads();

#pragma unroll
        for (int kk = 0; kk < 4; kk++) {
            uint32_t af[4][4];
#pragma unroll
            for (int mt = 0; mt < 4; mt++) {
                int row = warp_m * 64 + mt * 16 + (lane & 15);
                int ch = (kk * 2 + (lane >> 4)) ^ (row & 7);
                ldsm4(af[mt], as_base + b*GS_STG + row * 128 + ch * 16);
            }
            uint32_t bf[2][4];
#pragma unroll
            for (int nt2 = 0; nt2 < 2; nt2++) {
                int g = lane >> 3, l8 = lane & 7;
                int row = warp_n * 32 + nt2 * 16 + (g >> 1) * 8 + l8;
                int ch = (kk * 2 + (g & 1)) ^ (row & 7);
                ldsm4(bf[nt2], bs_base + b*GS_STG + row * 128 + ch * 16);
            }
#pragma unroll
            for (int mt = 0; mt < 4; mt++)
#pragma unroll
                for (int nt = 0; nt < 4; nt++)
                    mma_f16(acc[mt][nt], af[mt], &bf[nt >> 1][(nt & 1) * 2]);
        }

        if (i + 2 < NSTG) {
            int b2 = b + 2; if (b2 >= 3) b2 -= 3;
            load_stage(i + 2, b2);
        }
        if (++b == 3) b = 0;
    }

#pragma unroll
    for (int mt = 0; mt < 4; mt++) {
        int row = m0 + warp_m * 64 + mt * 16 + (lane >> 2);
#pragma unroll
        for (int nt = 0; nt < 4; nt++) {
            int col = n0 + warp_n * 32 + nt * 8 + (lane & 3) * 2;
            float2 v0 = make_float2(acc[mt][nt][0], acc[mt][nt][1]);
            float2 v1 = make_float2(acc[mt][nt][2], acc[mt][nt][3]);
            if (BIAS) {
                float2 bv = *(const float2*)&bias[col];
                v0.x += bv.x; v0.y += bv.y;
                v1.x += bv.x; v1.y += bv.y;
            }
            *(float2*)&Cmat[(size_t)row * Ntot + col]       = v0;
            *(float2*)&Cmat[(size_t)(row + 8) * Ntot + col] = v1;
        }
    }
}

// ======================= HMMA attention: intra + per-chunk KV contribution =======================
// smem layout (bytes); total 84 KB -> 2 CTAs/SM
#define AT_ED   0                     // 129 floats
#define AT_NQ   640
#define AT_NK   1152
#define AT_QHI  2048
#define AT_QLO  (AT_QHI  + 8192)
#define AT_KHI  (AT_QLO  + 8192)
#define AT_KTHI (AT_KHI  + 8192)
#define AT_KTLO (AT_KTHI + 8192)
#define AT_VTHI (AT_KTLO + 8192)
#define AT_SC0H (AT_VTHI + 8192)      // 128 rows x 128 B
#define AT_SC0L (AT_SC0H + 16384)
#define AT_SMEM (AT_SC0L + 16384)     // 83968 bytes
// aliases (regions dead by the time they're reused)
#define AT_SC1H AT_QHI                // 64 rows x 128 B
#define AT_SC1L AT_QLO
#define AT_CRED AT_SC0H               // 16 KB: 4 warps x 4 KB (sc0 dead after P4)
#define AT_STGQ AT_SC0H               // fp32 q staging (P1->P2), dead before P3
#define AT_STGK AT_SC0L               // fp32 k staging

__global__ void __launch_bounds__(256, 2) attn_chunk_hmma(
    const float* __restrict__ qg, const float* __restrict__ kg,
    __half* __restrict__ qhout, __half* __restrict__ qlout)
{
    extern __shared__ char sm[];
    float* ed = (float*)(sm + AT_ED);
    float* nq = (float*)(sm + AT_NQ);
    float* nk = (float*)(sm + AT_NK);
    const uint32_t sb = smem_u32(sm);

    const int n = blockIdx.x, h = blockIdx.y, b = blockIdx.z;
    const int tid = threadIdx.x, lane = tid & 31, wid = tid >> 5;
    const float s = exp2f(-(float)(h + 1));
    for (int i = tid; i <= CH; i += 256) ed[i] = expf(-s * (float)i);

    const size_t tok0 = (size_t)(b*LL + n*CH);
    const size_t base = tok0 * 768 + h*DD;
    const int c4 = (tid & 7) * 4;

    // ---- P1: load q,k,v once; stage q,k fp32 in smem; convert v -> VT hi ----
    float sq[4], sk[4];
#pragma unroll
    for (int l = 0; l < 4; l++) {
        int r = (tid >> 3) + l * 32;
        const float* rowp = &g_qkv[base + (size_t)r * 768 + c4];
        float4 a  = *(const float4*)(rowp);
        float4 bb = *(const float4*)(rowp + 256);
        float4 cc = *(const float4*)(rowp + 512);
        sq[l] = a.x*a.x + a.y*a.y + a.z*a.z + a.w*a.w;
        sk[l] = bb.x*bb.x + bb.y*bb.y + bb.z*bb.z + bb.w*bb.w;
        *(float4*)(sm + AT_STGQ + l*4096 + tid*16) = a;
        *(float4*)(sm + AT_STGK + l*4096 + tid*16) = bb;
        float vv[4] = {cc.x, cc.y, cc.z, cc.w};
#pragma unroll
        for (int j = 0; j < 4; j++) {
            int d = c4 + j;
            __half vh = __float2half_rn(vv[j]);
            int aT = d*256 + (((r >> 3) ^ (d & 7)) * 16) + ((r & 7) * 2);
            *(__half*)(sm + AT_VTHI + aT) = vh;
        }
    }
#pragma unroll
    for (int m = 1; m < 8; m <<= 1) {
#pragma unroll
        for (int l = 0; l < 4; l++) {
            sq[l] += __shfl_xor_sync(0xffffffffu, sq[l], m);
            sk[l] += __shfl_xor_sync(0xffffffffu, sk[l], m);
        }
    }
    if ((tid & 7) == 0) {
        const float sqD = 5.656854249492380f;
#pragma unroll
        for (int l = 0; l < 4; l++) {
            int r = (tid >> 3) + l * 32;
            nq[r] = (sq[l] > 1e-24f) ? sqD * rsqrtf(sq[l]) : sqD * 1e12f;
            nk[r] = (sk[l] > 1e-24f) ? sqD * rsqrtf(sk[l]) : sqD * 1e12f;
        }
    }
    __syncthreads();

    // ---- P2: convert q (hi/lo), k (hi), kT (hi/lo, decay-folded) from staged fp32 ----
    float gq[4], gk[4];
#pragma unroll
    for (int j = 0; j < 4; j++) {
        gq[j] = __ldg(&qg[h*DD + c4 + j]);
        gk[j] = __ldg(&kg[h*DD + c4 + j]);
    }
#pragma unroll
    for (int l = 0; l < 4; l++) {
        int r = (tid >> 3) + l * 32;
        float4 a  = *(const float4*)(sm + AT_STGQ + l*4096 + tid*16);
        float4 bb = *(const float4*)(sm + AT_STGK + l*4096 + tid*16);
        float rq = nq[r], rk = nk[r], dk = ed[CH - r];
        float qv[4] = {a.x, a.y, a.z, a.w};
        float kv[4] = {bb.x, bb.y, bb.z, bb.w};
        __half qh4[4], ql4[4], kh4[4];
#pragma unroll
        for (int j = 0; j < 4; j++) {
            int d = c4 + j;
            float qn = qv[j] * rq * gq[j];
            float kn = kv[j] * rk * gk[j];
            qh4[j] = __float2half_rn(qn);
            ql4[j] = __float2half_rn(qn - __half2float(qh4[j]));
            kh4[j] = __float2half_rn(kn);
            float kt = kn * dk;
            __half kth = __float2half_rn(kt);
            __half ktl = __float2half_rn(kt - __half2float(kth));
            int aT = d*256 + (((r >> 3) ^ (d & 7)) * 16) + ((r & 7) * 2);
            *(__half*)(sm + AT_KTHI + aT) = kth;
            *(__half*)(sm + AT_KTLO + aT) = ktl;
        }
        int a64 = r*64 + sw_chunk(r, c4 >> 3) * 16 + ((c4 & 7) * 2);
        *(uint2*)(sm + AT_QHI + a64) = *(uint2*)qh4;
        *(uint2*)(sm + AT_QLO + a64) = *(uint2*)ql4;
        *(uint2*)(sm + AT_KHI + a64) = *(uint2*)kh4;
        *(uint2*)(qhout + (tok0 + r)*CC + h*DD + c4) = *(uint2*)qh4;
        *(uint2*)(qlout + (tok0 + r)*CC + h*DD + c4) = *(uint2*)ql4;
    }
    __syncthreads();

    const uint32_t QB[2] = {sb + AT_QHI, sb + AT_QLO};
    const int g = lane >> 3, l8 = lane & 7;

    // ---- P3: scores half0  S[:, 0:64]  (all 128 rows), 2 passes ----
    float acc0[8][4];
#pragma unroll
    for (int nt = 0; nt < 8; nt++)
#pragma unroll
        for (int e = 0; e < 4; e++) acc0[nt][e] = 0.f;
#pragma unroll
    for (int p = 0; p < 2; p++) {
#pragma unroll
        for (int kk = 0; kk < 2; kk++) {
            uint32_t af[4];
            int row = wid * 16 + (lane & 15);
            ldsm4(af, QB[p] + row * 64 + sw_chunk(row, kk * 2 + (lane >> 4)) * 16);
            uint32_t bf[4][4];
#pragma unroll
            for (int nt2 = 0; nt2 < 4; nt2++) {
                int row2 = nt2 * 16 + (g >> 1) * 8 + l8;
                ldsm4(bf[nt2], sb + AT_KHI + row2 * 64 + sw_chunk(row2, kk * 2 + (g & 1)) * 16);
            }
#pragma unroll
            for (int nt = 0; nt < 8; nt++)
                mma_f16(acc0[nt], af, &bf[nt >> 1][(nt & 1) * 2]);
        }
    }
    // mask + decay + write sc0
    {
        int c_lo = wid * 16 + (lane >> 2);
#pragma unroll
        for (int nt = 0; nt < 8; nt++) {
            int mm = nt * 8 + (lane & 3) * 2;
#pragma unroll
            for (int half = 0; half < 2; half++) {
                int c = c_lo + half * 8;
                float v0 = acc0[nt][half*2+0], v1 = acc0[nt][half*2+1];
                int d0 = c - mm, d1 = c - mm - 1;
                float s0 = (d0 >= 0) ? v0 * ed[d0] : 0.f;
                float s1 = (d1 >= 0) ? v1 * ed[d1] : 0.f;
                __half h0 = __float2half_rn(s0);
                __half h1 = __float2half_rn(s1);
                __half l0 = __float2half_rn(s0 - __half2float(h0));
                __half l1 = __float2half_rn(s1 - __half2float(h1));
                int addr = c * 128 + (((mm >> 3) ^ (c & 7)) * 16) + ((mm * 2) & 15);
                *(uint32_t*)(sm + AT_SC0H + addr) = pack_h2(h0, h1);
                *(uint32_t*)(sm + AT_SC0L + addr) = pack_h2(l0, l1);
            }
        }
    }
    __syncthreads();

    // ---- P4: o_intra part A (K = 0..64, all rows), 2 passes ----
    float oacc[4][4];
#pragma unroll
    for (int nt = 0; nt < 4; nt++)
#pragma unroll
        for (int e = 0; e < 4; e++) oacc[nt][e] = 0.f;
    {
        const uint32_t AB[2] = {sb + AT_SC0H, sb + AT_SC0L};
        const int r0 = wid * 16;
#pragma unroll
        for (int p = 0; p < 2; p++) {
#pragma unroll
            for (int kk = 0; kk < 4; kk++) {
                uint32_t af[4];
                int row = r0 + (lane & 15);
                int ch = (kk * 2 + (lane >> 4)) ^ (row & 7);
                ldsm4(af, AB[p] + row * 128 + ch * 16);
                uint32_t bf[2][4];
#pragma unroll
                for (int nt2 = 0; nt2 < 2; nt2++) {
                    int row2 = nt2 * 16 + (g >> 1) * 8 + l8;
                    int ch2 = (kk * 2 + (g & 1)) ^ (row2 & 7);
                    ldsm4(bf[nt2], sb + AT_VTHI + row2 * 256 + ch2 * 16);
                }
#pragma unroll
                for (int nt = 0; nt < 4; nt++)
                    mma_f16(oacc[nt], af, &bf[nt >> 1][(nt & 1) * 2]);
            }
        }
    }
    // rows 0..63 are complete (cols 64+ masked to zero) -> store now
    if (wid < 4) {
        int c = wid * 16 + (lane >> 2);
#pragma unroll
        for (int nt = 0; nt < 4; nt++) {
            int e = nt * 8 + (lane & 3) * 2;
            size_t go = (tok0 + c) * CC + h*DD + e;
            *(float2*)&g_o[go]        = make_float2(oacc[nt][0], oacc[nt][1]);
            *(float2*)&g_o[go + 8*CC] = make_float2(oacc[nt][2], oacc[nt][3]);
        }
    }

    // ---- P5: scores half1  S[64:128, 64:128]  (all 8 warps), 2 passes ----
    float acc1[4][4];
#pragma unroll
    for (int nt = 0; nt < 4; nt++)
#pragma unroll
        for (int e = 0; e < 4; e++) acc1[nt][e] = 0.f;
    const int c0s = 64 + (wid & 3) * 16;
    const int mbs = 64 + (wid >> 2) * 32;
#pragma unroll
    for (int p = 0; p < 2; p++) {
#pragma unroll
        for (int kk = 0; kk < 2; kk++) {
            uint32_t af[4];
            int row = c0s + (lane & 15);
            ldsm4(af, QB[p] + row * 64 + sw_chunk(row, kk * 2 + (lane >> 4)) * 16);
            uint32_t bf[2][4];
#pragma unroll
            for (int nt2 = 0; nt2 < 2; nt2++) {
                int row2 = mbs + nt2 * 16 + (g >> 1) * 8 + l8;
                ldsm4(bf[nt2], sb + AT_KHI + row2 * 64 + sw_chunk(row2, kk * 2 + (g & 1)) * 16);
            }
#pragma unroll
            for (int nt = 0; nt < 4; nt++)
                mma_f16(acc1[nt], af, &bf[nt >> 1][(nt & 1) * 2]);
        }
    }
    __syncthreads();   // all Q/K fragment reads done; QHI/QLO become sc1

    {
        int c_lo = c0s + (lane >> 2);
#pragma unroll
        for (int nt = 0; nt < 4; nt++) {
            int mm = mbs + nt * 8 + (lane & 3) * 2;
#pragma unroll
            for (int half = 0; half < 2; half++) {
                int c = c_lo + half * 8;
                float v0 = acc1[nt][half*2+0], v1 = acc1[nt][half*2+1];
                int d0 = c - mm, d1 = c - mm - 1;
                float s0 = (d0 >= 0) ? v0 * ed[d0] : 0.f;
                float s1 = (d1 >= 0) ? v1 * ed[d1] : 0.f;
                __half h0 = __float2half_rn(s0);
                __half h1 = __float2half_rn(s1);
                __half l0 = __float2half_rn(s0 - __half2float(h0));
                __half l1 = __float2half_rn(s1 - __half2float(h1));
                int cr = c - 64, mr = mm - 64;
                int addr = cr * 128 + (((mr >> 3) ^ (cr & 7)) * 16) + ((mr * 2) & 15);
                *(uint32_t*)(sm + AT_SC1H + addr) = pack_h2(h0, h1);
                *(uint32_t*)(sm + AT_SC1L + addr) = pack_h2(l0, l1);
            }
        }
    }
    __syncthreads();

    // ---- P6: warps 4-7: o_intra part B (rows 64..127, K=64..128); warps 0-3: C_n ----
    if (wid >= 4) {
        const uint32_t AB1[2] = {sb + AT_SC1H, sb + AT_SC1L};
        const int r0 = (wid - 4) * 16;
#pragma unroll
        for (int p = 0; p < 2; p++) {
#pragma unroll
            for (int kk = 0; kk < 4; kk++) {
                uint32_t af[4];
                int row = r0 + (lane & 15);
                int ch = (kk * 2 + (lane >> 4)) ^ (row & 7);
                ldsm4(af, AB1[p] + row * 128 + ch * 16);
                uint32_t bf[2][4];
#pragma unroll
                for (int nt2 = 0; nt2 < 2; nt2++) {
                    int row2 = nt2 * 16 + (g >> 1) * 8 + l8;
                    int ch2 = ((kk + 4) * 2 + (g & 1)) ^ (row2 & 7);
                    ldsm4(bf[nt2], sb + AT_VTHI + row2 * 256 + ch2 * 16);
                }
#pragma unroll
                for (int nt = 0; nt < 4; nt++)
                    mma_f16(oacc[nt], af, &bf[nt >> 1][(nt & 1) * 2]);
            }
        }
        int c = wid * 16 + (lane >> 2);
#pragma unroll
        for (int nt = 0; nt < 4; nt++) {
            int e = nt * 8 + (lane & 3) * 2;
            size_t go = (tok0 + c) * CC + h*DD + e;
            *(float2*)&g_o[go]        = make_float2(oacc[nt][0], oacc[nt][1]);
            *(float2*)&g_o[go + 8*CC] = make_float2(oacc[nt][2], oacc[nt][3]);
        }
    } else {
        float cacc[2][4][4];
#pragma unroll
        for (int mt = 0; mt < 2; mt++)
#pragma unroll
            for (int nt = 0; nt < 4; nt++)
#pragma unroll
                for (int e = 0; e < 4; e++) cacc[mt][nt][e] = 0.f;

        const uint32_t KA[2] = {sb + AT_KTHI, sb + AT_KTLO};
#pragma unroll
        for (int p = 0; p < 2; p++) {
#pragma unroll
            for (int kl = 0; kl < 2; kl++) {
                int kk = wid * 2 + kl;
                uint32_t af[2][4];
#pragma unroll
                for (int mt = 0; mt < 2; mt++) {
                    int row = mt * 16 + (lane & 15);
                    int ch = (kk * 2 + (lane >> 4)) ^ (row & 7);
                    ldsm4(af[mt], KA[p] + row * 256 + ch * 16);
                }
                uint32_t bf[2][4];
#pragma unroll
                for (int nt2 = 0; nt2 < 2; nt2++) {
                    int row2 = nt2 * 16 + (g >> 1) * 8 + l8;
                    int ch2 = (kk * 2 + (g & 1)) ^ (row2 & 7);
                    ldsm4(bf[nt2], sb + AT_VTHI + row2 * 256 + ch2 * 16);
                }
#pragma unroll
                for (int mt = 0; mt < 2; mt++)
#pragma unroll
                    for (int nt = 0; nt < 4; nt++)
                        mma_f16(cacc[mt][nt], af[mt], &bf[nt >> 1][(nt & 1) * 2]);
            }
        }
        float* red = (float*)(sm + AT_CRED) + wid * 1024;
#pragma unroll
        for (int mt = 0; mt < 2; mt++) {
            int d = mt * 16 + (lane >> 2);
#pragma unroll
            for (int nt = 0; nt < 4; nt++) {
                int e = nt * 8 + (lane & 3) * 2;
                *(float2*)&red[d * 32 + e]       = make_float2(cacc[mt][nt][0], cacc[mt][nt][1]);
                *(float2*)&red[(d + 8) * 32 + e] = make_float2(cacc[mt][nt][2], cacc[mt][nt][3]);
            }
        }
    }
    __syncthreads();
    {
        const float* red = (const float*)(sm + AT_CRED);
        const size_t cb = ((size_t)((b*HH + h)*NC + n)) * 1024;
        for (int i = tid; i < 1024; i += 256)
            g_C[cb + i] = red[i] + red[1024 + i] + red[2048 + i] + red[3072 + i];
    }
}

// ======================= sequential KV scan (exclusive prefix) =======================
__global__ void kv_scan_kernel()
{
    const int bh = blockIdx.x;
    const int h = bh & 7;
    const int tid = threadIdx.x;
    const float bd = expf(-exp2f(-(float)(h+1)) * (float)CH);
    float4 kv = make_float4(0.f, 0.f, 0.f, 0.f);
    const size_t base = (size_t)bh * NC * 1024 + tid*4;
    for (int n = 0; n < NC; n++) {
        const size_t o = base + (size_t)n * 1024;
        *(float4*)&g_kvp[o] = kv;
        float4 c = *(const float4*)&g_C[o];
        kv.x = bd*kv.x + c.x; kv.y = bd*kv.y + c.y;
        kv.z = bd*kv.z + c.z; kv.w = bd*kv.w + c.w;
    }
}

// ======================= HMMA inter-chunk + fused hi/lo split of o -> A2 =======================
__global__ void __launch_bounds__(256) attn_inter_hmma(
    const __half* __restrict__ qh, const __half* __restrict__ ql,
    __half* __restrict__ A2)
{
    const int n = blockIdx.x;
    const int h = blockIdx.y, b = blockIdx.z;

    __shared__ __align__(16) char sm[8192*2 + 2048 + 1024];
    const int QHI = 0, QLO = 8192, KVHI = 16384, EDO = 18432;
    float* ed = (float*)(sm + EDO);
    const uint32_t sb = smem_u32(sm);

    const int tid = threadIdx.x, lane = tid & 31, wid = tid >> 5;
    const float s = exp2f(-(float)(h+1));
    for (int i = tid; i < CH; i += 256) ed[i] = expf(-s * (float)i);

    const size_t tok0 = (size_t)(b*LL + n*CH);
    for (int i = tid; i < 512; i += 256) {
        int r = i >> 2, c = i & 3;
        uint4 v = *(const uint4*)(qh + (tok0 + r)*CC + h*DD + c*8);
        *(uint4*)(sm + QHI + r*64 + sw_chunk(r, c)*16) = v;
        uint4 w = *(const uint4*)(ql + (tok0 + r)*CC + h*DD + c*8);
        *(uint4*)(sm + QLO + r*64 + sw_chunk(r, c)*16) = w;
    }
    const size_t kb = ((size_t)((b*HH + h)*NC + n)) * 1024;
    for (int i = tid; i < 1024; i += 256) {
        int d = i >> 5, e = i & 31;
        float v = g_kvp[kb + i];
        __half hh = __float2half_rn(v);
        int a = e*64 + sw_chunk(e, d >> 3)*16 + (d & 7)*2;
        *(__half*)(sm + KVHI + a) = hh;
    }
    __syncthreads();

    float acc[4][4];
#pragma unroll
    for (int nt = 0; nt < 4; nt++)
#pragma unroll
        for (int e = 0; e < 4; e++) acc[nt][e] = 0.f;

    const int r0 = wid * 16;
    const uint32_t QB[2] = {sb + QHI, sb + QLO};
#pragma unroll
    for (int p = 0; p < 2; p++) {
#pragma unroll
        for (int kk = 0; kk < 2; kk++) {
            uint32_t af[4];
            int row = r0 + (lane & 15);
            int ch = sw_chunk(row, kk * 2 + (lane >> 4));
            ldsm4(af, QB[p] + row * 64 + ch * 16);
            uint32_t bf[2][4];
#pragma unroll
            for (int nt2 = 0; nt2 < 2; nt2++) {
                int g = lane >> 3, l8 = lane & 7;
                int row2 = nt2 * 16 + (g >> 1) * 8 + l8;
                int ch2 = sw_chunk(row2, kk * 2 + (g & 1));
                ldsm4(bf[nt2], sb + KVHI + row2 * 64 + ch2 * 16);
            }
#pragma unroll
            for (int nt = 0; nt < 4; nt++)
                mma_f16(acc[nt], af, &bf[nt >> 1][(nt & 1) * 2]);
        }
    }

    int c = r0 + (lane >> 2);
    float a0 = ed[c], a1 = ed[c + 8];
#pragma unroll
    for (int nt = 0; nt < 4; nt++) {
        int e = nt * 8 + (lane & 3) * 2;
#pragma unroll
        for (int half = 0; half < 2; half++) {
            int cc2 = c + half * 8;
            float al = half ? a1 : a0;
            size_t go = (tok0 + cc2) * CC + h*DD + e;
            float2 o0 = *(float2*)&g_o[go];
            o0.x += al * acc[nt][half*2+0];
            o0.y += al * acc[nt][half*2+1];
            __half h0 = __float2half_rn(o0.x);
            __half h1 = __float2half_rn(o0.y);
            __half l0 = __float2half_rn(o0.x - __half2float(h0));
            __half l1 = __float2half_rn(o0.y - __half2float(h1));
            size_t a2b = (tok0 + cc2) * KA2 + h*DD + e;
            *(uint32_t*)&A2[a2b]       = pack_h2(h0, h1);
            *(uint32_t*)&A2[a2b + 256] = pack_h2(l0, l1);
        }
    }
}

// ======================= launch =======================
extern "C" void kernel_launch(void* const* d_in, const int* in_sizes, int n_in,
                              void* d_out, int out_size)
{
    const float* x    = (const float*)d_in[0];
    const float* rel  = (const float*)d_in[1];
    const float* qkvw = (const float*)d_in[2];
    const float* qg   = (const float*)d_in[3];
    const float* kg   = (const float*)d_in[4];
    const float* pw   = (const float*)d_in[5];
    const float* pb   = (const float*)d_in[6];
    float* out = (float*)d_out;

    void* p_qkv = nullptr; cudaGetSymbolAddress(&p_qkv, g_qkv);
    void* p_A2  = nullptr; cudaGetSymbolAddress(&p_A2,  g_A2);
    void* p_W1h = nullptr; cudaGetSymbolAddress(&p_W1h, g_W1h);
    void* p_W2h = nullptr; cudaGetSymbolAddress(&p_W2h, g_W2h);
    void* p_qh  = nullptr; cudaGetSymbolAddress(&p_qh,  g_qh);
    void* p_ql  = nullptr; cudaGetSymbolAddress(&p_ql,  g_ql);

    cudaFuncSetAttribute(attn_chunk_hmma,
                         cudaFuncAttributeMaxDynamicSharedMemorySize, AT_SMEM);
    cudaFuncSetAttribute(gemm_f16_hmma<false>,
                         cudaFuncAttributeMaxDynamicSharedMemorySize, GS_SMEM);
    cudaFuncSetAttribute(gemm_f16_hmma<true>,
                         cudaFuncAttributeMaxDynamicSharedMemorySize, GS_SMEM);

    // 1) split (x + rel_pos) into fp16 hi/lo; weights to fp16 (hi only)
    conv_act_kernel<<<TT*64/256, 256>>>(x, rel, (__half*)p_A2);
    conv_w_kernel<<<768*64/256, 256>>>(qkvw, (__half*)p_W1h);
    conv_w_kernel<<<256*64/256, 256>>>(pw, (__half*)p_W2h);

    // 2) qkv = [Ahi,Alo] @ W1h^T  (HMMA fp16, 2-pass K, BK=64) -> fp32 g_qkv
    gemm_f16_hmma<false><<<dim3(768/128, TT/128), 256, GS_SMEM>>>(
        (const __half*)p_A2, (const __half*)p_W1h, nullptr,
        (float*)p_qkv, 768);

    // 3) attention: intra + C_n, scan, inter (writes A2 [hi,lo] directly)
    attn_chunk_hmma<<<dim3(NC, HH, BB), 256, AT_SMEM>>>(
        qg, kg, (__half*)p_qh, (__half*)p_ql);
    kv_scan_kernel<<<BB*HH, 256>>>();
    attn_inter_hmma<<<dim3(NC, HH, BB), 256>>>(
        (const __half*)p_qh, (const __half*)p_ql, (__half*)p_A2);

    // 4) out = O2 @ W2h^T + bias
    gemm_f16_hmma<true><<<dim3(256/128, TT/128), 256, GS_SMEM>>>(
        (const __half*)p_A2, (const __half*)p_W2h, pb,
        out, 256);
}

// round 11
// speedup vs baseline: 3.4109x; 1.0904x over previous
#include <cuda_runtime.h>
#include <cuda_fp16.h>
#include <math.h>
#include <stdint.h>

// Problem constants
#define BB 8
#define LL 4096
#define CC 256
#define HH 8
#define DD 32
#define CH 128
#define NC 32          // LL / CH
#define TT (BB*LL)     // 32768 tokens
#define KA2  512       // A-operand storage width ([hi, lo])

// ---------------- static device scratch (no allocations allowed) ----------------
__device__ float g_qkv[(size_t)TT * 768];                 // qkv per token (fp32)
__device__ float g_o  [(size_t)TT * CC];                  // attention output (intra)
__device__ float g_C  [(size_t)BB*HH*NC * DD*DD];         // per-chunk KV contributions
__device__ float g_kvp[(size_t)BB*HH*NC * DD*DD];         // exclusive KV prefixes
__device__ __half g_A2 [(size_t)TT * KA2];                // [hi, lo] activations (fp16)
__device__ __half g_W1h[(size_t)768 * 256];               // qkv weight (fp16 hi only)
__device__ __half g_W2h[(size_t)256 * 256];               // proj weight (fp16 hi only)
__device__ __half g_qh [(size_t)TT * CC];                 // normalized q hat (hi)
__device__ __half g_ql [(size_t)TT * CC];                 // normalized q hat (lo)

// =========================== small PTX helpers ===========================
__device__ __forceinline__ uint32_t smem_u32(const void* p) {
    uint32_t a;
    asm("{ .reg .u64 t; cvta.to.shared.u64 t, %1; cvt.u32.u64 %0, t; }" : "=r"(a) : "l"(p));
    return a;
}
__device__ __forceinline__ void cpasync16(uint32_t dst, const void* src) {
    asm volatile("cp.async.cg.shared.global [%0], [%1], 16;" :: "r"(dst), "l"(src));
}
__device__ __forceinline__ void cp_commit() {
    asm volatile("cp.async.commit_group;" ::: "memory");
}
template<int N>
__device__ __forceinline__ void cp_wait() {
    asm volatile("cp.async.wait_group %0;" :: "n"(N) : "memory");
}
__device__ __forceinline__ void ldsm4(uint32_t* r, uint32_t addr) {
    asm volatile("ldmatrix.sync.aligned.m8n8.x4.shared.b16 {%0,%1,%2,%3}, [%4];"
                 : "=r"(r[0]), "=r"(r[1]), "=r"(r[2]), "=r"(r[3]) : "r"(addr));
}
__device__ __forceinline__ void mma_f16(float* c, const uint32_t* a, const uint32_t* b) {
    asm volatile("mma.sync.aligned.m16n8k16.row.col.f32.f16.f16.f32 "
                 "{%0,%1,%2,%3}, {%4,%5,%6,%7}, {%8,%9}, {%0,%1,%2,%3};"
                 : "+f"(c[0]), "+f"(c[1]), "+f"(c[2]), "+f"(c[3])
                 : "r"(a[0]), "r"(a[1]), "r"(a[2]), "r"(a[3]), "r"(b[0]), "r"(b[1]));
}
// xor swizzle of 16B chunk index within a 64B row (4 chunks)
__device__ __forceinline__ int sw_chunk(int r, int c) {
    return c ^ (r & 3) ^ ((r >> 2) & 1);
}
__device__ __forceinline__ uint32_t pack_h2(__half a, __half b) {
    uint32_t lo16 = *(uint16_t*)&a, hi16 = *(uint16_t*)&b;
    return lo16 | (hi16 << 16);
}

// =========================== hi/lo split conversion kernels ===========================
__global__ void conv_act_kernel(const float* __restrict__ x, const float* __restrict__ rp,
                                __half* __restrict__ A2)
{
    int idx = blockIdx.x * 256 + threadIdx.x;
    int m = idx >> 6, c4 = (idx & 63) << 2;
    float4 h = *(const float4*)&x[(size_t)m * 256 + c4];
    float4 r = *(const float4*)&rp[(size_t)(m & (LL-1)) * 256 + c4];
    h.x += r.x; h.y += r.y; h.z += r.z; h.w += r.w;
    float hv[4] = {h.x, h.y, h.z, h.w};
    __half hi[4], lo[4];
#pragma unroll
    for (int j = 0; j < 4; j++) {
        hi[j] = __float2half_rn(hv[j]);
        lo[j] = __float2half_rn(hv[j] - __half2float(hi[j]));
    }
    size_t base = (size_t)m * KA2 + c4;
    *(uint2*)&A2[base]       = *(uint2*)hi;
    *(uint2*)&A2[base + 256] = *(uint2*)lo;
}

__global__ void conv_w_kernel(const float* __restrict__ W, __half* __restrict__ Wh)
{
    int idx = blockIdx.x * 256 + threadIdx.x;
    int n = idx >> 6, c4 = (idx & 63) << 2;
    float4 h = *(const float4*)&W[(size_t)n * 256 + c4];
    float hv[4] = {h.x, h.y, h.z, h.w};
    __half hi[4];
#pragma unroll
    for (int j = 0; j < 4; j++) hi[j] = __float2half_rn(hv[j]);
    *(uint2*)&Wh[(size_t)n * 256 + c4] = *(uint2*)hi;
}

// =========================== HMMA fp16 GEMM: C = [Ahi,Alo] @ Wh^T (+bias) ===========================
// BK=64 slabs (8 total): A col s*64 (s 0-3 hi, 4-7 lo), B col (s&3)*64.
// 3-stage cp.async ring in dynamic smem (96 KB), ONE __syncthreads per slab.
#define NSTG 8
#define GS_STG 16384
#define GS_B0  (3*GS_STG)
#define GS_SMEM (6*GS_STG)   // 98304 bytes

template<bool BIAS>
__global__ void __launch_bounds__(256, 2) gemm_f16_hmma(
    const __half* __restrict__ A,
    const __half* __restrict__ Bw,
    const float* __restrict__ bias,
    float* __restrict__ Cmat, int Ntot)
{
    extern __shared__ __align__(16) char gsm[];
    const uint32_t as_base = smem_u32(gsm);
    const uint32_t bs_base = as_base + GS_B0;

    const int tid = threadIdx.x;
    const int wid = tid >> 5, lane = tid & 31;
    const int warp_m = wid & 1, warp_n = wid >> 1;
    const int m0 = blockIdx.y * 128;
    const int n0 = blockIdx.x * 128;

    float acc[4][4][4];
#pragma unroll
    for (int mt = 0; mt < 4; mt++)
#pragma unroll
        for (int nt = 0; nt < 4; nt++)
#pragma unroll
            for (int e = 0; e < 4; e++) acc[mt][nt][e] = 0.f;

    auto load_stage = [&](int s, int b) {
        const int sb_ = s & 3;
#pragma unroll
        for (int l = 0; l < 4; l++) {
            int i = tid + l * 256;
            int r = i >> 3, c = i & 7;
            int ch = c ^ (r & 7);
            cpasync16(as_base + b*GS_STG + r*128 + ch*16,
                      A  + (size_t)(m0 + r) * KA2 + s * 64 + c * 8);
            cpasync16(bs_base + b*GS_STG + r*128 + ch*16,
                      Bw + (size_t)(n0 + r) * 256 + sb_ * 64 + c * 8);
        }
        cp_commit();
    };

    load_stage(0, 0);
    load_stage(1, 1);

    int b = 0;
    for (int i = 0; i < NSTG; i++) {
        if (i + 1 < NSTG) cp_wait<1>(); else cp_wait<0>();
        __syncthreads();

#pragma unroll
        for (int kk = 0; kk < 4; kk++) {
            uint32_t af[4][4];
#pragma unroll
            for (int mt = 0; mt < 4; mt++) {
                int row = warp_m * 64 + mt * 16 + (lane & 15);
                int ch = (kk * 2 + (lane >> 4)) ^ (row & 7);
                ldsm4(af[mt], as_base + b*GS_STG + row * 128 + ch * 16);
            }
            uint32_t bf[2][4];
#pragma unroll
            for (int nt2 = 0; nt2 < 2; nt2++) {
                int g = lane >> 3, l8 = lane & 7;
                int row = warp_n * 32 + nt2 * 16 + (g >> 1) * 8 + l8;
                int ch = (kk * 2 + (g & 1)) ^ (row & 7);
                ldsm4(bf[nt2], bs_base + b*GS_STG + row * 128 + ch * 16);
            }
#pragma unroll
            for (int mt = 0; mt < 4; mt++)
#pragma unroll
                for (int nt = 0; nt < 4; nt++)
                    mma_f16(acc[mt][nt], af[mt], &bf[nt >> 1][(nt & 1) * 2]);
        }

        if (i + 2 < NSTG) {
            int b2 = b + 2; if (b2 >= 3) b2 -= 3;
            load_stage(i + 2, b2);
        }
        if (++b == 3) b = 0;
    }

#pragma unroll
    for (int mt = 0; mt < 4; mt++) {
        int row = m0 + warp_m * 64 + mt * 16 + (lane >> 2);
#pragma unroll
        for (int nt = 0; nt < 4; nt++) {
            int col = n0 + warp_n * 32 + nt * 8 + (lane & 3) * 2;
            float2 v0 = make_float2(acc[mt][nt][0], acc[mt][nt][1]);
            float2 v1 = make_float2(acc[mt][nt][2], acc[mt][nt][3]);
            if (BIAS) {
                float2 bv = *(const float2*)&bias[col];
                v0.x += bv.x; v0.y += bv.y;
                v1.x += bv.x; v1.y += bv.y;
            }
            *(float2*)&Cmat[(size_t)row * Ntot + col]       = v0;
            *(float2*)&Cmat[(size_t)(row + 8) * Ntot + col] = v1;
        }
    }
}

// ======================= HMMA attention: intra + per-chunk KV contribution =======================
// smem layout (bytes); total 84 KB -> 2 CTAs/SM (reg-bound at 2 anyway)
#define AT_ED   0                     // 129 floats
#define AT_NQ   640
#define AT_NK   1152
#define AT_QHI  2048
#define AT_QLO  (AT_QHI  + 8192)
#define AT_KHI  (AT_QLO  + 8192)
#define AT_KTHI (AT_KHI  + 8192)
#define AT_KTLO (AT_KTHI + 8192)      // unused region (kept for layout stability)
#define AT_VTHI (AT_KTLO + 8192)
#define AT_SC0H (AT_VTHI + 8192)      // 128 rows x 128 B
#define AT_SC0L (AT_SC0H + 16384)     // now only used as staging scratch
#define AT_SMEM (AT_SC0L + 16384)     // 83968 bytes
// aliases (regions dead by the time they're reused)
#define AT_SC1H AT_QHI                // 64 rows x 128 B
#define AT_CRED AT_SC0H               // 16 KB: 4 warps x 4 KB (sc0 dead after P4)
#define AT_STGQ AT_SC0H               // fp32 q staging (P1->P2), dead before P3
#define AT_STGK AT_SC0L               // fp32 k staging

__global__ void __launch_bounds__(256, 2) attn_chunk_hmma(
    const float* __restrict__ qg, const float* __restrict__ kg,
    __half* __restrict__ qhout, __half* __restrict__ qlout)
{
    extern __shared__ char sm[];
    float* ed = (float*)(sm + AT_ED);
    float* nq = (float*)(sm + AT_NQ);
    float* nk = (float*)(sm + AT_NK);
    const uint32_t sb = smem_u32(sm);

    const int n = blockIdx.x, h = blockIdx.y, b = blockIdx.z;
    const int tid = threadIdx.x, lane = tid & 31, wid = tid >> 5;
    const float s = exp2f(-(float)(h + 1));
    for (int i = tid; i <= CH; i += 256) ed[i] = expf(-s * (float)i);

    const size_t tok0 = (size_t)(b*LL + n*CH);
    const size_t base = tok0 * 768 + h*DD;
    const int c4 = (tid & 7) * 4;

    // ---- P1: load q,k,v once; stage q,k fp32 in smem; convert v -> VT hi ----
    float sq[4], sk[4];
#pragma unroll
    for (int l = 0; l < 4; l++) {
        int r = (tid >> 3) + l * 32;
        const float* rowp = &g_qkv[base + (size_t)r * 768 + c4];
        float4 a  = *(const float4*)(rowp);
        float4 bb = *(const float4*)(rowp + 256);
        float4 cc = *(const float4*)(rowp + 512);
        sq[l] = a.x*a.x + a.y*a.y + a.z*a.z + a.w*a.w;
        sk[l] = bb.x*bb.x + bb.y*bb.y + bb.z*bb.z + bb.w*bb.w;
        *(float4*)(sm + AT_STGQ + l*4096 + tid*16) = a;
        *(float4*)(sm + AT_STGK + l*4096 + tid*16) = bb;
        float vv[4] = {cc.x, cc.y, cc.z, cc.w};
#pragma unroll
        for (int j = 0; j < 4; j++) {
            int d = c4 + j;
            __half vh = __float2half_rn(vv[j]);
            int aT = d*256 + (((r >> 3) ^ (d & 7)) * 16) + ((r & 7) * 2);
            *(__half*)(sm + AT_VTHI + aT) = vh;
        }
    }
#pragma unroll
    for (int m = 1; m < 8; m <<= 1) {
#pragma unroll
        for (int l = 0; l < 4; l++) {
            sq[l] += __shfl_xor_sync(0xffffffffu, sq[l], m);
            sk[l] += __shfl_xor_sync(0xffffffffu, sk[l], m);
        }
    }
    if ((tid & 7) == 0) {
        const float sqD = 5.656854249492380f;
#pragma unroll
        for (int l = 0; l < 4; l++) {
            int r = (tid >> 3) + l * 32;
            nq[r] = (sq[l] > 1e-24f) ? sqD * rsqrtf(sq[l]) : sqD * 1e12f;
            nk[r] = (sk[l] > 1e-24f) ? sqD * rsqrtf(sk[l]) : sqD * 1e12f;
        }
    }
    __syncthreads();

    // ---- P2: convert q (hi/lo), k (hi), kT (hi, decay-folded) from staged fp32 ----
    float gq[4], gk[4];
#pragma unroll
    for (int j = 0; j < 4; j++) {
        gq[j] = __ldg(&qg[h*DD + c4 + j]);
        gk[j] = __ldg(&kg[h*DD + c4 + j]);
    }
#pragma unroll
    for (int l = 0; l < 4; l++) {
        int r = (tid >> 3) + l * 32;
        float4 a  = *(const float4*)(sm + AT_STGQ + l*4096 + tid*16);
        float4 bb = *(const float4*)(sm + AT_STGK + l*4096 + tid*16);
        float rq = nq[r], rk = nk[r], dk = ed[CH - r];
        float qv[4] = {a.x, a.y, a.z, a.w};
        float kv[4] = {bb.x, bb.y, bb.z, bb.w};
        __half qh4[4], ql4[4], kh4[4];
#pragma unroll
        for (int j = 0; j < 4; j++) {
            int d = c4 + j;
            float qn = qv[j] * rq * gq[j];
            float kn = kv[j] * rk * gk[j];
            qh4[j] = __float2half_rn(qn);
            ql4[j] = __float2half_rn(qn - __half2float(qh4[j]));
            kh4[j] = __float2half_rn(kn);
            __half kth = __float2half_rn(kn * dk);
            int aT = d*256 + (((r >> 3) ^ (d & 7)) * 16) + ((r & 7) * 2);
            *(__half*)(sm + AT_KTHI + aT) = kth;
        }
        int a64 = r*64 + sw_chunk(r, c4 >> 3) * 16 + ((c4 & 7) * 2);
        *(uint2*)(sm + AT_QHI + a64) = *(uint2*)qh4;
        *(uint2*)(sm + AT_QLO + a64) = *(uint2*)ql4;
        *(uint2*)(sm + AT_KHI + a64) = *(uint2*)kh4;
        *(uint2*)(qhout + (tok0 + r)*CC + h*DD + c4) = *(uint2*)qh4;
        *(uint2*)(qlout + (tok0 + r)*CC + h*DD + c4) = *(uint2*)ql4;
    }
    __syncthreads();

    const uint32_t QB[2] = {sb + AT_QHI, sb + AT_QLO};
    const int g = lane >> 3, l8 = lane & 7;

    // ---- P3: scores half0  S[:, 0:64]  (all 128 rows), 2 passes ----
    float acc0[8][4];
#pragma unroll
    for (int nt = 0; nt < 8; nt++)
#pragma unroll
        for (int e = 0; e < 4; e++) acc0[nt][e] = 0.f;
#pragma unroll
    for (int p = 0; p < 2; p++) {
#pragma unroll
        for (int kk = 0; kk < 2; kk++) {
            uint32_t af[4];
            int row = wid * 16 + (lane & 15);
            ldsm4(af, QB[p] + row * 64 + sw_chunk(row, kk * 2 + (lane >> 4)) * 16);
            uint32_t bf[4][4];
#pragma unroll
            for (int nt2 = 0; nt2 < 4; nt2++) {
                int row2 = nt2 * 16 + (g >> 1) * 8 + l8;
                ldsm4(bf[nt2], sb + AT_KHI + row2 * 64 + sw_chunk(row2, kk * 2 + (g & 1)) * 16);
            }
#pragma unroll
            for (int nt = 0; nt < 8; nt++)
                mma_f16(acc0[nt], af, &bf[nt >> 1][(nt & 1) * 2]);
        }
    }
    // mask + decay + write sc0 (hi only)
    {
        int c_lo = wid * 16 + (lane >> 2);
#pragma unroll
        for (int nt = 0; nt < 8; nt++) {
            int mm = nt * 8 + (lane & 3) * 2;
#pragma unroll
            for (int half = 0; half < 2; half++) {
                int c = c_lo + half * 8;
                float v0 = acc0[nt][half*2+0], v1 = acc0[nt][half*2+1];
                int d0 = c - mm, d1 = c - mm - 1;
                float s0 = (d0 >= 0) ? v0 * ed[d0] : 0.f;
                float s1 = (d1 >= 0) ? v1 * ed[d1] : 0.f;
                int addr = c * 128 + (((mm >> 3) ^ (c & 7)) * 16) + ((mm * 2) & 15);
                *(uint32_t*)(sm + AT_SC0H + addr) =
                    pack_h2(__float2half_rn(s0), __float2half_rn(s1));
            }
        }
    }
    __syncthreads();

    // ---- P4: o_intra part A (K = 0..64, all rows), hi only ----
    float oacc[4][4];
#pragma unroll
    for (int nt = 0; nt < 4; nt++)
#pragma unroll
        for (int e = 0; e < 4; e++) oacc[nt][e] = 0.f;
    {
        const int r0 = wid * 16;
#pragma unroll
        for (int kk = 0; kk < 4; kk++) {
            uint32_t af[4];
            int row = r0 + (lane & 15);
            int ch = (kk * 2 + (lane >> 4)) ^ (row & 7);
            ldsm4(af, sb + AT_SC0H + row * 128 + ch * 16);
            uint32_t bf[2][4];
#pragma unroll
            for (int nt2 = 0; nt2 < 2; nt2++) {
                int row2 = nt2 * 16 + (g >> 1) * 8 + l8;
                int ch2 = (kk * 2 + (g & 1)) ^ (row2 & 7);
                ldsm4(bf[nt2], sb + AT_VTHI + row2 * 256 + ch2 * 16);
            }
#pragma unroll
            for (int nt = 0; nt < 4; nt++)
                mma_f16(oacc[nt], af, &bf[nt >> 1][(nt & 1) * 2]);
        }
    }
    // rows 0..63 are complete (cols 64+ masked to zero) -> store now
    if (wid < 4) {
        int c = wid * 16 + (lane >> 2);
#pragma unroll
        for (int nt = 0; nt < 4; nt++) {
            int e = nt * 8 + (lane & 3) * 2;
            size_t go = (tok0 + c) * CC + h*DD + e;
            *(float2*)&g_o[go]        = make_float2(oacc[nt][0], oacc[nt][1]);
            *(float2*)&g_o[go + 8*CC] = make_float2(oacc[nt][2], oacc[nt][3]);
        }
    }

    // ---- P5: scores half1  S[64:128, 64:128]  (all 8 warps), 2 passes ----
    float acc1[4][4];
#pragma unroll
    for (int nt = 0; nt < 4; nt++)
#pragma unroll
        for (int e = 0; e < 4; e++) acc1[nt][e] = 0.f;
    const int c0s = 64 + (wid & 3) * 16;
    const int mbs = 64 + (wid >> 2) * 32;
#pragma unroll
    for (int p = 0; p < 2; p++) {
#pragma unroll
        for (int kk = 0; kk < 2; kk++) {
            uint32_t af[4];
            int row = c0s + (lane & 15);
            ldsm4(af, QB[p] + row * 64 + sw_chunk(row, kk * 2 + (lane >> 4)) * 16);
            uint32_t bf[2][4];
#pragma unroll
            for (int nt2 = 0; nt2 < 2; nt2++) {
                int row2 = mbs + nt2 * 16 + (g >> 1) * 8 + l8;
                ldsm4(bf[nt2], sb + AT_KHI + row2 * 64 + sw_chunk(row2, kk * 2 + (g & 1)) * 16);
            }
#pragma unroll
            for (int nt = 0; nt < 4; nt++)
                mma_f16(acc1[nt], af, &bf[nt >> 1][(nt & 1) * 2]);
        }
    }
    __syncthreads();   // all Q/K fragment reads done; QHI becomes sc1

    {
        int c_lo = c0s + (lane >> 2);
#pragma unroll
        for (int nt = 0; nt < 4; nt++) {
            int mm = mbs + nt * 8 + (lane & 3) * 2;
#pragma unroll
            for (int half = 0; half < 2; half++) {
                int c = c_lo + half * 8;
                float v0 = acc1[nt][half*2+0], v1 = acc1[nt][half*2+1];
                int d0 = c - mm, d1 = c - mm - 1;
                float s0 = (d0 >= 0) ? v0 * ed[d0] : 0.f;
                float s1 = (d1 >= 0) ? v1 * ed[d1] : 0.f;
                int cr = c - 64, mr = mm - 64;
                int addr = cr * 128 + (((mr >> 3) ^ (cr & 7)) * 16) + ((mr * 2) & 15);
                *(uint32_t*)(sm + AT_SC1H + addr) =
                    pack_h2(__float2half_rn(s0), __float2half_rn(s1));
            }
        }
    }
    __syncthreads();

    // ---- P6: warps 4-7: o_intra part B (rows 64..127, K=64..128, hi only);
    //          warps 0-3: C_n (kT hi only) ----
    if (wid >= 4) {
        const int r0 = (wid - 4) * 16;
#pragma unroll
        for (int kk = 0; kk < 4; kk++) {
            uint32_t af[4];
            int row = r0 + (lane & 15);
            int ch = (kk * 2 + (lane >> 4)) ^ (row & 7);
            ldsm4(af, sb + AT_SC1H + row * 128 + ch * 16);
            uint32_t bf[2][4];
#pragma unroll
            for (int nt2 = 0; nt2 < 2; nt2++) {
                int row2 = nt2 * 16 + (g >> 1) * 8 + l8;
                int ch2 = ((kk + 4) * 2 + (g & 1)) ^ (row2 & 7);
                ldsm4(bf[nt2], sb + AT_VTHI + row2 * 256 + ch2 * 16);
            }
#pragma unroll
            for (int nt = 0; nt < 4; nt++)
                mma_f16(oacc[nt], af, &bf[nt >> 1][(nt & 1) * 2]);
        }
        int c = wid * 16 + (lane >> 2);
#pragma unroll
        for (int nt = 0; nt < 4; nt++) {
            int e = nt * 8 + (lane & 3) * 2;
            size_t go = (tok0 + c) * CC + h*DD + e;
            *(float2*)&g_o[go]        = make_float2(oacc[nt][0], oacc[nt][1]);
            *(float2*)&g_o[go + 8*CC] = make_float2(oacc[nt][2], oacc[nt][3]);
        }
    } else {
        float cacc[2][4][4];
#pragma unroll
        for (int mt = 0; mt < 2; mt++)
#pragma unroll
            for (int nt = 0; nt < 4; nt++)
#pragma unroll
                for (int e = 0; e < 4; e++) cacc[mt][nt][e] = 0.f;

#pragma unroll
        for (int kl = 0; kl < 2; kl++) {
            int kk = wid * 2 + kl;
            uint32_t af[2][4];
#pragma unroll
            for (int mt = 0; mt < 2; mt++) {
                int row = mt * 16 + (lane & 15);
                int ch = (kk * 2 + (lane >> 4)) ^ (row & 7);
                ldsm4(af[mt], sb + AT_KTHI + row * 256 + ch * 16);
            }
            uint32_t bf[2][4];
#pragma unroll
            for (int nt2 = 0; nt2 < 2; nt2++) {
                int row2 = nt2 * 16 + (g >> 1) * 8 + l8;
                int ch2 = (kk * 2 + (g & 1)) ^ (row2 & 7);
                ldsm4(bf[nt2], sb + AT_VTHI + row2 * 256 + ch2 * 16);
            }
#pragma unroll
            for (int mt = 0; mt < 2; mt++)
#pragma unroll
                for (int nt = 0; nt < 4; nt++)
                    mma_f16(cacc[mt][nt], af[mt], &bf[nt >> 1][(nt & 1) * 2]);
        }
        float* red = (float*)(sm + AT_CRED) + wid * 1024;
#pragma unroll
        for (int mt = 0; mt < 2; mt++) {
            int d = mt * 16 + (lane >> 2);
#pragma unroll
            for (int nt = 0; nt < 4; nt++) {
                int e = nt * 8 + (lane & 3) * 2;
                *(float2*)&red[d * 32 + e]       = make_float2(cacc[mt][nt][0], cacc[mt][nt][1]);
                *(float2*)&red[(d + 8) * 32 + e] = make_float2(cacc[mt][nt][2], cacc[mt][nt][3]);
            }
        }
    }
    __syncthreads();
    {
        const float* red = (const float*)(sm + AT_CRED);
        const size_t cb = ((size_t)((b*HH + h)*NC + n)) * 1024;
        for (int i = tid; i < 1024; i += 256)
            g_C[cb + i] = red[i] + red[1024 + i] + red[2048 + i] + red[3072 + i];
    }
}

// ======================= KV scan: prefetch all stages to smem, then serial =======================
#define SCAN_SMEM (NC * 4096)   // 131072 bytes

__global__ void kv_scan_kernel()
{
    extern __shared__ __align__(16) float scs[];   // [NC][1024]
    const uint32_t sb = smem_u32(scs);
    const int bh = blockIdx.x;
    const int h = bh & 7;
    const int tid = threadIdx.x;
    const size_t cbase = (size_t)bh * NC * 1024;

    // prefetch all 32 C tiles (128 KB) via cp.async
    for (int i = tid; i < NC * 256; i += 256)
        cpasync16(sb + i * 16, &g_C[cbase + (size_t)i * 4]);
    cp_commit();
    cp_wait<0>();
    __syncthreads();

    const float bd = expf(-exp2f(-(float)(h+1)) * (float)CH);
    float4 kv = make_float4(0.f, 0.f, 0.f, 0.f);
    for (int n = 0; n < NC; n++) {
        *(float4*)&g_kvp[cbase + n*1024 + tid*4] = kv;
        float4 c = *(const float4*)&scs[n*1024 + tid*4];
        kv.x = bd*kv.x + c.x; kv.y = bd*kv.y + c.y;
        kv.z = bd*kv.z + c.z; kv.w = bd*kv.w + c.w;
    }
}

// ======================= HMMA inter-chunk + fused hi/lo split of o -> A2 =======================
__global__ void __launch_bounds__(256) attn_inter_hmma(
    const __half* __restrict__ qh, const __half* __restrict__ ql,
    __half* __restrict__ A2)
{
    const int n = blockIdx.x;
    const int h = blockIdx.y, b = blockIdx.z;

    __shared__ __align__(16) char sm[8192*2 + 2048 + 1024];
    const int QHI = 0, QLO = 8192, KVHI = 16384, EDO = 18432;
    float* ed = (float*)(sm + EDO);
    const uint32_t sb = smem_u32(sm);

    const int tid = threadIdx.x, lane = tid & 31, wid = tid >> 5;
    const float s = exp2f(-(float)(h+1));
    for (int i = tid; i < CH; i += 256) ed[i] = expf(-s * (float)i);

    const size_t tok0 = (size_t)(b*LL + n*CH);
    for (int i = tid; i < 512; i += 256) {
        int r = i >> 2, c = i & 3;
        uint4 v = *(const uint4*)(qh + (tok0 + r)*CC + h*DD + c*8);
        *(uint4*)(sm + QHI + r*64 + sw_chunk(r, c)*16) = v;
        uint4 w = *(const uint4*)(ql + (tok0 + r)*CC + h*DD + c*8);
        *(uint4*)(sm + QLO + r*64 + sw_chunk(r, c)*16) = w;
    }
    const size_t kb = ((size_t)((b*HH + h)*NC + n)) * 1024;
    for (int i = tid; i < 1024; i += 256) {
        int d = i >> 5, e = i & 31;
        float v = g_kvp[kb + i];
        __half hh = __float2half_rn(v);
        int a = e*64 + sw_chunk(e, d >> 3)*16 + (d & 7)*2;
        *(__half*)(sm + KVHI + a) = hh;
    }
    __syncthreads();

    float acc[4][4];
#pragma unroll
    for (int nt = 0; nt < 4; nt++)
#pragma unroll
        for (int e = 0; e < 4; e++) acc[nt][e] = 0.f;

    const int r0 = wid * 16;
    const uint32_t QB[2] = {sb + QHI, sb + QLO};
#pragma unroll
    for (int p = 0; p < 2; p++) {
#pragma unroll
        for (int kk = 0; kk < 2; kk++) {
            uint32_t af[4];
            int row = r0 + (lane & 15);
            int ch = sw_chunk(row, kk * 2 + (lane >> 4));
            ldsm4(af, QB[p] + row * 64 + ch * 16);
            uint32_t bf[2][4];
#pragma unroll
            for (int nt2 = 0; nt2 < 2; nt2++) {
                int g = lane >> 3, l8 = lane & 7;
                int row2 = nt2 * 16 + (g >> 1) * 8 + l8;
                int ch2 = sw_chunk(row2, kk * 2 + (g & 1));
                ldsm4(bf[nt2], sb + KVHI + row2 * 64 + ch2 * 16);
            }
#pragma unroll
            for (int nt = 0; nt < 4; nt++)
                mma_f16(acc[nt], af, &bf[nt >> 1][(nt & 1) * 2]);
        }
    }

    int c = r0 + (lane >> 2);
    float a0 = ed[c], a1 = ed[c + 8];
#pragma unroll
    for (int nt = 0; nt < 4; nt++) {
        int e = nt * 8 + (lane & 3) * 2;
#pragma unroll
        for (int half = 0; half < 2; half++) {
            int cc2 = c + half * 8;
            float al = half ? a1 : a0;
            size_t go = (tok0 + cc2) * CC + h*DD + e;
            float2 o0 = *(float2*)&g_o[go];
            o0.x += al * acc[nt][half*2+0];
            o0.y += al * acc[nt][half*2+1];
            __half h0 = __float2half_rn(o0.x);
            __half h1 = __float2half_rn(o0.y);
            __half l0 = __float2half_rn(o0.x - __half2float(h0));
            __half l1 = __float2half_rn(o0.y - __half2float(h1));
            size_t a2b = (tok0 + cc2) * KA2 + h*DD + e;
            *(uint32_t*)&A2[a2b]       = pack_h2(h0, h1);
            *(uint32_t*)&A2[a2b + 256] = pack_h2(l0, l1);
        }
    }
}

// ======================= launch =======================
extern "C" void kernel_launch(void* const* d_in, const int* in_sizes, int n_in,
                              void* d_out, int out_size)
{
    const float* x    = (const float*)d_in[0];
    const float* rel  = (const float*)d_in[1];
    const float* qkvw = (const float*)d_in[2];
    const float* qg   = (const float*)d_in[3];
    const float* kg   = (const float*)d_in[4];
    const float* pw   = (const float*)d_in[5];
    const float* pb   = (const float*)d_in[6];
    float* out = (float*)d_out;

    void* p_qkv = nullptr; cudaGetSymbolAddress(&p_qkv, g_qkv);
    void* p_A2  = nullptr; cudaGetSymbolAddress(&p_A2,  g_A2);
    void* p_W1h = nullptr; cudaGetSymbolAddress(&p_W1h, g_W1h);
    void* p_W2h = nullptr; cudaGetSymbolAddress(&p_W2h, g_W2h);
    void* p_qh  = nullptr; cudaGetSymbolAddress(&p_qh,  g_qh);
    void* p_ql  = nullptr; cudaGetSymbolAddress(&p_ql,  g_ql);

    cudaFuncSetAttribute(attn_chunk_hmma,
                         cudaFuncAttributeMaxDynamicSharedMemorySize, AT_SMEM);
    cudaFuncSetAttribute(gemm_f16_hmma<false>,
                         cudaFuncAttributeMaxDynamicSharedMemorySize, GS_SMEM);
    cudaFuncSetAttribute(gemm_f16_hmma<true>,
                         cudaFuncAttributeMaxDynamicSharedMemorySize, GS_SMEM);
    cudaFuncSetAttribute(kv_scan_kernel,
                         cudaFuncAttributeMaxDynamicSharedMemorySize, SCAN_SMEM);

    // 1) split (x + rel_pos) into fp16 hi/lo; weights to fp16 (hi only)
    conv_act_kernel<<<TT*64/256, 256>>>(x, rel, (__half*)p_A2);
    conv_w_kernel<<<768*64/256, 256>>>(qkvw, (__half*)p_W1h);
    conv_w_kernel<<<256*64/256, 256>>>(pw, (__half*)p_W2h);

    // 2) qkv = [Ahi,Alo] @ W1h^T  (HMMA fp16, 2-pass K, BK=64) -> fp32 g_qkv
    gemm_f16_hmma<false><<<dim3(768/128, TT/128), 256, GS_SMEM>>>(
        (const __half*)p_A2, (const __half*)p_W1h, nullptr,
        (float*)p_qkv, 768);

    // 3) attention: intra + C_n, scan (smem-prefetched), inter (writes A2 [hi,lo])
    attn_chunk_hmma<<<dim3(NC, HH, BB), 256, AT_SMEM>>>(
        qg, kg, (__half*)p_qh, (__half*)p_ql);
    kv_scan_kernel<<<BB*HH, 256, SCAN_SMEM>>>();
    attn_inter_hmma<<<dim3(NC, HH, BB), 256>>>(
        (const __half*)p_qh, (const __half*)p_ql, (__half*)p_A2);

    // 4) out = O2 @ W2h^T + bias
    gemm_f16_hmma<true><<<dim3(256/128, TT/128), 256, GS_SMEM>>>(
        (const __half*)p_A2, (const __half*)p_W2h, pb,
        out, 256);
}

// round 12
// speedup vs baseline: 4.0182x; 1.1780x over previous
#include <cuda_runtime.h>
#include <cuda_fp16.h>
#include <math.h>
#include <stdint.h>

// Problem constants
#define BB 8
#define LL 4096
#define CC 256
#define HH 8
#define DD 32
#define CH 128
#define NC 32          // LL / CH
#define TT (BB*LL)     // 32768 tokens
#define KA2  512       // A-operand storage width ([hi, lo])

// ---------------- static device scratch (no allocations allowed) ----------------
__device__ float g_qkv[(size_t)TT * 768];                 // qkv per token (fp32)
__device__ float g_o  [(size_t)TT * CC];                  // attention output (intra)
__device__ float g_C  [(size_t)BB*HH*NC * DD*DD];         // per-chunk KV contributions
__device__ float g_kvp[(size_t)BB*HH*NC * DD*DD];         // exclusive KV prefixes
__device__ __half g_A2 [(size_t)TT * KA2];                // [hi, lo] activations (fp16)
__device__ __half g_W1h[(size_t)768 * 256];               // qkv weight (fp16 hi only)
__device__ __half g_W2h[(size_t)256 * 256];               // proj weight (fp16 hi only)
__device__ __half g_qh [(size_t)TT * CC];                 // normalized q hat (hi)

// =========================== small PTX helpers ===========================
__device__ __forceinline__ uint32_t smem_u32(const void* p) {
    uint32_t a;
    asm("{ .reg .u64 t; cvta.to.shared.u64 t, %1; cvt.u32.u64 %0, t; }" : "=r"(a) : "l"(p));
    return a;
}
__device__ __forceinline__ void cpasync16(uint32_t dst, const void* src) {
    asm volatile("cp.async.cg.shared.global [%0], [%1], 16;" :: "r"(dst), "l"(src));
}
__device__ __forceinline__ void cp_commit() {
    asm volatile("cp.async.commit_group;" ::: "memory");
}
template<int N>
__device__ __forceinline__ void cp_wait() {
    asm volatile("cp.async.wait_group %0;" :: "n"(N) : "memory");
}
__device__ __forceinline__ void ldsm4(uint32_t* r, uint32_t addr) {
    asm volatile("ldmatrix.sync.aligned.m8n8.x4.shared.b16 {%0,%1,%2,%3}, [%4];"
                 : "=r"(r[0]), "=r"(r[1]), "=r"(r[2]), "=r"(r[3]) : "r"(addr));
}
__device__ __forceinline__ void mma_f16(float* c, const uint32_t* a, const uint32_t* b) {
    asm volatile("mma.sync.aligned.m16n8k16.row.col.f32.f16.f16.f32 "
                 "{%0,%1,%2,%3}, {%4,%5,%6,%7}, {%8,%9}, {%0,%1,%2,%3};"
                 : "+f"(c[0]), "+f"(c[1]), "+f"(c[2]), "+f"(c[3])
                 : "r"(a[0]), "r"(a[1]), "r"(a[2]), "r"(a[3]), "r"(b[0]), "r"(b[1]));
}
// xor swizzle of 16B chunk index within a 64B row (4 chunks)
__device__ __forceinline__ int sw_chunk(int r, int c) {
    return c ^ (r & 3) ^ ((r >> 2) & 1);
}
__device__ __forceinline__ uint32_t pack_h2(__half a, __half b) {
    uint32_t lo16 = *(uint16_t*)&a, hi16 = *(uint16_t*)&b;
    return lo16 | (hi16 << 16);
}

// =========================== hi/lo split conversion kernels ===========================
__global__ void conv_act_kernel(const float* __restrict__ x, const float* __restrict__ rp,
                                __half* __restrict__ A2)
{
    int idx = blockIdx.x * 256 + threadIdx.x;
    int m = idx >> 6, c4 = (idx & 63) << 2;
    float4 h = *(const float4*)&x[(size_t)m * 256 + c4];
    float4 r = *(const float4*)&rp[(size_t)(m & (LL-1)) * 256 + c4];
    h.x += r.x; h.y += r.y; h.z += r.z; h.w += r.w;
    float hv[4] = {h.x, h.y, h.z, h.w};
    __half hi[4], lo[4];
#pragma unroll
    for (int j = 0; j < 4; j++) {
        hi[j] = __float2half_rn(hv[j]);
        lo[j] = __float2half_rn(hv[j] - __half2float(hi[j]));
    }
    size_t base = (size_t)m * KA2 + c4;
    *(uint2*)&A2[base]       = *(uint2*)hi;
    *(uint2*)&A2[base + 256] = *(uint2*)lo;
}

__global__ void conv_w_kernel(const float* __restrict__ W, __half* __restrict__ Wh)
{
    int idx = blockIdx.x * 256 + threadIdx.x;
    int n = idx >> 6, c4 = (idx & 63) << 2;
    float4 h = *(const float4*)&W[(size_t)n * 256 + c4];
    float hv[4] = {h.x, h.y, h.z, h.w};
    __half hi[4];
#pragma unroll
    for (int j = 0; j < 4; j++) hi[j] = __float2half_rn(hv[j]);
    *(uint2*)&Wh[(size_t)n * 256 + c4] = *(uint2*)hi;
}

// =========================== HMMA fp16 GEMM: C = [Ahi,(Alo)] @ Wh^T (+bias) ===========================
// BK=64 slabs: A col s*64 (s 0-3 hi, 4-7 lo), B col (s&3)*64.
// N-blocks with n0 >= nv run hi-only (4 slabs); others 8 slabs.
// 3-stage cp.async ring in dynamic smem (96 KB), ONE __syncthreads per slab.
#define GS_STG 16384
#define GS_B0  (3*GS_STG)
#define GS_SMEM (6*GS_STG)   // 98304 bytes

template<bool BIAS>
__global__ void __launch_bounds__(256, 2) gemm_f16_hmma(
    const __half* __restrict__ A,
    const __half* __restrict__ Bw,
    const float* __restrict__ bias,
    float* __restrict__ Cmat, int Ntot, int nv)
{
    extern __shared__ __align__(16) char gsm[];
    const uint32_t as_base = smem_u32(gsm);
    const uint32_t bs_base = as_base + GS_B0;

    const int tid = threadIdx.x;
    const int wid = tid >> 5, lane = tid & 31;
    const int warp_m = wid & 1, warp_n = wid >> 1;
    const int m0 = blockIdx.y * 128;
    const int n0 = blockIdx.x * 128;
    const int nstg = (n0 >= nv) ? 4 : 8;

    float acc[4][4][4];
#pragma unroll
    for (int mt = 0; mt < 4; mt++)
#pragma unroll
        for (int nt = 0; nt < 4; nt++)
#pragma unroll
            for (int e = 0; e < 4; e++) acc[mt][nt][e] = 0.f;

    auto load_stage = [&](int s, int b) {
        const int sb_ = s & 3;
#pragma unroll
        for (int l = 0; l < 4; l++) {
            int i = tid + l * 256;
            int r = i >> 3, c = i & 7;
            int ch = c ^ (r & 7);
            cpasync16(as_base + b*GS_STG + r*128 + ch*16,
                      A  + (size_t)(m0 + r) * KA2 + s * 64 + c * 8);
            cpasync16(bs_base + b*GS_STG + r*128 + ch*16,
                      Bw + (size_t)(n0 + r) * 256 + sb_ * 64 + c * 8);
        }
        cp_commit();
    };

    load_stage(0, 0);
    load_stage(1, 1);

    int b = 0;
    for (int i = 0; i < nstg; i++) {
        if (i + 1 < nstg) cp_wait<1>(); else cp_wait<0>();
        __syncthreads();

#pragma unroll
        for (int kk = 0; kk < 4; kk++) {
            uint32_t af[4][4];
#pragma unroll
            for (int mt = 0; mt < 4; mt++) {
                int row = warp_m * 64 + mt * 16 + (lane & 15);
                int ch = (kk * 2 + (lane >> 4)) ^ (row & 7);
                ldsm4(af[mt], as_base + b*GS_STG + row * 128 + ch * 16);
            }
            uint32_t bf[2][4];
#pragma unroll
            for (int nt2 = 0; nt2 < 2; nt2++) {
                int g = lane >> 3, l8 = lane & 7;
                int row = warp_n * 32 + nt2 * 16 + (g >> 1) * 8 + l8;
                int ch = (kk * 2 + (g & 1)) ^ (row & 7);
                ldsm4(bf[nt2], bs_base + b*GS_STG + row * 128 + ch * 16);
            }
#pragma unroll
            for (int mt = 0; mt < 4; mt++)
#pragma unroll
                for (int nt = 0; nt < 4; nt++)
                    mma_f16(acc[mt][nt], af[mt], &bf[nt >> 1][(nt & 1) * 2]);
        }

        if (i + 2 < nstg) {
            int b2 = b + 2; if (b2 >= 3) b2 -= 3;
            load_stage(i + 2, b2);
        }
        if (++b == 3) b = 0;
    }

#pragma unroll
    for (int mt = 0; mt < 4; mt++) {
        int row = m0 + warp_m * 64 + mt * 16 + (lane >> 2);
#pragma unroll
        for (int nt = 0; nt < 4; nt++) {
            int col = n0 + warp_n * 32 + nt * 8 + (lane & 3) * 2;
            float2 v0 = make_float2(acc[mt][nt][0], acc[mt][nt][1]);
            float2 v1 = make_float2(acc[mt][nt][2], acc[mt][nt][3]);
            if (BIAS) {
                float2 bv = *(const float2*)&bias[col];
                v0.x += bv.x; v0.y += bv.y;
                v1.x += bv.x; v1.y += bv.y;
            }
            *(float2*)&Cmat[(size_t)row * Ntot + col]       = v0;
            *(float2*)&Cmat[(size_t)(row + 8) * Ntot + col] = v1;
        }
    }
}

// ======================= HMMA attention: intra + per-chunk KV contribution =======================
// smem layout (bytes); total 84 KB -> 2 CTAs/SM
#define AT_ED   0                     // 129 floats
#define AT_NQ   640
#define AT_NK   1152
#define AT_QHI  2048
#define AT_QLO  (AT_QHI  + 8192)
#define AT_KHI  (AT_QLO  + 8192)
#define AT_KTHI (AT_KHI  + 8192)
#define AT_KTLO (AT_KTHI + 8192)      // unused (layout stability)
#define AT_VTHI (AT_KTLO + 8192)
#define AT_SC0H (AT_VTHI + 8192)      // 128 rows x 128 B
#define AT_SC0L (AT_SC0H + 16384)     // staging scratch only
#define AT_SMEM (AT_SC0L + 16384)     // 83968 bytes
// aliases (regions dead by the time they're reused)
#define AT_SC1H AT_QHI                // 64 rows x 128 B
#define AT_CRED AT_SC0H               // 16 KB: 4 warps x 4 KB (sc0 dead after P4)
#define AT_STGQ AT_SC0H               // fp32 q staging (P1->P2), dead before P3
#define AT_STGK AT_SC0L               // fp32 k staging

__global__ void __launch_bounds__(256, 2) attn_chunk_hmma(
    const float* __restrict__ qg, const float* __restrict__ kg,
    __half* __restrict__ qhout)
{
    extern __shared__ char sm[];
    float* ed = (float*)(sm + AT_ED);
    float* nq = (float*)(sm + AT_NQ);
    float* nk = (float*)(sm + AT_NK);
    const uint32_t sb = smem_u32(sm);

    const int n = blockIdx.x, h = blockIdx.y, b = blockIdx.z;
    const int tid = threadIdx.x, lane = tid & 31, wid = tid >> 5;
    const float s = exp2f(-(float)(h + 1));
    for (int i = tid; i <= CH; i += 256) ed[i] = expf(-s * (float)i);

    const size_t tok0 = (size_t)(b*LL + n*CH);
    const size_t base = tok0 * 768 + h*DD;
    const int c4 = (tid & 7) * 4;

    // ---- P1: load q,k,v once; stage q,k fp32 in smem; convert v -> VT hi ----
    float sq[4], sk[4];
#pragma unroll
    for (int l = 0; l < 4; l++) {
        int r = (tid >> 3) + l * 32;
        const float* rowp = &g_qkv[base + (size_t)r * 768 + c4];
        float4 a  = *(const float4*)(rowp);
        float4 bb = *(const float4*)(rowp + 256);
        float4 cc = *(const float4*)(rowp + 512);
        sq[l] = a.x*a.x + a.y*a.y + a.z*a.z + a.w*a.w;
        sk[l] = bb.x*bb.x + bb.y*bb.y + bb.z*bb.z + bb.w*bb.w;
        *(float4*)(sm + AT_STGQ + l*4096 + tid*16) = a;
        *(float4*)(sm + AT_STGK + l*4096 + tid*16) = bb;
        float vv[4] = {cc.x, cc.y, cc.z, cc.w};
#pragma unroll
        for (int j = 0; j < 4; j++) {
            int d = c4 + j;
            __half vh = __float2half_rn(vv[j]);
            int aT = d*256 + (((r >> 3) ^ (d & 7)) * 16) + ((r & 7) * 2);
            *(__half*)(sm + AT_VTHI + aT) = vh;
        }
    }
#pragma unroll
    for (int m = 1; m < 8; m <<= 1) {
#pragma unroll
        for (int l = 0; l < 4; l++) {
            sq[l] += __shfl_xor_sync(0xffffffffu, sq[l], m);
            sk[l] += __shfl_xor_sync(0xffffffffu, sk[l], m);
        }
    }
    if ((tid & 7) == 0) {
        const float sqD = 5.656854249492380f;
#pragma unroll
        for (int l = 0; l < 4; l++) {
            int r = (tid >> 3) + l * 32;
            nq[r] = (sq[l] > 1e-24f) ? sqD * rsqrtf(sq[l]) : sqD * 1e12f;
            nk[r] = (sk[l] > 1e-24f) ? sqD * rsqrtf(sk[l]) : sqD * 1e12f;
        }
    }
    __syncthreads();

    // ---- P2: convert q (hi/lo), k (hi), kT (hi, decay-folded) from staged fp32 ----
    float gq[4], gk[4];
#pragma unroll
    for (int j = 0; j < 4; j++) {
        gq[j] = __ldg(&qg[h*DD + c4 + j]);
        gk[j] = __ldg(&kg[h*DD + c4 + j]);
    }
#pragma unroll
    for (int l = 0; l < 4; l++) {
        int r = (tid >> 3) + l * 32;
        float4 a  = *(const float4*)(sm + AT_STGQ + l*4096 + tid*16);
        float4 bb = *(const float4*)(sm + AT_STGK + l*4096 + tid*16);
        float rq = nq[r], rk = nk[r], dk = ed[CH - r];
        float qv[4] = {a.x, a.y, a.z, a.w};
        float kv[4] = {bb.x, bb.y, bb.z, bb.w};
        __half qh4[4], ql4[4], kh4[4];
#pragma unroll
        for (int j = 0; j < 4; j++) {
            int d = c4 + j;
            float qn = qv[j] * rq * gq[j];
            float kn = kv[j] * rk * gk[j];
            qh4[j] = __float2half_rn(qn);
            ql4[j] = __float2half_rn(qn - __half2float(qh4[j]));
            kh4[j] = __float2half_rn(kn);
            __half kth = __float2half_rn(kn * dk);
            int aT = d*256 + (((r >> 3) ^ (d & 7)) * 16) + ((r & 7) * 2);
            *(__half*)(sm + AT_KTHI + aT) = kth;
        }
        int a64 = r*64 + sw_chunk(r, c4 >> 3) * 16 + ((c4 & 7) * 2);
        *(uint2*)(sm + AT_QHI + a64) = *(uint2*)qh4;
        *(uint2*)(sm + AT_QLO + a64) = *(uint2*)ql4;
        *(uint2*)(sm + AT_KHI + a64) = *(uint2*)kh4;
        *(uint2*)(qhout + (tok0 + r)*CC + h*DD + c4) = *(uint2*)qh4;
    }
    __syncthreads();

    const uint32_t QB[2] = {sb + AT_QHI, sb + AT_QLO};
    const int g = lane >> 3, l8 = lane & 7;

    // ---- P3: scores half0  S[:, 0:64]  (all 128 rows), 2 passes ----
    float acc0[8][4];
#pragma unroll
    for (int nt = 0; nt < 8; nt++)
#pragma unroll
        for (int e = 0; e < 4; e++) acc0[nt][e] = 0.f;
#pragma unroll
    for (int p = 0; p < 2; p++) {
#pragma unroll
        for (int kk = 0; kk < 2; kk++) {
            uint32_t af[4];
            int row = wid * 16 + (lane & 15);
            ldsm4(af, QB[p] + row * 64 + sw_chunk(row, kk * 2 + (lane >> 4)) * 16);
            uint32_t bf[4][4];
#pragma unroll
            for (int nt2 = 0; nt2 < 4; nt2++) {
                int row2 = nt2 * 16 + (g >> 1) * 8 + l8;
                ldsm4(bf[nt2], sb + AT_KHI + row2 * 64 + sw_chunk(row2, kk * 2 + (g & 1)) * 16);
            }
#pragma unroll
            for (int nt = 0; nt < 8; nt++)
                mma_f16(acc0[nt], af, &bf[nt >> 1][(nt & 1) * 2]);
        }
    }
    // mask + decay + write sc0 (hi only)
    {
        int c_lo = wid * 16 + (lane >> 2);
#pragma unroll
        for (int nt = 0; nt < 8; nt++) {
            int mm = nt * 8 + (lane & 3) * 2;
#pragma unroll
            for (int half = 0; half < 2; half++) {
                int c = c_lo + half * 8;
                float v0 = acc0[nt][half*2+0], v1 = acc0[nt][half*2+1];
                int d0 = c - mm, d1 = c - mm - 1;
                float s0 = (d0 >= 0) ? v0 * ed[d0] : 0.f;
                float s1 = (d1 >= 0) ? v1 * ed[d1] : 0.f;
                int addr = c * 128 + (((mm >> 3) ^ (c & 7)) * 16) + ((mm * 2) & 15);
                *(uint32_t*)(sm + AT_SC0H + addr) =
                    pack_h2(__float2half_rn(s0), __float2half_rn(s1));
            }
        }
    }
    __syncthreads();

    // ---- P4: o_intra part A (K = 0..64, all rows), hi only ----
    float oacc[4][4];
#pragma unroll
    for (int nt = 0; nt < 4; nt++)
#pragma unroll
        for (int e = 0; e < 4; e++) oacc[nt][e] = 0.f;
    {
        const int r0 = wid * 16;
#pragma unroll
        for (int kk = 0; kk < 4; kk++) {
            uint32_t af[4];
            int row = r0 + (lane & 15);
            int ch = (kk * 2 + (lane >> 4)) ^ (row & 7);
            ldsm4(af, sb + AT_SC0H + row * 128 + ch * 16);
            uint32_t bf[2][4];
#pragma unroll
            for (int nt2 = 0; nt2 < 2; nt2++) {
                int row2 = nt2 * 16 + (g >> 1) * 8 + l8;
                int ch2 = (kk * 2 + (g & 1)) ^ (row2 & 7);
                ldsm4(bf[nt2], sb + AT_VTHI + row2 * 256 + ch2 * 16);
            }
#pragma unroll
            for (int nt = 0; nt < 4; nt++)
                mma_f16(oacc[nt], af, &bf[nt >> 1][(nt & 1) * 2]);
        }
    }
    // rows 0..63 are complete (cols 64+ masked to zero) -> store now
    if (wid < 4) {
        int c = wid * 16 + (lane >> 2);
#pragma unroll
        for (int nt = 0; nt < 4; nt++) {
            int e = nt * 8 + (lane & 3) * 2;
            size_t go = (tok0 + c) * CC + h*DD + e;
            *(float2*)&g_o[go]        = make_float2(oacc[nt][0], oacc[nt][1]);
            *(float2*)&g_o[go + 8*CC] = make_float2(oacc[nt][2], oacc[nt][3]);
        }
    }

    // ---- P5: scores half1  S[64:128, 64:128]  (all 8 warps), 2 passes ----
    float acc1[4][4];
#pragma unroll
    for (int nt = 0; nt < 4; nt++)
#pragma unroll
        for (int e = 0; e < 4; e++) acc1[nt][e] = 0.f;
    const int c0s = 64 + (wid & 3) * 16;
    const int mbs = 64 + (wid >> 2) * 32;
#pragma unroll
    for (int p = 0; p < 2; p++) {
#pragma unroll
        for (int kk = 0; kk < 2; kk++) {
            uint32_t af[4];
            int row = c0s + (lane & 15);
            ldsm4(af, QB[p] + row * 64 + sw_chunk(row, kk * 2 + (lane >> 4)) * 16);
            uint32_t bf[2][4];
#pragma unroll
            for (int nt2 = 0; nt2 < 2; nt2++) {
                int row2 = mbs + nt2 * 16 + (g >> 1) * 8 + l8;
                ldsm4(bf[nt2], sb + AT_KHI + row2 * 64 + sw_chunk(row2, kk * 2 + (g & 1)) * 16);
            }
#pragma unroll
            for (int nt = 0; nt < 4; nt++)
                mma_f16(acc1[nt], af, &bf[nt >> 1][(nt & 1) * 2]);
        }
    }
    __syncthreads();   // all Q/K fragment reads done; QHI becomes sc1

    {
        int c_lo = c0s + (lane >> 2);
#pragma unroll
        for (int nt = 0; nt < 4; nt++) {
            int mm = mbs + nt * 8 + (lane & 3) * 2;
#pragma unroll
            for (int half = 0; half < 2; half++) {
                int c = c_lo + half * 8;
                float v0 = acc1[nt][half*2+0], v1 = acc1[nt][half*2+1];
                int d0 = c - mm, d1 = c - mm - 1;
                float s0 = (d0 >= 0) ? v0 * ed[d0] : 0.f;
                float s1 = (d1 >= 0) ? v1 * ed[d1] : 0.f;
                int cr = c - 64, mr = mm - 64;
                int addr = cr * 128 + (((mr >> 3) ^ (cr & 7)) * 16) + ((mr * 2) & 15);
                *(uint32_t*)(sm + AT_SC1H + addr) =
                    pack_h2(__float2half_rn(s0), __float2half_rn(s1));
            }
        }
    }
    __syncthreads();

    // ---- P6: warps 4-7: o_intra part B (rows 64..127, K=64..128, hi only);
    //          warps 0-3: C_n (kT hi only) ----
    if (wid >= 4) {
        const int r0 = (wid - 4) * 16;
#pragma unroll
        for (int kk = 0; kk < 4; kk++) {
            uint32_t af[4];
            int row = r0 + (lane & 15);
            int ch = (kk * 2 + (lane >> 4)) ^ (row & 7);
            ldsm4(af, sb + AT_SC1H + row * 128 + ch * 16);
            uint32_t bf[2][4];
#pragma unroll
            for (int nt2 = 0; nt2 < 2; nt2++) {
                int row2 = nt2 * 16 + (g >> 1) * 8 + l8;
                int ch2 = ((kk + 4) * 2 + (g & 1)) ^ (row2 & 7);
                ldsm4(bf[nt2], sb + AT_VTHI + row2 * 256 + ch2 * 16);
            }
#pragma unroll
            for (int nt = 0; nt < 4; nt++)
                mma_f16(oacc[nt], af, &bf[nt >> 1][(nt & 1) * 2]);
        }
        int c = wid * 16 + (lane >> 2);
#pragma unroll
        for (int nt = 0; nt < 4; nt++) {
            int e = nt * 8 + (lane & 3) * 2;
            size_t go = (tok0 + c) * CC + h*DD + e;
            *(float2*)&g_o[go]        = make_float2(oacc[nt][0], oacc[nt][1]);
            *(float2*)&g_o[go + 8*CC] = make_float2(oacc[nt][2], oacc[nt][3]);
        }
    } else {
        float cacc[2][4][4];
#pragma unroll
        for (int mt = 0; mt < 2; mt++)
#pragma unroll
            for (int nt = 0; nt < 4; nt++)
#pragma unroll
                for (int e = 0; e < 4; e++) cacc[mt][nt][e] = 0.f;

#pragma unroll
        for (int kl = 0; kl < 2; kl++) {
            int kk = wid * 2 + kl;
            uint32_t af[2][4];
#pragma unroll
            for (int mt = 0; mt < 2; mt++) {
                int row = mt * 16 + (lane & 15);
                int ch = (kk * 2 + (lane >> 4)) ^ (row & 7);
                ldsm4(af[mt], sb + AT_KTHI + row * 256 + ch * 16);
            }
            uint32_t bf[2][4];
#pragma unroll
            for (int nt2 = 0; nt2 < 2; nt2++) {
                int row2 = nt2 * 16 + (g >> 1) * 8 + l8;
                int ch2 = (kk * 2 + (g & 1)) ^ (row2 & 7);
                ldsm4(bf[nt2], sb + AT_VTHI + row2 * 256 + ch2 * 16);
            }
#pragma unroll
            for (int mt = 0; mt < 2; mt++)
#pragma unroll
                for (int nt = 0; nt < 4; nt++)
                    mma_f16(cacc[mt][nt], af[mt], &bf[nt >> 1][(nt & 1) * 2]);
        }
        float* red = (float*)(sm + AT_CRED) + wid * 1024;
#pragma unroll
        for (int mt = 0; mt < 2; mt++) {
            int d = mt * 16 + (lane >> 2);
#pragma unroll
            for (int nt = 0; nt < 4; nt++) {
                int e = nt * 8 + (lane & 3) * 2;
                *(float2*)&red[d * 32 + e]       = make_float2(cacc[mt][nt][0], cacc[mt][nt][1]);
                *(float2*)&red[(d + 8) * 32 + e] = make_float2(cacc[mt][nt][2], cacc[mt][nt][3]);
            }
        }
    }
    __syncthreads();
    {
        const float* red = (const float*)(sm + AT_CRED);
        const size_t cb = ((size_t)((b*HH + h)*NC + n)) * 1024;
        for (int i = tid; i < 1024; i += 256)
            g_C[cb + i] = red[i] + red[1024 + i] + red[2048 + i] + red[3072 + i];
    }
}

// ======================= KV scan: prefetch all stages to smem, then serial =======================
#define SCAN_SMEM (NC * 4096)   // 131072 bytes

__global__ void kv_scan_kernel()
{
    extern __shared__ __align__(16) float scs[];   // [NC][1024]
    const uint32_t sb = smem_u32(scs);
    const int bh = blockIdx.x;
    const int h = bh & 7;
    const int tid = threadIdx.x;
    const size_t cbase = (size_t)bh * NC * 1024;

    for (int i = tid; i < NC * 256; i += 256)
        cpasync16(sb + i * 16, &g_C[cbase + (size_t)i * 4]);
    cp_commit();
    cp_wait<0>();
    __syncthreads();

    const float bd = expf(-exp2f(-(float)(h+1)) * (float)CH);
    float4 kv = make_float4(0.f, 0.f, 0.f, 0.f);
    for (int n = 0; n < NC; n++) {
        *(float4*)&g_kvp[cbase + n*1024 + tid*4] = kv;
        float4 c = *(const float4*)&scs[n*1024 + tid*4];
        kv.x = bd*kv.x + c.x; kv.y = bd*kv.y + c.y;
        kv.z = bd*kv.z + c.z; kv.w = bd*kv.w + c.w;
    }
}

// ======================= HMMA inter-chunk (q hi only) + fused split of o -> A2 hi =======================
__global__ void __launch_bounds__(256) attn_inter_hmma(
    const __half* __restrict__ qh, __half* __restrict__ A2)
{
    const int n = blockIdx.x;
    const int h = blockIdx.y, b = blockIdx.z;

    __shared__ __align__(16) char sm[8192 + 2048 + 1024];
    const int QHI = 0, KVHI = 8192, EDO = 10240;
    float* ed = (float*)(sm + EDO);
    const uint32_t sb = smem_u32(sm);

    const int tid = threadIdx.x, lane = tid & 31, wid = tid >> 5;
    const float s = exp2f(-(float)(h+1));
    for (int i = tid; i < CH; i += 256) ed[i] = expf(-s * (float)i);

    const size_t tok0 = (size_t)(b*LL + n*CH);
    for (int i = tid; i < 512; i += 256) {
        int r = i >> 2, c = i & 3;
        uint4 v = *(const uint4*)(qh + (tok0 + r)*CC + h*DD + c*8);
        *(uint4*)(sm + QHI + r*64 + sw_chunk(r, c)*16) = v;
    }
    const size_t kb = ((size_t)((b*HH + h)*NC + n)) * 1024;
    for (int i = tid; i < 1024; i += 256) {
        int d = i >> 5, e = i & 31;
        float v = g_kvp[kb + i];
        __half hh = __float2half_rn(v);
        int a = e*64 + sw_chunk(e, d >> 3)*16 + (d & 7)*2;
        *(__half*)(sm + KVHI + a) = hh;
    }
    __syncthreads();

    float acc[4][4];
#pragma unroll
    for (int nt = 0; nt < 4; nt++)
#pragma unroll
        for (int e = 0; e < 4; e++) acc[nt][e] = 0.f;

    const int r0 = wid * 16;
#pragma unroll
    for (int kk = 0; kk < 2; kk++) {
        uint32_t af[4];
        int row = r0 + (lane & 15);
        int ch = sw_chunk(row, kk * 2 + (lane >> 4));
        ldsm4(af, sb + QHI + row * 64 + ch * 16);
        uint32_t bf[2][4];
#pragma unroll
        for (int nt2 = 0; nt2 < 2; nt2++) {
            int g = lane >> 3, l8 = lane & 7;
            int row2 = nt2 * 16 + (g >> 1) * 8 + l8;
            int ch2 = sw_chunk(row2, kk * 2 + (g & 1));
            ldsm4(bf[nt2], sb + KVHI + row2 * 64 + ch2 * 16);
        }
#pragma unroll
        for (int nt = 0; nt < 4; nt++)
            mma_f16(acc[nt], af, &bf[nt >> 1][(nt & 1) * 2]);
    }

    int c = r0 + (lane >> 2);
    float a0 = ed[c], a1 = ed[c + 8];
#pragma unroll
    for (int nt = 0; nt < 4; nt++) {
        int e = nt * 8 + (lane & 3) * 2;
#pragma unroll
        for (int half = 0; half < 2; half++) {
            int cc2 = c + half * 8;
            float al = half ? a1 : a0;
            size_t go = (tok0 + cc2) * CC + h*DD + e;
            float2 o0 = *(float2*)&g_o[go];
            o0.x += al * acc[nt][half*2+0];
            o0.y += al * acc[nt][half*2+1];
            size_t a2b = (tok0 + cc2) * KA2 + h*DD + e;
            *(uint32_t*)&A2[a2b] =
                pack_h2(__float2half_rn(o0.x), __float2half_rn(o0.y));
        }
    }
}

// ======================= launch =======================
extern "C" void kernel_launch(void* const* d_in, const int* in_sizes, int n_in,
                              void* d_out, int out_size)
{
    const float* x    = (const float*)d_in[0];
    const float* rel  = (const float*)d_in[1];
    const float* qkvw = (const float*)d_in[2];
    const float* qg   = (const float*)d_in[3];
    const float* kg   = (const float*)d_in[4];
    const float* pw   = (const float*)d_in[5];
    const float* pb   = (const float*)d_in[6];
    float* out = (float*)d_out;

    void* p_qkv = nullptr; cudaGetSymbolAddress(&p_qkv, g_qkv);
    void* p_A2  = nullptr; cudaGetSymbolAddress(&p_A2,  g_A2);
    void* p_W1h = nullptr; cudaGetSymbolAddress(&p_W1h, g_W1h);
    void* p_W2h = nullptr; cudaGetSymbolAddress(&p_W2h, g_W2h);
    void* p_qh  = nullptr; cudaGetSymbolAddress(&p_qh,  g_qh);

    cudaFuncSetAttribute(attn_chunk_hmma,
                         cudaFuncAttributeMaxDynamicSharedMemorySize, AT_SMEM);
    cudaFuncSetAttribute(gemm_f16_hmma<false>,
                         cudaFuncAttributeMaxDynamicSharedMemorySize, GS_SMEM);
    cudaFuncSetAttribute(gemm_f16_hmma<true>,
                         cudaFuncAttributeMaxDynamicSharedMemorySize, GS_SMEM);
    cudaFuncSetAttribute(kv_scan_kernel,
                         cudaFuncAttributeMaxDynamicSharedMemorySize, SCAN_SMEM);

    // 1) split (x + rel_pos) into fp16 hi/lo; weights to fp16 (hi only)
    conv_act_kernel<<<TT*64/256, 256>>>(x, rel, (__half*)p_A2);
    conv_w_kernel<<<768*64/256, 256>>>(qkvw, (__half*)p_W1h);
    conv_w_kernel<<<256*64/256, 256>>>(pw, (__half*)p_W2h);

    // 2) qkv GEMM: q,k columns hi/lo (8 slabs), v columns hi-only (4 slabs)
    gemm_f16_hmma<false><<<dim3(768/128, TT/128), 256, GS_SMEM>>>(
        (const __half*)p_A2, (const __half*)p_W1h, nullptr,
        (float*)p_qkv, 768, 512);

    // 3) attention: intra + C_n, scan (smem-prefetched), inter (q hi, writes A2 hi)
    attn_chunk_hmma<<<dim3(NC, HH, BB), 256, AT_SMEM>>>(qg, kg, (__half*)p_qh);
    kv_scan_kernel<<<BB*HH, 256, SCAN_SMEM>>>();
    attn_inter_hmma<<<dim3(NC, HH, BB), 256>>>((const __half*)p_qh, (__half*)p_A2);

    // 4) out = Ohi @ W2h^T + bias (hi-only: nv=0 -> 4 slabs everywhere)
    gemm_f16_hmma<true><<<dim3(256/128, TT/128), 256, GS_SMEM>>>(
        (const __half*)p_A2, (const __half*)p_W2h, pb,
        out, 256, 0);
}

// round 13
// speedup vs baseline: 4.6703x; 1.1623x over previous
#include <cuda_runtime.h>
#include <cuda_fp16.h>
#include <math.h>
#include <stdint.h>

// Problem constants
#define BB 8
#define LL 4096
#define CC 256
#define HH 8
#define DD 32
#define CH 128
#define NC 32          // LL / CH
#define TT (BB*LL)     // 32768 tokens

// ---------------- static device scratch (no allocations allowed) ----------------
__device__ float g_qkv[(size_t)TT * 768];                 // qkv per token (fp32)
__device__ float g_o  [(size_t)TT * CC];                  // attention output (intra)
__device__ float g_C  [(size_t)BB*HH*NC * DD*DD];         // per-chunk KV contributions
__device__ float g_kvp[(size_t)BB*HH*NC * DD*DD];         // exclusive KV prefixes
__device__ __half g_A2 [(size_t)TT * CC];                 // fp16 activations (hi only)
__device__ __half g_W1h[(size_t)768 * 256];               // qkv weight (fp16)
__device__ __half g_W2h[(size_t)256 * 256];               // proj weight (fp16)
__device__ __half g_qh [(size_t)TT * CC];                 // normalized q hat (fp16)

// =========================== small PTX helpers ===========================
__device__ __forceinline__ uint32_t smem_u32(const void* p) {
    uint32_t a;
    asm("{ .reg .u64 t; cvta.to.shared.u64 t, %1; cvt.u32.u64 %0, t; }" : "=r"(a) : "l"(p));
    return a;
}
__device__ __forceinline__ void cpasync16(uint32_t dst, const void* src) {
    asm volatile("cp.async.cg.shared.global [%0], [%1], 16;" :: "r"(dst), "l"(src));
}
__device__ __forceinline__ void cp_commit() {
    asm volatile("cp.async.commit_group;" ::: "memory");
}
template<int N>
__device__ __forceinline__ void cp_wait() {
    asm volatile("cp.async.wait_group %0;" :: "n"(N) : "memory");
}
__device__ __forceinline__ void ldsm4(uint32_t* r, uint32_t addr) {
    asm volatile("ldmatrix.sync.aligned.m8n8.x4.shared.b16 {%0,%1,%2,%3}, [%4];"
                 : "=r"(r[0]), "=r"(r[1]), "=r"(r[2]), "=r"(r[3]) : "r"(addr));
}
__device__ __forceinline__ void mma_f16(float* c, const uint32_t* a, const uint32_t* b) {
    asm volatile("mma.sync.aligned.m16n8k16.row.col.f32.f16.f16.f32 "
                 "{%0,%1,%2,%3}, {%4,%5,%6,%7}, {%8,%9}, {%0,%1,%2,%3};"
                 : "+f"(c[0]), "+f"(c[1]), "+f"(c[2]), "+f"(c[3])
                 : "r"(a[0]), "r"(a[1]), "r"(a[2]), "r"(a[3]), "r"(b[0]), "r"(b[1]));
}
// xor swizzle of 16B chunk index within a 64B row (4 chunks)
__device__ __forceinline__ int sw_chunk(int r, int c) {
    return c ^ (r & 3) ^ ((r >> 2) & 1);
}
__device__ __forceinline__ uint32_t pack_h2(__half a, __half b) {
    uint32_t lo16 = *(uint16_t*)&a, hi16 = *(uint16_t*)&b;
    return lo16 | (hi16 << 16);
}

// =========================== fp16 conversion kernels ===========================
__global__ void conv_act_kernel(const float* __restrict__ x, const float* __restrict__ rp,
                                __half* __restrict__ A2)
{
    int idx = blockIdx.x * 256 + threadIdx.x;
    int m = idx >> 6, c4 = (idx & 63) << 2;
    float4 h = *(const float4*)&x[(size_t)m * 256 + c4];
    float4 r = *(const float4*)&rp[(size_t)(m & (LL-1)) * 256 + c4];
    h.x += r.x; h.y += r.y; h.z += r.z; h.w += r.w;
    float hv[4] = {h.x, h.y, h.z, h.w};
    __half hi[4];
#pragma unroll
    for (int j = 0; j < 4; j++) hi[j] = __float2half_rn(hv[j]);
    *(uint2*)&A2[(size_t)m * CC + c4] = *(uint2*)hi;
}

__global__ void conv_w_kernel(const float* __restrict__ W, __half* __restrict__ Wh)
{
    int idx = blockIdx.x * 256 + threadIdx.x;
    int n = idx >> 6, c4 = (idx & 63) << 2;
    float4 h = *(const float4*)&W[(size_t)n * 256 + c4];
    float hv[4] = {h.x, h.y, h.z, h.w};
    __half hi[4];
#pragma unroll
    for (int j = 0; j < 4; j++) hi[j] = __float2half_rn(hv[j]);
    *(uint2*)&Wh[(size_t)n * 256 + c4] = *(uint2*)hi;
}

// =========================== HMMA fp16 GEMM: C = A @ W^T (+bias) ===========================
// Pure fp16, K=256, BK=64 slabs (4 total). 3-stage cp.async ring (96 KB), one sync per slab.
#define NSTG 4
#define GS_STG 16384
#define GS_B0  (3*GS_STG)
#define GS_SMEM (6*GS_STG)   // 98304 bytes

template<bool BIAS>
__global__ void __launch_bounds__(256, 2) gemm_f16_hmma(
    const __half* __restrict__ A,
    const __half* __restrict__ Bw,
    const float* __restrict__ bias,
    float* __restrict__ Cmat, int Ntot)
{
    extern __shared__ __align__(16) char gsm[];
    const uint32_t as_base = smem_u32(gsm);
    const uint32_t bs_base = as_base + GS_B0;

    const int tid = threadIdx.x;
    const int wid = tid >> 5, lane = tid & 31;
    const int warp_m = wid & 1, warp_n = wid >> 1;
    const int m0 = blockIdx.y * 128;
    const int n0 = blockIdx.x * 128;

    float acc[4][4][4];
#pragma unroll
    for (int mt = 0; mt < 4; mt++)
#pragma unroll
        for (int nt = 0; nt < 4; nt++)
#pragma unroll
            for (int e = 0; e < 4; e++) acc[mt][nt][e] = 0.f;

    auto load_stage = [&](int s, int b) {
#pragma unroll
        for (int l = 0; l < 4; l++) {
            int i = tid + l * 256;
            int r = i >> 3, c = i & 7;
            int ch = c ^ (r & 7);
            cpasync16(as_base + b*GS_STG + r*128 + ch*16,
                      A  + (size_t)(m0 + r) * 256 + s * 64 + c * 8);
            cpasync16(bs_base + b*GS_STG + r*128 + ch*16,
                      Bw + (size_t)(n0 + r) * 256 + s * 64 + c * 8);
        }
        cp_commit();
    };

    load_stage(0, 0);
    load_stage(1, 1);

    int b = 0;
    for (int i = 0; i < NSTG; i++) {
        if (i + 1 < NSTG) cp_wait<1>(); else cp_wait<0>();
        __syncthreads();

#pragma unroll
        for (int kk = 0; kk < 4; kk++) {
            uint32_t af[4][4];
#pragma unroll
            for (int mt = 0; mt < 4; mt++) {
                int row = warp_m * 64 + mt * 16 + (lane & 15);
                int ch = (kk * 2 + (lane >> 4)) ^ (row & 7);
                ldsm4(af[mt], as_base + b*GS_STG + row * 128 + ch * 16);
            }
            uint32_t bf[2][4];
#pragma unroll
            for (int nt2 = 0; nt2 < 2; nt2++) {
                int g = lane >> 3, l8 = lane & 7;
                int row = warp_n * 32 + nt2 * 16 + (g >> 1) * 8 + l8;
                int ch = (kk * 2 + (g & 1)) ^ (row & 7);
                ldsm4(bf[nt2], bs_base + b*GS_STG + row * 128 + ch * 16);
            }
#pragma unroll
            for (int mt = 0; mt < 4; mt++)
#pragma unroll
                for (int nt = 0; nt < 4; nt++)
                    mma_f16(acc[mt][nt], af[mt], &bf[nt >> 1][(nt & 1) * 2]);
        }

        if (i + 2 < NSTG) {
            int b2 = b + 2; if (b2 >= 3) b2 -= 3;
            load_stage(i + 2, b2);
        }
        if (++b == 3) b = 0;
    }

#pragma unroll
    for (int mt = 0; mt < 4; mt++) {
        int row = m0 + warp_m * 64 + mt * 16 + (lane >> 2);
#pragma unroll
        for (int nt = 0; nt < 4; nt++) {
            int col = n0 + warp_n * 32 + nt * 8 + (lane & 3) * 2;
            float2 v0 = make_float2(acc[mt][nt][0], acc[mt][nt][1]);
            float2 v1 = make_float2(acc[mt][nt][2], acc[mt][nt][3]);
            if (BIAS) {
                float2 bv = *(const float2*)&bias[col];
                v0.x += bv.x; v0.y += bv.y;
                v1.x += bv.x; v1.y += bv.y;
            }
            *(float2*)&Cmat[(size_t)row * Ntot + col]       = v0;
            *(float2*)&Cmat[(size_t)(row + 8) * Ntot + col] = v1;
        }
    }
}

// ======================= HMMA attention: intra + per-chunk KV contribution =======================
// smem layout (bytes); total 84 KB -> 2 CTAs/SM
#define AT_ED   0                     // 129 floats
#define AT_NQ   640
#define AT_NK   1152
#define AT_QHI  2048
#define AT_QLO  (AT_QHI  + 8192)      // unused (layout stability)
#define AT_KHI  (AT_QLO  + 8192)
#define AT_KTHI (AT_KHI  + 8192)
#define AT_KTLO (AT_KTHI + 8192)      // unused
#define AT_VTHI (AT_KTLO + 8192)
#define AT_SC0H (AT_VTHI + 8192)      // 128 rows x 128 B
#define AT_SC0L (AT_SC0H + 16384)     // staging scratch only
#define AT_SMEM (AT_SC0L + 16384)     // 83968 bytes
// aliases (regions dead by the time they're reused)
#define AT_SC1H AT_QHI                // 64 rows x 128 B
#define AT_CRED AT_SC0H               // 16 KB: 4 warps x 4 KB (sc0 dead after P4)
#define AT_STGQ AT_SC0H               // fp32 q staging (P1->P2), dead before P3
#define AT_STGK AT_SC0L               // fp32 k staging

__global__ void __launch_bounds__(256, 2) attn_chunk_hmma(
    const float* __restrict__ qg, const float* __restrict__ kg,
    __half* __restrict__ qhout)
{
    extern __shared__ char sm[];
    float* ed = (float*)(sm + AT_ED);
    float* nq = (float*)(sm + AT_NQ);
    float* nk = (float*)(sm + AT_NK);
    const uint32_t sb = smem_u32(sm);

    const int n = blockIdx.x, h = blockIdx.y, b = blockIdx.z;
    const int tid = threadIdx.x, lane = tid & 31, wid = tid >> 5;
    const float s = exp2f(-(float)(h + 1));
    for (int i = tid; i <= CH; i += 256) ed[i] = expf(-s * (float)i);

    const size_t tok0 = (size_t)(b*LL + n*CH);
    const size_t base = tok0 * 768 + h*DD;
    const int c4 = (tid & 7) * 4;

    // ---- P1: load q,k,v once; stage q,k fp32 in smem; convert v -> VT hi ----
    float sq[4], sk[4];
#pragma unroll
    for (int l = 0; l < 4; l++) {
        int r = (tid >> 3) + l * 32;
        const float* rowp = &g_qkv[base + (size_t)r * 768 + c4];
        float4 a  = *(const float4*)(rowp);
        float4 bb = *(const float4*)(rowp + 256);
        float4 cc = *(const float4*)(rowp + 512);
        sq[l] = a.x*a.x + a.y*a.y + a.z*a.z + a.w*a.w;
        sk[l] = bb.x*bb.x + bb.y*bb.y + bb.z*bb.z + bb.w*bb.w;
        *(float4*)(sm + AT_STGQ + l*4096 + tid*16) = a;
        *(float4*)(sm + AT_STGK + l*4096 + tid*16) = bb;
        float vv[4] = {cc.x, cc.y, cc.z, cc.w};
#pragma unroll
        for (int j = 0; j < 4; j++) {
            int d = c4 + j;
            __half vh = __float2half_rn(vv[j]);
            int aT = d*256 + (((r >> 3) ^ (d & 7)) * 16) + ((r & 7) * 2);
            *(__half*)(sm + AT_VTHI + aT) = vh;
        }
    }
#pragma unroll
    for (int m = 1; m < 8; m <<= 1) {
#pragma unroll
        for (int l = 0; l < 4; l++) {
            sq[l] += __shfl_xor_sync(0xffffffffu, sq[l], m);
            sk[l] += __shfl_xor_sync(0xffffffffu, sk[l], m);
        }
    }
    if ((tid & 7) == 0) {
        const float sqD = 5.656854249492380f;
#pragma unroll
        for (int l = 0; l < 4; l++) {
            int r = (tid >> 3) + l * 32;
            nq[r] = (sq[l] > 1e-24f) ? sqD * rsqrtf(sq[l]) : sqD * 1e12f;
            nk[r] = (sk[l] > 1e-24f) ? sqD * rsqrtf(sk[l]) : sqD * 1e12f;
        }
    }
    __syncthreads();

    // ---- P2: convert q (hi), k (hi), kT (hi, decay-folded) from staged fp32 ----
    float gq[4], gk[4];
#pragma unroll
    for (int j = 0; j < 4; j++) {
        gq[j] = __ldg(&qg[h*DD + c4 + j]);
        gk[j] = __ldg(&kg[h*DD + c4 + j]);
    }
#pragma unroll
    for (int l = 0; l < 4; l++) {
        int r = (tid >> 3) + l * 32;
        float4 a  = *(const float4*)(sm + AT_STGQ + l*4096 + tid*16);
        float4 bb = *(const float4*)(sm + AT_STGK + l*4096 + tid*16);
        float rq = nq[r], rk = nk[r], dk = ed[CH - r];
        float qv[4] = {a.x, a.y, a.z, a.w};
        float kv[4] = {bb.x, bb.y, bb.z, bb.w};
        __half qh4[4], kh4[4];
#pragma unroll
        for (int j = 0; j < 4; j++) {
            int d = c4 + j;
            float qn = qv[j] * rq * gq[j];
            float kn = kv[j] * rk * gk[j];
            qh4[j] = __float2half_rn(qn);
            kh4[j] = __float2half_rn(kn);
            __half kth = __float2half_rn(kn * dk);
            int aT = d*256 + (((r >> 3) ^ (d & 7)) * 16) + ((r & 7) * 2);
            *(__half*)(sm + AT_KTHI + aT) = kth;
        }
        int a64 = r*64 + sw_chunk(r, c4 >> 3) * 16 + ((c4 & 7) * 2);
        *(uint2*)(sm + AT_QHI + a64) = *(uint2*)qh4;
        *(uint2*)(sm + AT_KHI + a64) = *(uint2*)kh4;
        *(uint2*)(qhout + (tok0 + r)*CC + h*DD + c4) = *(uint2*)qh4;
    }
    __syncthreads();

    const int g = lane >> 3, l8 = lane & 7;

    // ---- P3: scores half0  S[:, 0:64]  (all 128 rows), single pass ----
    float acc0[8][4];
#pragma unroll
    for (int nt = 0; nt < 8; nt++)
#pragma unroll
        for (int e = 0; e < 4; e++) acc0[nt][e] = 0.f;
#pragma unroll
    for (int kk = 0; kk < 2; kk++) {
        uint32_t af[4];
        int row = wid * 16 + (lane & 15);
        ldsm4(af, sb + AT_QHI + row * 64 + sw_chunk(row, kk * 2 + (lane >> 4)) * 16);
        uint32_t bf[4][4];
#pragma unroll
        for (int nt2 = 0; nt2 < 4; nt2++) {
            int row2 = nt2 * 16 + (g >> 1) * 8 + l8;
            ldsm4(bf[nt2], sb + AT_KHI + row2 * 64 + sw_chunk(row2, kk * 2 + (g & 1)) * 16);
        }
#pragma unroll
        for (int nt = 0; nt < 8; nt++)
            mma_f16(acc0[nt], af, &bf[nt >> 1][(nt & 1) * 2]);
    }
    // mask + decay + write sc0 (hi only)
    {
        int c_lo = wid * 16 + (lane >> 2);
#pragma unroll
        for (int nt = 0; nt < 8; nt++) {
            int mm = nt * 8 + (lane & 3) * 2;
#pragma unroll
            for (int half = 0; half < 2; half++) {
                int c = c_lo + half * 8;
                float v0 = acc0[nt][half*2+0], v1 = acc0[nt][half*2+1];
                int d0 = c - mm, d1 = c - mm - 1;
                float s0 = (d0 >= 0) ? v0 * ed[d0] : 0.f;
                float s1 = (d1 >= 0) ? v1 * ed[d1] : 0.f;
                int addr = c * 128 + (((mm >> 3) ^ (c & 7)) * 16) + ((mm * 2) & 15);
                *(uint32_t*)(sm + AT_SC0H + addr) =
                    pack_h2(__float2half_rn(s0), __float2half_rn(s1));
            }
        }
    }
    __syncthreads();

    // ---- P4: o_intra part A (K = 0..64, all rows), hi only ----
    float oacc[4][4];
#pragma unroll
    for (int nt = 0; nt < 4; nt++)
#pragma unroll
        for (int e = 0; e < 4; e++) oacc[nt][e] = 0.f;
    {
        const int r0 = wid * 16;
#pragma unroll
        for (int kk = 0; kk < 4; kk++) {
            uint32_t af[4];
            int row = r0 + (lane & 15);
            int ch = (kk * 2 + (lane >> 4)) ^ (row & 7);
            ldsm4(af, sb + AT_SC0H + row * 128 + ch * 16);
            uint32_t bf[2][4];
#pragma unroll
            for (int nt2 = 0; nt2 < 2; nt2++) {
                int row2 = nt2 * 16 + (g >> 1) * 8 + l8;
                int ch2 = (kk * 2 + (g & 1)) ^ (row2 & 7);
                ldsm4(bf[nt2], sb + AT_VTHI + row2 * 256 + ch2 * 16);
            }
#pragma unroll
            for (int nt = 0; nt < 4; nt++)
                mma_f16(oacc[nt], af, &bf[nt >> 1][(nt & 1) * 2]);
        }
    }
    // rows 0..63 are complete (cols 64+ masked to zero) -> store now
    if (wid < 4) {
        int c = wid * 16 + (lane >> 2);
#pragma unroll
        for (int nt = 0; nt < 4; nt++) {
            int e = nt * 8 + (lane & 3) * 2;
            size_t go = (tok0 + c) * CC + h*DD + e;
            *(float2*)&g_o[go]        = make_float2(oacc[nt][0], oacc[nt][1]);
            *(float2*)&g_o[go + 8*CC] = make_float2(oacc[nt][2], oacc[nt][3]);
        }
    }

    // ---- P5: scores half1  S[64:128, 64:128]  (all 8 warps), single pass ----
    float acc1[4][4];
#pragma unroll
    for (int nt = 0; nt < 4; nt++)
#pragma unroll
        for (int e = 0; e < 4; e++) acc1[nt][e] = 0.f;
    const int c0s = 64 + (wid & 3) * 16;
    const int mbs = 64 + (wid >> 2) * 32;
#pragma unroll
    for (int kk = 0; kk < 2; kk++) {
        uint32_t af[4];
        int row = c0s + (lane & 15);
        ldsm4(af, sb + AT_QHI + row * 64 + sw_chunk(row, kk * 2 + (lane >> 4)) * 16);
        uint32_t bf[2][4];
#pragma unroll
        for (int nt2 = 0; nt2 < 2; nt2++) {
            int row2 = mbs + nt2 * 16 + (g >> 1) * 8 + l8;
            ldsm4(bf[nt2], sb + AT_KHI + row2 * 64 + sw_chunk(row2, kk * 2 + (g & 1)) * 16);
        }
#pragma unroll
        for (int nt = 0; nt < 4; nt++)
            mma_f16(acc1[nt], af, &bf[nt >> 1][(nt & 1) * 2]);
    }
    __syncthreads();   // all Q/K fragment reads done; QHI becomes sc1

    {
        int c_lo = c0s + (lane >> 2);
#pragma unroll
        for (int nt = 0; nt < 4; nt++) {
            int mm = mbs + nt * 8 + (lane & 3) * 2;
#pragma unroll
            for (int half = 0; half < 2; half++) {
                int c = c_lo + half * 8;
                float v0 = acc1[nt][half*2+0], v1 = acc1[nt][half*2+1];
                int d0 = c - mm, d1 = c - mm - 1;
                float s0 = (d0 >= 0) ? v0 * ed[d0] : 0.f;
                float s1 = (d1 >= 0) ? v1 * ed[d1] : 0.f;
                int cr = c - 64, mr = mm - 64;
                int addr = cr * 128 + (((mr >> 3) ^ (cr & 7)) * 16) + ((mr * 2) & 15);
                *(uint32_t*)(sm + AT_SC1H + addr) =
                    pack_h2(__float2half_rn(s0), __float2half_rn(s1));
            }
        }
    }
    __syncthreads();

    // ---- P6: warps 4-7: o_intra part B (rows 64..127, K=64..128, hi only);
    //          warps 0-3: C_n (kT hi only) ----
    if (wid >= 4) {
        const int r0 = (wid - 4) * 16;
#pragma unroll
        for (int kk = 0; kk < 4; kk++) {
            uint32_t af[4];
            int row = r0 + (lane & 15);
            int ch = (kk * 2 + (lane >> 4)) ^ (row & 7);
            ldsm4(af, sb + AT_SC1H + row * 128 + ch * 16);
            uint32_t bf[2][4];
#pragma unroll
            for (int nt2 = 0; nt2 < 2; nt2++) {
                int row2 = nt2 * 16 + (g >> 1) * 8 + l8;
                int ch2 = ((kk + 4) * 2 + (g & 1)) ^ (row2 & 7);
                ldsm4(bf[nt2], sb + AT_VTHI + row2 * 256 + ch2 * 16);
            }
#pragma unroll
            for (int nt = 0; nt < 4; nt++)
                mma_f16(oacc[nt], af, &bf[nt >> 1][(nt & 1) * 2]);
        }
        int c = wid * 16 + (lane >> 2);
#pragma unroll
        for (int nt = 0; nt < 4; nt++) {
            int e = nt * 8 + (lane & 3) * 2;
            size_t go = (tok0 + c) * CC + h*DD + e;
            *(float2*)&g_o[go]        = make_float2(oacc[nt][0], oacc[nt][1]);
            *(float2*)&g_o[go + 8*CC] = make_float2(oacc[nt][2], oacc[nt][3]);
        }
    } else {
        float cacc[2][4][4];
#pragma unroll
        for (int mt = 0; mt < 2; mt++)
#pragma unroll
            for (int nt = 0; nt < 4; nt++)
#pragma unroll
                for (int e = 0; e < 4; e++) cacc[mt][nt][e] = 0.f;

#pragma unroll
        for (int kl = 0; kl < 2; kl++) {
            int kk = wid * 2 + kl;
            uint32_t af[2][4];
#pragma unroll
            for (int mt = 0; mt < 2; mt++) {
                int row = mt * 16 + (lane & 15);
                int ch = (kk * 2 + (lane >> 4)) ^ (row & 7);
                ldsm4(af[mt], sb + AT_KTHI + row * 256 + ch * 16);
            }
            uint32_t bf[2][4];
#pragma unroll
            for (int nt2 = 0; nt2 < 2; nt2++) {
                int row2 = nt2 * 16 + (g >> 1) * 8 + l8;
                int ch2 = (kk * 2 + (g & 1)) ^ (row2 & 7);
                ldsm4(bf[nt2], sb + AT_VTHI + row2 * 256 + ch2 * 16);
            }
#pragma unroll
            for (int mt = 0; mt < 2; mt++)
#pragma unroll
                for (int nt = 0; nt < 4; nt++)
                    mma_f16(cacc[mt][nt], af[mt], &bf[nt >> 1][(nt & 1) * 2]);
        }
        float* red = (float*)(sm + AT_CRED) + wid * 1024;
#pragma unroll
        for (int mt = 0; mt < 2; mt++) {
            int d = mt * 16 + (lane >> 2);
#pragma unroll
            for (int nt = 0; nt < 4; nt++) {
                int e = nt * 8 + (lane & 3) * 2;
                *(float2*)&red[d * 32 + e]       = make_float2(cacc[mt][nt][0], cacc[mt][nt][1]);
                *(float2*)&red[(d + 8) * 32 + e] = make_float2(cacc[mt][nt][2], cacc[mt][nt][3]);
            }
        }
    }
    __syncthreads();
    {
        const float* red = (const float*)(sm + AT_CRED);
        const size_t cb = ((size_t)((b*HH + h)*NC + n)) * 1024;
        for (int i = tid; i < 1024; i += 256)
            g_C[cb + i] = red[i] + red[1024 + i] + red[2048 + i] + red[3072 + i];
    }
}

// ======================= KV scan: prefetch all stages to smem, then serial =======================
#define SCAN_SMEM (NC * 4096)   // 131072 bytes

__global__ void kv_scan_kernel()
{
    extern __shared__ __align__(16) float scs[];   // [NC][1024]
    const uint32_t sb = smem_u32(scs);
    const int bh = blockIdx.x;
    const int h = bh & 7;
    const int tid = threadIdx.x;
    const size_t cbase = (size_t)bh * NC * 1024;

    for (int i = tid; i < NC * 256; i += 256)
        cpasync16(sb + i * 16, &g_C[cbase + (size_t)i * 4]);
    cp_commit();
    cp_wait<0>();
    __syncthreads();

    const float bd = expf(-exp2f(-(float)(h+1)) * (float)CH);
    float4 kv = make_float4(0.f, 0.f, 0.f, 0.f);
    for (int n = 0; n < NC; n++) {
        *(float4*)&g_kvp[cbase + n*1024 + tid*4] = kv;
        float4 c = *(const float4*)&scs[n*1024 + tid*4];
        kv.x = bd*kv.x + c.x; kv.y = bd*kv.y + c.y;
        kv.z = bd*kv.z + c.z; kv.w = bd*kv.w + c.w;
    }
}

// ======================= HMMA inter-chunk (q hi) + fused fp16 convert of o -> A2 =======================
__global__ void __launch_bounds__(256) attn_inter_hmma(
    const __half* __restrict__ qh, __half* __restrict__ A2)
{
    const int n = blockIdx.x;
    const int h = blockIdx.y, b = blockIdx.z;

    __shared__ __align__(16) char sm[8192 + 2048 + 1024];
    const int QHI = 0, KVHI = 8192, EDO = 10240;
    float* ed = (float*)(sm + EDO);
    const uint32_t sb = smem_u32(sm);

    const int tid = threadIdx.x, lane = tid & 31, wid = tid >> 5;
    const float s = exp2f(-(float)(h+1));
    for (int i = tid; i < CH; i += 256) ed[i] = expf(-s * (float)i);

    const size_t tok0 = (size_t)(b*LL + n*CH);
    for (int i = tid; i < 512; i += 256) {
        int r = i >> 2, c = i & 3;
        uint4 v = *(const uint4*)(qh + (tok0 + r)*CC + h*DD + c*8);
        *(uint4*)(sm + QHI + r*64 + sw_chunk(r, c)*16) = v;
    }
    const size_t kb = ((size_t)((b*HH + h)*NC + n)) * 1024;
    for (int i = tid; i < 1024; i += 256) {
        int d = i >> 5, e = i & 31;
        float v = g_kvp[kb + i];
        __half hh = __float2half_rn(v);
        int a = e*64 + sw_chunk(e, d >> 3)*16 + (d & 7)*2;
        *(__half*)(sm + KVHI + a) = hh;
    }
    __syncthreads();

    float acc[4][4];
#pragma unroll
    for (int nt = 0; nt < 4; nt++)
#pragma unroll
        for (int e = 0; e < 4; e++) acc[nt][e] = 0.f;

    const int r0 = wid * 16;
#pragma unroll
    for (int kk = 0; kk < 2; kk++) {
        uint32_t af[4];
        int row = r0 + (lane & 15);
        int ch = sw_chunk(row, kk * 2 + (lane >> 4));
        ldsm4(af, sb + QHI + row * 64 + ch * 16);
        uint32_t bf[2][4];
#pragma unroll
        for (int nt2 = 0; nt2 < 2; nt2++) {
            int g = lane >> 3, l8 = lane & 7;
            int row2 = nt2 * 16 + (g >> 1) * 8 + l8;
            int ch2 = sw_chunk(row2, kk * 2 + (g & 1));
            ldsm4(bf[nt2], sb + KVHI + row2 * 64 + ch2 * 16);
        }
#pragma unroll
        for (int nt = 0; nt < 4; nt++)
            mma_f16(acc[nt], af, &bf[nt >> 1][(nt & 1) * 2]);
    }

    int c = r0 + (lane >> 2);
    float a0 = ed[c], a1 = ed[c + 8];
#pragma unroll
    for (int nt = 0; nt < 4; nt++) {
        int e = nt * 8 + (lane & 3) * 2;
#pragma unroll
        for (int half = 0; half < 2; half++) {
            int cc2 = c + half * 8;
            float al = half ? a1 : a0;
            size_t go = (tok0 + cc2) * CC + h*DD + e;
            float2 o0 = *(float2*)&g_o[go];
            o0.x += al * acc[nt][half*2+0];
            o0.y += al * acc[nt][half*2+1];
            size_t a2b = (tok0 + cc2) * CC + h*DD + e;
            *(uint32_t*)&A2[a2b] =
                pack_h2(__float2half_rn(o0.x), __float2half_rn(o0.y));
        }
    }
}

// ======================= launch =======================
extern "C" void kernel_launch(void* const* d_in, const int* in_sizes, int n_in,
                              void* d_out, int out_size)
{
    const float* x    = (const float*)d_in[0];
    const float* rel  = (const float*)d_in[1];
    const float* qkvw = (const float*)d_in[2];
    const float* qg   = (const float*)d_in[3];
    const float* kg   = (const float*)d_in[4];
    const float* pw   = (const float*)d_in[5];
    const float* pb   = (const float*)d_in[6];
    float* out = (float*)d_out;

    void* p_qkv = nullptr; cudaGetSymbolAddress(&p_qkv, g_qkv);
    void* p_A2  = nullptr; cudaGetSymbolAddress(&p_A2,  g_A2);
    void* p_W1h = nullptr; cudaGetSymbolAddress(&p_W1h, g_W1h);
    void* p_W2h = nullptr; cudaGetSymbolAddress(&p_W2h, g_W2h);
    void* p_qh  = nullptr; cudaGetSymbolAddress(&p_qh,  g_qh);

    cudaFuncSetAttribute(attn_chunk_hmma,
                         cudaFuncAttributeMaxDynamicSharedMemorySize, AT_SMEM);
    cudaFuncSetAttribute(gemm_f16_hmma<false>,
                         cudaFuncAttributeMaxDynamicSharedMemorySize, GS_SMEM);
    cudaFuncSetAttribute(gemm_f16_hmma<true>,
                         cudaFuncAttributeMaxDynamicSharedMemorySize, GS_SMEM);
    cudaFuncSetAttribute(kv_scan_kernel,
                         cudaFuncAttributeMaxDynamicSharedMemorySize, SCAN_SMEM);

    // 1) convert (x + rel_pos) and weights to fp16
    conv_act_kernel<<<TT*64/256, 256>>>(x, rel, (__half*)p_A2);
    conv_w_kernel<<<768*64/256, 256>>>(qkvw, (__half*)p_W1h);
    conv_w_kernel<<<256*64/256, 256>>>(pw, (__half*)p_W2h);

    // 2) qkv = A @ W1h^T  (pure fp16 HMMA, K=256) -> fp32 g_qkv
    gemm_f16_hmma<false><<<dim3(768/128, TT/128), 256, GS_SMEM>>>(
        (const __half*)p_A2, (const __half*)p_W1h, nullptr,
        (float*)p_qkv, 768);

    // 3) attention: intra + C_n, scan (smem-prefetched), inter (writes A2 fp16)
    attn_chunk_hmma<<<dim3(NC, HH, BB), 256, AT_SMEM>>>(qg, kg, (__half*)p_qh);
    kv_scan_kernel<<<BB*HH, 256, SCAN_SMEM>>>();
    attn_inter_hmma<<<dim3(NC, HH, BB), 256>>>((const __half*)p_qh, (__half*)p_A2);

    // 4) out = O @ W2h^T + bias (pure fp16 HMMA)
    gemm_f16_hmma<true><<<dim3(256/128, TT/128), 256, GS_SMEM>>>(
        (const __half*)p_A2, (const __half*)p_W2h, pb,
        out, 256);
}

// round 14
// speedup vs baseline: 4.9328x; 1.0562x over previous
#include <cuda_runtime.h>
#include <cuda_fp16.h>
#include <math.h>
#include <stdint.h>

// Problem constants
#define BB 8
#define LL 4096
#define CC 256
#define HH 8
#define DD 32
#define CH 128
#define NC 32          // LL / CH
#define TT (BB*LL)     // 32768 tokens

// ---------------- static device scratch (no allocations allowed) ----------------
__device__ __half g_qkv[(size_t)TT * 768];                // qkv per token (fp16)
__device__ float g_o  [(size_t)TT * CC];                  // attention output (intra)
__device__ float g_C  [(size_t)BB*HH*NC * DD*DD];         // per-chunk KV contributions
__device__ float g_kvp[(size_t)BB*HH*NC * DD*DD];         // exclusive KV prefixes
__device__ __half g_A2 [(size_t)TT * CC];                 // fp16 activations
__device__ __half g_W1h[(size_t)768 * 256];               // qkv weight (fp16)
__device__ __half g_W2h[(size_t)256 * 256];               // proj weight (fp16)
__device__ __half g_qh [(size_t)TT * CC];                 // normalized q hat (fp16)

// =========================== small PTX helpers ===========================
__device__ __forceinline__ uint32_t smem_u32(const void* p) {
    uint32_t a;
    asm("{ .reg .u64 t; cvta.to.shared.u64 t, %1; cvt.u32.u64 %0, t; }" : "=r"(a) : "l"(p));
    return a;
}
__device__ __forceinline__ void cpasync16(uint32_t dst, const void* src) {
    asm volatile("cp.async.cg.shared.global [%0], [%1], 16;" :: "r"(dst), "l"(src));
}
__device__ __forceinline__ void cp_commit() {
    asm volatile("cp.async.commit_group;" ::: "memory");
}
template<int N>
__device__ __forceinline__ void cp_wait() {
    asm volatile("cp.async.wait_group %0;" :: "n"(N) : "memory");
}
__device__ __forceinline__ void ldsm4(uint32_t* r, uint32_t addr) {
    asm volatile("ldmatrix.sync.aligned.m8n8.x4.shared.b16 {%0,%1,%2,%3}, [%4];"
                 : "=r"(r[0]), "=r"(r[1]), "=r"(r[2]), "=r"(r[3]) : "r"(addr));
}
__device__ __forceinline__ void mma_f16(float* c, const uint32_t* a, const uint32_t* b) {
    asm volatile("mma.sync.aligned.m16n8k16.row.col.f32.f16.f16.f32 "
                 "{%0,%1,%2,%3}, {%4,%5,%6,%7}, {%8,%9}, {%0,%1,%2,%3};"
                 : "+f"(c[0]), "+f"(c[1]), "+f"(c[2]), "+f"(c[3])
                 : "r"(a[0]), "r"(a[1]), "r"(a[2]), "r"(a[3]), "r"(b[0]), "r"(b[1]));
}
// xor swizzle of 16B chunk index within a 64B row (4 chunks)
__device__ __forceinline__ int sw_chunk(int r, int c) {
    return c ^ (r & 3) ^ ((r >> 2) & 1);
}
__device__ __forceinline__ uint32_t pack_h2(__half a, __half b) {
    uint32_t lo16 = *(uint16_t*)&a, hi16 = *(uint16_t*)&b;
    return lo16 | (hi16 << 16);
}

// =========================== fp16 conversion kernels ===========================
__global__ void conv_act_kernel(const float* __restrict__ x, const float* __restrict__ rp,
                                __half* __restrict__ A2)
{
    int idx = blockIdx.x * 256 + threadIdx.x;
    int m = idx >> 6, c4 = (idx & 63) << 2;
    float4 h = *(const float4*)&x[(size_t)m * 256 + c4];
    float4 r = *(const float4*)&rp[(size_t)(m & (LL-1)) * 256 + c4];
    h.x += r.x; h.y += r.y; h.z += r.z; h.w += r.w;
    float hv[4] = {h.x, h.y, h.z, h.w};
    __half hi[4];
#pragma unroll
    for (int j = 0; j < 4; j++) hi[j] = __float2half_rn(hv[j]);
    *(uint2*)&A2[(size_t)m * CC + c4] = *(uint2*)hi;
}

__global__ void conv_w_kernel(const float* __restrict__ W, __half* __restrict__ Wh)
{
    int idx = blockIdx.x * 256 + threadIdx.x;
    int n = idx >> 6, c4 = (idx & 63) << 2;
    float4 h = *(const float4*)&W[(size_t)n * 256 + c4];
    float hv[4] = {h.x, h.y, h.z, h.w};
    __half hi[4];
#pragma unroll
    for (int j = 0; j < 4; j++) hi[j] = __float2half_rn(hv[j]);
    *(uint2*)&Wh[(size_t)n * 256 + c4] = *(uint2*)hi;
}

// =========================== HMMA fp16 GEMM: C = A @ W^T (+bias) ===========================
// Pure fp16, K=256, BK=64 slabs (4 total). 3-stage cp.async ring (96 KB), one sync per slab.
// OUT16: write fp16 output (no bias); else fp32 (+bias optional).
#define NSTG 4
#define GS_STG 16384
#define GS_B0  (3*GS_STG)
#define GS_SMEM (6*GS_STG)   // 98304 bytes

template<bool BIAS, bool OUT16>
__global__ void __launch_bounds__(256, 2) gemm_f16_hmma(
    const __half* __restrict__ A,
    const __half* __restrict__ Bw,
    const float* __restrict__ bias,
    void* __restrict__ Cout, int Ntot)
{
    extern __shared__ __align__(16) char gsm[];
    const uint32_t as_base = smem_u32(gsm);
    const uint32_t bs_base = as_base + GS_B0;

    const int tid = threadIdx.x;
    const int wid = tid >> 5, lane = tid & 31;
    const int warp_m = wid & 1, warp_n = wid >> 1;
    const int m0 = blockIdx.y * 128;
    const int n0 = blockIdx.x * 128;

    float acc[4][4][4];
#pragma unroll
    for (int mt = 0; mt < 4; mt++)
#pragma unroll
        for (int nt = 0; nt < 4; nt++)
#pragma unroll
            for (int e = 0; e < 4; e++) acc[mt][nt][e] = 0.f;

    auto load_stage = [&](int s, int b) {
#pragma unroll
        for (int l = 0; l < 4; l++) {
            int i = tid + l * 256;
            int r = i >> 3, c = i & 7;
            int ch = c ^ (r & 7);
            cpasync16(as_base + b*GS_STG + r*128 + ch*16,
                      A  + (size_t)(m0 + r) * 256 + s * 64 + c * 8);
            cpasync16(bs_base + b*GS_STG + r*128 + ch*16,
                      Bw + (size_t)(n0 + r) * 256 + s * 64 + c * 8);
        }
        cp_commit();
    };

    load_stage(0, 0);
    load_stage(1, 1);

    int b = 0;
    for (int i = 0; i < NSTG; i++) {
        if (i + 1 < NSTG) cp_wait<1>(); else cp_wait<0>();
        __syncthreads();

#pragma unroll
        for (int kk = 0; kk < 4; kk++) {
            uint32_t af[4][4];
#pragma unroll
            for (int mt = 0; mt < 4; mt++) {
                int row = warp_m * 64 + mt * 16 + (lane & 15);
                int ch = (kk * 2 + (lane >> 4)) ^ (row & 7);
                ldsm4(af[mt], as_base + b*GS_STG + row * 128 + ch * 16);
            }
            uint32_t bf[2][4];
#pragma unroll
            for (int nt2 = 0; nt2 < 2; nt2++) {
                int g = lane >> 3, l8 = lane & 7;
                int row = warp_n * 32 + nt2 * 16 + (g >> 1) * 8 + l8;
                int ch = (kk * 2 + (g & 1)) ^ (row & 7);
                ldsm4(bf[nt2], bs_base + b*GS_STG + row * 128 + ch * 16);
            }
#pragma unroll
            for (int mt = 0; mt < 4; mt++)
#pragma unroll
                for (int nt = 0; nt < 4; nt++)
                    mma_f16(acc[mt][nt], af[mt], &bf[nt >> 1][(nt & 1) * 2]);
        }

        if (i + 2 < NSTG) {
            int b2 = b + 2; if (b2 >= 3) b2 -= 3;
            load_stage(i + 2, b2);
        }
        if (++b == 3) b = 0;
    }

#pragma unroll
    for (int mt = 0; mt < 4; mt++) {
        int row = m0 + warp_m * 64 + mt * 16 + (lane >> 2);
#pragma unroll
        for (int nt = 0; nt < 4; nt++) {
            int col = n0 + warp_n * 32 + nt * 8 + (lane & 3) * 2;
            float2 v0 = make_float2(acc[mt][nt][0], acc[mt][nt][1]);
            float2 v1 = make_float2(acc[mt][nt][2], acc[mt][nt][3]);
            if (BIAS) {
                float2 bv = *(const float2*)&bias[col];
                v0.x += bv.x; v0.y += bv.y;
                v1.x += bv.x; v1.y += bv.y;
            }
            if (OUT16) {
                __half* Ch = (__half*)Cout;
                *(uint32_t*)&Ch[(size_t)row * Ntot + col] =
                    pack_h2(__float2half_rn(v0.x), __float2half_rn(v0.y));
                *(uint32_t*)&Ch[(size_t)(row + 8) * Ntot + col] =
                    pack_h2(__float2half_rn(v1.x), __float2half_rn(v1.y));
            } else {
                float* Cf = (float*)Cout;
                *(float2*)&Cf[(size_t)row * Ntot + col]       = v0;
                *(float2*)&Cf[(size_t)(row + 8) * Ntot + col] = v1;
            }
        }
    }
}

// ======================= HMMA attention: intra + per-chunk KV contribution =======================
// smem layout (bytes); total 84 KB -> 2 CTAs/SM
#define AT_ED   0                     // 129 floats
#define AT_NQ   640
#define AT_NK   1152
#define AT_QHI  2048
#define AT_QLO  (AT_QHI  + 8192)      // unused (layout stability)
#define AT_KHI  (AT_QLO  + 8192)
#define AT_KTHI (AT_KHI  + 8192)
#define AT_KTLO (AT_KTHI + 8192)      // unused
#define AT_VTHI (AT_KTLO + 8192)
#define AT_SC0H (AT_VTHI + 8192)      // 128 rows x 128 B
#define AT_SC0L (AT_SC0H + 16384)     // scratch
#define AT_SMEM (AT_SC0L + 16384)     // 83968 bytes
// aliases (regions dead by the time they're reused)
#define AT_SC1H AT_QHI                // 64 rows x 128 B
#define AT_CRED AT_SC0H               // 16 KB: 4 warps x 4 KB (sc0 dead after P4)

__global__ void __launch_bounds__(256, 2) attn_chunk_hmma(
    const float* __restrict__ qg, const float* __restrict__ kg,
    __half* __restrict__ qhout)
{
    extern __shared__ char sm[];
    float* ed = (float*)(sm + AT_ED);
    float* nq = (float*)(sm + AT_NQ);
    float* nk = (float*)(sm + AT_NK);
    const uint32_t sb = smem_u32(sm);

    const int n = blockIdx.x, h = blockIdx.y, b = blockIdx.z;
    const int tid = threadIdx.x, lane = tid & 31, wid = tid >> 5;
    const float s = exp2f(-(float)(h + 1));
    for (int i = tid; i <= CH; i += 256) ed[i] = expf(-s * (float)i);

    const size_t tok0 = (size_t)(b*LL + n*CH);
    const size_t base = tok0 * 768 + h*DD;
    const int c4 = (tid & 7) * 4;

    // ---- P1: load q,k,v (fp16); keep q,k in registers across norm barrier ----
    float qsv[4][4], ksv[4][4];
    float sq[4], sk[4];
#pragma unroll
    for (int l = 0; l < 4; l++) {
        int r = (tid >> 3) + l * 32;
        const __half* rowp = &g_qkv[base + (size_t)r * 768 + c4];
        __half hq[4], hk[4], hv4[4];
        *(uint2*)hq  = *(const uint2*)(rowp);
        *(uint2*)hk  = *(const uint2*)(rowp + 256);
        *(uint2*)hv4 = *(const uint2*)(rowp + 512);
        float s1 = 0.f, s2 = 0.f;
#pragma unroll
        for (int j = 0; j < 4; j++) {
            float a = __half2float(hq[j]);
            float c = __half2float(hk[j]);
            qsv[l][j] = a; ksv[l][j] = c;
            s1 += a*a; s2 += c*c;
            int d = c4 + j;
            int aT = d*256 + (((r >> 3) ^ (d & 7)) * 16) + ((r & 7) * 2);
            *(__half*)(sm + AT_VTHI + aT) = hv4[j];
        }
        sq[l] = s1; sk[l] = s2;
    }
#pragma unroll
    for (int m = 1; m < 8; m <<= 1) {
#pragma unroll
        for (int l = 0; l < 4; l++) {
            sq[l] += __shfl_xor_sync(0xffffffffu, sq[l], m);
            sk[l] += __shfl_xor_sync(0xffffffffu, sk[l], m);
        }
    }
    if ((tid & 7) == 0) {
        const float sqD = 5.656854249492380f;
#pragma unroll
        for (int l = 0; l < 4; l++) {
            int r = (tid >> 3) + l * 32;
            nq[r] = (sq[l] > 1e-24f) ? sqD * rsqrtf(sq[l]) : sqD * 1e12f;
            nk[r] = (sk[l] > 1e-24f) ? sqD * rsqrtf(sk[l]) : sqD * 1e12f;
        }
    }
    __syncthreads();

    // ---- P2: normalize + convert from registers ----
    float gq[4], gk[4];
#pragma unroll
    for (int j = 0; j < 4; j++) {
        gq[j] = __ldg(&qg[h*DD + c4 + j]);
        gk[j] = __ldg(&kg[h*DD + c4 + j]);
    }
#pragma unroll
    for (int l = 0; l < 4; l++) {
        int r = (tid >> 3) + l * 32;
        float rq = nq[r], rk = nk[r], dk = ed[CH - r];
        __half qh4[4], kh4[4];
#pragma unroll
        for (int j = 0; j < 4; j++) {
            int d = c4 + j;
            float qn = qsv[l][j] * rq * gq[j];
            float kn = ksv[l][j] * rk * gk[j];
            qh4[j] = __float2half_rn(qn);
            kh4[j] = __float2half_rn(kn);
            __half kth = __float2half_rn(kn * dk);
            int aT = d*256 + (((r >> 3) ^ (d & 7)) * 16) + ((r & 7) * 2);
            *(__half*)(sm + AT_KTHI + aT) = kth;
        }
        int a64 = r*64 + sw_chunk(r, c4 >> 3) * 16 + ((c4 & 7) * 2);
        *(uint2*)(sm + AT_QHI + a64) = *(uint2*)qh4;
        *(uint2*)(sm + AT_KHI + a64) = *(uint2*)kh4;
        *(uint2*)(qhout + (tok0 + r)*CC + h*DD + c4) = *(uint2*)qh4;
    }
    __syncthreads();

    const int g = lane >> 3, l8 = lane & 7;

    // ---- P3: scores half0  S[:, 0:64]  (all 128 rows) ----
    float acc0[8][4];
#pragma unroll
    for (int nt = 0; nt < 8; nt++)
#pragma unroll
        for (int e = 0; e < 4; e++) acc0[nt][e] = 0.f;
#pragma unroll
    for (int kk = 0; kk < 2; kk++) {
        uint32_t af[4];
        int row = wid * 16 + (lane & 15);
        ldsm4(af, sb + AT_QHI + row * 64 + sw_chunk(row, kk * 2 + (lane >> 4)) * 16);
        uint32_t bf[4][4];
#pragma unroll
        for (int nt2 = 0; nt2 < 4; nt2++) {
            int row2 = nt2 * 16 + (g >> 1) * 8 + l8;
            ldsm4(bf[nt2], sb + AT_KHI + row2 * 64 + sw_chunk(row2, kk * 2 + (g & 1)) * 16);
        }
#pragma unroll
        for (int nt = 0; nt < 8; nt++)
            mma_f16(acc0[nt], af, &bf[nt >> 1][(nt & 1) * 2]);
    }
    // mask + decay + write sc0
    {
        int c_lo = wid * 16 + (lane >> 2);
#pragma unroll
        for (int nt = 0; nt < 8; nt++) {
            int mm = nt * 8 + (lane & 3) * 2;
#pragma unroll
            for (int half = 0; half < 2; half++) {
                int c = c_lo + half * 8;
                float v0 = acc0[nt][half*2+0], v1 = acc0[nt][half*2+1];
                int d0 = c - mm, d1 = c - mm - 1;
                float s0 = (d0 >= 0) ? v0 * ed[d0] : 0.f;
                float s1 = (d1 >= 0) ? v1 * ed[d1] : 0.f;
                int addr = c * 128 + (((mm >> 3) ^ (c & 7)) * 16) + ((mm * 2) & 15);
                *(uint32_t*)(sm + AT_SC0H + addr) =
                    pack_h2(__float2half_rn(s0), __float2half_rn(s1));
            }
        }
    }
    __syncthreads();

    // ---- P4: o_intra part A (K = 0..64, all rows) ----
    float oacc[4][4];
#pragma unroll
    for (int nt = 0; nt < 4; nt++)
#pragma unroll
        for (int e = 0; e < 4; e++) oacc[nt][e] = 0.f;
    {
        const int r0 = wid * 16;
#pragma unroll
        for (int kk = 0; kk < 4; kk++) {
            uint32_t af[4];
            int row = r0 + (lane & 15);
            int ch = (kk * 2 + (lane >> 4)) ^ (row & 7);
            ldsm4(af, sb + AT_SC0H + row * 128 + ch * 16);
            uint32_t bf[2][4];
#pragma unroll
            for (int nt2 = 0; nt2 < 2; nt2++) {
                int row2 = nt2 * 16 + (g >> 1) * 8 + l8;
                int ch2 = (kk * 2 + (g & 1)) ^ (row2 & 7);
                ldsm4(bf[nt2], sb + AT_VTHI + row2 * 256 + ch2 * 16);
            }
#pragma unroll
            for (int nt = 0; nt < 4; nt++)
                mma_f16(oacc[nt], af, &bf[nt >> 1][(nt & 1) * 2]);
        }
    }
    if (wid < 4) {
        int c = wid * 16 + (lane >> 2);
#pragma unroll
        for (int nt = 0; nt < 4; nt++) {
            int e = nt * 8 + (lane & 3) * 2;
            size_t go = (tok0 + c) * CC + h*DD + e;
            *(float2*)&g_o[go]        = make_float2(oacc[nt][0], oacc[nt][1]);
            *(float2*)&g_o[go + 8*CC] = make_float2(oacc[nt][2], oacc[nt][3]);
        }
    }

    // ---- P5: scores half1  S[64:128, 64:128]  (all 8 warps) ----
    float acc1[4][4];
#pragma unroll
    for (int nt = 0; nt < 4; nt++)
#pragma unroll
        for (int e = 0; e < 4; e++) acc1[nt][e] = 0.f;
    const int c0s = 64 + (wid & 3) * 16;
    const int mbs = 64 + (wid >> 2) * 32;
#pragma unroll
    for (int kk = 0; kk < 2; kk++) {
        uint32_t af[4];
        int row = c0s + (lane & 15);
        ldsm4(af, sb + AT_QHI + row * 64 + sw_chunk(row, kk * 2 + (lane >> 4)) * 16);
        uint32_t bf[2][4];
#pragma unroll
        for (int nt2 = 0; nt2 < 2; nt2++) {
            int row2 = mbs + nt2 * 16 + (g >> 1) * 8 + l8;
            ldsm4(bf[nt2], sb + AT_KHI + row2 * 64 + sw_chunk(row2, kk * 2 + (g & 1)) * 16);
        }
#pragma unroll
        for (int nt = 0; nt < 4; nt++)
            mma_f16(acc1[nt], af, &bf[nt >> 1][(nt & 1) * 2]);
    }
    __syncthreads();   // all Q/K fragment reads done; QHI becomes sc1

    {
        int c_lo = c0s + (lane >> 2);
#pragma unroll
        for (int nt = 0; nt < 4; nt++) {
            int mm = mbs + nt * 8 + (lane & 3) * 2;
#pragma unroll
            for (int half = 0; half < 2; half++) {
                int c = c_lo + half * 8;
                float v0 = acc1[nt][half*2+0], v1 = acc1[nt][half*2+1];
                int d0 = c - mm, d1 = c - mm - 1;
                float s0 = (d0 >= 0) ? v0 * ed[d0] : 0.f;
                float s1 = (d1 >= 0) ? v1 * ed[d1] : 0.f;
                int cr = c - 64, mr = mm - 64;
                int addr = cr * 128 + (((mr >> 3) ^ (cr & 7)) * 16) + ((mr * 2) & 15);
                *(uint32_t*)(sm + AT_SC1H + addr) =
                    pack_h2(__float2half_rn(s0), __float2half_rn(s1));
            }
        }
    }
    __syncthreads();

    // ---- P6: warps 4-7: o_intra part B; warps 0-3: C_n ----
    if (wid >= 4) {
        const int r0 = (wid - 4) * 16;
#pragma unroll
        for (int kk = 0; kk < 4; kk++) {
            uint32_t af[4];
            int row = r0 + (lane & 15);
            int ch = (kk * 2 + (lane >> 4)) ^ (row & 7);
            ldsm4(af, sb + AT_SC1H + row * 128 + ch * 16);
            uint32_t bf[2][4];
#pragma unroll
            for (int nt2 = 0; nt2 < 2; nt2++) {
                int row2 = nt2 * 16 + (g >> 1) * 8 + l8;
                int ch2 = ((kk + 4) * 2 + (g & 1)) ^ (row2 & 7);
                ldsm4(bf[nt2], sb + AT_VTHI + row2 * 256 + ch2 * 16);
            }
#pragma unroll
            for (int nt = 0; nt < 4; nt++)
                mma_f16(oacc[nt], af, &bf[nt >> 1][(nt & 1) * 2]);
        }
        int c = wid * 16 + (lane >> 2);
#pragma unroll
        for (int nt = 0; nt < 4; nt++) {
            int e = nt * 8 + (lane & 3) * 2;
            size_t go = (tok0 + c) * CC + h*DD + e;
            *(float2*)&g_o[go]        = make_float2(oacc[nt][0], oacc[nt][1]);
            *(float2*)&g_o[go + 8*CC] = make_float2(oacc[nt][2], oacc[nt][3]);
        }
    } else {
        float cacc[2][4][4];
#pragma unroll
        for (int mt = 0; mt < 2; mt++)
#pragma unroll
            for (int nt = 0; nt < 4; nt++)
#pragma unroll
                for (int e = 0; e < 4; e++) cacc[mt][nt][e] = 0.f;

#pragma unroll
        for (int kl = 0; kl < 2; kl++) {
            int kk = wid * 2 + kl;
            uint32_t af[2][4];
#pragma unroll
            for (int mt = 0; mt < 2; mt++) {
                int row = mt * 16 + (lane & 15);
                int ch = (kk * 2 + (lane >> 4)) ^ (row & 7);
                ldsm4(af[mt], sb + AT_KTHI + row * 256 + ch * 16);
            }
            uint32_t bf[2][4];
#pragma unroll
            for (int nt2 = 0; nt2 < 2; nt2++) {
                int row2 = nt2 * 16 + (g >> 1) * 8 + l8;
                int ch2 = (kk * 2 + (g & 1)) ^ (row2 & 7);
                ldsm4(bf[nt2], sb + AT_VTHI + row2 * 256 + ch2 * 16);
            }
#pragma unroll
            for (int mt = 0; mt < 2; mt++)
#pragma unroll
                for (int nt = 0; nt < 4; nt++)
                    mma_f16(cacc[mt][nt], af[mt], &bf[nt >> 1][(nt & 1) * 2]);
        }
        float* red = (float*)(sm + AT_CRED) + wid * 1024;
#pragma unroll
        for (int mt = 0; mt < 2; mt++) {
            int d = mt * 16 + (lane >> 2);
#pragma unroll
            for (int nt = 0; nt < 4; nt++) {
                int e = nt * 8 + (lane & 3) * 2;
                *(float2*)&red[d * 32 + e]       = make_float2(cacc[mt][nt][0], cacc[mt][nt][1]);
                *(float2*)&red[(d + 8) * 32 + e] = make_float2(cacc[mt][nt][2], cacc[mt][nt][3]);
            }
        }
    }
    __syncthreads();
    {
        const float* red = (const float*)(sm + AT_CRED);
        const size_t cb = ((size_t)((b*HH + h)*NC + n)) * 1024;
        for (int i = tid; i < 1024; i += 256)
            g_C[cb + i] = red[i] + red[1024 + i] + red[2048 + i] + red[3072 + i];
    }
}

// ======================= KV scan: prefetch all stages to smem, then serial =======================
#define SCAN_SMEM (NC * 4096)   // 131072 bytes

__global__ void kv_scan_kernel()
{
    extern __shared__ __align__(16) float scs[];   // [NC][1024]
    const uint32_t sb = smem_u32(scs);
    const int bh = blockIdx.x;
    const int h = bh & 7;
    const int tid = threadIdx.x;
    const size_t cbase = (size_t)bh * NC * 1024;

    for (int i = tid; i < NC * 256; i += 256)
        cpasync16(sb + i * 16, &g_C[cbase + (size_t)i * 4]);
    cp_commit();
    cp_wait<0>();
    __syncthreads();

    const float bd = expf(-exp2f(-(float)(h+1)) * (float)CH);
    float4 kv = make_float4(0.f, 0.f, 0.f, 0.f);
    for (int n = 0; n < NC; n++) {
        *(float4*)&g_kvp[cbase + n*1024 + tid*4] = kv;
        float4 c = *(const float4*)&scs[n*1024 + tid*4];
        kv.x = bd*kv.x + c.x; kv.y = bd*kv.y + c.y;
        kv.z = bd*kv.z + c.z; kv.w = bd*kv.w + c.w;
    }
}

// ======================= HMMA inter-chunk (q hi) + fused fp16 convert of o -> A2 =======================
__global__ void __launch_bounds__(256) attn_inter_hmma(
    const __half* __restrict__ qh, __half* __restrict__ A2)
{
    const int n = blockIdx.x;
    const int h = blockIdx.y, b = blockIdx.z;

    __shared__ __align__(16) char sm[8192 + 2048 + 1024];
    const int QHI = 0, KVHI = 8192, EDO = 10240;
    float* ed = (float*)(sm + EDO);
    const uint32_t sb = smem_u32(sm);

    const int tid = threadIdx.x, lane = tid & 31, wid = tid >> 5;
    const float s = exp2f(-(float)(h+1));
    for (int i = tid; i < CH; i += 256) ed[i] = expf(-s * (float)i);

    const size_t tok0 = (size_t)(b*LL + n*CH);
    for (int i = tid; i < 512; i += 256) {
        int r = i >> 2, c = i & 3;
        uint4 v = *(const uint4*)(qh + (tok0 + r)*CC + h*DD + c*8);
        *(uint4*)(sm + QHI + r*64 + sw_chunk(r, c)*16) = v;
    }
    const size_t kb = ((size_t)((b*HH + h)*NC + n)) * 1024;
    for (int i = tid; i < 1024; i += 256) {
        int d = i >> 5, e = i & 31;
        float v = g_kvp[kb + i];
        __half hh = __float2half_rn(v);
        int a = e*64 + sw_chunk(e, d >> 3)*16 + (d & 7)*2;
        *(__half*)(sm + KVHI + a) = hh;
    }
    __syncthreads();

    float acc[4][4];
#pragma unroll
    for (int nt = 0; nt < 4; nt++)
#pragma unroll
        for (int e = 0; e < 4; e++) acc[nt][e] = 0.f;

    const int r0 = wid * 16;
#pragma unroll
    for (int kk = 0; kk < 2; kk++) {
        uint32_t af[4];
        int row = r0 + (lane & 15);
        int ch = sw_chunk(row, kk * 2 + (lane >> 4));
        ldsm4(af, sb + QHI + row * 64 + ch * 16);
        uint32_t bf[2][4];
#pragma unroll
        for (int nt2 = 0; nt2 < 2; nt2++) {
            int g = lane >> 3, l8 = lane & 7;
            int row2 = nt2 * 16 + (g >> 1) * 8 + l8;
            int ch2 = sw_chunk(row2, kk * 2 + (g & 1));
            ldsm4(bf[nt2], sb + KVHI + row2 * 64 + ch2 * 16);
        }
#pragma unroll
        for (int nt = 0; nt < 4; nt++)
            mma_f16(acc[nt], af, &bf[nt >> 1][(nt & 1) * 2]);
    }

    int c = r0 + (lane >> 2);
    float a0 = ed[c], a1 = ed[c + 8];
#pragma unroll
    for (int nt = 0; nt < 4; nt++) {
        int e = nt * 8 + (lane & 3) * 2;
#pragma unroll
        for (int half = 0; half < 2; half++) {
            int cc2 = c + half * 8;
            float al = half ? a1 : a0;
            size_t go = (tok0 + cc2) * CC + h*DD + e;
            float2 o0 = *(float2*)&g_o[go];
            o0.x += al * acc[nt][half*2+0];
            o0.y += al * acc[nt][half*2+1];
            size_t a2b = (tok0 + cc2) * CC + h*DD + e;
            *(uint32_t*)&A2[a2b] =
                pack_h2(__float2half_rn(o0.x), __float2half_rn(o0.y));
        }
    }
}

// ======================= launch =======================
extern "C" void kernel_launch(void* const* d_in, const int* in_sizes, int n_in,
                              void* d_out, int out_size)
{
    const float* x    = (const float*)d_in[0];
    const float* rel  = (const float*)d_in[1];
    const float* qkvw = (const float*)d_in[2];
    const float* qg   = (const float*)d_in[3];
    const float* kg   = (const float*)d_in[4];
    const float* pw   = (const float*)d_in[5];
    const float* pb   = (const float*)d_in[6];
    float* out = (float*)d_out;

    void* p_qkv = nullptr; cudaGetSymbolAddress(&p_qkv, g_qkv);
    void* p_A2  = nullptr; cudaGetSymbolAddress(&p_A2,  g_A2);
    void* p_W1h = nullptr; cudaGetSymbolAddress(&p_W1h, g_W1h);
    void* p_W2h = nullptr; cudaGetSymbolAddress(&p_W2h, g_W2h);
    void* p_qh  = nullptr; cudaGetSymbolAddress(&p_qh,  g_qh);

    cudaFuncSetAttribute(attn_chunk_hmma,
                         cudaFuncAttributeMaxDynamicSharedMemorySize, AT_SMEM);
    cudaFuncSetAttribute((gemm_f16_hmma<false, true>),
                         cudaFuncAttributeMaxDynamicSharedMemorySize, GS_SMEM);
    cudaFuncSetAttribute((gemm_f16_hmma<true, false>),
                         cudaFuncAttributeMaxDynamicSharedMemorySize, GS_SMEM);
    cudaFuncSetAttribute(kv_scan_kernel,
                         cudaFuncAttributeMaxDynamicSharedMemorySize, SCAN_SMEM);

    // 1) convert (x + rel_pos) and weights to fp16
    conv_act_kernel<<<TT*64/256, 256>>>(x, rel, (__half*)p_A2);
    conv_w_kernel<<<768*64/256, 256>>>(qkvw, (__half*)p_W1h);
    conv_w_kernel<<<256*64/256, 256>>>(pw, (__half*)p_W2h);

    // 2) qkv = A @ W1h^T  (pure fp16 HMMA, K=256) -> fp16 g_qkv
    gemm_f16_hmma<false, true><<<dim3(768/128, TT/128), 256, GS_SMEM>>>(
        (const __half*)p_A2, (const __half*)p_W1h, nullptr,
        p_qkv, 768);

    // 3) attention: intra + C_n, scan (smem-prefetched), inter (writes A2 fp16)
    attn_chunk_hmma<<<dim3(NC, HH, BB), 256, AT_SMEM>>>(qg, kg, (__half*)p_qh);
    kv_scan_kernel<<<BB*HH, 256, SCAN_SMEM>>>();
    attn_inter_hmma<<<dim3(NC, HH, BB), 256>>>((const __half*)p_qh, (__half*)p_A2);

    // 4) out = O @ W2h^T + bias (fp32 out)
    gemm_f16_hmma<true, false><<<dim3(256/128, TT/128), 256, GS_SMEM>>>(
        (const __half*)p_A2, (const __half*)p_W2h, pb,
        out, 256);
}

// round 15
// speedup vs baseline: 4.9896x; 1.0115x over previous
#include <cuda_runtime.h>
#include <cuda_fp16.h>
#include <math.h>
#include <stdint.h>

// Problem constants
#define BB 8
#define LL 4096
#define CC 256
#define HH 8
#define DD 32
#define CH 128
#define NC 32          // LL / CH
#define TT (BB*LL)     // 32768 tokens

// ---------------- static device scratch (no allocations allowed) ----------------
__device__ __half g_qkv[(size_t)TT * 768];                // qkv per token (fp16)
__device__ float g_C  [(size_t)BB*HH*NC * DD*DD];         // per-chunk KV contributions
__device__ float g_kvp[(size_t)BB*HH*NC * DD*DD];         // exclusive KV prefixes
__device__ __half g_A2 [(size_t)TT * CC];                 // fp16 activations / attention out
__device__ __half g_W1h[(size_t)768 * 256];               // qkv weight (fp16)
__device__ __half g_W2h[(size_t)256 * 256];               // proj weight (fp16)
__device__ __half g_qh [(size_t)TT * CC];                 // normalized q hat (fp16)

// =========================== small PTX helpers ===========================
__device__ __forceinline__ uint32_t smem_u32(const void* p) {
    uint32_t a;
    asm("{ .reg .u64 t; cvta.to.shared.u64 t, %1; cvt.u32.u64 %0, t; }" : "=r"(a) : "l"(p));
    return a;
}
__device__ __forceinline__ void cpasync16(uint32_t dst, const void* src) {
    asm volatile("cp.async.cg.shared.global [%0], [%1], 16;" :: "r"(dst), "l"(src));
}
__device__ __forceinline__ void cp_commit() {
    asm volatile("cp.async.commit_group;" ::: "memory");
}
template<int N>
__device__ __forceinline__ void cp_wait() {
    asm volatile("cp.async.wait_group %0;" :: "n"(N) : "memory");
}
__device__ __forceinline__ void ldsm4(uint32_t* r, uint32_t addr) {
    asm volatile("ldmatrix.sync.aligned.m8n8.x4.shared.b16 {%0,%1,%2,%3}, [%4];"
                 : "=r"(r[0]), "=r"(r[1]), "=r"(r[2]), "=r"(r[3]) : "r"(addr));
}
__device__ __forceinline__ void mma_f16(float* c, const uint32_t* a, const uint32_t* b) {
    asm volatile("mma.sync.aligned.m16n8k16.row.col.f32.f16.f16.f32 "
                 "{%0,%1,%2,%3}, {%4,%5,%6,%7}, {%8,%9}, {%0,%1,%2,%3};"
                 : "+f"(c[0]), "+f"(c[1]), "+f"(c[2]), "+f"(c[3])
                 : "r"(a[0]), "r"(a[1]), "r"(a[2]), "r"(a[3]), "r"(b[0]), "r"(b[1]));
}
// xor swizzle of 16B chunk index within a 64B row (4 chunks)
__device__ __forceinline__ int sw_chunk(int r, int c) {
    return c ^ (r & 3) ^ ((r >> 2) & 1);
}
__device__ __forceinline__ uint32_t pack_h2(__half a, __half b) {
    uint32_t lo16 = *(uint16_t*)&a, hi16 = *(uint16_t*)&b;
    return lo16 | (hi16 << 16);
}

// =========================== fused fp16 conversion kernel ===========================
// blocks [0, 8192): act = fp16(x + rel_pos) -> A2
// blocks [8192, 8384): W1 -> fp16
// blocks [8384, 8448): W2 -> fp16
#define CONV_ACT_BLK (TT*64/256)      // 8192
#define CONV_W1_BLK  (768*64/256)     // 192
#define CONV_GRID    (CONV_ACT_BLK + CONV_W1_BLK + 256*64/256)

__global__ void conv_all_kernel(const float* __restrict__ x, const float* __restrict__ rp,
                                const float* __restrict__ W1, const float* __restrict__ W2,
                                __half* __restrict__ A2,
                                __half* __restrict__ W1h, __half* __restrict__ W2h)
{
    int blk = blockIdx.x;
    if (blk < CONV_ACT_BLK) {
        int idx = blk * 256 + threadIdx.x;
        int m = idx >> 6, c4 = (idx & 63) << 2;
        float4 h = *(const float4*)&x[(size_t)m * 256 + c4];
        float4 r = *(const float4*)&rp[(size_t)(m & (LL-1)) * 256 + c4];
        h.x += r.x; h.y += r.y; h.z += r.z; h.w += r.w;
        *(uint2*)&A2[(size_t)m * CC + c4] = make_uint2(
            pack_h2(__float2half_rn(h.x), __float2half_rn(h.y)),
            pack_h2(__float2half_rn(h.z), __float2half_rn(h.w)));
    } else {
        const float* W; __half* Wh; int idx;
        if (blk < CONV_ACT_BLK + CONV_W1_BLK) {
            W = W1; Wh = W1h; idx = (blk - CONV_ACT_BLK) * 256 + threadIdx.x;
        } else {
            W = W2; Wh = W2h; idx = (blk - CONV_ACT_BLK - CONV_W1_BLK) * 256 + threadIdx.x;
        }
        int n = idx >> 6, c4 = (idx & 63) << 2;
        float4 h = *(const float4*)&W[(size_t)n * 256 + c4];
        *(uint2*)&Wh[(size_t)n * 256 + c4] = make_uint2(
            pack_h2(__float2half_rn(h.x), __float2half_rn(h.y)),
            pack_h2(__float2half_rn(h.z), __float2half_rn(h.w)));
    }
}

// =========================== HMMA fp16 GEMM: C = A @ W^T (+bias) ===========================
// Pure fp16, K=256, BK=64 slabs (4 total). 3-stage cp.async ring (96 KB), one sync per slab.
#define NSTG 4
#define GS_STG 16384
#define GS_B0  (3*GS_STG)
#define GS_SMEM (6*GS_STG)   // 98304 bytes

template<bool BIAS, bool OUT16>
__global__ void __launch_bounds__(256, 2) gemm_f16_hmma(
    const __half* __restrict__ A,
    const __half* __restrict__ Bw,
    const float* __restrict__ bias,
    void* __restrict__ Cout, int Ntot)
{
    extern __shared__ __align__(16) char gsm[];
    const uint32_t as_base = smem_u32(gsm);
    const uint32_t bs_base = as_base + GS_B0;

    const int tid = threadIdx.x;
    const int wid = tid >> 5, lane = tid & 31;
    const int warp_m = wid & 1, warp_n = wid >> 1;
    const int m0 = blockIdx.y * 128;
    const int n0 = blockIdx.x * 128;

    float acc[4][4][4];
#pragma unroll
    for (int mt = 0; mt < 4; mt++)
#pragma unroll
        for (int nt = 0; nt < 4; nt++)
#pragma unroll
            for (int e = 0; e < 4; e++) acc[mt][nt][e] = 0.f;

    auto load_stage = [&](int s, int b) {
#pragma unroll
        for (int l = 0; l < 4; l++) {
            int i = tid + l * 256;
            int r = i >> 3, c = i & 7;
            int ch = c ^ (r & 7);
            cpasync16(as_base + b*GS_STG + r*128 + ch*16,
                      A  + (size_t)(m0 + r) * 256 + s * 64 + c * 8);
            cpasync16(bs_base + b*GS_STG + r*128 + ch*16,
                      Bw + (size_t)(n0 + r) * 256 + s * 64 + c * 8);
        }
        cp_commit();
    };

    load_stage(0, 0);
    load_stage(1, 1);

    int b = 0;
    for (int i = 0; i < NSTG; i++) {
        if (i + 1 < NSTG) cp_wait<1>(); else cp_wait<0>();
        __syncthreads();

#pragma unroll
        for (int kk = 0; kk < 4; kk++) {
            uint32_t af[4][4];
#pragma unroll
            for (int mt = 0; mt < 4; mt++) {
                int row = warp_m * 64 + mt * 16 + (lane & 15);
                int ch = (kk * 2 + (lane >> 4)) ^ (row & 7);
                ldsm4(af[mt], as_base + b*GS_STG + row * 128 + ch * 16);
            }
            uint32_t bf[2][4];
#pragma unroll
            for (int nt2 = 0; nt2 < 2; nt2++) {
                int g = lane >> 3, l8 = lane & 7;
                int row = warp_n * 32 + nt2 * 16 + (g >> 1) * 8 + l8;
                int ch = (kk * 2 + (g & 1)) ^ (row & 7);
                ldsm4(bf[nt2], bs_base + b*GS_STG + row * 128 + ch * 16);
            }
#pragma unroll
            for (int mt = 0; mt < 4; mt++)
#pragma unroll
                for (int nt = 0; nt < 4; nt++)
                    mma_f16(acc[mt][nt], af[mt], &bf[nt >> 1][(nt & 1) * 2]);
        }

        if (i + 2 < NSTG) {
            int b2 = b + 2; if (b2 >= 3) b2 -= 3;
            load_stage(i + 2, b2);
        }
        if (++b == 3) b = 0;
    }

#pragma unroll
    for (int mt = 0; mt < 4; mt++) {
        int row = m0 + warp_m * 64 + mt * 16 + (lane >> 2);
#pragma unroll
        for (int nt = 0; nt < 4; nt++) {
            int col = n0 + warp_n * 32 + nt * 8 + (lane & 3) * 2;
            float2 v0 = make_float2(acc[mt][nt][0], acc[mt][nt][1]);
            float2 v1 = make_float2(acc[mt][nt][2], acc[mt][nt][3]);
            if (BIAS) {
                float2 bv = *(const float2*)&bias[col];
                v0.x += bv.x; v0.y += bv.y;
                v1.x += bv.x; v1.y += bv.y;
            }
            if (OUT16) {
                __half* Ch = (__half*)Cout;
                *(uint32_t*)&Ch[(size_t)row * Ntot + col] =
                    pack_h2(__float2half_rn(v0.x), __float2half_rn(v0.y));
                *(uint32_t*)&Ch[(size_t)(row + 8) * Ntot + col] =
                    pack_h2(__float2half_rn(v1.x), __float2half_rn(v1.y));
            } else {
                float* Cf = (float*)Cout;
                *(float2*)&Cf[(size_t)row * Ntot + col]       = v0;
                *(float2*)&Cf[(size_t)(row + 8) * Ntot + col] = v1;
            }
        }
    }
}

// ======================= HMMA attention: intra + per-chunk KV contribution =======================
// smem layout (bytes); total 84 KB -> 2 CTAs/SM
#define AT_ED   0                     // 129 floats
#define AT_NQ   640
#define AT_NK   1152
#define AT_QHI  2048
#define AT_QLO  (AT_QHI  + 8192)      // unused (layout stability)
#define AT_KHI  (AT_QLO  + 8192)
#define AT_KTHI (AT_KHI  + 8192)
#define AT_KTLO (AT_KTHI + 8192)      // unused
#define AT_VTHI (AT_KTLO + 8192)
#define AT_SC0H (AT_VTHI + 8192)      // 128 rows x 128 B
#define AT_SC0L (AT_SC0H + 16384)     // scratch
#define AT_SMEM (AT_SC0L + 16384)     // 83968 bytes
// aliases (regions dead by the time they're reused)
#define AT_SC1H AT_QHI                // 64 rows x 128 B
#define AT_CRED AT_SC0H               // 16 KB: 4 warps x 4 KB (sc0 dead after P4)

__global__ void __launch_bounds__(256, 2) attn_chunk_hmma(
    const float* __restrict__ qg, const float* __restrict__ kg,
    __half* __restrict__ qhout, __half* __restrict__ oout)
{
    extern __shared__ char sm[];
    float* ed = (float*)(sm + AT_ED);
    float* nq = (float*)(sm + AT_NQ);
    float* nk = (float*)(sm + AT_NK);
    const uint32_t sb = smem_u32(sm);

    const int n = blockIdx.x, h = blockIdx.y, b = blockIdx.z;
    const int tid = threadIdx.x, lane = tid & 31, wid = tid >> 5;
    const float s = exp2f(-(float)(h + 1));
    for (int i = tid; i <= CH; i += 256) ed[i] = expf(-s * (float)i);

    const size_t tok0 = (size_t)(b*LL + n*CH);
    const size_t base = tok0 * 768 + h*DD;
    const int c4 = (tid & 7) * 4;

    // ---- P1: load q,k,v (fp16); keep q,k in registers across norm barrier ----
    float qsv[4][4], ksv[4][4];
    float sq[4], sk[4];
#pragma unroll
    for (int l = 0; l < 4; l++) {
        int r = (tid >> 3) + l * 32;
        const __half* rowp = &g_qkv[base + (size_t)r * 768 + c4];
        __half hq[4], hk[4], hv4[4];
        *(uint2*)hq  = *(const uint2*)(rowp);
        *(uint2*)hk  = *(const uint2*)(rowp + 256);
        *(uint2*)hv4 = *(const uint2*)(rowp + 512);
        float s1 = 0.f, s2 = 0.f;
#pragma unroll
        for (int j = 0; j < 4; j++) {
            float a = __half2float(hq[j]);
            float c = __half2float(hk[j]);
            qsv[l][j] = a; ksv[l][j] = c;
            s1 += a*a; s2 += c*c;
            int d = c4 + j;
            int aT = d*256 + (((r >> 3) ^ (d & 7)) * 16) + ((r & 7) * 2);
            *(__half*)(sm + AT_VTHI + aT) = hv4[j];
        }
        sq[l] = s1; sk[l] = s2;
    }
#pragma unroll
    for (int m = 1; m < 8; m <<= 1) {
#pragma unroll
        for (int l = 0; l < 4; l++) {
            sq[l] += __shfl_xor_sync(0xffffffffu, sq[l], m);
            sk[l] += __shfl_xor_sync(0xffffffffu, sk[l], m);
        }
    }
    if ((tid & 7) == 0) {
        const float sqD = 5.656854249492380f;
#pragma unroll
        for (int l = 0; l < 4; l++) {
            int r = (tid >> 3) + l * 32;
            nq[r] = (sq[l] > 1e-24f) ? sqD * rsqrtf(sq[l]) : sqD * 1e12f;
            nk[r] = (sk[l] > 1e-24f) ? sqD * rsqrtf(sk[l]) : sqD * 1e12f;
        }
    }
    __syncthreads();

    // ---- P2: normalize + convert from registers ----
    float gq[4], gk[4];
#pragma unroll
    for (int j = 0; j < 4; j++) {
        gq[j] = __ldg(&qg[h*DD + c4 + j]);
        gk[j] = __ldg(&kg[h*DD + c4 + j]);
    }
#pragma unroll
    for (int l = 0; l < 4; l++) {
        int r = (tid >> 3) + l * 32;
        float rq = nq[r], rk = nk[r], dk = ed[CH - r];
        __half qh4[4], kh4[4];
#pragma unroll
        for (int j = 0; j < 4; j++) {
            int d = c4 + j;
            float qn = qsv[l][j] * rq * gq[j];
            float kn = ksv[l][j] * rk * gk[j];
            qh4[j] = __float2half_rn(qn);
            kh4[j] = __float2half_rn(kn);
            __half kth = __float2half_rn(kn * dk);
            int aT = d*256 + (((r >> 3) ^ (d & 7)) * 16) + ((r & 7) * 2);
            *(__half*)(sm + AT_KTHI + aT) = kth;
        }
        int a64 = r*64 + sw_chunk(r, c4 >> 3) * 16 + ((c4 & 7) * 2);
        *(uint2*)(sm + AT_QHI + a64) = *(uint2*)qh4;
        *(uint2*)(sm + AT_KHI + a64) = *(uint2*)kh4;
        *(uint2*)(qhout + (tok0 + r)*CC + h*DD + c4) = *(uint2*)qh4;
    }
    __syncthreads();

    const int g = lane >> 3, l8 = lane & 7;

    // ---- P3: scores half0  S[:, 0:64]  (all 128 rows) ----
    float acc0[8][4];
#pragma unroll
    for (int nt = 0; nt < 8; nt++)
#pragma unroll
        for (int e = 0; e < 4; e++) acc0[nt][e] = 0.f;
#pragma unroll
    for (int kk = 0; kk < 2; kk++) {
        uint32_t af[4];
        int row = wid * 16 + (lane & 15);
        ldsm4(af, sb + AT_QHI + row * 64 + sw_chunk(row, kk * 2 + (lane >> 4)) * 16);
        uint32_t bf[4][4];
#pragma unroll
        for (int nt2 = 0; nt2 < 4; nt2++) {
            int row2 = nt2 * 16 + (g >> 1) * 8 + l8;
            ldsm4(bf[nt2], sb + AT_KHI + row2 * 64 + sw_chunk(row2, kk * 2 + (g & 1)) * 16);
        }
#pragma unroll
        for (int nt = 0; nt < 8; nt++)
            mma_f16(acc0[nt], af, &bf[nt >> 1][(nt & 1) * 2]);
    }
    // mask + decay + write sc0
    {
        int c_lo = wid * 16 + (lane >> 2);
#pragma unroll
        for (int nt = 0; nt < 8; nt++) {
            int mm = nt * 8 + (lane & 3) * 2;
#pragma unroll
            for (int half = 0; half < 2; half++) {
                int c = c_lo + half * 8;
                float v0 = acc0[nt][half*2+0], v1 = acc0[nt][half*2+1];
                int d0 = c - mm, d1 = c - mm - 1;
                float s0 = (d0 >= 0) ? v0 * ed[d0] : 0.f;
                float s1 = (d1 >= 0) ? v1 * ed[d1] : 0.f;
                int addr = c * 128 + (((mm >> 3) ^ (c & 7)) * 16) + ((mm * 2) & 15);
                *(uint32_t*)(sm + AT_SC0H + addr) =
                    pack_h2(__float2half_rn(s0), __float2half_rn(s1));
            }
        }
    }
    __syncthreads();

    // ---- P4: o_intra part A (K = 0..64, all rows) ----
    float oacc[4][4];
#pragma unroll
    for (int nt = 0; nt < 4; nt++)
#pragma unroll
        for (int e = 0; e < 4; e++) oacc[nt][e] = 0.f;
    {
        const int r0 = wid * 16;
#pragma unroll
        for (int kk = 0; kk < 4; kk++) {
            uint32_t af[4];
            int row = r0 + (lane & 15);
            int ch = (kk * 2 + (lane >> 4)) ^ (row & 7);
            ldsm4(af, sb + AT_SC0H + row * 128 + ch * 16);
            uint32_t bf[2][4];
#pragma unroll
            for (int nt2 = 0; nt2 < 2; nt2++) {
                int row2 = nt2 * 16 + (g >> 1) * 8 + l8;
                int ch2 = (kk * 2 + (g & 1)) ^ (row2 & 7);
                ldsm4(bf[nt2], sb + AT_VTHI + row2 * 256 + ch2 * 16);
            }
#pragma unroll
            for (int nt = 0; nt < 4; nt++)
                mma_f16(oacc[nt], af, &bf[nt >> 1][(nt & 1) * 2]);
        }
    }
    // rows 0..63 complete -> write o_intra (fp16) to A2
    if (wid < 4) {
        int c = wid * 16 + (lane >> 2);
#pragma unroll
        for (int nt = 0; nt < 4; nt++) {
            int e = nt * 8 + (lane & 3) * 2;
            size_t go = (tok0 + c) * CC + h*DD + e;
            *(uint32_t*)&oout[go] =
                pack_h2(__float2half_rn(oacc[nt][0]), __float2half_rn(oacc[nt][1]));
            *(uint32_t*)&oout[go + 8*CC] =
                pack_h2(__float2half_rn(oacc[nt][2]), __float2half_rn(oacc[nt][3]));
        }
    }

    // ---- P5: scores half1  S[64:128, 64:128]  (all 8 warps) ----
    float acc1[4][4];
#pragma unroll
    for (int nt = 0; nt < 4; nt++)
#pragma unroll
        for (int e = 0; e < 4; e++) acc1[nt][e] = 0.f;
    const int c0s = 64 + (wid & 3) * 16;
    const int mbs = 64 + (wid >> 2) * 32;
#pragma unroll
    for (int kk = 0; kk < 2; kk++) {
        uint32_t af[4];
        int row = c0s + (lane & 15);
        ldsm4(af, sb + AT_QHI + row * 64 + sw_chunk(row, kk * 2 + (lane >> 4)) * 16);
        uint32_t bf[2][4];
#pragma unroll
        for (int nt2 = 0; nt2 < 2; nt2++) {
            int row2 = mbs + nt2 * 16 + (g >> 1) * 8 + l8;
            ldsm4(bf[nt2], sb + AT_KHI + row2 * 64 + sw_chunk(row2, kk * 2 + (g & 1)) * 16);
        }
#pragma unroll
        for (int nt = 0; nt < 4; nt++)
            mma_f16(acc1[nt], af, &bf[nt >> 1][(nt & 1) * 2]);
    }
    __syncthreads();   // all Q/K fragment reads done; QHI becomes sc1

    {
        int c_lo = c0s + (lane >> 2);
#pragma unroll
        for (int nt = 0; nt < 4; nt++) {
            int mm = mbs + nt * 8 + (lane & 3) * 2;
#pragma unroll
            for (int half = 0; half < 2; half++) {
                int c = c_lo + half * 8;
                float v0 = acc1[nt][half*2+0], v1 = acc1[nt][half*2+1];
                int d0 = c - mm, d1 = c - mm - 1;
                float s0 = (d0 >= 0) ? v0 * ed[d0] : 0.f;
                float s1 = (d1 >= 0) ? v1 * ed[d1] : 0.f;
                int cr = c - 64, mr = mm - 64;
                int addr = cr * 128 + (((mr >> 3) ^ (cr & 7)) * 16) + ((mr * 2) & 15);
                *(uint32_t*)(sm + AT_SC1H + addr) =
                    pack_h2(__float2half_rn(s0), __float2half_rn(s1));
            }
        }
    }
    __syncthreads();

    // ---- P6: warps 4-7: o_intra part B; warps 0-3: C_n ----
    if (wid >= 4) {
        const int r0 = (wid - 4) * 16;
#pragma unroll
        for (int kk = 0; kk < 4; kk++) {
            uint32_t af[4];
            int row = r0 + (lane & 15);
            int ch = (kk * 2 + (lane >> 4)) ^ (row & 7);
            ldsm4(af, sb + AT_SC1H + row * 128 + ch * 16);
            uint32_t bf[2][4];
#pragma unroll
            for (int nt2 = 0; nt2 < 2; nt2++) {
                int row2 = nt2 * 16 + (g >> 1) * 8 + l8;
                int ch2 = ((kk + 4) * 2 + (g & 1)) ^ (row2 & 7);
                ldsm4(bf[nt2], sb + AT_VTHI + row2 * 256 + ch2 * 16);
            }
#pragma unroll
            for (int nt = 0; nt < 4; nt++)
                mma_f16(oacc[nt], af, &bf[nt >> 1][(nt & 1) * 2]);
        }
        int c = wid * 16 + (lane >> 2);
#pragma unroll
        for (int nt = 0; nt < 4; nt++) {
            int e = nt * 8 + (lane & 3) * 2;
            size_t go = (tok0 + c) * CC + h*DD + e;
            *(uint32_t*)&oout[go] =
                pack_h2(__float2half_rn(oacc[nt][0]), __float2half_rn(oacc[nt][1]));
            *(uint32_t*)&oout[go + 8*CC] =
                pack_h2(__float2half_rn(oacc[nt][2]), __float2half_rn(oacc[nt][3]));
        }
    } else {
        float cacc[2][4][4];
#pragma unroll
        for (int mt = 0; mt < 2; mt++)
#pragma unroll
            for (int nt = 0; nt < 4; nt++)
#pragma unroll
                for (int e = 0; e < 4; e++) cacc[mt][nt][e] = 0.f;

#pragma unroll
        for (int kl = 0; kl < 2; kl++) {
            int kk = wid * 2 + kl;
            uint32_t af[2][4];
#pragma unroll
            for (int mt = 0; mt < 2; mt++) {
                int row = mt * 16 + (lane & 15);
                int ch = (kk * 2 + (lane >> 4)) ^ (row & 7);
                ldsm4(af[mt], sb + AT_KTHI + row * 256 + ch * 16);
            }
            uint32_t bf[2][4];
#pragma unroll
            for (int nt2 = 0; nt2 < 2; nt2++) {
                int row2 = nt2 * 16 + (g >> 1) * 8 + l8;
                int ch2 = (kk * 2 + (g & 1)) ^ (row2 & 7);
                ldsm4(bf[nt2], sb + AT_VTHI + row2 * 256 + ch2 * 16);
            }
#pragma unroll
            for (int mt = 0; mt < 2; mt++)
#pragma unroll
                for (int nt = 0; nt < 4; nt++)
                    mma_f16(cacc[mt][nt], af[mt], &bf[nt >> 1][(nt & 1) * 2]);
        }
        float* red = (float*)(sm + AT_CRED) + wid * 1024;
#pragma unroll
        for (int mt = 0; mt < 2; mt++) {
            int d = mt * 16 + (lane >> 2);
#pragma unroll
            for (int nt = 0; nt < 4; nt++) {
                int e = nt * 8 + (lane & 3) * 2;
                *(float2*)&red[d * 32 + e]       = make_float2(cacc[mt][nt][0], cacc[mt][nt][1]);
                *(float2*)&red[(d + 8) * 32 + e] = make_float2(cacc[mt][nt][2], cacc[mt][nt][3]);
            }
        }
    }
    __syncthreads();
    {
        const float* red = (const float*)(sm + AT_CRED);
        const size_t cb = ((size_t)((b*HH + h)*NC + n)) * 1024;
        for (int i = tid; i < 1024; i += 256)
            g_C[cb + i] = red[i] + red[1024 + i] + red[2048 + i] + red[3072 + i];
    }
}

// ======================= KV scan: prefetch all stages to smem, then serial =======================
#define SCAN_SMEM (NC * 4096)   // 131072 bytes

__global__ void kv_scan_kernel()
{
    extern __shared__ __align__(16) float scs[];   // [NC][1024]
    const uint32_t sb = smem_u32(scs);
    const int bh = blockIdx.x;
    const int h = bh & 7;
    const int tid = threadIdx.x;
    const size_t cbase = (size_t)bh * NC * 1024;

    for (int i = tid; i < NC * 256; i += 256)
        cpasync16(sb + i * 16, &g_C[cbase + (size_t)i * 4]);
    cp_commit();
    cp_wait<0>();
    __syncthreads();

    const float bd = expf(-exp2f(-(float)(h+1)) * (float)CH);
    float4 kv = make_float4(0.f, 0.f, 0.f, 0.f);
    for (int n = 0; n < NC; n++) {
        *(float4*)&g_kvp[cbase + n*1024 + tid*4] = kv;
        float4 c = *(const float4*)&scs[n*1024 + tid*4];
        kv.x = bd*kv.x + c.x; kv.y = bd*kv.y + c.y;
        kv.z = bd*kv.z + c.z; kv.w = bd*kv.w + c.w;
    }
}

// ======================= HMMA inter-chunk (q hi) + fp16 RMW of o in A2 =======================
__global__ void __launch_bounds__(256) attn_inter_hmma(
    const __half* __restrict__ qh, __half* __restrict__ A2)
{
    const int n = blockIdx.x;
    const int h = blockIdx.y, b = blockIdx.z;

    __shared__ __align__(16) char sm[8192 + 2048 + 1024];
    const int QHI = 0, KVHI = 8192, EDO = 10240;
    float* ed = (float*)(sm + EDO);
    const uint32_t sb = smem_u32(sm);

    const int tid = threadIdx.x, lane = tid & 31, wid = tid >> 5;
    const float s = exp2f(-(float)(h+1));
    for (int i = tid; i < CH; i += 256) ed[i] = expf(-s * (float)i);

    const size_t tok0 = (size_t)(b*LL + n*CH);
    for (int i = tid; i < 512; i += 256) {
        int r = i >> 2, c = i & 3;
        uint4 v = *(const uint4*)(qh + (tok0 + r)*CC + h*DD + c*8);
        *(uint4*)(sm + QHI + r*64 + sw_chunk(r, c)*16) = v;
    }
    const size_t kb = ((size_t)((b*HH + h)*NC + n)) * 1024;
    for (int i = tid; i < 1024; i += 256) {
        int d = i >> 5, e = i & 31;
        float v = g_kvp[kb + i];
        __half hh = __float2half_rn(v);
        int a = e*64 + sw_chunk(e, d >> 3)*16 + (d & 7)*2;
        *(__half*)(sm + KVHI + a) = hh;
    }
    __syncthreads();

    float acc[4][4];
#pragma unroll
    for (int nt = 0; nt < 4; nt++)
#pragma unroll
        for (int e = 0; e < 4; e++) acc[nt][e] = 0.f;

    const int r0 = wid * 16;
#pragma unroll
    for (int kk = 0; kk < 2; kk++) {
        uint32_t af[4];
        int row = r0 + (lane & 15);
        int ch = sw_chunk(row, kk * 2 + (lane >> 4));
        ldsm4(af, sb + QHI + row * 64 + ch * 16);
        uint32_t bf[2][4];
#pragma unroll
        for (int nt2 = 0; nt2 < 2; nt2++) {
            int g = lane >> 3, l8 = lane & 7;
            int row2 = nt2 * 16 + (g >> 1) * 8 + l8;
            int ch2 = sw_chunk(row2, kk * 2 + (g & 1));
            ldsm4(bf[nt2], sb + KVHI + row2 * 64 + ch2 * 16);
        }
#pragma unroll
        for (int nt = 0; nt < 4; nt++)
            mma_f16(acc[nt], af, &bf[nt >> 1][(nt & 1) * 2]);
    }

    int c = r0 + (lane >> 2);
    float a0 = ed[c], a1 = ed[c + 8];
#pragma unroll
    for (int nt = 0; nt < 4; nt++) {
        int e = nt * 8 + (lane & 3) * 2;
#pragma unroll
        for (int half = 0; half < 2; half++) {
            int cc2 = c + half * 8;
            float al = half ? a1 : a0;
            size_t go = (tok0 + cc2) * CC + h*DD + e;
            uint32_t prev = *(uint32_t*)&A2[go];
            __half2 ph = *(__half2*)&prev;
            float ox = __half2float(__low2half(ph))  + al * acc[nt][half*2+0];
            float oy = __half2float(__high2half(ph)) + al * acc[nt][half*2+1];
            *(uint32_t*)&A2[go] =
                pack_h2(__float2half_rn(ox), __float2half_rn(oy));
        }
    }
}

// ======================= launch =======================
extern "C" void kernel_launch(void* const* d_in, const int* in_sizes, int n_in,
                              void* d_out, int out_size)
{
    const float* x    = (const float*)d_in[0];
    const float* rel  = (const float*)d_in[1];
    const float* qkvw = (const float*)d_in[2];
    const float* qg   = (const float*)d_in[3];
    const float* kg   = (const float*)d_in[4];
    const float* pw   = (const float*)d_in[5];
    const float* pb   = (const float*)d_in[6];
    float* out = (float*)d_out;

    void* p_qkv = nullptr; cudaGetSymbolAddress(&p_qkv, g_qkv);
    void* p_A2  = nullptr; cudaGetSymbolAddress(&p_A2,  g_A2);
    void* p_W1h = nullptr; cudaGetSymbolAddress(&p_W1h, g_W1h);
    void* p_W2h = nullptr; cudaGetSymbolAddress(&p_W2h, g_W2h);
    void* p_qh  = nullptr; cudaGetSymbolAddress(&p_qh,  g_qh);

    cudaFuncSetAttribute(attn_chunk_hmma,
                         cudaFuncAttributeMaxDynamicSharedMemorySize, AT_SMEM);
    cudaFuncSetAttribute((gemm_f16_hmma<false, true>),
                         cudaFuncAttributeMaxDynamicSharedMemorySize, GS_SMEM);
    cudaFuncSetAttribute((gemm_f16_hmma<true, false>),
                         cudaFuncAttributeMaxDynamicSharedMemorySize, GS_SMEM);
    cudaFuncSetAttribute(kv_scan_kernel,
                         cudaFuncAttributeMaxDynamicSharedMemorySize, SCAN_SMEM);

    // 1) one fused conversion launch: act -> A2, W1 -> W1h, W2 -> W2h
    conv_all_kernel<<<CONV_GRID, 256>>>(x, rel, qkvw, pw,
        (__half*)p_A2, (__half*)p_W1h, (__half*)p_W2h);

    // 2) qkv = A @ W1h^T  (pure fp16 HMMA, K=256) -> fp16 g_qkv
    gemm_f16_hmma<false, true><<<dim3(768/128, TT/128), 256, GS_SMEM>>>(
        (const __half*)p_A2, (const __half*)p_W1h, nullptr,
        p_qkv, 768);

    // 3) attention: intra (writes o fp16 into A2) + C_n, scan, inter (RMW A2)
    attn_chunk_hmma<<<dim3(NC, HH, BB), 256, AT_SMEM>>>(
        qg, kg, (__half*)p_qh, (__half*)p_A2);
    kv_scan_kernel<<<BB*HH, 256, SCAN_SMEM>>>();
    attn_inter_hmma<<<dim3(NC, HH, BB), 256>>>((const __half*)p_qh, (__half*)p_A2);

    // 4) out = O @ W2h^T + bias (fp32 out)
    gemm_f16_hmma<true, false><<<dim3(256/128, TT/128), 256, GS_SMEM>>>(
        (const __half*)p_A2, (const __half*)p_W2h, pb,
        out, 256);
}

// round 16
// speedup vs baseline: 4.9970x; 1.0015x over previous
#include <cuda_runtime.h>
#include <cuda_fp16.h>
#include <math.h>
#include <stdint.h>

// Problem constants
#define BB 8
#define LL 4096
#define CC 256
#define HH 8
#define DD 32
#define CH 128
#define NC 32          // LL / CH
#define TT (BB*LL)     // 32768 tokens

// ---------------- static device scratch (no allocations allowed) ----------------
__device__ __half g_qkv[(size_t)TT * 768];                // qkv per token (fp16)
__device__ float g_C  [(size_t)BB*HH*NC * DD*DD];         // per-chunk KV contributions
__device__ float g_kvp[(size_t)BB*HH*NC * DD*DD];         // exclusive KV prefixes
__device__ __half g_A2 [(size_t)TT * CC];                 // fp16 activations / attention out
__device__ __half g_W1h[(size_t)768 * 256];               // qkv weight (fp16)
__device__ __half g_W2h[(size_t)256 * 256];               // proj weight (fp16)
__device__ __half g_qh [(size_t)TT * CC];                 // normalized q hat (fp16)

// =========================== small PTX helpers ===========================
__device__ __forceinline__ uint32_t smem_u32(const void* p) {
    uint32_t a;
    asm("{ .reg .u64 t; cvta.to.shared.u64 t, %1; cvt.u32.u64 %0, t; }" : "=r"(a) : "l"(p));
    return a;
}
__device__ __forceinline__ void cpasync16(uint32_t dst, const void* src) {
    asm volatile("cp.async.cg.shared.global [%0], [%1], 16;" :: "r"(dst), "l"(src));
}
__device__ __forceinline__ void cp_commit() {
    asm volatile("cp.async.commit_group;" ::: "memory");
}
template<int N>
__device__ __forceinline__ void cp_wait() {
    asm volatile("cp.async.wait_group %0;" :: "n"(N) : "memory");
}
__device__ __forceinline__ void ldsm4(uint32_t* r, uint32_t addr) {
    asm volatile("ldmatrix.sync.aligned.m8n8.x4.shared.b16 {%0,%1,%2,%3}, [%4];"
                 : "=r"(r[0]), "=r"(r[1]), "=r"(r[2]), "=r"(r[3]) : "r"(addr));
}
__device__ __forceinline__ void mma_f16(float* c, const uint32_t* a, const uint32_t* b) {
    asm volatile("mma.sync.aligned.m16n8k16.row.col.f32.f16.f16.f32 "
                 "{%0,%1,%2,%3}, {%4,%5,%6,%7}, {%8,%9}, {%0,%1,%2,%3};"
                 : "+f"(c[0]), "+f"(c[1]), "+f"(c[2]), "+f"(c[3])
                 : "r"(a[0]), "r"(a[1]), "r"(a[2]), "r"(a[3]), "r"(b[0]), "r"(b[1]));
}
// xor swizzle of 16B chunk index within a 64B row (4 chunks)
__device__ __forceinline__ int sw_chunk(int r, int c) {
    return c ^ (r & 3) ^ ((r >> 2) & 1);
}
__device__ __forceinline__ uint32_t pack_h2(__half a, __half b) {
    uint32_t lo16 = *(uint16_t*)&a, hi16 = *(uint16_t*)&b;
    return lo16 | (hi16 << 16);
}

// =========================== fused fp16 conversion kernel ===========================
#define CONV_ACT_BLK (TT*64/256)      // 8192
#define CONV_W1_BLK  (768*64/256)     // 192
#define CONV_GRID    (CONV_ACT_BLK + CONV_W1_BLK + 256*64/256)

__global__ void conv_all_kernel(const float* __restrict__ x, const float* __restrict__ rp,
                                const float* __restrict__ W1, const float* __restrict__ W2,
                                __half* __restrict__ A2,
                                __half* __restrict__ W1h, __half* __restrict__ W2h)
{
    int blk = blockIdx.x;
    if (blk < CONV_ACT_BLK) {
        int idx = blk * 256 + threadIdx.x;
        int m = idx >> 6, c4 = (idx & 63) << 2;
        float4 h = *(const float4*)&x[(size_t)m * 256 + c4];
        float4 r = *(const float4*)&rp[(size_t)(m & (LL-1)) * 256 + c4];
        h.x += r.x; h.y += r.y; h.z += r.z; h.w += r.w;
        *(uint2*)&A2[(size_t)m * CC + c4] = make_uint2(
            pack_h2(__float2half_rn(h.x), __float2half_rn(h.y)),
            pack_h2(__float2half_rn(h.z), __float2half_rn(h.w)));
    } else {
        const float* W; __half* Wh; int idx;
        if (blk < CONV_ACT_BLK + CONV_W1_BLK) {
            W = W1; Wh = W1h; idx = (blk - CONV_ACT_BLK) * 256 + threadIdx.x;
        } else {
            W = W2; Wh = W2h; idx = (blk - CONV_ACT_BLK - CONV_W1_BLK) * 256 + threadIdx.x;
        }
        int n = idx >> 6, c4 = (idx & 63) << 2;
        float4 h = *(const float4*)&W[(size_t)n * 256 + c4];
        *(uint2*)&Wh[(size_t)n * 256 + c4] = make_uint2(
            pack_h2(__float2half_rn(h.x), __float2half_rn(h.y)),
            pack_h2(__float2half_rn(h.z), __float2half_rn(h.w)));
    }
}

// =========================== HMMA fp16 GEMM: C = A @ W^T (+bias) ===========================
// Pure fp16, K=256, BK=32 slabs (8 total). 3-stage cp.async ring (49 KB static), one sync per slab.
#define NSTG 8

template<bool BIAS, bool OUT16>
__global__ void __launch_bounds__(256, 2) gemm_f16_hmma(
    const __half* __restrict__ A,
    const __half* __restrict__ Bw,
    const float* __restrict__ bias,
    void* __restrict__ Cout, int Ntot)
{
    __shared__ __align__(16) __half As[3][128][32];
    __shared__ __align__(16) __half Bs[3][128][32];
    const uint32_t as_base = smem_u32(As);
    const uint32_t bs_base = smem_u32(Bs);

    const int tid = threadIdx.x;
    const int wid = tid >> 5, lane = tid & 31;
    const int warp_m = wid & 1, warp_n = wid >> 1;
    const int m0 = blockIdx.y * 128;
    const int n0 = blockIdx.x * 128;

    float acc[4][4][4];
#pragma unroll
    for (int mt = 0; mt < 4; mt++)
#pragma unroll
        for (int nt = 0; nt < 4; nt++)
#pragma unroll
            for (int e = 0; e < 4; e++) acc[mt][nt][e] = 0.f;

    const int lr = tid >> 2;
    const int lc = tid & 3;

    auto load_stage = [&](int s, int b) {
#pragma unroll
        for (int l = 0; l < 2; l++) {
            int r = lr + l * 64;
            int ch = sw_chunk(r, lc);
            cpasync16(as_base + (b * 128 + r) * 64 + ch * 16,
                      A  + (size_t)(m0 + r) * 256 + s * 32 + lc * 8);
            cpasync16(bs_base + (b * 128 + r) * 64 + ch * 16,
                      Bw + (size_t)(n0 + r) * 256 + s * 32 + lc * 8);
        }
        cp_commit();
    };

    load_stage(0, 0);
    load_stage(1, 1);

    int b = 0;
    for (int i = 0; i < NSTG; i++) {
        if (i + 1 < NSTG) cp_wait<1>(); else cp_wait<0>();
        __syncthreads();

#pragma unroll
        for (int kk = 0; kk < 2; kk++) {
            uint32_t af[4][4];
#pragma unroll
            for (int mt = 0; mt < 4; mt++) {
                int row = warp_m * 64 + mt * 16 + (lane & 15);
                int ch = sw_chunk(row, kk * 2 + (lane >> 4));
                ldsm4(af[mt], as_base + (b * 128 + row) * 64 + ch * 16);
            }
            uint32_t bf[2][4];
#pragma unroll
            for (int nt2 = 0; nt2 < 2; nt2++) {
                int g = lane >> 3, l8 = lane & 7;
                int row = warp_n * 32 + nt2 * 16 + (g >> 1) * 8 + l8;
                int ch = sw_chunk(row, kk * 2 + (g & 1));
                ldsm4(bf[nt2], bs_base + (b * 128 + row) * 64 + ch * 16);
            }
#pragma unroll
            for (int mt = 0; mt < 4; mt++)
#pragma unroll
                for (int nt = 0; nt < 4; nt++)
                    mma_f16(acc[mt][nt], af[mt], &bf[nt >> 1][(nt & 1) * 2]);
        }

        if (i + 2 < NSTG) {
            int b2 = b + 2; if (b2 >= 3) b2 -= 3;
            load_stage(i + 2, b2);
        }
        if (++b == 3) b = 0;
    }

#pragma unroll
    for (int mt = 0; mt < 4; mt++) {
        int row = m0 + warp_m * 64 + mt * 16 + (lane >> 2);
#pragma unroll
        for (int nt = 0; nt < 4; nt++) {
            int col = n0 + warp_n * 32 + nt * 8 + (lane & 3) * 2;
            float2 v0 = make_float2(acc[mt][nt][0], acc[mt][nt][1]);
            float2 v1 = make_float2(acc[mt][nt][2], acc[mt][nt][3]);
            if (BIAS) {
                float2 bv = *(const float2*)&bias[col];
                v0.x += bv.x; v0.y += bv.y;
                v1.x += bv.x; v1.y += bv.y;
            }
            if (OUT16) {
                __half* Ch = (__half*)Cout;
                *(uint32_t*)&Ch[(size_t)row * Ntot + col] =
                    pack_h2(__float2half_rn(v0.x), __float2half_rn(v0.y));
                *(uint32_t*)&Ch[(size_t)(row + 8) * Ntot + col] =
                    pack_h2(__float2half_rn(v1.x), __float2half_rn(v1.y));
            } else {
                float* Cf = (float*)Cout;
                *(float2*)&Cf[(size_t)row * Ntot + col]       = v0;
                *(float2*)&Cf[(size_t)(row + 8) * Ntot + col] = v1;
            }
        }
    }
}

// ======================= HMMA attention: intra + per-chunk KV contribution =======================
// smem layout (bytes); total 84 KB -> 2 CTAs/SM
#define AT_ED   0                     // 129 floats
#define AT_NQ   640
#define AT_NK   1152
#define AT_QHI  2048
#define AT_QLO  (AT_QHI  + 8192)      // unused (layout stability)
#define AT_KHI  (AT_QLO  + 8192)
#define AT_KTHI (AT_KHI  + 8192)
#define AT_KTLO (AT_KTHI + 8192)      // unused
#define AT_VTHI (AT_KTLO + 8192)
#define AT_SC0H (AT_VTHI + 8192)      // 128 rows x 128 B
#define AT_SC0L (AT_SC0H + 16384)     // scratch
#define AT_SMEM (AT_SC0L + 16384)     // 83968 bytes
// aliases (regions dead by the time they're reused)
#define AT_SC1H AT_QHI                // 64 rows x 128 B
#define AT_CRED AT_SC0H               // 16 KB: 4 warps x 4 KB (sc0 dead after P4)

__global__ void __launch_bounds__(256, 2) attn_chunk_hmma(
    const float* __restrict__ qg, const float* __restrict__ kg,
    __half* __restrict__ qhout, __half* __restrict__ oout)
{
    extern __shared__ char sm[];
    float* ed = (float*)(sm + AT_ED);
    float* nq = (float*)(sm + AT_NQ);
    float* nk = (float*)(sm + AT_NK);
    const uint32_t sb = smem_u32(sm);

    const int n = blockIdx.x, h = blockIdx.y, b = blockIdx.z;
    const int tid = threadIdx.x, lane = tid & 31, wid = tid >> 5;
    const float s = exp2f(-(float)(h + 1));
    for (int i = tid; i <= CH; i += 256) ed[i] = expf(-s * (float)i);

    const size_t tok0 = (size_t)(b*LL + n*CH);
    const size_t base = tok0 * 768 + h*DD;
    const int c4 = (tid & 7) * 4;

    // ---- P1: load q,k,v (fp16); keep q,k in registers across norm barrier ----
    float qsv[4][4], ksv[4][4];
    float sq[4], sk[4];
#pragma unroll
    for (int l = 0; l < 4; l++) {
        int r = (tid >> 3) + l * 32;
        const __half* rowp = &g_qkv[base + (size_t)r * 768 + c4];
        __half hq[4], hk[4], hv4[4];
        *(uint2*)hq  = *(const uint2*)(rowp);
        *(uint2*)hk  = *(const uint2*)(rowp + 256);
        *(uint2*)hv4 = *(const uint2*)(rowp + 512);
        float s1 = 0.f, s2 = 0.f;
#pragma unroll
        for (int j = 0; j < 4; j++) {
            float a = __half2float(hq[j]);
            float c = __half2float(hk[j]);
            qsv[l][j] = a; ksv[l][j] = c;
            s1 += a*a; s2 += c*c;
            int d = c4 + j;
            int aT = d*256 + (((r >> 3) ^ (d & 7)) * 16) + ((r & 7) * 2);
            *(__half*)(sm + AT_VTHI + aT) = hv4[j];
        }
        sq[l] = s1; sk[l] = s2;
    }
#pragma unroll
    for (int m = 1; m < 8; m <<= 1) {
#pragma unroll
        for (int l = 0; l < 4; l++) {
            sq[l] += __shfl_xor_sync(0xffffffffu, sq[l], m);
            sk[l] += __shfl_xor_sync(0xffffffffu, sk[l], m);
        }
    }
    if ((tid & 7) == 0) {
        const float sqD = 5.656854249492380f;
#pragma unroll
        for (int l = 0; l < 4; l++) {
            int r = (tid >> 3) + l * 32;
            nq[r] = (sq[l] > 1e-24f) ? sqD * rsqrtf(sq[l]) : sqD * 1e12f;
            nk[r] = (sk[l] > 1e-24f) ? sqD * rsqrtf(sk[l]) : sqD * 1e12f;
        }
    }
    __syncthreads();

    // ---- P2: normalize + convert from registers ----
    float gq[4], gk[4];
#pragma unroll
    for (int j = 0; j < 4; j++) {
        gq[j] = __ldg(&qg[h*DD + c4 + j]);
        gk[j] = __ldg(&kg[h*DD + c4 + j]);
    }
#pragma unroll
    for (int l = 0; l < 4; l++) {
        int r = (tid >> 3) + l * 32;
        float rq = nq[r], rk = nk[r], dk = ed[CH - r];
        __half qh4[4], kh4[4];
#pragma unroll
        for (int j = 0; j < 4; j++) {
            int d = c4 + j;
            float qn = qsv[l][j] * rq * gq[j];
            float kn = ksv[l][j] * rk * gk[j];
            qh4[j] = __float2half_rn(qn);
            kh4[j] = __float2half_rn(kn);
            __half kth = __float2half_rn(kn * dk);
            int aT = d*256 + (((r >> 3) ^ (d & 7)) * 16) + ((r & 7) * 2);
            *(__half*)(sm + AT_KTHI + aT) = kth;
        }
        int a64 = r*64 + sw_chunk(r, c4 >> 3) * 16 + ((c4 & 7) * 2);
        *(uint2*)(sm + AT_QHI + a64) = *(uint2*)qh4;
        *(uint2*)(sm + AT_KHI + a64) = *(uint2*)kh4;
        *(uint2*)(qhout + (tok0 + r)*CC + h*DD + c4) = *(uint2*)qh4;
    }
    __syncthreads();

    const int g = lane >> 3, l8 = lane & 7;

    // ---- P3: scores half0  S[:, 0:64]  (all 128 rows) ----
    float acc0[8][4];
#pragma unroll
    for (int nt = 0; nt < 8; nt++)
#pragma unroll
        for (int e = 0; e < 4; e++) acc0[nt][e] = 0.f;
#pragma unroll
    for (int kk = 0; kk < 2; kk++) {
        uint32_t af[4];
        int row = wid * 16 + (lane & 15);
        ldsm4(af, sb + AT_QHI + row * 64 + sw_chunk(row, kk * 2 + (lane >> 4)) * 16);
        uint32_t bf[4][4];
#pragma unroll
        for (int nt2 = 0; nt2 < 4; nt2++) {
            int row2 = nt2 * 16 + (g >> 1) * 8 + l8;
            ldsm4(bf[nt2], sb + AT_KHI + row2 * 64 + sw_chunk(row2, kk * 2 + (g & 1)) * 16);
        }
#pragma unroll
        for (int nt = 0; nt < 8; nt++)
            mma_f16(acc0[nt], af, &bf[nt >> 1][(nt & 1) * 2]);
    }
    // mask + decay + write sc0
    {
        int c_lo = wid * 16 + (lane >> 2);
#pragma unroll
        for (int nt = 0; nt < 8; nt++) {
            int mm = nt * 8 + (lane & 3) * 2;
#pragma unroll
            for (int half = 0; half < 2; half++) {
                int c = c_lo + half * 8;
                float v0 = acc0[nt][half*2+0], v1 = acc0[nt][half*2+1];
                int d0 = c - mm, d1 = c - mm - 1;
                float s0 = (d0 >= 0) ? v0 * ed[d0] : 0.f;
                float s1 = (d1 >= 0) ? v1 * ed[d1] : 0.f;
                int addr = c * 128 + (((mm >> 3) ^ (c & 7)) * 16) + ((mm * 2) & 15);
                *(uint32_t*)(sm + AT_SC0H + addr) =
                    pack_h2(__float2half_rn(s0), __float2half_rn(s1));
            }
        }
    }
    __syncthreads();

    // ---- P4: o_intra part A (K = 0..64, all rows) ----
    float oacc[4][4];
#pragma unroll
    for (int nt = 0; nt < 4; nt++)
#pragma unroll
        for (int e = 0; e < 4; e++) oacc[nt][e] = 0.f;
    {
        const int r0 = wid * 16;
#pragma unroll
        for (int kk = 0; kk < 4; kk++) {
            uint32_t af[4];
            int row = r0 + (lane & 15);
            int ch = (kk * 2 + (lane >> 4)) ^ (row & 7);
            ldsm4(af, sb + AT_SC0H + row * 128 + ch * 16);
            uint32_t bf[2][4];
#pragma unroll
            for (int nt2 = 0; nt2 < 2; nt2++) {
                int row2 = nt2 * 16 + (g >> 1) * 8 + l8;
                int ch2 = (kk * 2 + (g & 1)) ^ (row2 & 7);
                ldsm4(bf[nt2], sb + AT_VTHI + row2 * 256 + ch2 * 16);
            }
#pragma unroll
            for (int nt = 0; nt < 4; nt++)
                mma_f16(oacc[nt], af, &bf[nt >> 1][(nt & 1) * 2]);
        }
    }
    // rows 0..63 complete -> write o_intra (fp16) to A2
    if (wid < 4) {
        int c = wid * 16 + (lane >> 2);
#pragma unroll
        for (int nt = 0; nt < 4; nt++) {
            int e = nt * 8 + (lane & 3) * 2;
            size_t go = (tok0 + c) * CC + h*DD + e;
            *(uint32_t*)&oout[go] =
                pack_h2(__float2half_rn(oacc[nt][0]), __float2half_rn(oacc[nt][1]));
            *(uint32_t*)&oout[go + 8*CC] =
                pack_h2(__float2half_rn(oacc[nt][2]), __float2half_rn(oacc[nt][3]));
        }
    }

    // ---- P5: scores half1  S[64:128, 64:128]  (all 8 warps) ----
    float acc1[4][4];
#pragma unroll
    for (int nt = 0; nt < 4; nt++)
#pragma unroll
        for (int e = 0; e < 4; e++) acc1[nt][e] = 0.f;
    const int c0s = 64 + (wid & 3) * 16;
    const int mbs = 64 + (wid >> 2) * 32;
#pragma unroll
    for (int kk = 0; kk < 2; kk++) {
        uint32_t af[4];
        int row = c0s + (lane & 15);
        ldsm4(af, sb + AT_QHI + row * 64 + sw_chunk(row, kk * 2 + (lane >> 4)) * 16);
        uint32_t bf[2][4];
#pragma unroll
        for (int nt2 = 0; nt2 < 2; nt2++) {
            int row2 = mbs + nt2 * 16 + (g >> 1) * 8 + l8;
            ldsm4(bf[nt2], sb + AT_KHI + row2 * 64 + sw_chunk(row2, kk * 2 + (g & 1)) * 16);
        }
#pragma unroll
        for (int nt = 0; nt < 4; nt++)
            mma_f16(acc1[nt], af, &bf[nt >> 1][(nt & 1) * 2]);
    }
    __syncthreads();   // all Q/K fragment reads done; QHI becomes sc1

    {
        int c_lo = c0s + (lane >> 2);
#pragma unroll
        for (int nt = 0; nt < 4; nt++) {
            int mm = mbs + nt * 8 + (lane & 3) * 2;
#pragma unroll
            for (int half = 0; half < 2; half++) {
                int c = c_lo + half * 8;
                float v0 = acc1[nt][half*2+0], v1 = acc1[nt][half*2+1];
                int d0 = c - mm, d1 = c - mm - 1;
                float s0 = (d0 >= 0) ? v0 * ed[d0] : 0.f;
                float s1 = (d1 >= 0) ? v1 * ed[d1] : 0.f;
                int cr = c - 64, mr = mm - 64;
                int addr = cr * 128 + (((mr >> 3) ^ (cr & 7)) * 16) + ((mr * 2) & 15);
                *(uint32_t*)(sm + AT_SC1H + addr) =
                    pack_h2(__float2half_rn(s0), __float2half_rn(s1));
            }
        }
    }
    __syncthreads();

    // ---- P6: warps 4-7: o_intra part B; warps 0-3: C_n ----
    if (wid >= 4) {
        const int r0 = (wid - 4) * 16;
#pragma unroll
        for (int kk = 0; kk < 4; kk++) {
            uint32_t af[4];
            int row = r0 + (lane & 15);
            int ch = (kk * 2 + (lane >> 4)) ^ (row & 7);
            ldsm4(af, sb + AT_SC1H + row * 128 + ch * 16);
            uint32_t bf[2][4];
#pragma unroll
            for (int nt2 = 0; nt2 < 2; nt2++) {
                int row2 = nt2 * 16 + (g >> 1) * 8 + l8;
                int ch2 = ((kk + 4) * 2 + (g & 1)) ^ (row2 & 7);
                ldsm4(bf[nt2], sb + AT_VTHI + row2 * 256 + ch2 * 16);
            }
#pragma unroll
            for (int nt = 0; nt < 4; nt++)
                mma_f16(oacc[nt], af, &bf[nt >> 1][(nt & 1) * 2]);
        }
        int c = wid * 16 + (lane >> 2);
#pragma unroll
        for (int nt = 0; nt < 4; nt++) {
            int e = nt * 8 + (lane & 3) * 2;
            size_t go = (tok0 + c) * CC + h*DD + e;
            *(uint32_t*)&oout[go] =
                pack_h2(__float2half_rn(oacc[nt][0]), __float2half_rn(oacc[nt][1]));
            *(uint32_t*)&oout[go + 8*CC] =
                pack_h2(__float2half_rn(oacc[nt][2]), __float2half_rn(oacc[nt][3]));
        }
    } else {
        float cacc[2][4][4];
#pragma unroll
        for (int mt = 0; mt < 2; mt++)
#pragma unroll
            for (int nt = 0; nt < 4; nt++)
#pragma unroll
                for (int e = 0; e < 4; e++) cacc[mt][nt][e] = 0.f;

#pragma unroll
        for (int kl = 0; kl < 2; kl++) {
            int kk = wid * 2 + kl;
            uint32_t af[2][4];
#pragma unroll
            for (int mt = 0; mt < 2; mt++) {
                int row = mt * 16 + (lane & 15);
                int ch = (kk * 2 + (lane >> 4)) ^ (row & 7);
                ldsm4(af[mt], sb + AT_KTHI + row * 256 + ch * 16);
            }
            uint32_t bf[2][4];
#pragma unroll
            for (int nt2 = 0; nt2 < 2; nt2++) {
                int row2 = nt2 * 16 + (g >> 1) * 8 + l8;
                int ch2 = (kk * 2 + (g & 1)) ^ (row2 & 7);
                ldsm4(bf[nt2], sb + AT_VTHI + row2 * 256 + ch2 * 16);
            }
#pragma unroll
            for (int mt = 0; mt < 2; mt++)
#pragma unroll
                for (int nt = 0; nt < 4; nt++)
                    mma_f16(cacc[mt][nt], af[mt], &bf[nt >> 1][(nt & 1) * 2]);
        }
        float* red = (float*)(sm + AT_CRED) + wid * 1024;
#pragma unroll
        for (int mt = 0; mt < 2; mt++) {
            int d = mt * 16 + (lane >> 2);
#pragma unroll
            for (int nt = 0; nt < 4; nt++) {
                int e = nt * 8 + (lane & 3) * 2;
                *(float2*)&red[d * 32 + e]       = make_float2(cacc[mt][nt][0], cacc[mt][nt][1]);
                *(float2*)&red[(d + 8) * 32 + e] = make_float2(cacc[mt][nt][2], cacc[mt][nt][3]);
            }
        }
    }
    __syncthreads();
    {
        const float* red = (const float*)(sm + AT_CRED);
        const size_t cb = ((size_t)((b*HH + h)*NC + n)) * 1024;
        for (int i = tid; i < 1024; i += 256)
            g_C[cb + i] = red[i] + red[1024 + i] + red[2048 + i] + red[3072 + i];
    }
}

// ======================= KV scan: 256 blocks, one scalar scan per thread =======================
// block = (bh, quarter); each thread scans one of 256 elements over 32 chunks.
#define SCAN_SMEM (NC * 1024)   // 32768 bytes

__global__ void kv_scan_kernel()
{
    extern __shared__ __align__(16) float scs[];   // [NC][256]
    const uint32_t sb = smem_u32(scs);
    const int bh = blockIdx.x >> 2;
    const int qd = blockIdx.x & 3;        // quarter
    const int h = bh & 7;
    const int tid = threadIdx.x;
    const size_t cbase = (size_t)bh * NC * 1024 + qd * 256;

    // prefetch 32 x 256 floats (32 KB): i indexes 16B chunks
    for (int i = tid; i < NC * 64; i += 256) {
        int n = i >> 6, c16 = i & 63;
        cpasync16(sb + i * 16, &g_C[cbase + (size_t)n * 1024 + c16 * 4]);
    }
    cp_commit();
    cp_wait<0>();
    __syncthreads();

    const float bd = expf(-exp2f(-(float)(h+1)) * (float)CH);
    float kv = 0.f;
    for (int n = 0; n < NC; n++) {
        g_kvp[cbase + (size_t)n * 1024 + tid] = kv;
        kv = bd * kv + scs[n * 256 + tid];
    }
}

// ======================= HMMA inter-chunk (q hi) + fp16 RMW of o in A2 =======================
__global__ void __launch_bounds__(256) attn_inter_hmma(
    const __half* __restrict__ qh, __half* __restrict__ A2)
{
    const int n = blockIdx.x + 1;        // chunk 0 has zero prefix -> skipped
    const int h = blockIdx.y, b = blockIdx.z;

    __shared__ __align__(16) char sm[8192 + 2048 + 1024];
    const int QHI = 0, KVHI = 8192, EDO = 10240;
    float* ed = (float*)(sm + EDO);
    const uint32_t sb = smem_u32(sm);

    const int tid = threadIdx.x, lane = tid & 31, wid = tid >> 5;
    const float s = exp2f(-(float)(h+1));
    for (int i = tid; i < CH; i += 256) ed[i] = expf(-s * (float)i);

    const size_t tok0 = (size_t)(b*LL + n*CH);
    for (int i = tid; i < 512; i += 256) {
        int r = i >> 2, c = i & 3;
        uint4 v = *(const uint4*)(qh + (tok0 + r)*CC + h*DD + c*8);
        *(uint4*)(sm + QHI + r*64 + sw_chunk(r, c)*16) = v;
    }
    const size_t kb = ((size_t)((b*HH + h)*NC + n)) * 1024;
    for (int i = tid; i < 1024; i += 256) {
        int d = i >> 5, e = i & 31;
        float v = g_kvp[kb + i];
        __half hh = __float2half_rn(v);
        int a = e*64 + sw_chunk(e, d >> 3)*16 + (d & 7)*2;
        *(__half*)(sm + KVHI + a) = hh;
    }
    __syncthreads();

    float acc[4][4];
#pragma unroll
    for (int nt = 0; nt < 4; nt++)
#pragma unroll
        for (int e = 0; e < 4; e++) acc[nt][e] = 0.f;

    const int r0 = wid * 16;
#pragma unroll
    for (int kk = 0; kk < 2; kk++) {
        uint32_t af[4];
        int row = r0 + (lane & 15);
        int ch = sw_chunk(row, kk * 2 + (lane >> 4));
        ldsm4(af, sb + QHI + row * 64 + ch * 16);
        uint32_t bf[2][4];
#pragma unroll
        for (int nt2 = 0; nt2 < 2; nt2++) {
            int g = lane >> 3, l8 = lane & 7;
            int row2 = nt2 * 16 + (g >> 1) * 8 + l8;
            int ch2 = sw_chunk(row2, kk * 2 + (g & 1));
            ldsm4(bf[nt2], sb + KVHI + row2 * 64 + ch2 * 16);
        }
#pragma unroll
        for (int nt = 0; nt < 4; nt++)
            mma_f16(acc[nt], af, &bf[nt >> 1][(nt & 1) * 2]);
    }

    int c = r0 + (lane >> 2);
    float a0 = ed[c], a1 = ed[c + 8];
#pragma unroll
    for (int nt = 0; nt < 4; nt++) {
        int e = nt * 8 + (lane & 3) * 2;
#pragma unroll
        for (int half = 0; half < 2; half++) {
            int cc2 = c + half * 8;
            float al = half ? a1 : a0;
            size_t go = (tok0 + cc2) * CC + h*DD + e;
            uint32_t prev = *(uint32_t*)&A2[go];
            __half2 ph = *(__half2*)&prev;
            float ox = __half2float(__low2half(ph))  + al * acc[nt][half*2+0];
            float oy = __half2float(__high2half(ph)) + al * acc[nt][half*2+1];
            *(uint32_t*)&A2[go] =
                pack_h2(__float2half_rn(ox), __float2half_rn(oy));
        }
    }
}

// ======================= launch =======================
extern "C" void kernel_launch(void* const* d_in, const int* in_sizes, int n_in,
                              void* d_out, int out_size)
{
    const float* x    = (const float*)d_in[0];
    const float* rel  = (const float*)d_in[1];
    const float* qkvw = (const float*)d_in[2];
    const float* qg   = (const float*)d_in[3];
    const float* kg   = (const float*)d_in[4];
    const float* pw   = (const float*)d_in[5];
    const float* pb   = (const float*)d_in[6];
    float* out = (float*)d_out;

    void* p_qkv = nullptr; cudaGetSymbolAddress(&p_qkv, g_qkv);
    void* p_A2  = nullptr; cudaGetSymbolAddress(&p_A2,  g_A2);
    void* p_W1h = nullptr; cudaGetSymbolAddress(&p_W1h, g_W1h);
    void* p_W2h = nullptr; cudaGetSymbolAddress(&p_W2h, g_W2h);
    void* p_qh  = nullptr; cudaGetSymbolAddress(&p_qh,  g_qh);

    cudaFuncSetAttribute(attn_chunk_hmma,
                         cudaFuncAttributeMaxDynamicSharedMemorySize, AT_SMEM);
    cudaFuncSetAttribute(kv_scan_kernel,
                         cudaFuncAttributeMaxDynamicSharedMemorySize, SCAN_SMEM);

    // 1) one fused conversion launch: act -> A2, W1 -> W1h, W2 -> W2h
    conv_all_kernel<<<CONV_GRID, 256>>>(x, rel, qkvw, pw,
        (__half*)p_A2, (__half*)p_W1h, (__half*)p_W2h);

    // 2) qkv = A @ W1h^T  (pure fp16 HMMA, K=256, BK=32) -> fp16 g_qkv
    gemm_f16_hmma<false, true><<<dim3(768/128, TT/128), 256>>>(
        (const __half*)p_A2, (const __half*)p_W1h, nullptr,
        p_qkv, 768);

    // 3) attention: intra (writes o fp16 into A2) + C_n, scan, inter (RMW A2)
    attn_chunk_hmma<<<dim3(NC, HH, BB), 256, AT_SMEM>>>(
        qg, kg, (__half*)p_qh, (__half*)p_A2);
    kv_scan_kernel<<<BB*HH*4, 256, SCAN_SMEM>>>();
    attn_inter_hmma<<<dim3(NC-1, HH, BB), 256>>>((const __half*)p_qh, (__half*)p_A2);

    // 4) out = O @ W2h^T + bias (fp32 out)
    gemm_f16_hmma<true, false><<<dim3(256/128, TT/128), 256>>>(
        (const __half*)p_A2, (const __half*)p_W2h, pb,
        out, 256);
}